// round 3
// baseline (speedup 1.0000x reference)
#include <cuda_runtime.h>
#include <cstdint>
#include <cstddef>

// ---------------- problem constants ----------------
#define Hh_ 384
#define Ww_ 384
#define C_ 200
#define N_ 147456           // Hh_*Ww_
#define E_ 1179648
#define HIDE_ 128
#define OUT_ 64
#define NCLS_ 16
#define EPS_ 1e-5f
#define SLOPE_ 0.01f
#define NBLK_ 576           // N_/256

// ---------------- scratch (device globals; no allocation allowed) ----------------
__device__ float g_P[(size_t)N_ * 128];
__device__ float g_Q[(size_t)N_ * 128];
__device__ float g_Hm[(size_t)N_ * 128];
__device__ float g_cnn[(size_t)N_ * 64];
__device__ float g_cnnres[(size_t)N_ * 64];
__device__ float g_dinv[N_];
__device__ float g_invn[N_];
__device__ float g_sum[6 * 256];
__device__ float g_sq[6 * 256];
__device__ float g_wf[C_ * 128];
__device__ float g_bf[128];
// CSR
__device__ int g_degi[N_];
__device__ int g_rowptr[N_ + 1];
__device__ int g_cursor[N_];
__device__ int g_blksum[NBLK_];
__device__ int g_col[E_];

// ---------------- init: zero all stat slots + degree array ----------------
__global__ void k_init() {
    int i = blockIdx.x * 256 + threadIdx.x;
    if (i < N_) g_degi[i] = 0;
    if (i < 6 * 256) { g_sum[i] = 0.f; g_sq[i] = 0.f; }
}

// plain column stats: blockDim == C, lanes coalesced across columns
template <int C>
__global__ void k_colstats(const float* __restrict__ X, int slot) {
    const int c = threadIdx.x;
    const int rpb = N_ / 128;
    const int r0 = blockIdx.x * rpb;
    float s = 0.f, q = 0.f;
    for (int r = r0; r < r0 + rpb; ++r) {
        float v = X[(size_t)r * C + c];
        s += v; q += v * v;
    }
    atomicAdd(&g_sum[slot * 256 + c], s);
    atomicAdd(&g_sq[slot * 256 + c], q);
}

// rownorm stats: computes invnorm per row (after optional leaky) and
// column stats of the normalized rows. Does NOT write normalized data.
template <bool LK>
__global__ void k_rownorm_stats(const float* __restrict__ X, int slot) {
    __shared__ float sp[8][128];
    __shared__ float sq[8][128];
    const int tid = threadIdx.x;
    const int wid = tid >> 5, lane = tid & 31;
    const int gw = blockIdx.x * 8 + wid;
    float4 s4 = {0.f, 0.f, 0.f, 0.f}, q4 = {0.f, 0.f, 0.f, 0.f};
    for (int r = gw; r < N_; r += 288 * 8) {
        float4 v = *(const float4*)&X[(size_t)r * 128 + lane * 4];
        if (LK) {
            v.x = v.x > 0.f ? v.x : SLOPE_ * v.x;
            v.y = v.y > 0.f ? v.y : SLOPE_ * v.y;
            v.z = v.z > 0.f ? v.z : SLOPE_ * v.z;
            v.w = v.w > 0.f ? v.w : SLOPE_ * v.w;
        }
        float ss = v.x * v.x + v.y * v.y + v.z * v.z + v.w * v.w;
#pragma unroll
        for (int o = 16; o > 0; o >>= 1) ss += __shfl_xor_sync(0xffffffffu, ss, o);
        float inv = 1.0f / fmaxf(sqrtf(ss), 1e-12f);
        if (lane == 0) g_invn[r] = inv;
        v.x *= inv; v.y *= inv; v.z *= inv; v.w *= inv;
        s4.x += v.x; s4.y += v.y; s4.z += v.z; s4.w += v.w;
        q4.x += v.x * v.x; q4.y += v.y * v.y; q4.z += v.z * v.z; q4.w += v.w * v.w;
    }
    sp[wid][lane * 4 + 0] = s4.x; sp[wid][lane * 4 + 1] = s4.y;
    sp[wid][lane * 4 + 2] = s4.z; sp[wid][lane * 4 + 3] = s4.w;
    sq[wid][lane * 4 + 0] = q4.x; sq[wid][lane * 4 + 1] = q4.y;
    sq[wid][lane * 4 + 2] = q4.z; sq[wid][lane * 4 + 3] = q4.w;
    __syncthreads();
    if (tid < 128) {
        float a = 0.f, b = 0.f;
#pragma unroll
        for (int w = 0; w < 8; ++w) { a += sp[w][tid]; b += sq[w][tid]; }
        atomicAdd(&g_sum[slot * 256 + tid], a);
        atomicAdd(&g_sq[slot * 256 + tid], b);
    }
}

// merged fold: blocks [0, K*M/256) fold weights, last block folds bias
template <int K, int M>
__global__ void k_fold(const float* __restrict__ W, const float* __restrict__ bng,
                       const float* __restrict__ bnb, const float* __restrict__ bias,
                       int slot) {
    const float* su = &g_sum[slot * 256];
    const float* qu = &g_sq[slot * 256];
    if (blockIdx.x == (K * M) / 256) {
        int m = threadIdx.x;
        if (m < M) {
            float acc = bias ? bias[m] : 0.0f;
            for (int c = 0; c < K; ++c) {
                float mean = su[c] * (1.0f / N_);
                float var  = qu[c] * (1.0f / N_) - mean * mean;
                float scale = bng[c] * rsqrtf(var + EPS_);
                float shift = bnb[c] - mean * scale;
                acc += shift * W[c * M + m];
            }
            g_bf[m] = acc;
        }
        return;
    }
    int i = blockIdx.x * 256 + threadIdx.x;
    int c = i / M;
    float mean = su[c] * (1.0f / N_);
    float var  = qu[c] * (1.0f / N_) - mean * mean;
    float scale = bng[c] * rsqrtf(var + EPS_);
    g_wf[i] = scale * W[i];
}

// ---------------- GEMM: Y = epi( lk?(X) @ g_wf + g_bf ) ----------------
// thread tile: TR rows x 8 cols; TCOLS = M/8; BM = (256/TCOLS)*TR.
// EPI 0: out = leaky(acc)            (acc init = bf)
// EPI 1: out = (acc*invn[r] + bf) * dinv[r]   (acc init = 0)
template <int K, int M, int BM, int TR, int EPI, bool LKIN>
__global__ __launch_bounds__(256)
void k_gemm(const float* __restrict__ X, float* __restrict__ Y) {
    extern __shared__ float sm[];
    float* Ws = sm;                 // K*M
    float* Xs = sm + K * M;         // BM*(K+4)
    const int tid = threadIdx.x;
    const size_t row0 = (size_t)blockIdx.x * BM;

    for (int i = tid; i < K * M; i += 256) Ws[i] = g_wf[i];
    for (int q = tid; q < BM * (K / 4); q += 256) {
        int r = q / (K / 4), kq = q - r * (K / 4);
        float4 t = *(const float4*)&X[(row0 + r) * K + kq * 4];
        if (LKIN) {
            t.x = t.x > 0.f ? t.x : SLOPE_ * t.x;
            t.y = t.y > 0.f ? t.y : SLOPE_ * t.y;
            t.z = t.z > 0.f ? t.z : SLOPE_ * t.z;
            t.w = t.w > 0.f ? t.w : SLOPE_ * t.w;
        }
        *(float4*)&Xs[r * (K + 4) + kq * 4] = t;
    }
    __syncthreads();

    constexpr int TCOLS = M / 8;
    const int tc = tid % TCOLS, tr = tid / TCOLS;
    const int c0 = tc * 8, r0 = tr * TR;

    unsigned long long acc[TR][4];
    if (EPI == 0) {
        unsigned long long binit[4];
#pragma unroll
        for (int j = 0; j < 4; ++j) {
            unsigned lo = __float_as_uint(g_bf[c0 + 2 * j]);
            unsigned hi = __float_as_uint(g_bf[c0 + 2 * j + 1]);
            asm("mov.b64 %0, {%1,%2};" : "=l"(binit[j]) : "r"(lo), "r"(hi));
        }
#pragma unroll
        for (int i = 0; i < TR; ++i)
#pragma unroll
            for (int j = 0; j < 4; ++j) acc[i][j] = binit[j];
    } else {
#pragma unroll
        for (int i = 0; i < TR; ++i)
#pragma unroll
            for (int j = 0; j < 4; ++j) acc[i][j] = 0ull;
    }

    for (int kk = 0; kk < K; kk += 4) {
        float xv[TR][4];
#pragma unroll
        for (int i = 0; i < TR; ++i) {
            float4 t = *(const float4*)&Xs[(r0 + i) * (K + 4) + kk];
            xv[i][0] = t.x; xv[i][1] = t.y; xv[i][2] = t.z; xv[i][3] = t.w;
        }
#pragma unroll
        for (int q = 0; q < 4; ++q) {
            const int k = kk + q;
            const ulonglong2 wA = *(const ulonglong2*)&Ws[k * M + c0];
            const ulonglong2 wB = *(const ulonglong2*)&Ws[k * M + c0 + 4];
#pragma unroll
            for (int i = 0; i < TR; ++i) {
                unsigned xu = __float_as_uint(xv[i][q]);
                unsigned long long xp;
                asm("mov.b64 %0, {%1,%1};" : "=l"(xp) : "r"(xu));
                asm("fma.rn.f32x2 %0, %1, %2, %0;" : "+l"(acc[i][0]) : "l"(xp), "l"(wA.x));
                asm("fma.rn.f32x2 %0, %1, %2, %0;" : "+l"(acc[i][1]) : "l"(xp), "l"(wA.y));
                asm("fma.rn.f32x2 %0, %1, %2, %0;" : "+l"(acc[i][2]) : "l"(xp), "l"(wB.x));
                asm("fma.rn.f32x2 %0, %1, %2, %0;" : "+l"(acc[i][3]) : "l"(xp), "l"(wB.y));
            }
        }
    }

    float bfv[8];
    if (EPI == 1) {
#pragma unroll
        for (int j = 0; j < 8; ++j) bfv[j] = g_bf[c0 + j];
    }

#pragma unroll
    for (int i = 0; i < TR; ++i) {
        float outv[8];
#pragma unroll
        for (int j = 0; j < 4; ++j) {
            unsigned lo, hi;
            asm("mov.b64 {%0,%1}, %2;" : "=r"(lo), "=r"(hi) : "l"(acc[i][j]));
            outv[2 * j]     = __uint_as_float(lo);
            outv[2 * j + 1] = __uint_as_float(hi);
        }
        if (EPI == 0) {
#pragma unroll
            for (int j = 0; j < 8; ++j) outv[j] = outv[j] > 0.f ? outv[j] : SLOPE_ * outv[j];
        } else {
            float sr = g_invn[row0 + r0 + i];
            float dv = g_dinv[row0 + r0 + i];
#pragma unroll
            for (int j = 0; j < 8; ++j) outv[j] = (outv[j] * sr + bfv[j]) * dv;
        }
        float* yp = &Y[(row0 + r0 + i) * M + c0];
        *(float4*)(yp)     = *(float4*)&outv[0];
        *(float4*)(yp + 4) = *(float4*)&outv[4];
    }
}

// ---------------- CSR build ----------------
__global__ void k_deg_count(const int* __restrict__ dst) {
    int e = blockIdx.x * blockDim.x + threadIdx.x;
    if (e < E_) atomicAdd(&g_degi[dst[e]], 1);
}
__global__ void k_scan1() {
    __shared__ int s[256];
    int t = threadIdx.x;
    int idx = blockIdx.x * 256 + t;
    int v = g_degi[idx];
    s[t] = v;
    __syncthreads();
#pragma unroll
    for (int off = 1; off < 256; off <<= 1) {
        int a = 0;
        if (t >= off) a = s[t - off];
        __syncthreads();
        s[t] += a;
        __syncthreads();
    }
    g_rowptr[idx] = s[t] - v;
    if (t == 255) g_blksum[blockIdx.x] = s[255];
}
__global__ void k_scan2() {
    __shared__ int s[NBLK_];
    int t = threadIdx.x;
    if (t < NBLK_) s[t] = g_blksum[t];
    __syncthreads();
    for (int off = 1; off < NBLK_; off <<= 1) {
        int a = 0;
        if (t >= off && t < NBLK_) a = s[t - off];
        __syncthreads();
        if (t < NBLK_) s[t] += a;
        __syncthreads();
    }
    if (t < NBLK_) g_blksum[t] = s[t];
}
__global__ void k_scan3() {
    int idx = blockIdx.x * 256 + threadIdx.x;
    int off = blockIdx.x == 0 ? 0 : g_blksum[blockIdx.x - 1];
    int rp = g_rowptr[idx] + off;
    g_rowptr[idx] = rp;
    g_cursor[idx] = rp;
    g_dinv[idx] = rsqrtf((float)g_degi[idx] + 1.0f);
    if (idx == 0) g_rowptr[N_] = E_;
}
__global__ void k_csr_fill(const int* __restrict__ src, const int* __restrict__ dst) {
    int e = blockIdx.x * blockDim.x + threadIdx.x;
    if (e < E_) {
        int pos = atomicAdd(&g_cursor[dst[e]], 1);
        g_col[pos] = src[e];
    }
}

// ---------------- GCN gather ----------------
__global__ void k_gather128(const float* __restrict__ Hs, const float* __restrict__ gb,
                            float* __restrict__ out) {
    int i = (int)(((size_t)blockIdx.x * blockDim.x + threadIdx.x) >> 5);
    if (i >= N_) return;
    int lane = threadIdx.x & 31;
    int beg = __ldg(&g_rowptr[i]), end = __ldg(&g_rowptr[i + 1]);
    float4 acc = *(const float4*)&Hs[(size_t)i * 128 + lane * 4];
    for (int base = beg; base < end; base += 32) {
        int e = base + lane;
        int sidx = (e < end) ? g_col[e] : 0;
        int cnt = min(32, end - base);
        int j = 0;
        for (; j + 8 <= cnt; j += 8) {
            int s0 = __shfl_sync(0xffffffffu, sidx, j);
            int s1 = __shfl_sync(0xffffffffu, sidx, j + 1);
            int s2 = __shfl_sync(0xffffffffu, sidx, j + 2);
            int s3 = __shfl_sync(0xffffffffu, sidx, j + 3);
            int s4 = __shfl_sync(0xffffffffu, sidx, j + 4);
            int s5 = __shfl_sync(0xffffffffu, sidx, j + 5);
            int s6 = __shfl_sync(0xffffffffu, sidx, j + 6);
            int s7 = __shfl_sync(0xffffffffu, sidx, j + 7);
            float4 v0 = *(const float4*)&Hs[(size_t)s0 * 128 + lane * 4];
            float4 v1 = *(const float4*)&Hs[(size_t)s1 * 128 + lane * 4];
            float4 v2 = *(const float4*)&Hs[(size_t)s2 * 128 + lane * 4];
            float4 v3 = *(const float4*)&Hs[(size_t)s3 * 128 + lane * 4];
            float4 v4 = *(const float4*)&Hs[(size_t)s4 * 128 + lane * 4];
            float4 v5 = *(const float4*)&Hs[(size_t)s5 * 128 + lane * 4];
            float4 v6 = *(const float4*)&Hs[(size_t)s6 * 128 + lane * 4];
            float4 v7 = *(const float4*)&Hs[(size_t)s7 * 128 + lane * 4];
            acc.x += (v0.x + v1.x) + (v2.x + v3.x) + ((v4.x + v5.x) + (v6.x + v7.x));
            acc.y += (v0.y + v1.y) + (v2.y + v3.y) + ((v4.y + v5.y) + (v6.y + v7.y));
            acc.z += (v0.z + v1.z) + (v2.z + v3.z) + ((v4.z + v5.z) + (v6.z + v7.z));
            acc.w += (v0.w + v1.w) + (v2.w + v3.w) + ((v4.w + v5.w) + (v6.w + v7.w));
        }
        for (; j + 4 <= cnt; j += 4) {
            int s0 = __shfl_sync(0xffffffffu, sidx, j);
            int s1 = __shfl_sync(0xffffffffu, sidx, j + 1);
            int s2 = __shfl_sync(0xffffffffu, sidx, j + 2);
            int s3 = __shfl_sync(0xffffffffu, sidx, j + 3);
            float4 v0 = *(const float4*)&Hs[(size_t)s0 * 128 + lane * 4];
            float4 v1 = *(const float4*)&Hs[(size_t)s1 * 128 + lane * 4];
            float4 v2 = *(const float4*)&Hs[(size_t)s2 * 128 + lane * 4];
            float4 v3 = *(const float4*)&Hs[(size_t)s3 * 128 + lane * 4];
            acc.x += v0.x + v1.x + v2.x + v3.x;
            acc.y += v0.y + v1.y + v2.y + v3.y;
            acc.z += v0.z + v1.z + v2.z + v3.z;
            acc.w += v0.w + v1.w + v2.w + v3.w;
        }
        for (; j < cnt; ++j) {
            int s = __shfl_sync(0xffffffffu, sidx, j);
            float4 v = *(const float4*)&Hs[(size_t)s * 128 + lane * 4];
            acc.x += v.x; acc.y += v.y; acc.z += v.z; acc.w += v.w;
        }
    }
    float di = g_dinv[i];
    float4 b = *(const float4*)&gb[lane * 4];
    acc.x = b.x + di * acc.x;
    acc.y = b.y + di * acc.y;
    acc.z = b.z + di * acc.z;
    acc.w = b.w + di * acc.w;
    *(float4*)&out[(size_t)i * 128 + lane * 4] = acc;
}

__global__ void k_gather64(const float* __restrict__ Hs, const float* __restrict__ gb,
                           float* __restrict__ out) {
    int i = (int)(((size_t)blockIdx.x * blockDim.x + threadIdx.x) >> 5);
    if (i >= N_) return;
    int lane = threadIdx.x & 31;
    int beg = __ldg(&g_rowptr[i]), end = __ldg(&g_rowptr[i + 1]);
    float2 acc = *(const float2*)&Hs[(size_t)i * 64 + lane * 2];
    for (int base = beg; base < end; base += 32) {
        int e = base + lane;
        int sidx = (e < end) ? g_col[e] : 0;
        int cnt = min(32, end - base);
        int j = 0;
        for (; j + 8 <= cnt; j += 8) {
            int s0 = __shfl_sync(0xffffffffu, sidx, j);
            int s1 = __shfl_sync(0xffffffffu, sidx, j + 1);
            int s2 = __shfl_sync(0xffffffffu, sidx, j + 2);
            int s3 = __shfl_sync(0xffffffffu, sidx, j + 3);
            int s4 = __shfl_sync(0xffffffffu, sidx, j + 4);
            int s5 = __shfl_sync(0xffffffffu, sidx, j + 5);
            int s6 = __shfl_sync(0xffffffffu, sidx, j + 6);
            int s7 = __shfl_sync(0xffffffffu, sidx, j + 7);
            float2 v0 = *(const float2*)&Hs[(size_t)s0 * 64 + lane * 2];
            float2 v1 = *(const float2*)&Hs[(size_t)s1 * 64 + lane * 2];
            float2 v2 = *(const float2*)&Hs[(size_t)s2 * 64 + lane * 2];
            float2 v3 = *(const float2*)&Hs[(size_t)s3 * 64 + lane * 2];
            float2 v4 = *(const float2*)&Hs[(size_t)s4 * 64 + lane * 2];
            float2 v5 = *(const float2*)&Hs[(size_t)s5 * 64 + lane * 2];
            float2 v6 = *(const float2*)&Hs[(size_t)s6 * 64 + lane * 2];
            float2 v7 = *(const float2*)&Hs[(size_t)s7 * 64 + lane * 2];
            acc.x += (v0.x + v1.x) + (v2.x + v3.x) + ((v4.x + v5.x) + (v6.x + v7.x));
            acc.y += (v0.y + v1.y) + (v2.y + v3.y) + ((v4.y + v5.y) + (v6.y + v7.y));
        }
        for (; j < cnt; ++j) {
            int s = __shfl_sync(0xffffffffu, sidx, j);
            float2 v = *(const float2*)&Hs[(size_t)s * 64 + lane * 2];
            acc.x += v.x; acc.y += v.y;
        }
    }
    float di = g_dinv[i];
    float2 b = *(const float2*)&gb[lane * 2];
    acc.x = b.x + di * acc.x;
    acc.y = b.y + di * acc.y;
    *(float2*)&out[(size_t)i * 64 + lane * 2] = acc;
}

// ---------------- depthwise 5x5 conv ----------------
__global__ void k_dwconv(const float* __restrict__ In, const float* __restrict__ dw,
                         const float* __restrict__ db, float* __restrict__ Out) {
    __shared__ float wt[25 * 64];
    int tid = threadIdx.x;
    for (int i = tid; i < 25 * 64; i += 256) {
        int t = i >> 6, c = i & 63;
        wt[i] = dw[c * 25 + t];
    }
    __syncthreads();
    int c4 = tid & 15;
    int p = blockIdx.x * 16 + (tid >> 4);
    int y = p / Ww_, x = p % Ww_;
    float4 acc = {0.f, 0.f, 0.f, 0.f};
#pragma unroll
    for (int ky = 0; ky < 5; ++ky) {
        int yy = y + ky - 2;
        if (yy < 0 || yy >= Hh_) continue;
#pragma unroll
        for (int kx = 0; kx < 5; ++kx) {
            int xx = x + kx - 2;
            if (xx < 0 || xx >= Ww_) continue;
            float4 v  = *(const float4*)&In[((size_t)yy * Ww_ + xx) * 64 + c4 * 4];
            float4 wv = *(const float4*)&wt[(ky * 5 + kx) * 64 + c4 * 4];
            acc.x += v.x * wv.x; acc.y += v.y * wv.y;
            acc.z += v.z * wv.z; acc.w += v.w * wv.w;
        }
    }
    float4 b = *(const float4*)&db[c4 * 4];
    acc.x += b.x; acc.y += b.y; acc.z += b.z; acc.w += b.w;
    acc.x = acc.x > 0.f ? acc.x : SLOPE_ * acc.x;
    acc.y = acc.y > 0.f ? acc.y : SLOPE_ * acc.y;
    acc.z = acc.z > 0.f ? acc.z : SLOPE_ * acc.z;
    acc.w = acc.w > 0.f ? acc.w : SLOPE_ * acc.w;
    *(float4*)&Out[(size_t)p * 64 + c4 * 4] = acc;
}

// ---------------- head: leaky(G) concat Cn -> linear -> softmax ----------------
__global__ void k_final(const float* __restrict__ G, const float* __restrict__ Cn,
                        const float* __restrict__ lw, const float* __restrict__ lb,
                        float* __restrict__ out) {
    __shared__ float slw[128 * 16];
    __shared__ float slb[16];
    __shared__ float sg[16][64];
    __shared__ float sc[16][64];
    int tid = threadIdx.x;
    for (int i = tid; i < 2048; i += 256) slw[i] = lw[i];
    if (tid < 16) slb[tid] = lb[tid];
    int tx = tid & 15, ty = tid >> 4;
    size_t row = (size_t)blockIdx.x * 16 + ty;
    float4 gv = *(const float4*)&G[row * 64 + tx * 4];
    gv.x = gv.x > 0.f ? gv.x : SLOPE_ * gv.x;
    gv.y = gv.y > 0.f ? gv.y : SLOPE_ * gv.y;
    gv.z = gv.z > 0.f ? gv.z : SLOPE_ * gv.z;
    gv.w = gv.w > 0.f ? gv.w : SLOPE_ * gv.w;
    *(float4*)&sg[ty][tx * 4] = gv;
    *(float4*)&sc[ty][tx * 4] = *(const float4*)&Cn[row * 64 + tx * 4];
    __syncthreads();
    float acc = slb[tx];
#pragma unroll 4
    for (int k = 0; k < 64; ++k) acc += sg[ty][k] * slw[k * 16 + tx];
#pragma unroll 4
    for (int k = 0; k < 64; ++k) acc += sc[ty][k] * slw[(64 + k) * 16 + tx];
    float mx = acc;
#pragma unroll
    for (int o = 8; o > 0; o >>= 1) mx = fmaxf(mx, __shfl_xor_sync(0xffffffffu, mx, o));
    float e = __expf(acc - mx);
    float sum = e;
#pragma unroll
    for (int o = 8; o > 0; o >>= 1) sum += __shfl_xor_sync(0xffffffffu, sum, o);
    out[row * 16 + tx] = e / sum;
}

// ---------------- host launchers ----------------
template <int K, int M, int BM, int TR, int EPI, bool LKIN>
static void launch_gemm(const float* X, float* Y) {
    size_t smem = (size_t)(K * M + BM * (K + 4)) * 4;
    cudaFuncSetAttribute(k_gemm<K, M, BM, TR, EPI, LKIN>,
                         cudaFuncAttributeMaxDynamicSharedMemorySize, (int)smem);
    k_gemm<K, M, BM, TR, EPI, LKIN><<<N_ / BM, 256, smem>>>(X, Y);
}

extern "C" void kernel_launch(void* const* d_in, const int* in_sizes, int n_in,
                              void* d_out, int out_size) {
    const float* x   = (const float*)d_in[0];
    const int*   ei  = (const int*)d_in[1];
    const int*   src = ei;
    const int*   dst = ei + E_;
    const float* dn_bn1_g = (const float*)d_in[2];
    const float* dn_bn1_b = (const float*)d_in[3];
    const float* dn_w1    = (const float*)d_in[4];
    const float* dn_b1    = (const float*)d_in[5];
    const float* dn_bn2_g = (const float*)d_in[6];
    const float* dn_bn2_b = (const float*)d_in[7];
    const float* dn_w2    = (const float*)d_in[8];
    const float* dn_b2    = (const float*)d_in[9];
    const float* cnn_bn_g = (const float*)d_in[10];
    const float* cnn_bn_b = (const float*)d_in[11];
    const float* cnn_pw   = (const float*)d_in[12];
    const float* cnn_dw   = (const float*)d_in[13];
    const float* cnn_db   = (const float*)d_in[14];
    const float* g1_bn_g  = (const float*)d_in[15];
    const float* g1_bn_b  = (const float*)d_in[16];
    const float* g1_w     = (const float*)d_in[17];
    const float* g1_b     = (const float*)d_in[18];
    const float* g2_bn_g  = (const float*)d_in[19];
    const float* g2_bn_b  = (const float*)d_in[20];
    const float* g2_w     = (const float*)d_in[21];
    const float* g2_b     = (const float*)d_in[22];
    const float* g3_bn_g  = (const float*)d_in[23];
    const float* g3_bn_b  = (const float*)d_in[24];
    const float* g3_w     = (const float*)d_in[25];
    const float* g3_b     = (const float*)d_in[26];
    const float* lin_w    = (const float*)d_in[27];
    const float* lin_b    = (const float*)d_in[28];
    float* out = (float*)d_out;

    float *pP, *pQ, *pH, *pC, *pCR;
    cudaGetSymbolAddress((void**)&pP, g_P);
    cudaGetSymbolAddress((void**)&pQ, g_Q);
    cudaGetSymbolAddress((void**)&pH, g_Hm);
    cudaGetSymbolAddress((void**)&pC, g_cnn);
    cudaGetSymbolAddress((void**)&pCR, g_cnnres);

    // 1-4: denoise layer 1 (positions the big GEMM as the profiled launch)
    k_init<<<NBLK_ + 1, 256>>>();
    k_colstats<200><<<128, 200>>>(x, 0);
    k_fold<200, 128><<<101, 256>>>(dn_w1, dn_bn1_g, dn_bn1_b, dn_b1, 0);
    launch_gemm<200, 128, 128, 8, 0, false>(x, pQ);

    // CSR build + dinv
    k_deg_count<<<(E_ + 255) / 256, 256>>>(dst);
    k_scan1<<<NBLK_, 256>>>();
    k_scan2<<<1, 1024>>>();
    k_scan3<<<NBLK_, 256>>>();
    k_csr_fill<<<(E_ + 255) / 256, 256>>>(src, dst);

    // denoise layer 2
    k_colstats<128><<<128, 128>>>(pQ, 1);
    k_fold<128, 128><<<65, 256>>>(dn_w2, dn_bn2_g, dn_bn2_b, dn_b2, 1);
    launch_gemm<128, 128, 64, 4, 0, false>(pQ, pP);    // pP = clean

    // CNN branch
    k_colstats<128><<<128, 128>>>(pP, 2);
    k_fold<128, 64><<<33, 256>>>(cnn_pw, cnn_bn_g, cnn_bn_b, nullptr, 2);
    launch_gemm<128, 64, 128, 4, 0, false>(pP, pC);
    k_dwconv<<<N_ / 16, 256>>>(pC, cnn_dw, cnn_db, pCR);

    // GCN layer 1 (input clean: no leaky on load)
    k_rownorm_stats<false><<<288, 256>>>(pP, 3);
    k_fold<128, 128><<<65, 256>>>(g1_w, g1_bn_g, g1_bn_b, nullptr, 3);
    launch_gemm<128, 128, 64, 4, 1, false>(pP, pH);
    k_gather128<<<(N_ * 32) / 256, 256>>>(pH, g1_b, pP);

    // GCN layer 2
    k_rownorm_stats<true><<<288, 256>>>(pP, 4);
    k_fold<128, 128><<<65, 256>>>(g2_w, g2_bn_g, g2_bn_b, nullptr, 4);
    launch_gemm<128, 128, 64, 4, 1, true>(pP, pH);
    k_gather128<<<(N_ * 32) / 256, 256>>>(pH, g2_b, pP);

    // GCN layer 3 (128 -> 64)
    k_rownorm_stats<true><<<288, 256>>>(pP, 5);
    k_fold<128, 64><<<33, 256>>>(g3_w, g3_bn_g, g3_bn_b, nullptr, 5);
    launch_gemm<128, 64, 128, 4, 1, true>(pP, pH);
    k_gather64<<<(N_ * 32) / 256, 256>>>(pH, g3_b, pP);

    // head
    k_final<<<N_ / 16, 256>>>(pP, pCR, lin_w, lin_b, out);
}

// round 5
// speedup vs baseline: 1.3448x; 1.3448x over previous
#include <cuda_runtime.h>
#include <cuda_bf16.h>
#include <mma.h>
#include <cstdint>
#include <cstddef>

using namespace nvcuda;

// ---------------- problem constants ----------------
#define Hh_ 384
#define Ww_ 384
#define C_ 200
#define N_ 147456           // Hh_*Ww_
#define E_ 1179648
#define HIDE_ 128
#define OUT_ 64
#define NCLS_ 16
#define EPS_ 1e-5f
#define SLOPE_ 0.01f
#define NBLK_ 576           // N_/256

// ---------------- scratch (device globals; no allocation allowed) ----------------
__device__ float g_P[(size_t)N_ * 128];
__device__ float g_Q[(size_t)N_ * 128];
__device__ float g_Hm[(size_t)N_ * 128];
__device__ float g_cnn[(size_t)N_ * 64];
__device__ float g_cnnres[(size_t)N_ * 64];
__device__ float g_dinv[N_];
__device__ float g_invn[N_];
__device__ float g_sum[6 * 256];
__device__ float g_sq[6 * 256];
__device__ float g_bf[128];
__device__ __nv_bfloat16 g_Wh[256 * 128];   // folded weights hi, row-major [KPAD][M]
__device__ __nv_bfloat16 g_Wl[256 * 128];   // folded weights lo
// CSR
__device__ int g_degi[N_];
__device__ int g_rowptr[N_ + 1];
__device__ int g_cursor[N_];
__device__ int g_blksum[NBLK_];
__device__ int g_col[E_];

// ---------------- init: zero all stat slots + degree array ----------------
__global__ void k_init() {
    int i = blockIdx.x * 256 + threadIdx.x;
    if (i < N_) g_degi[i] = 0;
    if (i < 6 * 256) { g_sum[i] = 0.f; g_sq[i] = 0.f; }
}

// plain column stats: blockDim == C
template <int C>
__global__ void k_colstats(const float* __restrict__ X, int slot) {
    const int c = threadIdx.x;
    const int rpb = N_ / 128;
    const int r0 = blockIdx.x * rpb;
    float s = 0.f, q = 0.f;
    for (int r = r0; r < r0 + rpb; ++r) {
        float v = X[(size_t)r * C + c];
        s += v; q += v * v;
    }
    atomicAdd(&g_sum[slot * 256 + c], s);
    atomicAdd(&g_sq[slot * 256 + c], q);
}

// rownorm stats: invnorm per row (after optional leaky) + column stats of normalized rows.
template <bool LK>
__global__ void k_rownorm_stats(const float* __restrict__ X, int slot) {
    __shared__ float sp[8][128];
    __shared__ float sq[8][128];
    const int tid = threadIdx.x;
    const int wid = tid >> 5, lane = tid & 31;
    const int gw = blockIdx.x * 8 + wid;
    float4 s4 = {0.f, 0.f, 0.f, 0.f}, q4 = {0.f, 0.f, 0.f, 0.f};
    for (int r = gw; r < N_; r += 288 * 8) {
        float4 v = *(const float4*)&X[(size_t)r * 128 + lane * 4];
        if (LK) {
            v.x = v.x > 0.f ? v.x : SLOPE_ * v.x;
            v.y = v.y > 0.f ? v.y : SLOPE_ * v.y;
            v.z = v.z > 0.f ? v.z : SLOPE_ * v.z;
            v.w = v.w > 0.f ? v.w : SLOPE_ * v.w;
        }
        float ss = v.x * v.x + v.y * v.y + v.z * v.z + v.w * v.w;
#pragma unroll
        for (int o = 16; o > 0; o >>= 1) ss += __shfl_xor_sync(0xffffffffu, ss, o);
        float inv = 1.0f / fmaxf(sqrtf(ss), 1e-12f);
        if (lane == 0) g_invn[r] = inv;
        v.x *= inv; v.y *= inv; v.z *= inv; v.w *= inv;
        s4.x += v.x; s4.y += v.y; s4.z += v.z; s4.w += v.w;
        q4.x += v.x * v.x; q4.y += v.y * v.y; q4.z += v.z * v.z; q4.w += v.w * v.w;
    }
    sp[wid][lane * 4 + 0] = s4.x; sp[wid][lane * 4 + 1] = s4.y;
    sp[wid][lane * 4 + 2] = s4.z; sp[wid][lane * 4 + 3] = s4.w;
    sq[wid][lane * 4 + 0] = q4.x; sq[wid][lane * 4 + 1] = q4.y;
    sq[wid][lane * 4 + 2] = q4.z; sq[wid][lane * 4 + 3] = q4.w;
    __syncthreads();
    if (tid < 128) {
        float a = 0.f, b = 0.f;
#pragma unroll
        for (int w = 0; w < 8; ++w) { a += sp[w][tid]; b += sq[w][tid]; }
        atomicAdd(&g_sum[slot * 256 + tid], a);
        atomicAdd(&g_sq[slot * 256 + tid], b);
    }
}

// ---------------- weight prep: BN fold + bf16 hi/lo split, row-major [KPAD][M] ----------------
template <int KREAL, int KPAD, int M>
__global__ void k_prepw(const float* __restrict__ W, const float* __restrict__ bng,
                        const float* __restrict__ bnb, const float* __restrict__ bias,
                        int slot) {
    const float* su = &g_sum[slot * 256];
    const float* qu = &g_sq[slot * 256];
    constexpr int NW = M * KPAD;
    if (blockIdx.x == NW / 256) {
        int m = threadIdx.x;
        if (m < M) {
            float acc = bias ? bias[m] : 0.f;
            for (int c = 0; c < KREAL; ++c) {
                float mean = su[c] * (1.f / N_);
                float var  = qu[c] * (1.f / N_) - mean * mean;
                float scale = bng[c] * rsqrtf(var + EPS_);
                acc += (bnb[c] - mean * scale) * W[c * M + m];
            }
            g_bf[m] = acc;
        }
        return;
    }
    int e = blockIdx.x * 256 + threadIdx.x;
    int k = e / M, n = e % M;
    float w = 0.f;
    if (k < KREAL) {
        float mean = su[k] * (1.f / N_);
        float var  = qu[k] * (1.f / N_) - mean * mean;
        float scale = bng[k] * rsqrtf(var + EPS_);
        w = scale * W[k * M + n];
    }
    __nv_bfloat16 h = __float2bfloat16(w);
    __nv_bfloat16 l = __float2bfloat16(w - __bfloat162float(h));
    g_Wh[e] = h;
    g_Wl[e] = l;
}

// ---------------- tensor GEMM via wmma (bf16 hi/lo split, fp32 accum) ----------------
// Y[N,M] = epi( lk?(X[N,KREAL]) @ Wf + bf )
// EPI 0: out = leaky(acc + bf)
// EPI 1: out = (acc*invn[r] + bf) * dinv[r]
// 256 threads = 8 warps; warp w computes rows [w*16, w*16+16) x all M cols.
template <int KREAL, int KPAD, int M, int EPI, bool LKIN>
__global__ __launch_bounds__(256)
void k_wgemm(const float* __restrict__ X, float* __restrict__ Y) {
    constexpr int KC = 64;            // K chunk
    constexpr int AS = KC + 8;        // A smem stride (halves)
    constexpr int BS = M + 8;         // B smem stride (halves)
    constexpr int NT = M / 16;        // n-tiles per warp
    extern __shared__ char smraw[];
    __nv_bfloat16* Ah = (__nv_bfloat16*)smraw;          // 128*AS halves
    __nv_bfloat16* Al = Ah + 128 * AS;
    __nv_bfloat16* Bh = Al + 128 * AS;                  // KC*BS halves
    __nv_bfloat16* Bl = Bh + (size_t)KC * BS;
    float* stage = (float*)smraw;                       // reused post-compute

    const int tid = threadIdx.x, wid = tid >> 5, lane = tid & 31;
    const size_t row0 = (size_t)blockIdx.x * 128;

    wmma::fragment<wmma::accumulator, 16, 16, 16, float> acc[NT];
#pragma unroll
    for (int n = 0; n < NT; ++n) wmma::fill_fragment(acc[n], 0.0f);

    for (int c = 0; c < KPAD / KC; ++c) {
        // A chunk: 128 rows x KC cols, fp32 -> bf16 hi/lo (float2 loads, KREAL is even)
        for (int p = tid; p < 128 * (KC / 2); p += 256) {
            int r = p / (KC / 2), kq = p % (KC / 2);
            int kg = c * KC + kq * 2;
            float2 v = {0.f, 0.f};
            if (kg < KREAL) v = *(const float2*)&X[(row0 + r) * KREAL + kg];
            if (LKIN) {
                v.x = v.x > 0.f ? v.x : SLOPE_ * v.x;
                v.y = v.y > 0.f ? v.y : SLOPE_ * v.y;
            }
            __nv_bfloat16 h0 = __float2bfloat16(v.x);
            __nv_bfloat16 h1 = __float2bfloat16(v.y);
            __nv_bfloat16 l0 = __float2bfloat16(v.x - __bfloat162float(h0));
            __nv_bfloat16 l1 = __float2bfloat16(v.y - __bfloat162float(h1));
            *(__nv_bfloat162*)&Ah[r * AS + kq * 2] = __nv_bfloat162(h0, h1);
            *(__nv_bfloat162*)&Al[r * AS + kq * 2] = __nv_bfloat162(l0, l1);
        }
        // B chunk: copy prebuilt bf16 image rows [c*KC, c*KC+KC) x M
        for (int p = tid; p < KC * (M / 2); p += 256) {
            int k = p / (M / 2), nq = p % (M / 2);
            *(uint32_t*)&Bh[k * BS + nq * 2] = *(const uint32_t*)&g_Wh[(c * KC + k) * M + nq * 2];
            *(uint32_t*)&Bl[k * BS + nq * 2] = *(const uint32_t*)&g_Wl[(c * KC + k) * M + nq * 2];
        }
        __syncthreads();

#pragma unroll
        for (int ks = 0; ks < KC / 16; ++ks) {
            wmma::fragment<wmma::matrix_a, 16, 16, 16, __nv_bfloat16, wmma::row_major> aH, aL;
            wmma::load_matrix_sync(aH, Ah + wid * 16 * AS + ks * 16, AS);
            wmma::load_matrix_sync(aL, Al + wid * 16 * AS + ks * 16, AS);
#pragma unroll
            for (int n = 0; n < NT; ++n) {
                wmma::fragment<wmma::matrix_b, 16, 16, 16, __nv_bfloat16, wmma::row_major> bH, bL;
                wmma::load_matrix_sync(bH, Bh + ks * 16 * BS + n * 16, BS);
                wmma::load_matrix_sync(bL, Bl + ks * 16 * BS + n * 16, BS);
                wmma::mma_sync(acc[n], aH, bH, acc[n]);
                wmma::mma_sync(acc[n], aH, bL, acc[n]);
                wmma::mma_sync(acc[n], aL, bH, acc[n]);
            }
        }
        __syncthreads();
    }

    // epilogue: stage accumulators, then coalesced epi + store
    float* sw = stage + (size_t)wid * 16 * (M + 8);
#pragma unroll
    for (int n = 0; n < NT; ++n)
        wmma::store_matrix_sync(sw + n * 16, acc[n], M + 8, wmma::mem_row_major);
    __syncwarp();
    for (int rr = 0; rr < 16; ++rr) {
        size_t r = row0 + wid * 16 + rr;
        float sr = 1.f, dv = 1.f;
        if (EPI == 1) { sr = g_invn[r]; dv = g_dinv[r]; }
        for (int cb = lane * 4; cb < M; cb += 128) {
            float4 v = *(float4*)&sw[rr * (M + 8) + cb];
            float4 b = *(const float4*)&g_bf[cb];
            if (EPI == 0) {
                v.x += b.x; v.y += b.y; v.z += b.z; v.w += b.w;
                v.x = v.x > 0.f ? v.x : SLOPE_ * v.x;
                v.y = v.y > 0.f ? v.y : SLOPE_ * v.y;
                v.z = v.z > 0.f ? v.z : SLOPE_ * v.z;
                v.w = v.w > 0.f ? v.w : SLOPE_ * v.w;
            } else {
                v.x = (v.x * sr + b.x) * dv;
                v.y = (v.y * sr + b.y) * dv;
                v.z = (v.z * sr + b.z) * dv;
                v.w = (v.w * sr + b.w) * dv;
            }
            *(float4*)&Y[r * M + cb] = v;
        }
    }
}

// ---------------- CSR build ----------------
__global__ void k_deg_count(const int* __restrict__ dst) {
    int e = blockIdx.x * blockDim.x + threadIdx.x;
    if (e < E_) atomicAdd(&g_degi[dst[e]], 1);
}
__global__ void k_scan1() {
    __shared__ int s[256];
    int t = threadIdx.x;
    int idx = blockIdx.x * 256 + t;
    int v = g_degi[idx];
    s[t] = v;
    __syncthreads();
#pragma unroll
    for (int off = 1; off < 256; off <<= 1) {
        int a = 0;
        if (t >= off) a = s[t - off];
        __syncthreads();
        s[t] += a;
        __syncthreads();
    }
    g_rowptr[idx] = s[t] - v;
    if (t == 255) g_blksum[blockIdx.x] = s[255];
}
__global__ void k_scan2() {
    __shared__ int s[NBLK_];
    int t = threadIdx.x;
    if (t < NBLK_) s[t] = g_blksum[t];
    __syncthreads();
    for (int off = 1; off < NBLK_; off <<= 1) {
        int a = 0;
        if (t >= off && t < NBLK_) a = s[t - off];
        __syncthreads();
        if (t < NBLK_) s[t] += a;
        __syncthreads();
    }
    if (t < NBLK_) g_blksum[t] = s[t];
}
__global__ void k_scan3() {
    int idx = blockIdx.x * 256 + threadIdx.x;
    int off = blockIdx.x == 0 ? 0 : g_blksum[blockIdx.x - 1];
    int rp = g_rowptr[idx] + off;
    g_rowptr[idx] = rp;
    g_cursor[idx] = rp;
    g_dinv[idx] = rsqrtf((float)g_degi[idx] + 1.0f);
    if (idx == 0) g_rowptr[N_] = E_;
}
__global__ void k_csr_fill(const int* __restrict__ src, const int* __restrict__ dst) {
    int e = blockIdx.x * blockDim.x + threadIdx.x;
    if (e < E_) {
        int pos = atomicAdd(&g_cursor[dst[e]], 1);
        g_col[pos] = src[e];
    }
}

// ---------------- GCN gather ----------------
__global__ void k_gather128(const float* __restrict__ Hs, const float* __restrict__ gb,
                            float* __restrict__ out) {
    int i = (int)(((size_t)blockIdx.x * blockDim.x + threadIdx.x) >> 5);
    if (i >= N_) return;
    int lane = threadIdx.x & 31;
    int beg = __ldg(&g_rowptr[i]), end = __ldg(&g_rowptr[i + 1]);
    float4 acc = *(const float4*)&Hs[(size_t)i * 128 + lane * 4];
    for (int base = beg; base < end; base += 32) {
        int e = base + lane;
        int sidx = (e < end) ? g_col[e] : 0;
        int cnt = min(32, end - base);
        int j = 0;
        for (; j + 8 <= cnt; j += 8) {
            int s0 = __shfl_sync(0xffffffffu, sidx, j);
            int s1 = __shfl_sync(0xffffffffu, sidx, j + 1);
            int s2 = __shfl_sync(0xffffffffu, sidx, j + 2);
            int s3 = __shfl_sync(0xffffffffu, sidx, j + 3);
            int s4 = __shfl_sync(0xffffffffu, sidx, j + 4);
            int s5 = __shfl_sync(0xffffffffu, sidx, j + 5);
            int s6 = __shfl_sync(0xffffffffu, sidx, j + 6);
            int s7 = __shfl_sync(0xffffffffu, sidx, j + 7);
            float4 v0 = *(const float4*)&Hs[(size_t)s0 * 128 + lane * 4];
            float4 v1 = *(const float4*)&Hs[(size_t)s1 * 128 + lane * 4];
            float4 v2 = *(const float4*)&Hs[(size_t)s2 * 128 + lane * 4];
            float4 v3 = *(const float4*)&Hs[(size_t)s3 * 128 + lane * 4];
            float4 v4 = *(const float4*)&Hs[(size_t)s4 * 128 + lane * 4];
            float4 v5 = *(const float4*)&Hs[(size_t)s5 * 128 + lane * 4];
            float4 v6 = *(const float4*)&Hs[(size_t)s6 * 128 + lane * 4];
            float4 v7 = *(const float4*)&Hs[(size_t)s7 * 128 + lane * 4];
            acc.x += (v0.x + v1.x) + (v2.x + v3.x) + ((v4.x + v5.x) + (v6.x + v7.x));
            acc.y += (v0.y + v1.y) + (v2.y + v3.y) + ((v4.y + v5.y) + (v6.y + v7.y));
            acc.z += (v0.z + v1.z) + (v2.z + v3.z) + ((v4.z + v5.z) + (v6.z + v7.z));
            acc.w += (v0.w + v1.w) + (v2.w + v3.w) + ((v4.w + v5.w) + (v6.w + v7.w));
        }
        for (; j < cnt; ++j) {
            int s = __shfl_sync(0xffffffffu, sidx, j);
            float4 v = *(const float4*)&Hs[(size_t)s * 128 + lane * 4];
            acc.x += v.x; acc.y += v.y; acc.z += v.z; acc.w += v.w;
        }
    }
    float di = g_dinv[i];
    float4 b = *(const float4*)&gb[lane * 4];
    acc.x = b.x + di * acc.x;
    acc.y = b.y + di * acc.y;
    acc.z = b.z + di * acc.z;
    acc.w = b.w + di * acc.w;
    *(float4*)&out[(size_t)i * 128 + lane * 4] = acc;
}

__global__ void k_gather64(const float* __restrict__ Hs, const float* __restrict__ gb,
                           float* __restrict__ out) {
    int i = (int)(((size_t)blockIdx.x * blockDim.x + threadIdx.x) >> 5);
    if (i >= N_) return;
    int lane = threadIdx.x & 31;
    int beg = __ldg(&g_rowptr[i]), end = __ldg(&g_rowptr[i + 1]);
    float2 acc = *(const float2*)&Hs[(size_t)i * 64 + lane * 2];
    for (int base = beg; base < end; base += 32) {
        int e = base + lane;
        int sidx = (e < end) ? g_col[e] : 0;
        int cnt = min(32, end - base);
        int j = 0;
        for (; j + 8 <= cnt; j += 8) {
            int s0 = __shfl_sync(0xffffffffu, sidx, j);
            int s1 = __shfl_sync(0xffffffffu, sidx, j + 1);
            int s2 = __shfl_sync(0xffffffffu, sidx, j + 2);
            int s3 = __shfl_sync(0xffffffffu, sidx, j + 3);
            int s4 = __shfl_sync(0xffffffffu, sidx, j + 4);
            int s5 = __shfl_sync(0xffffffffu, sidx, j + 5);
            int s6 = __shfl_sync(0xffffffffu, sidx, j + 6);
            int s7 = __shfl_sync(0xffffffffu, sidx, j + 7);
            float2 v0 = *(const float2*)&Hs[(size_t)s0 * 64 + lane * 2];
            float2 v1 = *(const float2*)&Hs[(size_t)s1 * 64 + lane * 2];
            float2 v2 = *(const float2*)&Hs[(size_t)s2 * 64 + lane * 2];
            float2 v3 = *(const float2*)&Hs[(size_t)s3 * 64 + lane * 2];
            float2 v4 = *(const float2*)&Hs[(size_t)s4 * 64 + lane * 2];
            float2 v5 = *(const float2*)&Hs[(size_t)s5 * 64 + lane * 2];
            float2 v6 = *(const float2*)&Hs[(size_t)s6 * 64 + lane * 2];
            float2 v7 = *(const float2*)&Hs[(size_t)s7 * 64 + lane * 2];
            acc.x += (v0.x + v1.x) + (v2.x + v3.x) + ((v4.x + v5.x) + (v6.x + v7.x));
            acc.y += (v0.y + v1.y) + (v2.y + v3.y) + ((v4.y + v5.y) + (v6.y + v7.y));
        }
        for (; j < cnt; ++j) {
            int s = __shfl_sync(0xffffffffu, sidx, j);
            float2 v = *(const float2*)&Hs[(size_t)s * 64 + lane * 2];
            acc.x += v.x; acc.y += v.y;
        }
    }
    float di = g_dinv[i];
    float2 b = *(const float2*)&gb[lane * 2];
    acc.x = b.x + di * acc.x;
    acc.y = b.y + di * acc.y;
    *(float2*)&out[(size_t)i * 64 + lane * 2] = acc;
}

// ---------------- depthwise 5x5 conv ----------------
__global__ void k_dwconv(const float* __restrict__ In, const float* __restrict__ dw,
                         const float* __restrict__ db, float* __restrict__ Out) {
    __shared__ float wt[25 * 64];
    int tid = threadIdx.x;
    for (int i = tid; i < 25 * 64; i += 256) {
        int t = i >> 6, c = i & 63;
        wt[i] = dw[c * 25 + t];
    }
    __syncthreads();
    int c4 = tid & 15;
    int p = blockIdx.x * 16 + (tid >> 4);
    int y = p / Ww_, x = p % Ww_;
    float4 acc = {0.f, 0.f, 0.f, 0.f};
#pragma unroll
    for (int ky = 0; ky < 5; ++ky) {
        int yy = y + ky - 2;
        if (yy < 0 || yy >= Hh_) continue;
#pragma unroll
        for (int kx = 0; kx < 5; ++kx) {
            int xx = x + kx - 2;
            if (xx < 0 || xx >= Ww_) continue;
            float4 v  = *(const float4*)&In[((size_t)yy * Ww_ + xx) * 64 + c4 * 4];
            float4 wv = *(const float4*)&wt[(ky * 5 + kx) * 64 + c4 * 4];
            acc.x += v.x * wv.x; acc.y += v.y * wv.y;
            acc.z += v.z * wv.z; acc.w += v.w * wv.w;
        }
    }
    float4 b = *(const float4*)&db[c4 * 4];
    acc.x += b.x; acc.y += b.y; acc.z += b.z; acc.w += b.w;
    acc.x = acc.x > 0.f ? acc.x : SLOPE_ * acc.x;
    acc.y = acc.y > 0.f ? acc.y : SLOPE_ * acc.y;
    acc.z = acc.z > 0.f ? acc.z : SLOPE_ * acc.z;
    acc.w = acc.w > 0.f ? acc.w : SLOPE_ * acc.w;
    *(float4*)&Out[(size_t)p * 64 + c4 * 4] = acc;
}

// ---------------- head: leaky(G) concat Cn -> linear -> softmax ----------------
__global__ void k_final(const float* __restrict__ G, const float* __restrict__ Cn,
                        const float* __restrict__ lw, const float* __restrict__ lb,
                        float* __restrict__ out) {
    __shared__ float slw[128 * 16];
    __shared__ float slb[16];
    __shared__ float sg[16][64];
    __shared__ float sc[16][64];
    int tid = threadIdx.x;
    for (int i = tid; i < 2048; i += 256) slw[i] = lw[i];
    if (tid < 16) slb[tid] = lb[tid];
    int tx = tid & 15, ty = tid >> 4;
    size_t row = (size_t)blockIdx.x * 16 + ty;
    float4 gv = *(const float4*)&G[row * 64 + tx * 4];
    gv.x = gv.x > 0.f ? gv.x : SLOPE_ * gv.x;
    gv.y = gv.y > 0.f ? gv.y : SLOPE_ * gv.y;
    gv.z = gv.z > 0.f ? gv.z : SLOPE_ * gv.z;
    gv.w = gv.w > 0.f ? gv.w : SLOPE_ * gv.w;
    *(float4*)&sg[ty][tx * 4] = gv;
    *(float4*)&sc[ty][tx * 4] = *(const float4*)&Cn[row * 64 + tx * 4];
    __syncthreads();
    float acc = slb[tx];
#pragma unroll 4
    for (int k = 0; k < 64; ++k) acc += sg[ty][k] * slw[k * 16 + tx];
#pragma unroll 4
    for (int k = 0; k < 64; ++k) acc += sc[ty][k] * slw[(64 + k) * 16 + tx];
    float mx = acc;
#pragma unroll
    for (int o = 8; o > 0; o >>= 1) mx = fmaxf(mx, __shfl_xor_sync(0xffffffffu, mx, o));
    float e = __expf(acc - mx);
    float sum = e;
#pragma unroll
    for (int o = 8; o > 0; o >>= 1) sum += __shfl_xor_sync(0xffffffffu, sum, o);
    out[row * 16 + tx] = e / sum;
}

// ---------------- host launchers ----------------
template <int KREAL, int KPAD, int M, int EPI, bool LKIN>
static void launch_wgemm(const float* X, float* Y) {
    constexpr int KC = 64;
    constexpr size_t comp = (size_t)(2 * 128 * (KC + 8) + 2 * KC * (M + 8)) * 2;
    constexpr size_t stg  = (size_t)8 * 16 * (M + 8) * 4;
    constexpr size_t smem = comp > stg ? comp : stg;
    cudaFuncSetAttribute(k_wgemm<KREAL, KPAD, M, EPI, LKIN>,
                         cudaFuncAttributeMaxDynamicSharedMemorySize, (int)smem);
    k_wgemm<KREAL, KPAD, M, EPI, LKIN><<<N_ / 128, 256, smem>>>(X, Y);
}

extern "C" void kernel_launch(void* const* d_in, const int* in_sizes, int n_in,
                              void* d_out, int out_size) {
    const float* x   = (const float*)d_in[0];
    const int*   ei  = (const int*)d_in[1];
    const int*   src = ei;
    const int*   dst = ei + E_;
    const float* dn_bn1_g = (const float*)d_in[2];
    const float* dn_bn1_b = (const float*)d_in[3];
    const float* dn_w1    = (const float*)d_in[4];
    const float* dn_b1    = (const float*)d_in[5];
    const float* dn_bn2_g = (const float*)d_in[6];
    const float* dn_bn2_b = (const float*)d_in[7];
    const float* dn_w2    = (const float*)d_in[8];
    const float* dn_b2    = (const float*)d_in[9];
    const float* cnn_bn_g = (const float*)d_in[10];
    const float* cnn_bn_b = (const float*)d_in[11];
    const float* cnn_pw   = (const float*)d_in[12];
    const float* cnn_dw   = (const float*)d_in[13];
    const float* cnn_db   = (const float*)d_in[14];
    const float* g1_bn_g  = (const float*)d_in[15];
    const float* g1_bn_b  = (const float*)d_in[16];
    const float* g1_w     = (const float*)d_in[17];
    const float* g1_b     = (const float*)d_in[18];
    const float* g2_bn_g  = (const float*)d_in[19];
    const float* g2_bn_b  = (const float*)d_in[20];
    const float* g2_w     = (const float*)d_in[21];
    const float* g2_b     = (const float*)d_in[22];
    const float* g3_bn_g  = (const float*)d_in[23];
    const float* g3_bn_b  = (const float*)d_in[24];
    const float* g3_w     = (const float*)d_in[25];
    const float* g3_b     = (const float*)d_in[26];
    const float* lin_w    = (const float*)d_in[27];
    const float* lin_b    = (const float*)d_in[28];
    float* out = (float*)d_out;

    float *pP, *pQ, *pH, *pC, *pCR;
    cudaGetSymbolAddress((void**)&pP, g_P);
    cudaGetSymbolAddress((void**)&pQ, g_Q);
    cudaGetSymbolAddress((void**)&pH, g_Hm);
    cudaGetSymbolAddress((void**)&pC, g_cnn);
    cudaGetSymbolAddress((void**)&pCR, g_cnnres);

    // denoise layer 1 (launch #4 = big tensor GEMM, for profiling)
    k_init<<<NBLK_ + 1, 256>>>();
    k_colstats<200><<<128, 200>>>(x, 0);
    k_prepw<200, 256, 128><<<129, 256>>>(dn_w1, dn_bn1_g, dn_bn1_b, dn_b1, 0);
    launch_wgemm<200, 256, 128, 0, false>(x, pQ);

    // CSR build + dinv
    k_deg_count<<<(E_ + 255) / 256, 256>>>(dst);
    k_scan1<<<NBLK_, 256>>>();
    k_scan2<<<1, 1024>>>();
    k_scan3<<<NBLK_, 256>>>();
    k_csr_fill<<<(E_ + 255) / 256, 256>>>(src, dst);

    // denoise layer 2
    k_colstats<128><<<128, 128>>>(pQ, 1);
    k_prepw<128, 128, 128><<<65, 256>>>(dn_w2, dn_bn2_g, dn_bn2_b, dn_b2, 1);
    launch_wgemm<128, 128, 128, 0, false>(pQ, pP);    // pP = clean

    // CNN branch
    k_colstats<128><<<128, 128>>>(pP, 2);
    k_prepw<128, 128, 64><<<33, 256>>>(cnn_pw, cnn_bn_g, cnn_bn_b, nullptr, 2);
    launch_wgemm<128, 128, 64, 0, false>(pP, pC);
    k_dwconv<<<N_ / 16, 256>>>(pC, cnn_dw, cnn_db, pCR);

    // GCN layer 1
    k_rownorm_stats<false><<<288, 256>>>(pP, 3);
    k_prepw<128, 128, 128><<<65, 256>>>(g1_w, g1_bn_g, g1_bn_b, nullptr, 3);
    launch_wgemm<128, 128, 128, 1, false>(pP, pH);
    k_gather128<<<(N_ * 32) / 256, 256>>>(pH, g1_b, pP);

    // GCN layer 2
    k_rownorm_stats<true><<<288, 256>>>(pP, 4);
    k_prepw<128, 128, 128><<<65, 256>>>(g2_w, g2_bn_g, g2_bn_b, nullptr, 4);
    launch_wgemm<128, 128, 128, 1, true>(pP, pH);
    k_gather128<<<(N_ * 32) / 256, 256>>>(pH, g2_b, pP);

    // GCN layer 3 (128 -> 64)
    k_rownorm_stats<true><<<288, 256>>>(pP, 5);
    k_prepw<128, 128, 64><<<33, 256>>>(g3_w, g3_bn_g, g3_bn_b, nullptr, 5);
    launch_wgemm<128, 128, 64, 1, true>(pP, pH);
    k_gather64<<<(N_ * 32) / 256, 256>>>(pH, g3_b, pP);

    // head
    k_final<<<N_ / 16, 256>>>(pP, pCR, lin_w, lin_b, out);
}

// round 6
// speedup vs baseline: 1.4518x; 1.0795x over previous
#include <cuda_runtime.h>
#include <cuda_bf16.h>
#include <mma.h>
#include <cstdint>
#include <cstddef>

using namespace nvcuda;

// ---------------- problem constants ----------------
#define Hh_ 384
#define Ww_ 384
#define C_ 200
#define N_ 147456           // Hh_*Ww_
#define E_ 1179648
#define HIDE_ 128
#define OUT_ 64
#define NCLS_ 16
#define EPS_ 1e-5f
#define SLOPE_ 0.01f
#define NBLK_ 576           // N_/256

// ---------------- scratch (device globals; no allocation allowed) ----------------
__device__ float g_P[(size_t)N_ * 128];
__device__ float g_Q[(size_t)N_ * 128];
__device__ float g_Hm[(size_t)N_ * 128];
__device__ float g_cnn[(size_t)N_ * 64];
__device__ float g_cnnres[(size_t)N_ * 64];
__device__ float g_dinv[N_];
__device__ float g_invn[N_];
__device__ float g_sum[6 * 256];
__device__ float g_sq[6 * 256];
__device__ float g_bf[128];
__device__ __nv_bfloat16 g_Wh[256 * 128];   // folded weights hi, row-major [KPAD][M]
__device__ __nv_bfloat16 g_Wl[256 * 128];   // folded weights lo
// CSR
__device__ int g_degi[N_];
__device__ int g_rowptr[N_ + 1];
__device__ int g_cursor[N_];
__device__ int g_blksum[NBLK_];
__device__ int g_col[E_];

// ---------------- init: zero all stat slots + degree array ----------------
__global__ void k_init() {
    int i = blockIdx.x * 256 + threadIdx.x;
    if (i < N_) g_degi[i] = 0;
    if (i < 6 * 256) { g_sum[i] = 0.f; g_sq[i] = 0.f; }
}

// plain column stats: blockDim == C
template <int C>
__global__ void k_colstats(const float* __restrict__ X, int slot) {
    const int c = threadIdx.x;
    const int rpb = N_ / 128;
    const int r0 = blockIdx.x * rpb;
    float s = 0.f, q = 0.f;
    for (int r = r0; r < r0 + rpb; ++r) {
        float v = X[(size_t)r * C + c];
        s += v; q += v * v;
    }
    atomicAdd(&g_sum[slot * 256 + c], s);
    atomicAdd(&g_sq[slot * 256 + c], q);
}

// rownorm stats: invnorm per row (after optional leaky) + column stats of normalized rows.
template <bool LK>
__global__ void k_rownorm_stats(const float* __restrict__ X, int slot) {
    __shared__ float sp[8][128];
    __shared__ float sq[8][128];
    const int tid = threadIdx.x;
    const int wid = tid >> 5, lane = tid & 31;
    const int gw = blockIdx.x * 8 + wid;
    float4 s4 = {0.f, 0.f, 0.f, 0.f}, q4 = {0.f, 0.f, 0.f, 0.f};
    for (int r = gw; r < N_; r += 288 * 8) {
        float4 v = *(const float4*)&X[(size_t)r * 128 + lane * 4];
        if (LK) {
            v.x = v.x > 0.f ? v.x : SLOPE_ * v.x;
            v.y = v.y > 0.f ? v.y : SLOPE_ * v.y;
            v.z = v.z > 0.f ? v.z : SLOPE_ * v.z;
            v.w = v.w > 0.f ? v.w : SLOPE_ * v.w;
        }
        float ss = v.x * v.x + v.y * v.y + v.z * v.z + v.w * v.w;
#pragma unroll
        for (int o = 16; o > 0; o >>= 1) ss += __shfl_xor_sync(0xffffffffu, ss, o);
        float inv = 1.0f / fmaxf(sqrtf(ss), 1e-12f);
        if (lane == 0) g_invn[r] = inv;
        v.x *= inv; v.y *= inv; v.z *= inv; v.w *= inv;
        s4.x += v.x; s4.y += v.y; s4.z += v.z; s4.w += v.w;
        q4.x += v.x * v.x; q4.y += v.y * v.y; q4.z += v.z * v.z; q4.w += v.w * v.w;
    }
    sp[wid][lane * 4 + 0] = s4.x; sp[wid][lane * 4 + 1] = s4.y;
    sp[wid][lane * 4 + 2] = s4.z; sp[wid][lane * 4 + 3] = s4.w;
    sq[wid][lane * 4 + 0] = q4.x; sq[wid][lane * 4 + 1] = q4.y;
    sq[wid][lane * 4 + 2] = q4.z; sq[wid][lane * 4 + 3] = q4.w;
    __syncthreads();
    if (tid < 128) {
        float a = 0.f, b = 0.f;
#pragma unroll
        for (int w = 0; w < 8; ++w) { a += sp[w][tid]; b += sq[w][tid]; }
        atomicAdd(&g_sum[slot * 256 + tid], a);
        atomicAdd(&g_sq[slot * 256 + tid], b);
    }
}

// ---------------- weight prep: BN fold + bf16 hi/lo split, row-major [KPAD][M] ----------------
template <int KREAL, int KPAD, int M>
__global__ void k_prepw(const float* __restrict__ W, const float* __restrict__ bng,
                        const float* __restrict__ bnb, const float* __restrict__ bias,
                        int slot) {
    const float* su = &g_sum[slot * 256];
    const float* qu = &g_sq[slot * 256];
    constexpr int NW = M * KPAD;
    if (blockIdx.x == NW / 256) {
        int m = threadIdx.x;
        if (m < M) {
            float acc = bias ? bias[m] : 0.f;
            for (int c = 0; c < KREAL; ++c) {
                float mean = su[c] * (1.f / N_);
                float var  = qu[c] * (1.f / N_) - mean * mean;
                float scale = bng[c] * rsqrtf(var + EPS_);
                acc += (bnb[c] - mean * scale) * W[c * M + m];
            }
            g_bf[m] = acc;
        }
        return;
    }
    int e = blockIdx.x * 256 + threadIdx.x;
    int k = e / M, n = e % M;
    float w = 0.f;
    if (k < KREAL) {
        float mean = su[k] * (1.f / N_);
        float var  = qu[k] * (1.f / N_) - mean * mean;
        float scale = bng[k] * rsqrtf(var + EPS_);
        w = scale * W[k * M + n];
    }
    __nv_bfloat16 h = __float2bfloat16(w);
    __nv_bfloat16 l = __float2bfloat16(w - __bfloat162float(h));
    g_Wh[e] = h;
    g_Wl[e] = l;
}

// ---------------- tensor GEMM via wmma (bf16 hi/lo split, fp32 accum) ----------------
// Y[N,M] = epi( lk?(X[N,KREAL]) @ Wf + bf )
// EPI 0: out = leaky(acc + bf)
// EPI 1: out = (acc*invn[r] + bf) * dinv[r]
// 256 threads = 8 warps in a 4(m) x 2(n) grid. Warp tile: 32 rows x M/2 cols.
template <int KREAL, int KPAD, int M, int EPI, bool LKIN>
__global__ __launch_bounds__(256, 2)
void k_wgemm(const float* __restrict__ X, float* __restrict__ Y) {
    constexpr int KC = 64;            // K chunk
    constexpr int AS = KC + 8;        // A smem stride (halves)
    constexpr int BS = M + 8;         // B smem stride (halves)
    constexpr int MT = 2;             // m-tiles per warp (32 rows)
    constexpr int NT2 = M / 32;       // n-tiles per warp (M/2 cols)
    extern __shared__ char smraw[];
    __nv_bfloat16* Ah = (__nv_bfloat16*)smraw;          // 128*AS halves
    __nv_bfloat16* Al = Ah + 128 * AS;
    __nv_bfloat16* Bh = Al + 128 * AS;                  // KC*BS halves
    __nv_bfloat16* Bl = Bh + (size_t)KC * BS;
    float* stage = (float*)smraw;                       // reused post-compute

    const int tid = threadIdx.x, wid = tid >> 5;
    const int wm = wid & 3, wn = wid >> 2;
    const size_t row0 = (size_t)blockIdx.x * 128;

    wmma::fragment<wmma::accumulator, 16, 16, 16, float> acc[MT][NT2];
#pragma unroll
    for (int m = 0; m < MT; ++m)
#pragma unroll
        for (int n = 0; n < NT2; ++n) wmma::fill_fragment(acc[m][n], 0.0f);

    for (int c = 0; c < KPAD / KC; ++c) {
        // A chunk: 128 rows x KC cols, fp32 -> bf16 hi/lo
        for (int p = tid; p < 128 * (KC / 2); p += 256) {
            int r = p / (KC / 2), kq = p % (KC / 2);
            int kg = c * KC + kq * 2;
            float2 v = {0.f, 0.f};
            if (kg < KREAL) v = *(const float2*)&X[(row0 + r) * KREAL + kg];
            if (LKIN) {
                v.x = v.x > 0.f ? v.x : SLOPE_ * v.x;
                v.y = v.y > 0.f ? v.y : SLOPE_ * v.y;
            }
            __nv_bfloat16 h0 = __float2bfloat16(v.x);
            __nv_bfloat16 h1 = __float2bfloat16(v.y);
            __nv_bfloat16 l0 = __float2bfloat16(v.x - __bfloat162float(h0));
            __nv_bfloat16 l1 = __float2bfloat16(v.y - __bfloat162float(h1));
            *(__nv_bfloat162*)&Ah[r * AS + kq * 2] = __nv_bfloat162(h0, h1);
            *(__nv_bfloat162*)&Al[r * AS + kq * 2] = __nv_bfloat162(l0, l1);
        }
        // B chunk: copy prebuilt bf16 image rows [c*KC, c*KC+KC) x M
        for (int p = tid; p < KC * (M / 2); p += 256) {
            int k = p / (M / 2), nq = p % (M / 2);
            *(uint32_t*)&Bh[k * BS + nq * 2] = *(const uint32_t*)&g_Wh[(c * KC + k) * M + nq * 2];
            *(uint32_t*)&Bl[k * BS + nq * 2] = *(const uint32_t*)&g_Wl[(c * KC + k) * M + nq * 2];
        }
        __syncthreads();

#pragma unroll
        for (int ks = 0; ks < KC / 16; ++ks) {
            wmma::fragment<wmma::matrix_a, 16, 16, 16, __nv_bfloat16, wmma::row_major> aH[MT], aL[MT];
#pragma unroll
            for (int m = 0; m < MT; ++m) {
                int rbase = wm * 32 + m * 16;
                wmma::load_matrix_sync(aH[m], Ah + rbase * AS + ks * 16, AS);
                wmma::load_matrix_sync(aL[m], Al + rbase * AS + ks * 16, AS);
            }
#pragma unroll
            for (int n = 0; n < NT2; ++n) {
                int cbase = wn * (M / 2) + n * 16;
                wmma::fragment<wmma::matrix_b, 16, 16, 16, __nv_bfloat16, wmma::row_major> bH, bL;
                wmma::load_matrix_sync(bH, Bh + ks * 16 * BS + cbase, BS);
                wmma::load_matrix_sync(bL, Bl + ks * 16 * BS + cbase, BS);
#pragma unroll
                for (int m = 0; m < MT; ++m) {
                    wmma::mma_sync(acc[m][n], aH[m], bH, acc[m][n]);
                    wmma::mma_sync(acc[m][n], aH[m], bL, acc[m][n]);
                    wmma::mma_sync(acc[m][n], aL[m], bH, acc[m][n]);
                }
            }
        }
        __syncthreads();
    }

    // stage accumulators to smem (128 x (M+8) floats), then coalesced epi + store
#pragma unroll
    for (int m = 0; m < MT; ++m)
#pragma unroll
        for (int n = 0; n < NT2; ++n)
            wmma::store_matrix_sync(stage + (wm * 32 + m * 16) * (M + 8) + wn * (M / 2) + n * 16,
                                    acc[m][n], M + 8, wmma::mem_row_major);
    __syncthreads();

    for (int idx = tid; idx < 128 * (M / 4); idx += 256) {
        int r = idx / (M / 4), cq = idx % (M / 4);
        size_t gr = row0 + r;
        float4 v = *(float4*)&stage[r * (M + 8) + cq * 4];
        float4 b = *(const float4*)&g_bf[cq * 4];
        if (EPI == 0) {
            v.x += b.x; v.y += b.y; v.z += b.z; v.w += b.w;
            v.x = v.x > 0.f ? v.x : SLOPE_ * v.x;
            v.y = v.y > 0.f ? v.y : SLOPE_ * v.y;
            v.z = v.z > 0.f ? v.z : SLOPE_ * v.z;
            v.w = v.w > 0.f ? v.w : SLOPE_ * v.w;
        } else {
            float sr = g_invn[gr], dv = g_dinv[gr];
            v.x = (v.x * sr + b.x) * dv;
            v.y = (v.y * sr + b.y) * dv;
            v.z = (v.z * sr + b.z) * dv;
            v.w = (v.w * sr + b.w) * dv;
        }
        *(float4*)&Y[gr * M + cq * 4] = v;
    }
}

// ---------------- CSR build ----------------
__global__ void k_deg_count(const int* __restrict__ dst) {
    int e = blockIdx.x * blockDim.x + threadIdx.x;
    if (e < E_) atomicAdd(&g_degi[dst[e]], 1);
}
__global__ void k_scan1() {
    __shared__ int s[256];
    int t = threadIdx.x;
    int idx = blockIdx.x * 256 + t;
    int v = g_degi[idx];
    s[t] = v;
    __syncthreads();
#pragma unroll
    for (int off = 1; off < 256; off <<= 1) {
        int a = 0;
        if (t >= off) a = s[t - off];
        __syncthreads();
        s[t] += a;
        __syncthreads();
    }
    g_rowptr[idx] = s[t] - v;
    if (t == 255) g_blksum[blockIdx.x] = s[255];
}
__global__ void k_scan2() {
    __shared__ int s[NBLK_];
    int t = threadIdx.x;
    if (t < NBLK_) s[t] = g_blksum[t];
    __syncthreads();
    for (int off = 1; off < NBLK_; off <<= 1) {
        int a = 0;
        if (t >= off && t < NBLK_) a = s[t - off];
        __syncthreads();
        if (t < NBLK_) s[t] += a;
        __syncthreads();
    }
    if (t < NBLK_) g_blksum[t] = s[t];
}
__global__ void k_scan3() {
    int idx = blockIdx.x * 256 + threadIdx.x;
    int off = blockIdx.x == 0 ? 0 : g_blksum[blockIdx.x - 1];
    int rp = g_rowptr[idx] + off;
    g_rowptr[idx] = rp;
    g_cursor[idx] = rp;
    g_dinv[idx] = rsqrtf((float)g_degi[idx] + 1.0f);
    if (idx == 0) g_rowptr[N_] = E_;
}
__global__ void k_csr_fill(const int* __restrict__ src, const int* __restrict__ dst) {
    int e = blockIdx.x * blockDim.x + threadIdx.x;
    if (e < E_) {
        int pos = atomicAdd(&g_cursor[dst[e]], 1);
        g_col[pos] = src[e];
    }
}

// ---------------- GCN gather ----------------
__global__ void k_gather128(const float* __restrict__ Hs, const float* __restrict__ gb,
                            float* __restrict__ out) {
    int i = (int)(((size_t)blockIdx.x * blockDim.x + threadIdx.x) >> 5);
    if (i >= N_) return;
    int lane = threadIdx.x & 31;
    int beg = __ldg(&g_rowptr[i]), end = __ldg(&g_rowptr[i + 1]);
    float4 acc = *(const float4*)&Hs[(size_t)i * 128 + lane * 4];
    for (int base = beg; base < end; base += 32) {
        int e = base + lane;
        int sidx = (e < end) ? g_col[e] : 0;
        int cnt = min(32, end - base);
        int j = 0;
        for (; j + 8 <= cnt; j += 8) {
            int s0 = __shfl_sync(0xffffffffu, sidx, j);
            int s1 = __shfl_sync(0xffffffffu, sidx, j + 1);
            int s2 = __shfl_sync(0xffffffffu, sidx, j + 2);
            int s3 = __shfl_sync(0xffffffffu, sidx, j + 3);
            int s4 = __shfl_sync(0xffffffffu, sidx, j + 4);
            int s5 = __shfl_sync(0xffffffffu, sidx, j + 5);
            int s6 = __shfl_sync(0xffffffffu, sidx, j + 6);
            int s7 = __shfl_sync(0xffffffffu, sidx, j + 7);
            float4 v0 = *(const float4*)&Hs[(size_t)s0 * 128 + lane * 4];
            float4 v1 = *(const float4*)&Hs[(size_t)s1 * 128 + lane * 4];
            float4 v2 = *(const float4*)&Hs[(size_t)s2 * 128 + lane * 4];
            float4 v3 = *(const float4*)&Hs[(size_t)s3 * 128 + lane * 4];
            float4 v4 = *(const float4*)&Hs[(size_t)s4 * 128 + lane * 4];
            float4 v5 = *(const float4*)&Hs[(size_t)s5 * 128 + lane * 4];
            float4 v6 = *(const float4*)&Hs[(size_t)s6 * 128 + lane * 4];
            float4 v7 = *(const float4*)&Hs[(size_t)s7 * 128 + lane * 4];
            acc.x += (v0.x + v1.x) + (v2.x + v3.x) + ((v4.x + v5.x) + (v6.x + v7.x));
            acc.y += (v0.y + v1.y) + (v2.y + v3.y) + ((v4.y + v5.y) + (v6.y + v7.y));
            acc.z += (v0.z + v1.z) + (v2.z + v3.z) + ((v4.z + v5.z) + (v6.z + v7.z));
            acc.w += (v0.w + v1.w) + (v2.w + v3.w) + ((v4.w + v5.w) + (v6.w + v7.w));
        }
        for (; j < cnt; ++j) {
            int s = __shfl_sync(0xffffffffu, sidx, j);
            float4 v = *(const float4*)&Hs[(size_t)s * 128 + lane * 4];
            acc.x += v.x; acc.y += v.y; acc.z += v.z; acc.w += v.w;
        }
    }
    float di = g_dinv[i];
    float4 b = *(const float4*)&gb[lane * 4];
    acc.x = b.x + di * acc.x;
    acc.y = b.y + di * acc.y;
    acc.z = b.z + di * acc.z;
    acc.w = b.w + di * acc.w;
    *(float4*)&out[(size_t)i * 128 + lane * 4] = acc;
}

__global__ void k_gather64(const float* __restrict__ Hs, const float* __restrict__ gb,
                           float* __restrict__ out) {
    int i = (int)(((size_t)blockIdx.x * blockDim.x + threadIdx.x) >> 5);
    if (i >= N_) return;
    int lane = threadIdx.x & 31;
    int beg = __ldg(&g_rowptr[i]), end = __ldg(&g_rowptr[i + 1]);
    float2 acc = *(const float2*)&Hs[(size_t)i * 64 + lane * 2];
    for (int base = beg; base < end; base += 32) {
        int e = base + lane;
        int sidx = (e < end) ? g_col[e] : 0;
        int cnt = min(32, end - base);
        int j = 0;
        for (; j + 8 <= cnt; j += 8) {
            int s0 = __shfl_sync(0xffffffffu, sidx, j);
            int s1 = __shfl_sync(0xffffffffu, sidx, j + 1);
            int s2 = __shfl_sync(0xffffffffu, sidx, j + 2);
            int s3 = __shfl_sync(0xffffffffu, sidx, j + 3);
            int s4 = __shfl_sync(0xffffffffu, sidx, j + 4);
            int s5 = __shfl_sync(0xffffffffu, sidx, j + 5);
            int s6 = __shfl_sync(0xffffffffu, sidx, j + 6);
            int s7 = __shfl_sync(0xffffffffu, sidx, j + 7);
            float2 v0 = *(const float2*)&Hs[(size_t)s0 * 64 + lane * 2];
            float2 v1 = *(const float2*)&Hs[(size_t)s1 * 64 + lane * 2];
            float2 v2 = *(const float2*)&Hs[(size_t)s2 * 64 + lane * 2];
            float2 v3 = *(const float2*)&Hs[(size_t)s3 * 64 + lane * 2];
            float2 v4 = *(const float2*)&Hs[(size_t)s4 * 64 + lane * 2];
            float2 v5 = *(const float2*)&Hs[(size_t)s5 * 64 + lane * 2];
            float2 v6 = *(const float2*)&Hs[(size_t)s6 * 64 + lane * 2];
            float2 v7 = *(const float2*)&Hs[(size_t)s7 * 64 + lane * 2];
            acc.x += (v0.x + v1.x) + (v2.x + v3.x) + ((v4.x + v5.x) + (v6.x + v7.x));
            acc.y += (v0.y + v1.y) + (v2.y + v3.y) + ((v4.y + v5.y) + (v6.y + v7.y));
        }
        for (; j < cnt; ++j) {
            int s = __shfl_sync(0xffffffffu, sidx, j);
            float2 v = *(const float2*)&Hs[(size_t)s * 64 + lane * 2];
            acc.x += v.x; acc.y += v.y;
        }
    }
    float di = g_dinv[i];
    float2 b = *(const float2*)&gb[lane * 2];
    acc.x = b.x + di * acc.x;
    acc.y = b.y + di * acc.y;
    *(float2*)&out[(size_t)i * 64 + lane * 2] = acc;
}

// ---------------- depthwise 5x5 conv ----------------
__global__ void k_dwconv(const float* __restrict__ In, const float* __restrict__ dw,
                         const float* __restrict__ db, float* __restrict__ Out) {
    __shared__ float wt[25 * 64];
    int tid = threadIdx.x;
    for (int i = tid; i < 25 * 64; i += 256) {
        int t = i >> 6, c = i & 63;
        wt[i] = dw[c * 25 + t];
    }
    __syncthreads();
    int c4 = tid & 15;
    int p = blockIdx.x * 16 + (tid >> 4);
    int y = p / Ww_, x = p % Ww_;
    float4 acc = {0.f, 0.f, 0.f, 0.f};
#pragma unroll
    for (int ky = 0; ky < 5; ++ky) {
        int yy = y + ky - 2;
        if (yy < 0 || yy >= Hh_) continue;
#pragma unroll
        for (int kx = 0; kx < 5; ++kx) {
            int xx = x + kx - 2;
            if (xx < 0 || xx >= Ww_) continue;
            float4 v  = *(const float4*)&In[((size_t)yy * Ww_ + xx) * 64 + c4 * 4];
            float4 wv = *(const float4*)&wt[(ky * 5 + kx) * 64 + c4 * 4];
            acc.x += v.x * wv.x; acc.y += v.y * wv.y;
            acc.z += v.z * wv.z; acc.w += v.w * wv.w;
        }
    }
    float4 b = *(const float4*)&db[c4 * 4];
    acc.x += b.x; acc.y += b.y; acc.z += b.z; acc.w += b.w;
    acc.x = acc.x > 0.f ? acc.x : SLOPE_ * acc.x;
    acc.y = acc.y > 0.f ? acc.y : SLOPE_ * acc.y;
    acc.z = acc.z > 0.f ? acc.z : SLOPE_ * acc.z;
    acc.w = acc.w > 0.f ? acc.w : SLOPE_ * acc.w;
    *(float4*)&Out[(size_t)p * 64 + c4 * 4] = acc;
}

// ---------------- head: leaky(G) concat Cn -> linear -> softmax ----------------
__global__ void k_final(const float* __restrict__ G, const float* __restrict__ Cn,
                        const float* __restrict__ lw, const float* __restrict__ lb,
                        float* __restrict__ out) {
    __shared__ float slw[128 * 16];
    __shared__ float slb[16];
    __shared__ float sg[16][64];
    __shared__ float sc[16][64];
    int tid = threadIdx.x;
    for (int i = tid; i < 2048; i += 256) slw[i] = lw[i];
    if (tid < 16) slb[tid] = lb[tid];
    int tx = tid & 15, ty = tid >> 4;
    size_t row = (size_t)blockIdx.x * 16 + ty;
    float4 gv = *(const float4*)&G[row * 64 + tx * 4];
    gv.x = gv.x > 0.f ? gv.x : SLOPE_ * gv.x;
    gv.y = gv.y > 0.f ? gv.y : SLOPE_ * gv.y;
    gv.z = gv.z > 0.f ? gv.z : SLOPE_ * gv.z;
    gv.w = gv.w > 0.f ? gv.w : SLOPE_ * gv.w;
    *(float4*)&sg[ty][tx * 4] = gv;
    *(float4*)&sc[ty][tx * 4] = *(const float4*)&Cn[row * 64 + tx * 4];
    __syncthreads();
    float acc = slb[tx];
#pragma unroll 4
    for (int k = 0; k < 64; ++k) acc += sg[ty][k] * slw[k * 16 + tx];
#pragma unroll 4
    for (int k = 0; k < 64; ++k) acc += sc[ty][k] * slw[(64 + k) * 16 + tx];
    float mx = acc;
#pragma unroll
    for (int o = 8; o > 0; o >>= 1) mx = fmaxf(mx, __shfl_xor_sync(0xffffffffu, mx, o));
    float e = __expf(acc - mx);
    float sum = e;
#pragma unroll
    for (int o = 8; o > 0; o >>= 1) sum += __shfl_xor_sync(0xffffffffu, sum, o);
    out[row * 16 + tx] = e / sum;
}

// ---------------- host launchers ----------------
template <int KREAL, int KPAD, int M, int EPI, bool LKIN>
static void launch_wgemm(const float* X, float* Y) {
    constexpr int KC = 64;
    constexpr size_t comp = (size_t)(2 * 128 * (KC + 8) + 2 * KC * (M + 8)) * 2;
    constexpr size_t stg  = (size_t)128 * (M + 8) * 4;
    constexpr size_t smem = comp > stg ? comp : stg;
    cudaFuncSetAttribute(k_wgemm<KREAL, KPAD, M, EPI, LKIN>,
                         cudaFuncAttributeMaxDynamicSharedMemorySize, (int)smem);
    k_wgemm<KREAL, KPAD, M, EPI, LKIN><<<N_ / 128, 256, smem>>>(X, Y);
}

extern "C" void kernel_launch(void* const* d_in, const int* in_sizes, int n_in,
                              void* d_out, int out_size) {
    const float* x   = (const float*)d_in[0];
    const int*   ei  = (const int*)d_in[1];
    const int*   src = ei;
    const int*   dst = ei + E_;
    const float* dn_bn1_g = (const float*)d_in[2];
    const float* dn_bn1_b = (const float*)d_in[3];
    const float* dn_w1    = (const float*)d_in[4];
    const float* dn_b1    = (const float*)d_in[5];
    const float* dn_bn2_g = (const float*)d_in[6];
    const float* dn_bn2_b = (const float*)d_in[7];
    const float* dn_w2    = (const float*)d_in[8];
    const float* dn_b2    = (const float*)d_in[9];
    const float* cnn_bn_g = (const float*)d_in[10];
    const float* cnn_bn_b = (const float*)d_in[11];
    const float* cnn_pw   = (const float*)d_in[12];
    const float* cnn_dw   = (const float*)d_in[13];
    const float* cnn_db   = (const float*)d_in[14];
    const float* g1_bn_g  = (const float*)d_in[15];
    const float* g1_bn_b  = (const float*)d_in[16];
    const float* g1_w     = (const float*)d_in[17];
    const float* g1_b     = (const float*)d_in[18];
    const float* g2_bn_g  = (const float*)d_in[19];
    const float* g2_bn_b  = (const float*)d_in[20];
    const float* g2_w     = (const float*)d_in[21];
    const float* g2_b     = (const float*)d_in[22];
    const float* g3_bn_g  = (const float*)d_in[23];
    const float* g3_bn_b  = (const float*)d_in[24];
    const float* g3_w     = (const float*)d_in[25];
    const float* g3_b     = (const float*)d_in[26];
    const float* lin_w    = (const float*)d_in[27];
    const float* lin_b    = (const float*)d_in[28];
    float* out = (float*)d_out;

    float *pP, *pQ, *pH, *pC, *pCR;
    cudaGetSymbolAddress((void**)&pP, g_P);
    cudaGetSymbolAddress((void**)&pQ, g_Q);
    cudaGetSymbolAddress((void**)&pH, g_Hm);
    cudaGetSymbolAddress((void**)&pC, g_cnn);
    cudaGetSymbolAddress((void**)&pCR, g_cnnres);

    // denoise layer 1 (launch #4 = big tensor GEMM, for profiling)
    k_init<<<NBLK_ + 1, 256>>>();
    k_colstats<200><<<128, 200>>>(x, 0);
    k_prepw<200, 256, 128><<<129, 256>>>(dn_w1, dn_bn1_g, dn_bn1_b, dn_b1, 0);
    launch_wgemm<200, 256, 128, 0, false>(x, pQ);

    // CSR build + dinv
    k_deg_count<<<(E_ + 255) / 256, 256>>>(dst);
    k_scan1<<<NBLK_, 256>>>();
    k_scan2<<<1, 1024>>>();
    k_scan3<<<NBLK_, 256>>>();
    k_csr_fill<<<(E_ + 255) / 256, 256>>>(src, dst);

    // denoise layer 2
    k_colstats<128><<<128, 128>>>(pQ, 1);
    k_prepw<128, 128, 128><<<65, 256>>>(dn_w2, dn_bn2_g, dn_bn2_b, dn_b2, 1);
    launch_wgemm<128, 128, 128, 0, false>(pQ, pP);    // pP = clean

    // CNN branch
    k_colstats<128><<<128, 128>>>(pP, 2);
    k_prepw<128, 128, 64><<<33, 256>>>(cnn_pw, cnn_bn_g, cnn_bn_b, nullptr, 2);
    launch_wgemm<128, 128, 64, 0, false>(pP, pC);
    k_dwconv<<<N_ / 16, 256>>>(pC, cnn_dw, cnn_db, pCR);

    // GCN layer 1
    k_rownorm_stats<false><<<288, 256>>>(pP, 3);
    k_prepw<128, 128, 128><<<65, 256>>>(g1_w, g1_bn_g, g1_bn_b, nullptr, 3);
    launch_wgemm<128, 128, 128, 1, false>(pP, pH);
    k_gather128<<<(N_ * 32) / 256, 256>>>(pH, g1_b, pP);

    // GCN layer 2
    k_rownorm_stats<true><<<288, 256>>>(pP, 4);
    k_prepw<128, 128, 128><<<65, 256>>>(g2_w, g2_bn_g, g2_bn_b, nullptr, 4);
    launch_wgemm<128, 128, 128, 1, true>(pP, pH);
    k_gather128<<<(N_ * 32) / 256, 256>>>(pH, g2_b, pP);

    // GCN layer 3 (128 -> 64)
    k_rownorm_stats<true><<<288, 256>>>(pP, 5);
    k_prepw<128, 128, 64><<<33, 256>>>(g3_w, g3_bn_g, g3_bn_b, nullptr, 5);
    launch_wgemm<128, 128, 64, 1, true>(pP, pH);
    k_gather64<<<(N_ * 32) / 256, 256>>>(pH, g3_b, pP);

    // head
    k_final<<<N_ / 16, 256>>>(pP, pCR, lin_w, lin_b, out);
}

// round 7
// speedup vs baseline: 1.7333x; 1.1939x over previous
#include <cuda_runtime.h>
#include <cuda_bf16.h>
#include <mma.h>
#include <cstdint>
#include <cstddef>

using namespace nvcuda;

// ---------------- problem constants ----------------
#define Hh_ 384
#define Ww_ 384
#define C_ 200
#define N_ 147456           // Hh_*Ww_
#define E_ 1179648
#define HIDE_ 128
#define OUT_ 64
#define NCLS_ 16
#define EPS_ 1e-5f
#define SLOPE_ 0.01f
#define NBLK_ 576           // N_/256

// ---------------- scratch (device globals; no allocation allowed) ----------------
__device__ float g_P[(size_t)N_ * 128];
__device__ float g_Q[(size_t)N_ * 128];
__device__ float g_Hm[(size_t)N_ * 128];
__device__ float g_cnn[(size_t)N_ * 64];
__device__ float g_cnnres[(size_t)N_ * 64];
__device__ float g_dinv[N_];
__device__ float g_invn[N_];
__device__ float g_sum[6 * 256];
__device__ float g_sq[6 * 256];
__device__ float g_bf[128];
__device__ __nv_bfloat16 g_Wh[256 * 128];   // folded weights hi, row-major [KPAD][M]
__device__ __nv_bfloat16 g_Wl[256 * 128];   // folded weights lo
// CSR
__device__ int g_degi[N_];
__device__ int g_rowptr[N_ + 1];
__device__ int g_cursor[N_];
__device__ int g_blksum[NBLK_];
__device__ int g_col[E_];

// ---------------- init: zero all stat slots + degree array ----------------
__global__ void k_init() {
    int i = blockIdx.x * 256 + threadIdx.x;
    if (i < N_) g_degi[i] = 0;
    if (i < 6 * 256) { g_sum[i] = 0.f; g_sq[i] = 0.f; }
}

// plain column stats (only used for raw input x): blockDim == C
template <int C>
__global__ void k_colstats(const float* __restrict__ X, int slot) {
    const int c = threadIdx.x;
    const int rpb = N_ / 128;
    const int r0 = blockIdx.x * rpb;
    float s = 0.f, q = 0.f;
    for (int r = r0; r < r0 + rpb; ++r) {
        float v = X[(size_t)r * C + c];
        s += v; q += v * v;
    }
    atomicAdd(&g_sum[slot * 256 + c], s);
    atomicAdd(&g_sq[slot * 256 + c], q);
}

// ---------------- weight prep: BN fold + bf16 hi/lo split, row-major [KPAD][M] ----------------
template <int KREAL, int KPAD, int M>
__global__ void k_prepw(const float* __restrict__ W, const float* __restrict__ bng,
                        const float* __restrict__ bnb, const float* __restrict__ bias,
                        int slot) {
    const float* su = &g_sum[slot * 256];
    const float* qu = &g_sq[slot * 256];
    constexpr int NW = M * KPAD;
    if (blockIdx.x == NW / 256) {
        int m = threadIdx.x;
        if (m < M) {
            float acc = bias ? bias[m] : 0.f;
            for (int c = 0; c < KREAL; ++c) {
                float mean = su[c] * (1.f / N_);
                float var  = qu[c] * (1.f / N_) - mean * mean;
                float scale = bng[c] * rsqrtf(var + EPS_);
                acc += (bnb[c] - mean * scale) * W[c * M + m];
            }
            g_bf[m] = acc;
        }
        return;
    }
    int e = blockIdx.x * 256 + threadIdx.x;
    int k = e / M, n = e % M;
    float w = 0.f;
    if (k < KREAL) {
        float mean = su[k] * (1.f / N_);
        float var  = qu[k] * (1.f / N_) - mean * mean;
        float scale = bng[k] * rsqrtf(var + EPS_);
        w = scale * W[k * M + n];
    }
    __nv_bfloat16 h = __float2bfloat16(w);
    __nv_bfloat16 l = __float2bfloat16(w - __bfloat162float(h));
    g_Wh[e] = h;
    g_Wl[e] = l;
}

// ---------------- tensor GEMM via wmma (bf16 hi/lo split, fp32 accum) ----------------
// Y[N,M] = epi( X[N,KREAL] @ Wf + bf )
// EPI 0: out = leaky(acc + bf)
// EPI 1: out = (acc*invn[r] + bf) * dinv[r]
// STAT (EPI0, M=128 only): 1 = plain col stats -> slotA;
//                          2 = plain -> slotA AND invn + normalized col stats -> slotB
// 256 threads = 8 warps in a 4(m) x 2(n) grid. Warp tile: 32 rows x M/2 cols.
template <int KREAL, int KPAD, int M, int EPI, int STAT>
__global__ __launch_bounds__(256, 2)
void k_wgemm(const float* __restrict__ X, float* __restrict__ Y, int slotA, int slotB) {
    constexpr int KC = 64;            // K chunk
    constexpr int AS = KC + 8;        // A smem stride (halves)
    constexpr int BS = M + 8;         // B smem stride (halves)
    constexpr int MT = 2;             // m-tiles per warp (32 rows)
    constexpr int NT2 = M / 32;       // n-tiles per warp (M/2 cols)
    extern __shared__ char smraw[];
    __nv_bfloat16* Ah = (__nv_bfloat16*)smraw;          // 128*AS halves
    __nv_bfloat16* Al = Ah + 128 * AS;
    __nv_bfloat16* Bh = Al + 128 * AS;                  // KC*BS halves
    __nv_bfloat16* Bl = Bh + (size_t)KC * BS;
    float* stage = (float*)smraw;                       // reused post-compute

    const int tid = threadIdx.x, wid = tid >> 5, lane = tid & 31;
    const int wm = wid & 3, wn = wid >> 2;
    const size_t row0 = (size_t)blockIdx.x * 128;

    wmma::fragment<wmma::accumulator, 16, 16, 16, float> acc[MT][NT2];
#pragma unroll
    for (int m = 0; m < MT; ++m)
#pragma unroll
        for (int n = 0; n < NT2; ++n) wmma::fill_fragment(acc[m][n], 0.0f);

    for (int c = 0; c < KPAD / KC; ++c) {
        // A chunk: 128 rows x KC cols, fp32 -> bf16 hi/lo
        for (int p = tid; p < 128 * (KC / 2); p += 256) {
            int r = p / (KC / 2), kq = p % (KC / 2);
            int kg = c * KC + kq * 2;
            float2 v = {0.f, 0.f};
            if (kg < KREAL) v = *(const float2*)&X[(row0 + r) * KREAL + kg];
            __nv_bfloat16 h0 = __float2bfloat16(v.x);
            __nv_bfloat16 h1 = __float2bfloat16(v.y);
            __nv_bfloat16 l0 = __float2bfloat16(v.x - __bfloat162float(h0));
            __nv_bfloat16 l1 = __float2bfloat16(v.y - __bfloat162float(h1));
            *(__nv_bfloat162*)&Ah[r * AS + kq * 2] = __nv_bfloat162(h0, h1);
            *(__nv_bfloat162*)&Al[r * AS + kq * 2] = __nv_bfloat162(l0, l1);
        }
        // B chunk: copy prebuilt bf16 image rows [c*KC, c*KC+KC) x M
        for (int p = tid; p < KC * (M / 2); p += 256) {
            int k = p / (M / 2), nq = p % (M / 2);
            *(uint32_t*)&Bh[k * BS + nq * 2] = *(const uint32_t*)&g_Wh[(c * KC + k) * M + nq * 2];
            *(uint32_t*)&Bl[k * BS + nq * 2] = *(const uint32_t*)&g_Wl[(c * KC + k) * M + nq * 2];
        }
        __syncthreads();

#pragma unroll
        for (int ks = 0; ks < KC / 16; ++ks) {
            wmma::fragment<wmma::matrix_a, 16, 16, 16, __nv_bfloat16, wmma::row_major> aH[MT], aL[MT];
#pragma unroll
            for (int m = 0; m < MT; ++m) {
                int rbase = wm * 32 + m * 16;
                wmma::load_matrix_sync(aH[m], Ah + rbase * AS + ks * 16, AS);
                wmma::load_matrix_sync(aL[m], Al + rbase * AS + ks * 16, AS);
            }
#pragma unroll
            for (int n = 0; n < NT2; ++n) {
                int cbase = wn * (M / 2) + n * 16;
                wmma::fragment<wmma::matrix_b, 16, 16, 16, __nv_bfloat16, wmma::row_major> bH, bL;
                wmma::load_matrix_sync(bH, Bh + ks * 16 * BS + cbase, BS);
                wmma::load_matrix_sync(bL, Bl + ks * 16 * BS + cbase, BS);
#pragma unroll
                for (int m = 0; m < MT; ++m) {
                    wmma::mma_sync(acc[m][n], aH[m], bH, acc[m][n]);
                    wmma::mma_sync(acc[m][n], aH[m], bL, acc[m][n]);
                    wmma::mma_sync(acc[m][n], aL[m], bH, acc[m][n]);
                }
            }
        }
        __syncthreads();
    }

    // stage accumulators to smem (128 x (M+8) floats), then coalesced epi + store
#pragma unroll
    for (int m = 0; m < MT; ++m)
#pragma unroll
        for (int n = 0; n < NT2; ++n)
            wmma::store_matrix_sync(stage + (wm * 32 + m * 16) * (M + 8) + wn * (M / 2) + n * 16,
                                    acc[m][n], M + 8, wmma::mem_row_major);
    __syncthreads();

    float s1[4] = {0.f, 0.f, 0.f, 0.f}, q1[4] = {0.f, 0.f, 0.f, 0.f};
    float s2[4] = {0.f, 0.f, 0.f, 0.f}, q2[4] = {0.f, 0.f, 0.f, 0.f};

    for (int idx = tid; idx < 128 * (M / 4); idx += 256) {
        int r = idx / (M / 4), cq = idx % (M / 4);
        size_t gr = row0 + r;
        float4 v = *(float4*)&stage[r * (M + 8) + cq * 4];
        float4 b = *(const float4*)&g_bf[cq * 4];
        if (EPI == 0) {
            v.x += b.x; v.y += b.y; v.z += b.z; v.w += b.w;
            v.x = v.x > 0.f ? v.x : SLOPE_ * v.x;
            v.y = v.y > 0.f ? v.y : SLOPE_ * v.y;
            v.z = v.z > 0.f ? v.z : SLOPE_ * v.z;
            v.w = v.w > 0.f ? v.w : SLOPE_ * v.w;
            if (STAT >= 1) {
                s1[0] += v.x; s1[1] += v.y; s1[2] += v.z; s1[3] += v.w;
                q1[0] += v.x * v.x; q1[1] += v.y * v.y; q1[2] += v.z * v.z; q1[3] += v.w * v.w;
            }
            if (STAT == 2) {
                // M==128: warp covers the full row
                float ss = v.x * v.x + v.y * v.y + v.z * v.z + v.w * v.w;
#pragma unroll
                for (int o = 16; o > 0; o >>= 1) ss += __shfl_xor_sync(0xffffffffu, ss, o);
                float inv = 1.0f / fmaxf(sqrtf(ss), 1e-12f);
                if (lane == 0) g_invn[gr] = inv;
                float nx = v.x * inv, ny = v.y * inv, nz = v.z * inv, nw = v.w * inv;
                s2[0] += nx; s2[1] += ny; s2[2] += nz; s2[3] += nw;
                q2[0] += nx * nx; q2[1] += ny * ny; q2[2] += nz * nz; q2[3] += nw * nw;
            }
        } else {
            float sr = g_invn[gr], dv = g_dinv[gr];
            v.x = (v.x * sr + b.x) * dv;
            v.y = (v.y * sr + b.y) * dv;
            v.z = (v.z * sr + b.z) * dv;
            v.w = (v.w * sr + b.w) * dv;
        }
        *(float4*)&Y[gr * M + cq * 4] = v;
    }

    if (EPI == 0 && STAT >= 1) {
        __syncthreads();
        float* red = stage;           // 4 regions of [8][128] floats = 16KB
#pragma unroll
        for (int j = 0; j < 4; ++j) {
            red[0 * 1024 + wid * 128 + lane * 4 + j] = s1[j];
            red[1 * 1024 + wid * 128 + lane * 4 + j] = q1[j];
            if (STAT == 2) {
                red[2 * 1024 + wid * 128 + lane * 4 + j] = s2[j];
                red[3 * 1024 + wid * 128 + lane * 4 + j] = q2[j];
            }
        }
        __syncthreads();
        if (tid < 128) {
            float a = 0.f, b = 0.f, c2 = 0.f, d2 = 0.f;
#pragma unroll
            for (int w = 0; w < 8; ++w) {
                a  += red[0 * 1024 + w * 128 + tid];
                b  += red[1 * 1024 + w * 128 + tid];
                if (STAT == 2) {
                    c2 += red[2 * 1024 + w * 128 + tid];
                    d2 += red[3 * 1024 + w * 128 + tid];
                }
            }
            atomicAdd(&g_sum[slotA * 256 + tid], a);
            atomicAdd(&g_sq[slotA * 256 + tid], b);
            if (STAT == 2) {
                atomicAdd(&g_sum[slotB * 256 + tid], c2);
                atomicAdd(&g_sq[slotB * 256 + tid], d2);
            }
        }
    }
}

// ---------------- CSR build ----------------
__global__ void k_deg_count(const int* __restrict__ dst) {
    int e = blockIdx.x * blockDim.x + threadIdx.x;
    if (e < E_) atomicAdd(&g_degi[dst[e]], 1);
}
__global__ void k_scan1() {
    __shared__ int s[256];
    int t = threadIdx.x;
    int idx = blockIdx.x * 256 + t;
    int v = g_degi[idx];
    s[t] = v;
    __syncthreads();
#pragma unroll
    for (int off = 1; off < 256; off <<= 1) {
        int a = 0;
        if (t >= off) a = s[t - off];
        __syncthreads();
        s[t] += a;
        __syncthreads();
    }
    g_rowptr[idx] = s[t] - v;
    if (t == 255) g_blksum[blockIdx.x] = s[255];
}
__global__ void k_scan2() {
    __shared__ int s[NBLK_];
    int t = threadIdx.x;
    if (t < NBLK_) s[t] = g_blksum[t];
    __syncthreads();
    for (int off = 1; off < NBLK_; off <<= 1) {
        int a = 0;
        if (t >= off && t < NBLK_) a = s[t - off];
        __syncthreads();
        if (t < NBLK_) s[t] += a;
        __syncthreads();
    }
    if (t < NBLK_) g_blksum[t] = s[t];
}
__global__ void k_scan3() {
    int idx = blockIdx.x * 256 + threadIdx.x;
    int off = blockIdx.x == 0 ? 0 : g_blksum[blockIdx.x - 1];
    int rp = g_rowptr[idx] + off;
    g_rowptr[idx] = rp;
    g_cursor[idx] = rp;
    g_dinv[idx] = rsqrtf((float)g_degi[idx] + 1.0f);
    if (idx == 0) g_rowptr[N_] = E_;
}
__global__ void k_csr_fill(const int* __restrict__ src, const int* __restrict__ dst) {
    int e = blockIdx.x * blockDim.x + threadIdx.x;
    if (e < E_) {
        int pos = atomicAdd(&g_cursor[dst[e]], 1);
        g_col[pos] = src[e];
    }
}

// ---------------- GCN gather (fused: bias + scale + leaky [+ rownorm stats]) ----------------
// out[i] = leaky(gb + dinv[i] * (Hs[i] + sum_nbr Hs[s]))
// RSTAT: also write invn[i] and accumulate normalized column stats into slot.
// grid 1152 x 256: 9216 warps, each handles 16 nodes.
template <bool RSTAT>
__global__ void k_gather128(const float* __restrict__ Hs, const float* __restrict__ gb,
                            float* __restrict__ out, int slot) {
    __shared__ float sred[2][8][128];
    const int tid = threadIdx.x, wid = tid >> 5, lane = tid & 31;
    const float4 b = *(const float4*)&gb[lane * 4];
    float4 s4 = {0.f, 0.f, 0.f, 0.f}, q4 = {0.f, 0.f, 0.f, 0.f};

    for (int i = blockIdx.x * 8 + wid; i < N_; i += 9216) {
        int beg = __ldg(&g_rowptr[i]), end = __ldg(&g_rowptr[i + 1]);
        float4 acc = *(const float4*)&Hs[(size_t)i * 128 + lane * 4];
        for (int base = beg; base < end; base += 32) {
            int e = base + lane;
            int sidx = (e < end) ? g_col[e] : 0;
            int cnt = min(32, end - base);
            int j = 0;
            for (; j + 8 <= cnt; j += 8) {
                int s0 = __shfl_sync(0xffffffffu, sidx, j);
                int s1 = __shfl_sync(0xffffffffu, sidx, j + 1);
                int s2 = __shfl_sync(0xffffffffu, sidx, j + 2);
                int s3 = __shfl_sync(0xffffffffu, sidx, j + 3);
                int s4i = __shfl_sync(0xffffffffu, sidx, j + 4);
                int s5 = __shfl_sync(0xffffffffu, sidx, j + 5);
                int s6 = __shfl_sync(0xffffffffu, sidx, j + 6);
                int s7 = __shfl_sync(0xffffffffu, sidx, j + 7);
                float4 v0 = *(const float4*)&Hs[(size_t)s0 * 128 + lane * 4];
                float4 v1 = *(const float4*)&Hs[(size_t)s1 * 128 + lane * 4];
                float4 v2 = *(const float4*)&Hs[(size_t)s2 * 128 + lane * 4];
                float4 v3 = *(const float4*)&Hs[(size_t)s3 * 128 + lane * 4];
                float4 v4 = *(const float4*)&Hs[(size_t)s4i * 128 + lane * 4];
                float4 v5 = *(const float4*)&Hs[(size_t)s5 * 128 + lane * 4];
                float4 v6 = *(const float4*)&Hs[(size_t)s6 * 128 + lane * 4];
                float4 v7 = *(const float4*)&Hs[(size_t)s7 * 128 + lane * 4];
                acc.x += (v0.x + v1.x) + (v2.x + v3.x) + ((v4.x + v5.x) + (v6.x + v7.x));
                acc.y += (v0.y + v1.y) + (v2.y + v3.y) + ((v4.y + v5.y) + (v6.y + v7.y));
                acc.z += (v0.z + v1.z) + (v2.z + v3.z) + ((v4.z + v5.z) + (v6.z + v7.z));
                acc.w += (v0.w + v1.w) + (v2.w + v3.w) + ((v4.w + v5.w) + (v6.w + v7.w));
            }
            for (; j < cnt; ++j) {
                int s = __shfl_sync(0xffffffffu, sidx, j);
                float4 v = *(const float4*)&Hs[(size_t)s * 128 + lane * 4];
                acc.x += v.x; acc.y += v.y; acc.z += v.z; acc.w += v.w;
            }
        }
        float di = g_dinv[i];
        acc.x = b.x + di * acc.x;
        acc.y = b.y + di * acc.y;
        acc.z = b.z + di * acc.z;
        acc.w = b.w + di * acc.w;
        acc.x = acc.x > 0.f ? acc.x : SLOPE_ * acc.x;
        acc.y = acc.y > 0.f ? acc.y : SLOPE_ * acc.y;
        acc.z = acc.z > 0.f ? acc.z : SLOPE_ * acc.z;
        acc.w = acc.w > 0.f ? acc.w : SLOPE_ * acc.w;
        if (RSTAT) {
            float ss = acc.x * acc.x + acc.y * acc.y + acc.z * acc.z + acc.w * acc.w;
#pragma unroll
            for (int o = 16; o > 0; o >>= 1) ss += __shfl_xor_sync(0xffffffffu, ss, o);
            float inv = 1.0f / fmaxf(sqrtf(ss), 1e-12f);
            if (lane == 0) g_invn[i] = inv;
            float nx = acc.x * inv, ny = acc.y * inv, nz = acc.z * inv, nw = acc.w * inv;
            s4.x += nx; s4.y += ny; s4.z += nz; s4.w += nw;
            q4.x += nx * nx; q4.y += ny * ny; q4.z += nz * nz; q4.w += nw * nw;
        }
        *(float4*)&out[(size_t)i * 128 + lane * 4] = acc;
    }

    if (RSTAT) {
        sred[0][wid][lane * 4 + 0] = s4.x; sred[0][wid][lane * 4 + 1] = s4.y;
        sred[0][wid][lane * 4 + 2] = s4.z; sred[0][wid][lane * 4 + 3] = s4.w;
        sred[1][wid][lane * 4 + 0] = q4.x; sred[1][wid][lane * 4 + 1] = q4.y;
        sred[1][wid][lane * 4 + 2] = q4.z; sred[1][wid][lane * 4 + 3] = q4.w;
        __syncthreads();
        if (tid < 128) {
            float a = 0.f, b2 = 0.f;
#pragma unroll
            for (int w = 0; w < 8; ++w) { a += sred[0][w][tid]; b2 += sred[1][w][tid]; }
            atomicAdd(&g_sum[slot * 256 + tid], a);
            atomicAdd(&g_sq[slot * 256 + tid], b2);
        }
    }
}

// gather64: bias + scale + leaky fused (k_final no longer applies leaky)
__global__ void k_gather64(const float* __restrict__ Hs, const float* __restrict__ gb,
                           float* __restrict__ out) {
    int i = (int)(((size_t)blockIdx.x * blockDim.x + threadIdx.x) >> 5);
    if (i >= N_) return;
    int lane = threadIdx.x & 31;
    int beg = __ldg(&g_rowptr[i]), end = __ldg(&g_rowptr[i + 1]);
    float2 acc = *(const float2*)&Hs[(size_t)i * 64 + lane * 2];
    for (int base = beg; base < end; base += 32) {
        int e = base + lane;
        int sidx = (e < end) ? g_col[e] : 0;
        int cnt = min(32, end - base);
        int j = 0;
        for (; j + 8 <= cnt; j += 8) {
            int s0 = __shfl_sync(0xffffffffu, sidx, j);
            int s1 = __shfl_sync(0xffffffffu, sidx, j + 1);
            int s2 = __shfl_sync(0xffffffffu, sidx, j + 2);
            int s3 = __shfl_sync(0xffffffffu, sidx, j + 3);
            int s4 = __shfl_sync(0xffffffffu, sidx, j + 4);
            int s5 = __shfl_sync(0xffffffffu, sidx, j + 5);
            int s6 = __shfl_sync(0xffffffffu, sidx, j + 6);
            int s7 = __shfl_sync(0xffffffffu, sidx, j + 7);
            float2 v0 = *(const float2*)&Hs[(size_t)s0 * 64 + lane * 2];
            float2 v1 = *(const float2*)&Hs[(size_t)s1 * 64 + lane * 2];
            float2 v2 = *(const float2*)&Hs[(size_t)s2 * 64 + lane * 2];
            float2 v3 = *(const float2*)&Hs[(size_t)s3 * 64 + lane * 2];
            float2 v4 = *(const float2*)&Hs[(size_t)s4 * 64 + lane * 2];
            float2 v5 = *(const float2*)&Hs[(size_t)s5 * 64 + lane * 2];
            float2 v6 = *(const float2*)&Hs[(size_t)s6 * 64 + lane * 2];
            float2 v7 = *(const float2*)&Hs[(size_t)s7 * 64 + lane * 2];
            acc.x += (v0.x + v1.x) + (v2.x + v3.x) + ((v4.x + v5.x) + (v6.x + v7.x));
            acc.y += (v0.y + v1.y) + (v2.y + v3.y) + ((v4.y + v5.y) + (v6.y + v7.y));
        }
        for (; j < cnt; ++j) {
            int s = __shfl_sync(0xffffffffu, sidx, j);
            float2 v = *(const float2*)&Hs[(size_t)s * 64 + lane * 2];
            acc.x += v.x; acc.y += v.y;
        }
    }
    float di = g_dinv[i];
    float2 b = *(const float2*)&gb[lane * 2];
    acc.x = b.x + di * acc.x;
    acc.y = b.y + di * acc.y;
    acc.x = acc.x > 0.f ? acc.x : SLOPE_ * acc.x;
    acc.y = acc.y > 0.f ? acc.y : SLOPE_ * acc.y;
    *(float2*)&out[(size_t)i * 64 + lane * 2] = acc;
}

// ---------------- depthwise 5x5 conv ----------------
__global__ void k_dwconv(const float* __restrict__ In, const float* __restrict__ dw,
                         const float* __restrict__ db, float* __restrict__ Out) {
    __shared__ float wt[25 * 64];
    int tid = threadIdx.x;
    for (int i = tid; i < 25 * 64; i += 256) {
        int t = i >> 6, c = i & 63;
        wt[i] = dw[c * 25 + t];
    }
    __syncthreads();
    int c4 = tid & 15;
    int p = blockIdx.x * 16 + (tid >> 4);
    int y = p / Ww_, x = p % Ww_;
    float4 acc = {0.f, 0.f, 0.f, 0.f};
#pragma unroll
    for (int ky = 0; ky < 5; ++ky) {
        int yy = y + ky - 2;
        if (yy < 0 || yy >= Hh_) continue;
#pragma unroll
        for (int kx = 0; kx < 5; ++kx) {
            int xx = x + kx - 2;
            if (xx < 0 || xx >= Ww_) continue;
            float4 v  = *(const float4*)&In[((size_t)yy * Ww_ + xx) * 64 + c4 * 4];
            float4 wv = *(const float4*)&wt[(ky * 5 + kx) * 64 + c4 * 4];
            acc.x += v.x * wv.x; acc.y += v.y * wv.y;
            acc.z += v.z * wv.z; acc.w += v.w * wv.w;
        }
    }
    float4 b = *(const float4*)&db[c4 * 4];
    acc.x += b.x; acc.y += b.y; acc.z += b.z; acc.w += b.w;
    acc.x = acc.x > 0.f ? acc.x : SLOPE_ * acc.x;
    acc.y = acc.y > 0.f ? acc.y : SLOPE_ * acc.y;
    acc.z = acc.z > 0.f ? acc.z : SLOPE_ * acc.z;
    acc.w = acc.w > 0.f ? acc.w : SLOPE_ * acc.w;
    *(float4*)&Out[(size_t)p * 64 + c4 * 4] = acc;
}

// ---------------- head: G (already leaky) concat Cn -> linear -> softmax ----------------
__global__ void k_final(const float* __restrict__ G, const float* __restrict__ Cn,
                        const float* __restrict__ lw, const float* __restrict__ lb,
                        float* __restrict__ out) {
    __shared__ float slw[128 * 16];
    __shared__ float slb[16];
    __shared__ float sg[16][64];
    __shared__ float sc[16][64];
    int tid = threadIdx.x;
    for (int i = tid; i < 2048; i += 256) slw[i] = lw[i];
    if (tid < 16) slb[tid] = lb[tid];
    int tx = tid & 15, ty = tid >> 4;
    size_t row = (size_t)blockIdx.x * 16 + ty;
    *(float4*)&sg[ty][tx * 4] = *(const float4*)&G[row * 64 + tx * 4];
    *(float4*)&sc[ty][tx * 4] = *(const float4*)&Cn[row * 64 + tx * 4];
    __syncthreads();
    float acc = slb[tx];
#pragma unroll 4
    for (int k = 0; k < 64; ++k) acc += sg[ty][k] * slw[k * 16 + tx];
#pragma unroll 4
    for (int k = 0; k < 64; ++k) acc += sc[ty][k] * slw[(64 + k) * 16 + tx];
    float mx = acc;
#pragma unroll
    for (int o = 8; o > 0; o >>= 1) mx = fmaxf(mx, __shfl_xor_sync(0xffffffffu, mx, o));
    float e = __expf(acc - mx);
    float sum = e;
#pragma unroll
    for (int o = 8; o > 0; o >>= 1) sum += __shfl_xor_sync(0xffffffffu, sum, o);
    out[row * 16 + tx] = e / sum;
}

// ---------------- host launchers ----------------
template <int KREAL, int KPAD, int M, int EPI, int STAT>
static void launch_wgemm(const float* X, float* Y, int slotA = 0, int slotB = 0) {
    constexpr int KC = 64;
    constexpr size_t comp = (size_t)(2 * 128 * (KC + 8) + 2 * KC * (M + 8)) * 2;
    constexpr size_t stg  = (size_t)128 * (M + 8) * 4;
    constexpr size_t smem = comp > stg ? comp : stg;
    cudaFuncSetAttribute(k_wgemm<KREAL, KPAD, M, EPI, STAT>,
                         cudaFuncAttributeMaxDynamicSharedMemorySize, (int)smem);
    k_wgemm<KREAL, KPAD, M, EPI, STAT><<<N_ / 128, 256, smem>>>(X, Y, slotA, slotB);
}

extern "C" void kernel_launch(void* const* d_in, const int* in_sizes, int n_in,
                              void* d_out, int out_size) {
    const float* x   = (const float*)d_in[0];
    const int*   ei  = (const int*)d_in[1];
    const int*   src = ei;
    const int*   dst = ei + E_;
    const float* dn_bn1_g = (const float*)d_in[2];
    const float* dn_bn1_b = (const float*)d_in[3];
    const float* dn_w1    = (const float*)d_in[4];
    const float* dn_b1    = (const float*)d_in[5];
    const float* dn_bn2_g = (const float*)d_in[6];
    const float* dn_bn2_b = (const float*)d_in[7];
    const float* dn_w2    = (const float*)d_in[8];
    const float* dn_b2    = (const float*)d_in[9];
    const float* cnn_bn_g = (const float*)d_in[10];
    const float* cnn_bn_b = (const float*)d_in[11];
    const float* cnn_pw   = (const float*)d_in[12];
    const float* cnn_dw   = (const float*)d_in[13];
    const float* cnn_db   = (const float*)d_in[14];
    const float* g1_bn_g  = (const float*)d_in[15];
    const float* g1_bn_b  = (const float*)d_in[16];
    const float* g1_w     = (const float*)d_in[17];
    const float* g1_b     = (const float*)d_in[18];
    const float* g2_bn_g  = (const float*)d_in[19];
    const float* g2_bn_b  = (const float*)d_in[20];
    const float* g2_w     = (const float*)d_in[21];
    const float* g2_b     = (const float*)d_in[22];
    const float* g3_bn_g  = (const float*)d_in[23];
    const float* g3_bn_b  = (const float*)d_in[24];
    const float* g3_w     = (const float*)d_in[25];
    const float* g3_b     = (const float*)d_in[26];
    const float* lin_w    = (const float*)d_in[27];
    const float* lin_b    = (const float*)d_in[28];
    float* out = (float*)d_out;

    float *pP, *pQ, *pH, *pC, *pCR;
    cudaGetSymbolAddress((void**)&pP, g_P);
    cudaGetSymbolAddress((void**)&pQ, g_Q);
    cudaGetSymbolAddress((void**)&pH, g_Hm);
    cudaGetSymbolAddress((void**)&pC, g_cnn);
    cudaGetSymbolAddress((void**)&pCR, g_cnnres);

    // denoise layer 1 (launch #4 = big tensor GEMM, for profiling)
    // GEMM epilogue also produces col stats of pQ -> slot 1.
    k_init<<<NBLK_ + 1, 256>>>();
    k_colstats<200><<<128, 200>>>(x, 0);
    k_prepw<200, 256, 128><<<129, 256>>>(dn_w1, dn_bn1_g, dn_bn1_b, dn_b1, 0);
    launch_wgemm<200, 256, 128, 0, 1>(x, pQ, 1);

    // CSR build + dinv
    k_deg_count<<<(E_ + 255) / 256, 256>>>(dst);
    k_scan1<<<NBLK_, 256>>>();
    k_scan2<<<1, 1024>>>();
    k_scan3<<<NBLK_, 256>>>();
    k_csr_fill<<<(E_ + 255) / 256, 256>>>(src, dst);

    // denoise layer 2: epilogue produces plain stats (slot 2, for CNN fold)
    // AND invn + normalized stats (slot 3, for GCN1 fold)
    k_prepw<128, 128, 128><<<65, 256>>>(dn_w2, dn_bn2_g, dn_bn2_b, dn_b2, 1);
    launch_wgemm<128, 128, 128, 0, 2>(pQ, pP, 2, 3);   // pP = clean

    // CNN branch
    k_prepw<128, 128, 64><<<33, 256>>>(cnn_pw, cnn_bn_g, cnn_bn_b, nullptr, 2);
    launch_wgemm<128, 128, 64, 0, 0>(pP, pC);
    k_dwconv<<<N_ / 16, 256>>>(pC, cnn_dw, cnn_db, pCR);

    // GCN layer 1 (uses invn from denoise2 epilogue; gather writes leaky + stats slot 4)
    k_prepw<128, 128, 128><<<65, 256>>>(g1_w, g1_bn_g, g1_bn_b, nullptr, 3);
    launch_wgemm<128, 128, 128, 1, 0>(pP, pH);
    k_gather128<true><<<1152, 256>>>(pH, g1_b, pP, 4);

    // GCN layer 2
    k_prepw<128, 128, 128><<<65, 256>>>(g2_w, g2_bn_g, g2_bn_b, nullptr, 4);
    launch_wgemm<128, 128, 128, 1, 0>(pP, pH);
    k_gather128<true><<<1152, 256>>>(pH, g2_b, pP, 5);

    // GCN layer 3 (128 -> 64); gather64 fuses leaky
    k_prepw<128, 128, 64><<<33, 256>>>(g3_w, g3_bn_g, g3_bn_b, nullptr, 5);
    launch_wgemm<128, 128, 64, 1, 0>(pP, pH);
    k_gather64<<<(N_ * 32) / 256, 256>>>(pH, g3_b, pP);

    // head
    k_final<<<N_ / 16, 256>>>(pP, pCR, lin_w, lin_b, out);
}

// round 8
// speedup vs baseline: 1.9019x; 1.0972x over previous
#include <cuda_runtime.h>
#include <cuda_bf16.h>
#include <mma.h>
#include <cstdint>
#include <cstddef>

using namespace nvcuda;

// ---------------- problem constants ----------------
#define Hh_ 384
#define Ww_ 384
#define C_ 200
#define N_ 147456           // Hh_*Ww_
#define E_ 1179648
#define HIDE_ 128
#define OUT_ 64
#define NCLS_ 16
#define EPS_ 1e-5f
#define SLOPE_ 0.01f
#define NBLK_ 576           // N_/256

// ---------------- scratch (device globals; no allocation allowed) ----------------
__device__ float g_P[(size_t)N_ * 128];
__device__ float g_Q[(size_t)N_ * 128];
__device__ float g_Hm[(size_t)N_ * 128];
__device__ float g_cnn[(size_t)N_ * 64];
__device__ float g_cnnres[(size_t)N_ * 64];
__device__ float g_dinv[N_];
__device__ float g_invn[N_];
__device__ float g_sum[6 * 256];
__device__ float g_sq[6 * 256];
// CSR
__device__ int g_degi[N_];
__device__ int g_rowptr[N_ + 1];
__device__ int g_cursor[N_];
__device__ int g_blksum[NBLK_];
__device__ int g_col[E_];

// ---------------- init: zero all stat slots + degree array ----------------
__global__ void k_init() {
    int i = blockIdx.x * 256 + threadIdx.x;
    if (i < N_) g_degi[i] = 0;
    if (i < 6 * 256) { g_sum[i] = 0.f; g_sq[i] = 0.f; }
}

// plain column stats (only used for raw input x): blockDim == C
template <int C>
__global__ void k_colstats(const float* __restrict__ X, int slot) {
    const int c = threadIdx.x;
    const int rpb = N_ / 128;
    const int r0 = blockIdx.x * rpb;
    float s = 0.f, q = 0.f;
    for (int r = r0; r < r0 + rpb; ++r) {
        float v = X[(size_t)r * C + c];
        s += v; q += v * v;
    }
    atomicAdd(&g_sum[slot * 256 + c], s);
    atomicAdd(&g_sq[slot * 256 + c], q);
}

// ---------------- tensor GEMM via wmma (bf16 hi/lo split, fp32 accum) ----------------
// Fully self-contained: BN fold + bf16 split of W happens inside (from stats slotF),
// folded bias accumulated as a side product of the B fill.
// Y[N,M] = epi( X[N,KREAL] @ (diag(scale)·W) + bf )
// EPI 0: out = leaky(acc + bf)
// EPI 1: out = (acc*invn[r] + bf) * dinv[r]
// STAT (EPI0, M=128 only): 1 = plain col stats -> slotA;
//                          2 = plain -> slotA AND invn + normalized col stats -> slotB
// 256 threads = 8 warps in a 4(m) x 2(n) grid. Warp tile: 32 rows x M/2 cols.
template <int KREAL, int M, int EPI, int STAT>
__global__ __launch_bounds__(256, 2)
void k_wgemm(const float* __restrict__ X, float* __restrict__ Y,
             const float* __restrict__ W, const float* __restrict__ bng,
             const float* __restrict__ bnb, const float* __restrict__ bias,
             int slotF, int slotA, int slotB) {
    constexpr int KC = 64;            // full K chunk
    constexpr int AS = KC + 8;        // A smem stride (halves)
    constexpr int BS = M + 8;         // B smem stride (halves)
    constexpr int MT = 2;             // m-tiles per warp (32 rows)
    constexpr int NT2 = M / 32;       // n-tiles per warp (M/2 cols)
    constexpr int NCHF = KREAL / 64;  // full chunks
    constexpr int TREAL = KREAL - NCHF * 64;            // leftover real cols
    constexpr int TAILW = (TREAL > 0) ? ((TREAL + 15) / 16) * 16 : 0;
    extern __shared__ char smraw[];
    __nv_bfloat16* Ah = (__nv_bfloat16*)smraw;          // 128*AS halves
    __nv_bfloat16* Al = Ah + 128 * AS;
    __nv_bfloat16* Bh = Al + 128 * AS;                  // KC*BS halves
    __nv_bfloat16* Bl = Bh + (size_t)KC * BS;
    float* stage = (float*)smraw;                       // reused post-compute

    __shared__ float s_scale[256];
    __shared__ float s_shift[256];
    __shared__ float s_bf[128];

    const int tid = threadIdx.x, wid = tid >> 5, lane = tid & 31;
    const int wm = wid & 3, wn = wid >> 2;
    const size_t row0 = (size_t)blockIdx.x * 128;

    // fold coefficients from stats
    {
        float sc = 0.f, sh = 0.f;
        if (tid < KREAL) {
            float mean = g_sum[slotF * 256 + tid] * (1.f / N_);
            float var  = g_sq[slotF * 256 + tid] * (1.f / N_) - mean * mean;
            sc = bng[tid] * rsqrtf(var + EPS_);
            sh = bnb[tid] - mean * sc;
        }
        s_scale[tid] = sc;
        s_shift[tid] = sh;
        if (tid < M) s_bf[tid] = bias ? bias[tid] : 0.f;
    }
    __syncthreads();

    wmma::fragment<wmma::accumulator, 16, 16, 16, float> acc[MT][NT2];
#pragma unroll
    for (int m = 0; m < MT; ++m)
#pragma unroll
        for (int n = 0; n < NT2; ++n) wmma::fill_fragment(acc[m][n], 0.0f);

    float pbf0 = 0.f, pbf1 = 0.f;        // partial folded-bias for this thread's fixed column pair
    const int myn2 = tid % (M / 2);      // column pair this thread always touches in B fill

    auto fillA = [&](int base, int kw) {
        for (int p = tid; p < 128 * (kw / 2); p += 256) {
            int r = p / (kw / 2), kq = p % (kw / 2);
            int kg = base + kq * 2;
            float2 v = {0.f, 0.f};
            if (kg + 1 < KREAL) v = *(const float2*)&X[(row0 + r) * KREAL + kg];
            else if (kg < KREAL) v.x = X[(row0 + r) * KREAL + kg];
            __nv_bfloat16 h0 = __float2bfloat16(v.x);
            __nv_bfloat16 h1 = __float2bfloat16(v.y);
            __nv_bfloat16 l0 = __float2bfloat16(v.x - __bfloat162float(h0));
            __nv_bfloat16 l1 = __float2bfloat16(v.y - __bfloat162float(h1));
            *(__nv_bfloat162*)&Ah[r * AS + kq * 2] = __nv_bfloat162(h0, h1);
            *(__nv_bfloat162*)&Al[r * AS + kq * 2] = __nv_bfloat162(l0, l1);
        }
    };
    auto fillB = [&](int base, int kw) {
        for (int p = tid; p < kw * (M / 2); p += 256) {
            int kl = p / (M / 2), n2 = p % (M / 2);
            int k = base + kl;
            float2 w = {0.f, 0.f};
            if (k < KREAL) w = *(const float2*)&W[(size_t)k * M + n2 * 2];
            float sh = s_shift[k];
            pbf0 += sh * w.x;
            pbf1 += sh * w.y;
            float sc = s_scale[k];
            w.x *= sc; w.y *= sc;
            __nv_bfloat16 h0 = __float2bfloat16(w.x);
            __nv_bfloat16 h1 = __float2bfloat16(w.y);
            __nv_bfloat16 l0 = __float2bfloat16(w.x - __bfloat162float(h0));
            __nv_bfloat16 l1 = __float2bfloat16(w.y - __bfloat162float(h1));
            *(__nv_bfloat162*)&Bh[kl * BS + n2 * 2] = __nv_bfloat162(h0, h1);
            *(__nv_bfloat162*)&Bl[kl * BS + n2 * 2] = __nv_bfloat162(l0, l1);
        }
    };
    auto do_ks = [&](int ks) {
        wmma::fragment<wmma::matrix_a, 16, 16, 16, __nv_bfloat16, wmma::row_major> aH[MT], aL[MT];
#pragma unroll
        for (int m = 0; m < MT; ++m) {
            int rbase = wm * 32 + m * 16;
            wmma::load_matrix_sync(aH[m], Ah + rbase * AS + ks * 16, AS);
            wmma::load_matrix_sync(aL[m], Al + rbase * AS + ks * 16, AS);
        }
#pragma unroll
        for (int n = 0; n < NT2; ++n) {
            int cbase = wn * (M / 2) + n * 16;
            wmma::fragment<wmma::matrix_b, 16, 16, 16, __nv_bfloat16, wmma::row_major> bH, bL;
            wmma::load_matrix_sync(bH, Bh + ks * 16 * BS + cbase, BS);
            wmma::load_matrix_sync(bL, Bl + ks * 16 * BS + cbase, BS);
#pragma unroll
            for (int m = 0; m < MT; ++m) {
                wmma::mma_sync(acc[m][n], aH[m], bH, acc[m][n]);
                wmma::mma_sync(acc[m][n], aH[m], bL, acc[m][n]);
                wmma::mma_sync(acc[m][n], aL[m], bH, acc[m][n]);
            }
        }
    };

    for (int c = 0; c < NCHF; ++c) {
        fillA(c * KC, KC);
        fillB(c * KC, KC);
        __syncthreads();
#pragma unroll
        for (int ks = 0; ks < KC / 16; ++ks) do_ks(ks);
        __syncthreads();
    }
    if (TAILW > 0) {
        fillA(NCHF * KC, TAILW);
        fillB(NCHF * KC, TAILW);
        __syncthreads();
#pragma unroll
        for (int ks = 0; ks < TAILW / 16; ++ks) do_ks(ks);
        __syncthreads();
    }

    // finish folded bias (threads sharing a column pair combine)
    atomicAdd(&s_bf[myn2 * 2 + 0], pbf0);
    atomicAdd(&s_bf[myn2 * 2 + 1], pbf1);

    // stage accumulators to smem (128 x (M+8) floats), then coalesced epi + store
#pragma unroll
    for (int m = 0; m < MT; ++m)
#pragma unroll
        for (int n = 0; n < NT2; ++n)
            wmma::store_matrix_sync(stage + (wm * 32 + m * 16) * (M + 8) + wn * (M / 2) + n * 16,
                                    acc[m][n], M + 8, wmma::mem_row_major);
    __syncthreads();

    float s1[4] = {0.f, 0.f, 0.f, 0.f}, q1[4] = {0.f, 0.f, 0.f, 0.f};
    float s2[4] = {0.f, 0.f, 0.f, 0.f}, q2[4] = {0.f, 0.f, 0.f, 0.f};

    for (int idx = tid; idx < 128 * (M / 4); idx += 256) {
        int r = idx / (M / 4), cq = idx % (M / 4);
        size_t gr = row0 + r;
        float4 v = *(float4*)&stage[r * (M + 8) + cq * 4];
        float4 b = *(const float4*)&s_bf[cq * 4];
        if (EPI == 0) {
            v.x += b.x; v.y += b.y; v.z += b.z; v.w += b.w;
            v.x = v.x > 0.f ? v.x : SLOPE_ * v.x;
            v.y = v.y > 0.f ? v.y : SLOPE_ * v.y;
            v.z = v.z > 0.f ? v.z : SLOPE_ * v.z;
            v.w = v.w > 0.f ? v.w : SLOPE_ * v.w;
            if (STAT >= 1) {
                s1[0] += v.x; s1[1] += v.y; s1[2] += v.z; s1[3] += v.w;
                q1[0] += v.x * v.x; q1[1] += v.y * v.y; q1[2] += v.z * v.z; q1[3] += v.w * v.w;
            }
            if (STAT == 2) {
                // M==128: warp covers the full row
                float ss = v.x * v.x + v.y * v.y + v.z * v.z + v.w * v.w;
#pragma unroll
                for (int o = 16; o > 0; o >>= 1) ss += __shfl_xor_sync(0xffffffffu, ss, o);
                float inv = 1.0f / fmaxf(sqrtf(ss), 1e-12f);
                if (lane == 0) g_invn[gr] = inv;
                float nx = v.x * inv, ny = v.y * inv, nz = v.z * inv, nw = v.w * inv;
                s2[0] += nx; s2[1] += ny; s2[2] += nz; s2[3] += nw;
                q2[0] += nx * nx; q2[1] += ny * ny; q2[2] += nz * nz; q2[3] += nw * nw;
            }
        } else {
            float sr = g_invn[gr], dv = g_dinv[gr];
            v.x = (v.x * sr + b.x) * dv;
            v.y = (v.y * sr + b.y) * dv;
            v.z = (v.z * sr + b.z) * dv;
            v.w = (v.w * sr + b.w) * dv;
        }
        *(float4*)&Y[gr * M + cq * 4] = v;
    }

    if (EPI == 0 && STAT >= 1) {
        __syncthreads();
        float* red = stage;           // 4 regions of [8][128] floats = 16KB
#pragma unroll
        for (int j = 0; j < 4; ++j) {
            red[0 * 1024 + wid * 128 + lane * 4 + j] = s1[j];
            red[1 * 1024 + wid * 128 + lane * 4 + j] = q1[j];
            if (STAT == 2) {
                red[2 * 1024 + wid * 128 + lane * 4 + j] = s2[j];
                red[3 * 1024 + wid * 128 + lane * 4 + j] = q2[j];
            }
        }
        __syncthreads();
        if (tid < 128) {
            float a = 0.f, b = 0.f, c2 = 0.f, d2 = 0.f;
#pragma unroll
            for (int w = 0; w < 8; ++w) {
                a  += red[0 * 1024 + w * 128 + tid];
                b  += red[1 * 1024 + w * 128 + tid];
                if (STAT == 2) {
                    c2 += red[2 * 1024 + w * 128 + tid];
                    d2 += red[3 * 1024 + w * 128 + tid];
                }
            }
            atomicAdd(&g_sum[slotA * 256 + tid], a);
            atomicAdd(&g_sq[slotA * 256 + tid], b);
            if (STAT == 2) {
                atomicAdd(&g_sum[slotB * 256 + tid], c2);
                atomicAdd(&g_sq[slotB * 256 + tid], d2);
            }
        }
    }
}

// ---------------- CSR build ----------------
__global__ void k_deg_count(const int* __restrict__ dst) {
    int e = blockIdx.x * blockDim.x + threadIdx.x;
    if (e < E_) atomicAdd(&g_degi[dst[e]], 1);
}
__global__ void k_scan1() {
    __shared__ int s[256];
    int t = threadIdx.x;
    int idx = blockIdx.x * 256 + t;
    int v = g_degi[idx];
    s[t] = v;
    __syncthreads();
#pragma unroll
    for (int off = 1; off < 256; off <<= 1) {
        int a = 0;
        if (t >= off) a = s[t - off];
        __syncthreads();
        s[t] += a;
        __syncthreads();
    }
    g_rowptr[idx] = s[t] - v;
    if (t == 255) g_blksum[blockIdx.x] = s[255];
}
__global__ void k_scan2() {
    __shared__ int s[NBLK_];
    int t = threadIdx.x;
    if (t < NBLK_) s[t] = g_blksum[t];
    __syncthreads();
    for (int off = 1; off < NBLK_; off <<= 1) {
        int a = 0;
        if (t >= off && t < NBLK_) a = s[t - off];
        __syncthreads();
        if (t < NBLK_) s[t] += a;
        __syncthreads();
    }
    if (t < NBLK_) g_blksum[t] = s[t];
}
__global__ void k_scan3() {
    int idx = blockIdx.x * 256 + threadIdx.x;
    int off = blockIdx.x == 0 ? 0 : g_blksum[blockIdx.x - 1];
    int rp = g_rowptr[idx] + off;
    g_rowptr[idx] = rp;
    g_cursor[idx] = rp;
    g_dinv[idx] = rsqrtf((float)g_degi[idx] + 1.0f);
    if (idx == 0) g_rowptr[N_] = E_;
}
__global__ void k_csr_fill(const int* __restrict__ src, const int* __restrict__ dst) {
    int e = blockIdx.x * blockDim.x + threadIdx.x;
    if (e < E_) {
        int pos = atomicAdd(&g_cursor[dst[e]], 1);
        g_col[pos] = src[e];
    }
}

// ---------------- GCN gather (fused: bias + scale + leaky [+ rownorm stats]) ----------------
// out[i] = leaky(gb + dinv[i] * (Hs[i] + sum_nbr Hs[s]))
// RSTAT: also write invn[i] and accumulate normalized column stats into slot.
// grid 1152 x 256: 9216 warps, each handles 16 nodes.
template <bool RSTAT>
__global__ void k_gather128(const float* __restrict__ Hs, const float* __restrict__ gb,
                            float* __restrict__ out, int slot) {
    __shared__ float sred[2][8][128];
    const int tid = threadIdx.x, wid = tid >> 5, lane = tid & 31;
    const float4 b = *(const float4*)&gb[lane * 4];
    float4 s4 = {0.f, 0.f, 0.f, 0.f}, q4 = {0.f, 0.f, 0.f, 0.f};

    for (int i = blockIdx.x * 8 + wid; i < N_; i += 9216) {
        int beg = __ldg(&g_rowptr[i]), end = __ldg(&g_rowptr[i + 1]);
        float4 acc = *(const float4*)&Hs[(size_t)i * 128 + lane * 4];
        for (int base = beg; base < end; base += 32) {
            int e = base + lane;
            int sidx = (e < end) ? g_col[e] : 0;
            int cnt = min(32, end - base);
            int j = 0;
            for (; j + 8 <= cnt; j += 8) {
                int s0 = __shfl_sync(0xffffffffu, sidx, j);
                int s1 = __shfl_sync(0xffffffffu, sidx, j + 1);
                int s2 = __shfl_sync(0xffffffffu, sidx, j + 2);
                int s3 = __shfl_sync(0xffffffffu, sidx, j + 3);
                int s4i = __shfl_sync(0xffffffffu, sidx, j + 4);
                int s5 = __shfl_sync(0xffffffffu, sidx, j + 5);
                int s6 = __shfl_sync(0xffffffffu, sidx, j + 6);
                int s7 = __shfl_sync(0xffffffffu, sidx, j + 7);
                float4 v0 = *(const float4*)&Hs[(size_t)s0 * 128 + lane * 4];
                float4 v1 = *(const float4*)&Hs[(size_t)s1 * 128 + lane * 4];
                float4 v2 = *(const float4*)&Hs[(size_t)s2 * 128 + lane * 4];
                float4 v3 = *(const float4*)&Hs[(size_t)s3 * 128 + lane * 4];
                float4 v4 = *(const float4*)&Hs[(size_t)s4i * 128 + lane * 4];
                float4 v5 = *(const float4*)&Hs[(size_t)s5 * 128 + lane * 4];
                float4 v6 = *(const float4*)&Hs[(size_t)s6 * 128 + lane * 4];
                float4 v7 = *(const float4*)&Hs[(size_t)s7 * 128 + lane * 4];
                acc.x += (v0.x + v1.x) + (v2.x + v3.x) + ((v4.x + v5.x) + (v6.x + v7.x));
                acc.y += (v0.y + v1.y) + (v2.y + v3.y) + ((v4.y + v5.y) + (v6.y + v7.y));
                acc.z += (v0.z + v1.z) + (v2.z + v3.z) + ((v4.z + v5.z) + (v6.z + v7.z));
                acc.w += (v0.w + v1.w) + (v2.w + v3.w) + ((v4.w + v5.w) + (v6.w + v7.w));
            }
            for (; j < cnt; ++j) {
                int s = __shfl_sync(0xffffffffu, sidx, j);
                float4 v = *(const float4*)&Hs[(size_t)s * 128 + lane * 4];
                acc.x += v.x; acc.y += v.y; acc.z += v.z; acc.w += v.w;
            }
        }
        float di = g_dinv[i];
        acc.x = b.x + di * acc.x;
        acc.y = b.y + di * acc.y;
        acc.z = b.z + di * acc.z;
        acc.w = b.w + di * acc.w;
        acc.x = acc.x > 0.f ? acc.x : SLOPE_ * acc.x;
        acc.y = acc.y > 0.f ? acc.y : SLOPE_ * acc.y;
        acc.z = acc.z > 0.f ? acc.z : SLOPE_ * acc.z;
        acc.w = acc.w > 0.f ? acc.w : SLOPE_ * acc.w;
        if (RSTAT) {
            float ss = acc.x * acc.x + acc.y * acc.y + acc.z * acc.z + acc.w * acc.w;
#pragma unroll
            for (int o = 16; o > 0; o >>= 1) ss += __shfl_xor_sync(0xffffffffu, ss, o);
            float inv = 1.0f / fmaxf(sqrtf(ss), 1e-12f);
            if (lane == 0) g_invn[i] = inv;
            float nx = acc.x * inv, ny = acc.y * inv, nz = acc.z * inv, nw = acc.w * inv;
            s4.x += nx; s4.y += ny; s4.z += nz; s4.w += nw;
            q4.x += nx * nx; q4.y += ny * ny; q4.z += nz * nz; q4.w += nw * nw;
        }
        *(float4*)&out[(size_t)i * 128 + lane * 4] = acc;
    }

    if (RSTAT) {
        sred[0][wid][lane * 4 + 0] = s4.x; sred[0][wid][lane * 4 + 1] = s4.y;
        sred[0][wid][lane * 4 + 2] = s4.z; sred[0][wid][lane * 4 + 3] = s4.w;
        sred[1][wid][lane * 4 + 0] = q4.x; sred[1][wid][lane * 4 + 1] = q4.y;
        sred[1][wid][lane * 4 + 2] = q4.z; sred[1][wid][lane * 4 + 3] = q4.w;
        __syncthreads();
        if (tid < 128) {
            float a = 0.f, b2 = 0.f;
#pragma unroll
            for (int w = 0; w < 8; ++w) { a += sred[0][w][tid]; b2 += sred[1][w][tid]; }
            atomicAdd(&g_sum[slot * 256 + tid], a);
            atomicAdd(&g_sq[slot * 256 + tid], b2);
        }
    }
}

// gather64: bias + scale + leaky fused
__global__ void k_gather64(const float* __restrict__ Hs, const float* __restrict__ gb,
                           float* __restrict__ out) {
    int i = (int)(((size_t)blockIdx.x * blockDim.x + threadIdx.x) >> 5);
    if (i >= N_) return;
    int lane = threadIdx.x & 31;
    int beg = __ldg(&g_rowptr[i]), end = __ldg(&g_rowptr[i + 1]);
    float2 acc = *(const float2*)&Hs[(size_t)i * 64 + lane * 2];
    for (int base = beg; base < end; base += 32) {
        int e = base + lane;
        int sidx = (e < end) ? g_col[e] : 0;
        int cnt = min(32, end - base);
        int j = 0;
        for (; j + 8 <= cnt; j += 8) {
            int s0 = __shfl_sync(0xffffffffu, sidx, j);
            int s1 = __shfl_sync(0xffffffffu, sidx, j + 1);
            int s2 = __shfl_sync(0xffffffffu, sidx, j + 2);
            int s3 = __shfl_sync(0xffffffffu, sidx, j + 3);
            int s4 = __shfl_sync(0xffffffffu, sidx, j + 4);
            int s5 = __shfl_sync(0xffffffffu, sidx, j + 5);
            int s6 = __shfl_sync(0xffffffffu, sidx, j + 6);
            int s7 = __shfl_sync(0xffffffffu, sidx, j + 7);
            float2 v0 = *(const float2*)&Hs[(size_t)s0 * 64 + lane * 2];
            float2 v1 = *(const float2*)&Hs[(size_t)s1 * 64 + lane * 2];
            float2 v2 = *(const float2*)&Hs[(size_t)s2 * 64 + lane * 2];
            float2 v3 = *(const float2*)&Hs[(size_t)s3 * 64 + lane * 2];
            float2 v4 = *(const float2*)&Hs[(size_t)s4 * 64 + lane * 2];
            float2 v5 = *(const float2*)&Hs[(size_t)s5 * 64 + lane * 2];
            float2 v6 = *(const float2*)&Hs[(size_t)s6 * 64 + lane * 2];
            float2 v7 = *(const float2*)&Hs[(size_t)s7 * 64 + lane * 2];
            acc.x += (v0.x + v1.x) + (v2.x + v3.x) + ((v4.x + v5.x) + (v6.x + v7.x));
            acc.y += (v0.y + v1.y) + (v2.y + v3.y) + ((v4.y + v5.y) + (v6.y + v7.y));
        }
        for (; j < cnt; ++j) {
            int s = __shfl_sync(0xffffffffu, sidx, j);
            float2 v = *(const float2*)&Hs[(size_t)s * 64 + lane * 2];
            acc.x += v.x; acc.y += v.y;
        }
    }
    float di = g_dinv[i];
    float2 b = *(const float2*)&gb[lane * 2];
    acc.x = b.x + di * acc.x;
    acc.y = b.y + di * acc.y;
    acc.x = acc.x > 0.f ? acc.x : SLOPE_ * acc.x;
    acc.y = acc.y > 0.f ? acc.y : SLOPE_ * acc.y;
    *(float2*)&out[(size_t)i * 64 + lane * 2] = acc;
}

// ---------------- depthwise 5x5 conv ----------------
__global__ void k_dwconv(const float* __restrict__ In, const float* __restrict__ dw,
                         const float* __restrict__ db, float* __restrict__ Out) {
    __shared__ float wt[25 * 64];
    int tid = threadIdx.x;
    for (int i = tid; i < 25 * 64; i += 256) {
        int t = i >> 6, c = i & 63;
        wt[i] = dw[c * 25 + t];
    }
    __syncthreads();
    int c4 = tid & 15;
    int p = blockIdx.x * 16 + (tid >> 4);
    int y = p / Ww_, x = p % Ww_;
    float4 acc = {0.f, 0.f, 0.f, 0.f};
#pragma unroll
    for (int ky = 0; ky < 5; ++ky) {
        int yy = y + ky - 2;
        if (yy < 0 || yy >= Hh_) continue;
#pragma unroll
        for (int kx = 0; kx < 5; ++kx) {
            int xx = x + kx - 2;
            if (xx < 0 || xx >= Ww_) continue;
            float4 v  = *(const float4*)&In[((size_t)yy * Ww_ + xx) * 64 + c4 * 4];
            float4 wv = *(const float4*)&wt[(ky * 5 + kx) * 64 + c4 * 4];
            acc.x += v.x * wv.x; acc.y += v.y * wv.y;
            acc.z += v.z * wv.z; acc.w += v.w * wv.w;
        }
    }
    float4 b = *(const float4*)&db[c4 * 4];
    acc.x += b.x; acc.y += b.y; acc.z += b.z; acc.w += b.w;
    acc.x = acc.x > 0.f ? acc.x : SLOPE_ * acc.x;
    acc.y = acc.y > 0.f ? acc.y : SLOPE_ * acc.y;
    acc.z = acc.z > 0.f ? acc.z : SLOPE_ * acc.z;
    acc.w = acc.w > 0.f ? acc.w : SLOPE_ * acc.w;
    *(float4*)&Out[(size_t)p * 64 + c4 * 4] = acc;
}

// ---------------- head: G (already leaky) concat Cn -> linear -> softmax ----------------
__global__ void k_final(const float* __restrict__ G, const float* __restrict__ Cn,
                        const float* __restrict__ lw, const float* __restrict__ lb,
                        float* __restrict__ out) {
    __shared__ float slw[128 * 16];
    __shared__ float slb[16];
    __shared__ float sg[16][64];
    __shared__ float sc[16][64];
    int tid = threadIdx.x;
    for (int i = tid; i < 2048; i += 256) slw[i] = lw[i];
    if (tid < 16) slb[tid] = lb[tid];
    int tx = tid & 15, ty = tid >> 4;
    size_t row = (size_t)blockIdx.x * 16 + ty;
    *(float4*)&sg[ty][tx * 4] = *(const float4*)&G[row * 64 + tx * 4];
    *(float4*)&sc[ty][tx * 4] = *(const float4*)&Cn[row * 64 + tx * 4];
    __syncthreads();
    float acc = slb[tx];
#pragma unroll 4
    for (int k = 0; k < 64; ++k) acc += sg[ty][k] * slw[k * 16 + tx];
#pragma unroll 4
    for (int k = 0; k < 64; ++k) acc += sc[ty][k] * slw[(64 + k) * 16 + tx];
    float mx = acc;
#pragma unroll
    for (int o = 8; o > 0; o >>= 1) mx = fmaxf(mx, __shfl_xor_sync(0xffffffffu, mx, o));
    float e = __expf(acc - mx);
    float sum = e;
#pragma unroll
    for (int o = 8; o > 0; o >>= 1) sum += __shfl_xor_sync(0xffffffffu, sum, o);
    out[row * 16 + tx] = e / sum;
}

// ---------------- host launchers ----------------
template <int KREAL, int M, int EPI, int STAT>
static void launch_wgemm(const float* X, float* Y, const float* W, const float* bng,
                         const float* bnb, const float* bias, int slotF,
                         int slotA = 0, int slotB = 0) {
    constexpr int KC = 64;
    constexpr size_t comp = (size_t)(2 * 128 * (KC + 8) + 2 * KC * (M + 8)) * 2;
    constexpr size_t stg  = (size_t)128 * (M + 8) * 4;
    constexpr size_t smem = comp > stg ? comp : stg;
    cudaFuncSetAttribute(k_wgemm<KREAL, M, EPI, STAT>,
                         cudaFuncAttributeMaxDynamicSharedMemorySize, (int)smem);
    k_wgemm<KREAL, M, EPI, STAT><<<N_ / 128, 256, smem>>>(X, Y, W, bng, bnb, bias,
                                                          slotF, slotA, slotB);
}

extern "C" void kernel_launch(void* const* d_in, const int* in_sizes, int n_in,
                              void* d_out, int out_size) {
    const float* x   = (const float*)d_in[0];
    const int*   ei  = (const int*)d_in[1];
    const int*   src = ei;
    const int*   dst = ei + E_;
    const float* dn_bn1_g = (const float*)d_in[2];
    const float* dn_bn1_b = (const float*)d_in[3];
    const float* dn_w1    = (const float*)d_in[4];
    const float* dn_b1    = (const float*)d_in[5];
    const float* dn_bn2_g = (const float*)d_in[6];
    const float* dn_bn2_b = (const float*)d_in[7];
    const float* dn_w2    = (const float*)d_in[8];
    const float* dn_b2    = (const float*)d_in[9];
    const float* cnn_bn_g = (const float*)d_in[10];
    const float* cnn_bn_b = (const float*)d_in[11];
    const float* cnn_pw   = (const float*)d_in[12];
    const float* cnn_dw   = (const float*)d_in[13];
    const float* cnn_db   = (const float*)d_in[14];
    const float* g1_bn_g  = (const float*)d_in[15];
    const float* g1_bn_b  = (const float*)d_in[16];
    const float* g1_w     = (const float*)d_in[17];
    const float* g1_b     = (const float*)d_in[18];
    const float* g2_bn_g  = (const float*)d_in[19];
    const float* g2_bn_b  = (const float*)d_in[20];
    const float* g2_w     = (const float*)d_in[21];
    const float* g2_b     = (const float*)d_in[22];
    const float* g3_bn_g  = (const float*)d_in[23];
    const float* g3_bn_b  = (const float*)d_in[24];
    const float* g3_w     = (const float*)d_in[25];
    const float* g3_b     = (const float*)d_in[26];
    const float* lin_w    = (const float*)d_in[27];
    const float* lin_b    = (const float*)d_in[28];
    float* out = (float*)d_out;

    float *pP, *pQ, *pH, *pC, *pCR;
    cudaGetSymbolAddress((void**)&pP, g_P);
    cudaGetSymbolAddress((void**)&pQ, g_Q);
    cudaGetSymbolAddress((void**)&pH, g_Hm);
    cudaGetSymbolAddress((void**)&pC, g_cnn);
    cudaGetSymbolAddress((void**)&pCR, g_cnnres);

    // launches 1-3, then #4 = big tensor GEMM (kept at position 4 for profiling)
    k_init<<<NBLK_ + 1, 256>>>();
    k_colstats<200><<<128, 200>>>(x, 0);
    k_deg_count<<<(E_ + 255) / 256, 256>>>(dst);
    launch_wgemm<200, 128, 0, 1>(x, pQ, dn_w1, dn_bn1_g, dn_bn1_b, dn_b1, 0, 1);

    // CSR build + dinv
    k_scan1<<<NBLK_, 256>>>();
    k_scan2<<<1, 1024>>>();
    k_scan3<<<NBLK_, 256>>>();
    k_csr_fill<<<(E_ + 255) / 256, 256>>>(src, dst);

    // denoise layer 2: epilogue produces plain stats (slot 2, CNN fold)
    // AND invn + normalized stats (slot 3, GCN1 fold)
    launch_wgemm<128, 128, 0, 2>(pQ, pP, dn_w2, dn_bn2_g, dn_bn2_b, dn_b2, 1, 2, 3);  // pP = clean

    // CNN branch
    launch_wgemm<128, 64, 0, 0>(pP, pC, cnn_pw, cnn_bn_g, cnn_bn_b, nullptr, 2);
    k_dwconv<<<N_ / 16, 256>>>(pC, cnn_dw, cnn_db, pCR);

    // GCN layer 1 (invn from denoise2 epilogue; gather writes leaky + stats slot 4)
    launch_wgemm<128, 128, 1, 0>(pP, pH, g1_w, g1_bn_g, g1_bn_b, nullptr, 3);
    k_gather128<true><<<1152, 256>>>(pH, g1_b, pP, 4);

    // GCN layer 2
    launch_wgemm<128, 128, 1, 0>(pP, pH, g2_w, g2_bn_g, g2_bn_b, nullptr, 4);
    k_gather128<true><<<1152, 256>>>(pH, g2_b, pP, 5);

    // GCN layer 3 (128 -> 64); gather64 fuses leaky
    launch_wgemm<128, 64, 1, 0>(pP, pH, g3_w, g3_bn_g, g3_bn_b, nullptr, 5);
    k_gather64<<<(N_ * 32) / 256, 256>>>(pH, g3_b, pP);

    // head
    k_final<<<N_ / 16, 256>>>(pP, pCR, lin_w, lin_b, out);
}

// round 9
// speedup vs baseline: 1.9267x; 1.0130x over previous
#include <cuda_runtime.h>
#include <cuda_bf16.h>
#include <cuda_pipeline.h>
#include <mma.h>
#include <cstdint>
#include <cstddef>

using namespace nvcuda;

// ---------------- problem constants ----------------
#define Hh_ 384
#define Ww_ 384
#define C_ 200
#define N_ 147456           // Hh_*Ww_
#define E_ 1179648
#define HIDE_ 128
#define OUT_ 64
#define NCLS_ 16
#define EPS_ 1e-5f
#define SLOPE_ 0.01f
#define NBLK_ 576           // N_/256

// ---------------- scratch (device globals; no allocation allowed) ----------------
__device__ float g_P[(size_t)N_ * 128];
__device__ float g_Q[(size_t)N_ * 128];
__device__ float g_Hm[(size_t)N_ * 128];
__device__ float g_cnn[(size_t)N_ * 64];
__device__ float g_cnnres[(size_t)N_ * 64];
__device__ float g_dinv[N_];
__device__ float g_invn[N_];
__device__ float g_sum[6 * 256];
__device__ float g_sq[6 * 256];
// CSR
__device__ int g_degi[N_];
__device__ int g_rowptr[N_ + 1];
__device__ int g_cursor[N_];
__device__ int g_blksum[NBLK_];
__device__ int g_col[E_];

// ---------------- init: zero all stat slots + degree array ----------------
__global__ void k_init() {
    int i = blockIdx.x * 256 + threadIdx.x;
    if (i < N_) g_degi[i] = 0;
    if (i < 6 * 256) { g_sum[i] = 0.f; g_sq[i] = 0.f; }
}

// plain column stats (only used for raw input x): blockDim == C
template <int C>
__global__ void k_colstats(const float* __restrict__ X, int slot) {
    const int c = threadIdx.x;
    const int rpb = N_ / 128;
    const int r0 = blockIdx.x * rpb;
    float s = 0.f, q = 0.f;
    for (int r = r0; r < r0 + rpb; ++r) {
        float v = X[(size_t)r * C + c];
        s += v; q += v * v;
    }
    atomicAdd(&g_sum[slot * 256 + c], s);
    atomicAdd(&g_sq[slot * 256 + c], q);
}

// ---------------- tensor GEMM via wmma (bf16 hi/lo split, fp32 accum) ----------------
// cp.async double-buffered raw staging of X and W; BN fold + bf16 split from smem.
// Y[N,M] = epi( X[N,KREAL] @ (diag(scale)·W) + bf )
// EPI 0: out = leaky(acc + bf)         EPI 1: out = (acc*invn[r] + bf) * dinv[r]
// STAT (EPI0, M=128): 1 = plain col stats -> slotA; 2 = plain->slotA AND invn+norm stats->slotB
// 256 threads = 8 warps in a 4(m) x 2(n) grid. Warp tile: 32 rows x M/2 cols.
template <int KREAL, int M, int EPI, int STAT>
__global__ __launch_bounds__(256, 2)
void k_wgemm(const float* __restrict__ X, float* __restrict__ Y,
             const float* __restrict__ W, const float* __restrict__ bng,
             const float* __restrict__ bnb, const float* __restrict__ bias,
             int slotF, int slotA, int slotB) {
    constexpr int KC = 32;            // K chunk
    constexpr int AS = KC + 8;        // A smem stride (halves)
    constexpr int BS = M + 8;         // B smem stride (halves)
    constexpr int MT = 2;             // m-tiles per warp (32 rows)
    constexpr int NT2 = M / 32;       // n-tiles per warp (M/2 cols)
    constexpr int NCH = (KREAL + KC - 1) / KC;
    constexpr int LASTR = KREAL - (NCH - 1) * KC;
    constexpr int KS_LAST = (LASTR + 15) / 16;

    constexpr int SZ_A = 128 * AS * 2;        // one bf16 plane
    constexpr int SZ_B = KC * BS * 2;
    constexpr int SZ_RX = 128 * KC * 4;       // one raw X slot
    constexpr int SZ_RW = KC * M * 4;         // one raw W slot

    extern __shared__ char smraw[];
    __nv_bfloat16* Ah = (__nv_bfloat16*)smraw;
    __nv_bfloat16* Al = (__nv_bfloat16*)(smraw + SZ_A);
    __nv_bfloat16* Bh = (__nv_bfloat16*)(smraw + 2 * SZ_A);
    __nv_bfloat16* Bl = (__nv_bfloat16*)(smraw + 2 * SZ_A + SZ_B);
    float* rawX[2] = { (float*)(smraw + 2 * SZ_A + 2 * SZ_B),
                       (float*)(smraw + 2 * SZ_A + 2 * SZ_B + SZ_RX) };
    float* rawW[2] = { (float*)(smraw + 2 * SZ_A + 2 * SZ_B + 2 * SZ_RX),
                       (float*)(smraw + 2 * SZ_A + 2 * SZ_B + 2 * SZ_RX + SZ_RW) };
    float* stage = (float*)smraw;             // reused post-compute

    __shared__ float s_scale[256];
    __shared__ float s_shift[256];
    __shared__ float s_bf[128];

    const int tid = threadIdx.x, wid = tid >> 5, lane = tid & 31;
    const int wm = wid & 3, wn = wid >> 2;
    const size_t row0 = (size_t)blockIdx.x * 128;

    // fold coefficients from stats
    {
        float sc = 0.f, sh = 0.f;
        if (tid < KREAL) {
            float mean = g_sum[slotF * 256 + tid] * (1.f / N_);
            float var  = g_sq[slotF * 256 + tid] * (1.f / N_) - mean * mean;
            sc = bng[tid] * rsqrtf(var + EPS_);
            sh = bnb[tid] - mean * sc;
        }
        s_scale[tid] = sc;
        s_shift[tid] = sh;
        if (tid < M) s_bf[tid] = bias ? bias[tid] : 0.f;
    }

    wmma::fragment<wmma::accumulator, 16, 16, 16, float> acc[MT][NT2];
#pragma unroll
    for (int m = 0; m < MT; ++m)
#pragma unroll
        for (int n = 0; n < NT2; ++n) wmma::fill_fragment(acc[m][n], 0.0f);

    float pbf0 = 0.f, pbf1 = 0.f;
    const int myn2 = tid % (M / 2);

    // issue cp.async for chunk c into slot
    auto cp_chunk = [&](int c, int slot) {
        // X: 128 rows x KC cols = 128*(KC/4) 16B segments
        for (int p = tid; p < 128 * (KC / 4); p += 256) {
            int r = p / (KC / 4), s = p % (KC / 4);
            int col0 = c * KC + s * 4;
            int real = KREAL - col0; real = real < 0 ? 0 : (real > 4 ? 4 : real);
            const float* src = &X[(row0 + r) * KREAL + (real ? col0 : 0)];
            __pipeline_memcpy_async(&rawX[slot][r * KC + s * 4], src, 16,
                                    (size_t)(4 - real) * 4);
        }
        // W: KC rows x M cols = KC*(M/4) segments
        for (int p = tid; p < KC * (M / 4); p += 256) {
            int k = p / (M / 4), n4 = p % (M / 4);
            int kg = c * KC + k;
            bool ok = kg < KREAL;
            const float* src = &W[(size_t)(ok ? kg : 0) * M + n4 * 4];
            __pipeline_memcpy_async(&rawW[slot][k * M + n4 * 4], src, 16,
                                    ok ? 0 : 16);
        }
        __pipeline_commit();
    };

    // convert raw slot -> bf16 planes (+ bias fold from raw W)
    auto convert = [&](int c, int slot) {
        for (int p = tid; p < 128 * (KC / 2); p += 256) {
            int r = p / (KC / 2), q = p % (KC / 2);
            float2 v = *(float2*)&rawX[slot][r * KC + q * 2];
            __nv_bfloat16 h0 = __float2bfloat16(v.x);
            __nv_bfloat16 h1 = __float2bfloat16(v.y);
            __nv_bfloat16 l0 = __float2bfloat16(v.x - __bfloat162float(h0));
            __nv_bfloat16 l1 = __float2bfloat16(v.y - __bfloat162float(h1));
            *(__nv_bfloat162*)&Ah[r * AS + q * 2] = __nv_bfloat162(h0, h1);
            *(__nv_bfloat162*)&Al[r * AS + q * 2] = __nv_bfloat162(l0, l1);
        }
        for (int p = tid; p < KC * (M / 2); p += 256) {
            int kl = p / (M / 2), n2 = p % (M / 2);
            float2 w = *(float2*)&rawW[slot][kl * M + n2 * 2];
            int kg = c * KC + kl;
            float sh = s_shift[kg];
            pbf0 += sh * w.x;
            pbf1 += sh * w.y;
            float sc = s_scale[kg];
            w.x *= sc; w.y *= sc;
            __nv_bfloat16 h0 = __float2bfloat16(w.x);
            __nv_bfloat16 h1 = __float2bfloat16(w.y);
            __nv_bfloat16 l0 = __float2bfloat16(w.x - __bfloat162float(h0));
            __nv_bfloat16 l1 = __float2bfloat16(w.y - __bfloat162float(h1));
            *(__nv_bfloat162*)&Bh[kl * BS + n2 * 2] = __nv_bfloat162(h0, h1);
            *(__nv_bfloat162*)&Bl[kl * BS + n2 * 2] = __nv_bfloat162(l0, l1);
        }
    };

    auto do_ks = [&](int ks) {
        wmma::fragment<wmma::matrix_a, 16, 16, 16, __nv_bfloat16, wmma::row_major> aH[MT], aL[MT];
#pragma unroll
        for (int m = 0; m < MT; ++m) {
            int rbase = wm * 32 + m * 16;
            wmma::load_matrix_sync(aH[m], Ah + rbase * AS + ks * 16, AS);
            wmma::load_matrix_sync(aL[m], Al + rbase * AS + ks * 16, AS);
        }
#pragma unroll
        for (int n = 0; n < NT2; ++n) {
            int cbase = wn * (M / 2) + n * 16;
            wmma::fragment<wmma::matrix_b, 16, 16, 16, __nv_bfloat16, wmma::row_major> bH, bL;
            wmma::load_matrix_sync(bH, Bh + ks * 16 * BS + cbase, BS);
            wmma::load_matrix_sync(bL, Bl + ks * 16 * BS + cbase, BS);
#pragma unroll
            for (int m = 0; m < MT; ++m) {
                wmma::mma_sync(acc[m][n], aH[m], bH, acc[m][n]);
                wmma::mma_sync(acc[m][n], aH[m], bL, acc[m][n]);
                wmma::mma_sync(acc[m][n], aL[m], bH, acc[m][n]);
            }
        }
    };

    cp_chunk(0, 0);
    for (int c = 0; c < NCH; ++c) {
        const int slot = c & 1;
        if (c + 1 < NCH) cp_chunk(c + 1, (c + 1) & 1);
        __pipeline_wait_prior((c + 1 < NCH) ? 1 : 0);
        __syncthreads();                    // raw chunk c visible to all
        convert(c, slot);
        __syncthreads();                    // bf16 planes ready
        const int nks = (c == NCH - 1) ? KS_LAST : 2;
        for (int ks = 0; ks < nks; ++ks) do_ks(ks);
        __syncthreads();                    // MMA done before planes overwritten
    }

    // finish folded bias (threads sharing a column pair combine)
    atomicAdd(&s_bf[myn2 * 2 + 0], pbf0);
    atomicAdd(&s_bf[myn2 * 2 + 1], pbf1);

    // stage accumulators to smem (128 x (M+8) floats), then coalesced epi + store
#pragma unroll
    for (int m = 0; m < MT; ++m)
#pragma unroll
        for (int n = 0; n < NT2; ++n)
            wmma::store_matrix_sync(stage + (wm * 32 + m * 16) * (M + 8) + wn * (M / 2) + n * 16,
                                    acc[m][n], M + 8, wmma::mem_row_major);
    __syncthreads();

    float s1[4] = {0.f, 0.f, 0.f, 0.f}, q1[4] = {0.f, 0.f, 0.f, 0.f};
    float s2[4] = {0.f, 0.f, 0.f, 0.f}, q2[4] = {0.f, 0.f, 0.f, 0.f};

    for (int idx = tid; idx < 128 * (M / 4); idx += 256) {
        int r = idx / (M / 4), cq = idx % (M / 4);
        size_t gr = row0 + r;
        float4 v = *(float4*)&stage[r * (M + 8) + cq * 4];
        float4 b = *(const float4*)&s_bf[cq * 4];
        if (EPI == 0) {
            v.x += b.x; v.y += b.y; v.z += b.z; v.w += b.w;
            v.x = v.x > 0.f ? v.x : SLOPE_ * v.x;
            v.y = v.y > 0.f ? v.y : SLOPE_ * v.y;
            v.z = v.z > 0.f ? v.z : SLOPE_ * v.z;
            v.w = v.w > 0.f ? v.w : SLOPE_ * v.w;
            if (STAT >= 1) {
                s1[0] += v.x; s1[1] += v.y; s1[2] += v.z; s1[3] += v.w;
                q1[0] += v.x * v.x; q1[1] += v.y * v.y; q1[2] += v.z * v.z; q1[3] += v.w * v.w;
            }
            if (STAT == 2) {
                float ss = v.x * v.x + v.y * v.y + v.z * v.z + v.w * v.w;
#pragma unroll
                for (int o = 16; o > 0; o >>= 1) ss += __shfl_xor_sync(0xffffffffu, ss, o);
                float inv = 1.0f / fmaxf(sqrtf(ss), 1e-12f);
                if (lane == 0) g_invn[gr] = inv;
                float nx = v.x * inv, ny = v.y * inv, nz = v.z * inv, nw = v.w * inv;
                s2[0] += nx; s2[1] += ny; s2[2] += nz; s2[3] += nw;
                q2[0] += nx * nx; q2[1] += ny * ny; q2[2] += nz * nz; q2[3] += nw * nw;
            }
        } else {
            float sr = g_invn[gr], dv = g_dinv[gr];
            v.x = (v.x * sr + b.x) * dv;
            v.y = (v.y * sr + b.y) * dv;
            v.z = (v.z * sr + b.z) * dv;
            v.w = (v.w * sr + b.w) * dv;
        }
        *(float4*)&Y[gr * M + cq * 4] = v;
    }

    if (EPI == 0 && STAT >= 1) {
        __syncthreads();
        float* red = stage;
#pragma unroll
        for (int j = 0; j < 4; ++j) {
            red[0 * 1024 + wid * 128 + lane * 4 + j] = s1[j];
            red[1 * 1024 + wid * 128 + lane * 4 + j] = q1[j];
            if (STAT == 2) {
                red[2 * 1024 + wid * 128 + lane * 4 + j] = s2[j];
                red[3 * 1024 + wid * 128 + lane * 4 + j] = q2[j];
            }
        }
        __syncthreads();
        if (tid < 128) {
            float a = 0.f, b = 0.f, c2 = 0.f, d2 = 0.f;
#pragma unroll
            for (int w = 0; w < 8; ++w) {
                a  += red[0 * 1024 + w * 128 + tid];
                b  += red[1 * 1024 + w * 128 + tid];
                if (STAT == 2) {
                    c2 += red[2 * 1024 + w * 128 + tid];
                    d2 += red[3 * 1024 + w * 128 + tid];
                }
            }
            atomicAdd(&g_sum[slotA * 256 + tid], a);
            atomicAdd(&g_sq[slotA * 256 + tid], b);
            if (STAT == 2) {
                atomicAdd(&g_sum[slotB * 256 + tid], c2);
                atomicAdd(&g_sq[slotB * 256 + tid], d2);
            }
        }
    }
}

// ---------------- CSR build ----------------
__global__ void k_deg_count(const int* __restrict__ dst) {
    int e = blockIdx.x * blockDim.x + threadIdx.x;
    if (e < E_) atomicAdd(&g_degi[dst[e]], 1);
}
__global__ void k_scan1() {
    __shared__ int s[256];
    int t = threadIdx.x;
    int idx = blockIdx.x * 256 + t;
    int v = g_degi[idx];
    s[t] = v;
    __syncthreads();
#pragma unroll
    for (int off = 1; off < 256; off <<= 1) {
        int a = 0;
        if (t >= off) a = s[t - off];
        __syncthreads();
        s[t] += a;
        __syncthreads();
    }
    g_rowptr[idx] = s[t] - v;
    if (t == 255) g_blksum[blockIdx.x] = s[255];
}
__global__ void k_scan2() {
    __shared__ int s[NBLK_];
    int t = threadIdx.x;
    if (t < NBLK_) s[t] = g_blksum[t];
    __syncthreads();
    for (int off = 1; off < NBLK_; off <<= 1) {
        int a = 0;
        if (t >= off && t < NBLK_) a = s[t - off];
        __syncthreads();
        if (t < NBLK_) s[t] += a;
        __syncthreads();
    }
    if (t < NBLK_) g_blksum[t] = s[t];
}
__global__ void k_scan3() {
    int idx = blockIdx.x * 256 + threadIdx.x;
    int off = blockIdx.x == 0 ? 0 : g_blksum[blockIdx.x - 1];
    int rp = g_rowptr[idx] + off;
    g_rowptr[idx] = rp;
    g_cursor[idx] = rp;
    g_dinv[idx] = rsqrtf((float)g_degi[idx] + 1.0f);
    if (idx == 0) g_rowptr[N_] = E_;
}
__global__ void k_csr_fill(const int* __restrict__ src, const int* __restrict__ dst) {
    int e = blockIdx.x * blockDim.x + threadIdx.x;
    if (e < E_) {
        int pos = atomicAdd(&g_cursor[dst[e]], 1);
        g_col[pos] = src[e];
    }
}

// ---------------- GCN gather (fused: bias + scale + leaky [+ rownorm stats]) ----------------
template <bool RSTAT>
__global__ void k_gather128(const float* __restrict__ Hs, const float* __restrict__ gb,
                            float* __restrict__ out, int slot) {
    __shared__ float sred[2][8][128];
    const int tid = threadIdx.x, wid = tid >> 5, lane = tid & 31;
    const float4 b = *(const float4*)&gb[lane * 4];
    float4 s4 = {0.f, 0.f, 0.f, 0.f}, q4 = {0.f, 0.f, 0.f, 0.f};

    for (int i = blockIdx.x * 8 + wid; i < N_; i += 9216) {
        int beg = __ldg(&g_rowptr[i]), end = __ldg(&g_rowptr[i + 1]);
        float4 acc = *(const float4*)&Hs[(size_t)i * 128 + lane * 4];
        for (int base = beg; base < end; base += 32) {
            int e = base + lane;
            int sidx = (e < end) ? g_col[e] : 0;
            int cnt = min(32, end - base);
            int j = 0;
            for (; j + 8 <= cnt; j += 8) {
                int s0 = __shfl_sync(0xffffffffu, sidx, j);
                int s1 = __shfl_sync(0xffffffffu, sidx, j + 1);
                int s2 = __shfl_sync(0xffffffffu, sidx, j + 2);
                int s3 = __shfl_sync(0xffffffffu, sidx, j + 3);
                int s4i = __shfl_sync(0xffffffffu, sidx, j + 4);
                int s5 = __shfl_sync(0xffffffffu, sidx, j + 5);
                int s6 = __shfl_sync(0xffffffffu, sidx, j + 6);
                int s7 = __shfl_sync(0xffffffffu, sidx, j + 7);
                float4 v0 = *(const float4*)&Hs[(size_t)s0 * 128 + lane * 4];
                float4 v1 = *(const float4*)&Hs[(size_t)s1 * 128 + lane * 4];
                float4 v2 = *(const float4*)&Hs[(size_t)s2 * 128 + lane * 4];
                float4 v3 = *(const float4*)&Hs[(size_t)s3 * 128 + lane * 4];
                float4 v4 = *(const float4*)&Hs[(size_t)s4i * 128 + lane * 4];
                float4 v5 = *(const float4*)&Hs[(size_t)s5 * 128 + lane * 4];
                float4 v6 = *(const float4*)&Hs[(size_t)s6 * 128 + lane * 4];
                float4 v7 = *(const float4*)&Hs[(size_t)s7 * 128 + lane * 4];
                acc.x += (v0.x + v1.x) + (v2.x + v3.x) + ((v4.x + v5.x) + (v6.x + v7.x));
                acc.y += (v0.y + v1.y) + (v2.y + v3.y) + ((v4.y + v5.y) + (v6.y + v7.y));
                acc.z += (v0.z + v1.z) + (v2.z + v3.z) + ((v4.z + v5.z) + (v6.z + v7.z));
                acc.w += (v0.w + v1.w) + (v2.w + v3.w) + ((v4.w + v5.w) + (v6.w + v7.w));
            }
            for (; j < cnt; ++j) {
                int s = __shfl_sync(0xffffffffu, sidx, j);
                float4 v = *(const float4*)&Hs[(size_t)s * 128 + lane * 4];
                acc.x += v.x; acc.y += v.y; acc.z += v.z; acc.w += v.w;
            }
        }
        float di = g_dinv[i];
        acc.x = b.x + di * acc.x;
        acc.y = b.y + di * acc.y;
        acc.z = b.z + di * acc.z;
        acc.w = b.w + di * acc.w;
        acc.x = acc.x > 0.f ? acc.x : SLOPE_ * acc.x;
        acc.y = acc.y > 0.f ? acc.y : SLOPE_ * acc.y;
        acc.z = acc.z > 0.f ? acc.z : SLOPE_ * acc.z;
        acc.w = acc.w > 0.f ? acc.w : SLOPE_ * acc.w;
        if (RSTAT) {
            float ss = acc.x * acc.x + acc.y * acc.y + acc.z * acc.z + acc.w * acc.w;
#pragma unroll
            for (int o = 16; o > 0; o >>= 1) ss += __shfl_xor_sync(0xffffffffu, ss, o);
            float inv = 1.0f / fmaxf(sqrtf(ss), 1e-12f);
            if (lane == 0) g_invn[i] = inv;
            float nx = acc.x * inv, ny = acc.y * inv, nz = acc.z * inv, nw = acc.w * inv;
            s4.x += nx; s4.y += ny; s4.z += nz; s4.w += nw;
            q4.x += nx * nx; q4.y += ny * ny; q4.z += nz * nz; q4.w += nw * nw;
        }
        *(float4*)&out[(size_t)i * 128 + lane * 4] = acc;
    }

    if (RSTAT) {
        sred[0][wid][lane * 4 + 0] = s4.x; sred[0][wid][lane * 4 + 1] = s4.y;
        sred[0][wid][lane * 4 + 2] = s4.z; sred[0][wid][lane * 4 + 3] = s4.w;
        sred[1][wid][lane * 4 + 0] = q4.x; sred[1][wid][lane * 4 + 1] = q4.y;
        sred[1][wid][lane * 4 + 2] = q4.z; sred[1][wid][lane * 4 + 3] = q4.w;
        __syncthreads();
        if (tid < 128) {
            float a = 0.f, b2 = 0.f;
#pragma unroll
            for (int w = 0; w < 8; ++w) { a += sred[0][w][tid]; b2 += sred[1][w][tid]; }
            atomicAdd(&g_sum[slot * 256 + tid], a);
            atomicAdd(&g_sq[slot * 256 + tid], b2);
        }
    }
}

// gather64: bias + scale + leaky fused
__global__ void k_gather64(const float* __restrict__ Hs, const float* __restrict__ gb,
                           float* __restrict__ out) {
    int i = (int)(((size_t)blockIdx.x * blockDim.x + threadIdx.x) >> 5);
    if (i >= N_) return;
    int lane = threadIdx.x & 31;
    int beg = __ldg(&g_rowptr[i]), end = __ldg(&g_rowptr[i + 1]);
    float2 acc = *(const float2*)&Hs[(size_t)i * 64 + lane * 2];
    for (int base = beg; base < end; base += 32) {
        int e = base + lane;
        int sidx = (e < end) ? g_col[e] : 0;
        int cnt = min(32, end - base);
        int j = 0;
        for (; j + 8 <= cnt; j += 8) {
            int s0 = __shfl_sync(0xffffffffu, sidx, j);
            int s1 = __shfl_sync(0xffffffffu, sidx, j + 1);
            int s2 = __shfl_sync(0xffffffffu, sidx, j + 2);
            int s3 = __shfl_sync(0xffffffffu, sidx, j + 3);
            int s4 = __shfl_sync(0xffffffffu, sidx, j + 4);
            int s5 = __shfl_sync(0xffffffffu, sidx, j + 5);
            int s6 = __shfl_sync(0xffffffffu, sidx, j + 6);
            int s7 = __shfl_sync(0xffffffffu, sidx, j + 7);
            float2 v0 = *(const float2*)&Hs[(size_t)s0 * 64 + lane * 2];
            float2 v1 = *(const float2*)&Hs[(size_t)s1 * 64 + lane * 2];
            float2 v2 = *(const float2*)&Hs[(size_t)s2 * 64 + lane * 2];
            float2 v3 = *(const float2*)&Hs[(size_t)s3 * 64 + lane * 2];
            float2 v4 = *(const float2*)&Hs[(size_t)s4 * 64 + lane * 2];
            float2 v5 = *(const float2*)&Hs[(size_t)s5 * 64 + lane * 2];
            float2 v6 = *(const float2*)&Hs[(size_t)s6 * 64 + lane * 2];
            float2 v7 = *(const float2*)&Hs[(size_t)s7 * 64 + lane * 2];
            acc.x += (v0.x + v1.x) + (v2.x + v3.x) + ((v4.x + v5.x) + (v6.x + v7.x));
            acc.y += (v0.y + v1.y) + (v2.y + v3.y) + ((v4.y + v5.y) + (v6.y + v7.y));
        }
        for (; j < cnt; ++j) {
            int s = __shfl_sync(0xffffffffu, sidx, j);
            float2 v = *(const float2*)&Hs[(size_t)s * 64 + lane * 2];
            acc.x += v.x; acc.y += v.y;
        }
    }
    float di = g_dinv[i];
    float2 b = *(const float2*)&gb[lane * 2];
    acc.x = b.x + di * acc.x;
    acc.y = b.y + di * acc.y;
    acc.x = acc.x > 0.f ? acc.x : SLOPE_ * acc.x;
    acc.y = acc.y > 0.f ? acc.y : SLOPE_ * acc.y;
    *(float2*)&out[(size_t)i * 64 + lane * 2] = acc;
}

// ---------------- depthwise 5x5 conv ----------------
__global__ void k_dwconv(const float* __restrict__ In, const float* __restrict__ dw,
                         const float* __restrict__ db, float* __restrict__ Out) {
    __shared__ float wt[25 * 64];
    int tid = threadIdx.x;
    for (int i = tid; i < 25 * 64; i += 256) {
        int t = i >> 6, c = i & 63;
        wt[i] = dw[c * 25 + t];
    }
    __syncthreads();
    int c4 = tid & 15;
    int p = blockIdx.x * 16 + (tid >> 4);
    int y = p / Ww_, x = p % Ww_;
    float4 acc = {0.f, 0.f, 0.f, 0.f};
#pragma unroll
    for (int ky = 0; ky < 5; ++ky) {
        int yy = y + ky - 2;
        if (yy < 0 || yy >= Hh_) continue;
#pragma unroll
        for (int kx = 0; kx < 5; ++kx) {
            int xx = x + kx - 2;
            if (xx < 0 || xx >= Ww_) continue;
            float4 v  = *(const float4*)&In[((size_t)yy * Ww_ + xx) * 64 + c4 * 4];
            float4 wv = *(const float4*)&wt[(ky * 5 + kx) * 64 + c4 * 4];
            acc.x += v.x * wv.x; acc.y += v.y * wv.y;
            acc.z += v.z * wv.z; acc.w += v.w * wv.w;
        }
    }
    float4 b = *(const float4*)&db[c4 * 4];
    acc.x += b.x; acc.y += b.y; acc.z += b.z; acc.w += b.w;
    acc.x = acc.x > 0.f ? acc.x : SLOPE_ * acc.x;
    acc.y = acc.y > 0.f ? acc.y : SLOPE_ * acc.y;
    acc.z = acc.z > 0.f ? acc.z : SLOPE_ * acc.z;
    acc.w = acc.w > 0.f ? acc.w : SLOPE_ * acc.w;
    *(float4*)&Out[(size_t)p * 64 + c4 * 4] = acc;
}

// ---------------- head: G (already leaky) concat Cn -> linear -> softmax ----------------
__global__ void k_final(const float* __restrict__ G, const float* __restrict__ Cn,
                        const float* __restrict__ lw, const float* __restrict__ lb,
                        float* __restrict__ out) {
    __shared__ float slw[128 * 16];
    __shared__ float slb[16];
    __shared__ float sg[16][64];
    __shared__ float sc[16][64];
    int tid = threadIdx.x;
    for (int i = tid; i < 2048; i += 256) slw[i] = lw[i];
    if (tid < 16) slb[tid] = lb[tid];
    int tx = tid & 15, ty = tid >> 4;
    size_t row = (size_t)blockIdx.x * 16 + ty;
    *(float4*)&sg[ty][tx * 4] = *(const float4*)&G[row * 64 + tx * 4];
    *(float4*)&sc[ty][tx * 4] = *(const float4*)&Cn[row * 64 + tx * 4];
    __syncthreads();
    float acc = slb[tx];
#pragma unroll 4
    for (int k = 0; k < 64; ++k) acc += sg[ty][k] * slw[k * 16 + tx];
#pragma unroll 4
    for (int k = 0; k < 64; ++k) acc += sc[ty][k] * slw[(64 + k) * 16 + tx];
    float mx = acc;
#pragma unroll
    for (int o = 8; o > 0; o >>= 1) mx = fmaxf(mx, __shfl_xor_sync(0xffffffffu, mx, o));
    float e = __expf(acc - mx);
    float sum = e;
#pragma unroll
    for (int o = 8; o > 0; o >>= 1) sum += __shfl_xor_sync(0xffffffffu, sum, o);
    out[row * 16 + tx] = e / sum;
}

// ---------------- host launchers ----------------
template <int KREAL, int M, int EPI, int STAT>
static void launch_wgemm(const float* X, float* Y, const float* W, const float* bng,
                         const float* bnb, const float* bias, int slotF,
                         int slotA = 0, int slotB = 0) {
    constexpr int KC = 32;
    constexpr size_t comp = (size_t)(2 * 128 * (KC + 8) + 2 * KC * (M + 8)) * 2
                          + (size_t)2 * 128 * KC * 4 + (size_t)2 * KC * M * 4;
    constexpr size_t stg  = (size_t)128 * (M + 8) * 4;
    constexpr size_t smem = comp > stg ? comp : stg;
    cudaFuncSetAttribute(k_wgemm<KREAL, M, EPI, STAT>,
                         cudaFuncAttributeMaxDynamicSharedMemorySize, (int)smem);
    k_wgemm<KREAL, M, EPI, STAT><<<N_ / 128, 256, smem>>>(X, Y, W, bng, bnb, bias,
                                                          slotF, slotA, slotB);
}

extern "C" void kernel_launch(void* const* d_in, const int* in_sizes, int n_in,
                              void* d_out, int out_size) {
    const float* x   = (const float*)d_in[0];
    const int*   ei  = (const int*)d_in[1];
    const int*   src = ei;
    const int*   dst = ei + E_;
    const float* dn_bn1_g = (const float*)d_in[2];
    const float* dn_bn1_b = (const float*)d_in[3];
    const float* dn_w1    = (const float*)d_in[4];
    const float* dn_b1    = (const float*)d_in[5];
    const float* dn_bn2_g = (const float*)d_in[6];
    const float* dn_bn2_b = (const float*)d_in[7];
    const float* dn_w2    = (const float*)d_in[8];
    const float* dn_b2    = (const float*)d_in[9];
    const float* cnn_bn_g = (const float*)d_in[10];
    const float* cnn_bn_b = (const float*)d_in[11];
    const float* cnn_pw   = (const float*)d_in[12];
    const float* cnn_dw   = (const float*)d_in[13];
    const float* cnn_db   = (const float*)d_in[14];
    const float* g1_bn_g  = (const float*)d_in[15];
    const float* g1_bn_b  = (const float*)d_in[16];
    const float* g1_w     = (const float*)d_in[17];
    const float* g1_b     = (const float*)d_in[18];
    const float* g2_bn_g  = (const float*)d_in[19];
    const float* g2_bn_b  = (const float*)d_in[20];
    const float* g2_w     = (const float*)d_in[21];
    const float* g2_b     = (const float*)d_in[22];
    const float* g3_bn_g  = (const float*)d_in[23];
    const float* g3_bn_b  = (const float*)d_in[24];
    const float* g3_w     = (const float*)d_in[25];
    const float* g3_b     = (const float*)d_in[26];
    const float* lin_w    = (const float*)d_in[27];
    const float* lin_b    = (const float*)d_in[28];
    float* out = (float*)d_out;

    float *pP, *pQ, *pH, *pC, *pCR;
    cudaGetSymbolAddress((void**)&pP, g_P);
    cudaGetSymbolAddress((void**)&pQ, g_Q);
    cudaGetSymbolAddress((void**)&pH, g_Hm);
    cudaGetSymbolAddress((void**)&pC, g_cnn);
    cudaGetSymbolAddress((void**)&pCR, g_cnnres);

    // launches 1-3, then #4 = big tensor GEMM (kept at position 4 for profiling)
    k_init<<<NBLK_ + 1, 256>>>();
    k_colstats<200><<<128, 200>>>(x, 0);
    k_deg_count<<<(E_ + 255) / 256, 256>>>(dst);
    launch_wgemm<200, 128, 0, 1>(x, pQ, dn_w1, dn_bn1_g, dn_bn1_b, dn_b1, 0, 1);

    // CSR build + dinv
    k_scan1<<<NBLK_, 256>>>();
    k_scan2<<<1, 1024>>>();
    k_scan3<<<NBLK_, 256>>>();
    k_csr_fill<<<(E_ + 255) / 256, 256>>>(src, dst);

    // denoise layer 2: epilogue -> plain stats (slot 2, CNN fold) + invn/norm stats (slot 3)
    launch_wgemm<128, 128, 0, 2>(pQ, pP, dn_w2, dn_bn2_g, dn_bn2_b, dn_b2, 1, 2, 3);

    // CNN branch
    launch_wgemm<128, 64, 0, 0>(pP, pC, cnn_pw, cnn_bn_g, cnn_bn_b, nullptr, 2);
    k_dwconv<<<N_ / 16, 256>>>(pC, cnn_dw, cnn_db, pCR);

    // GCN layer 1
    launch_wgemm<128, 128, 1, 0>(pP, pH, g1_w, g1_bn_g, g1_bn_b, nullptr, 3);
    k_gather128<true><<<1152, 256>>>(pH, g1_b, pP, 4);

    // GCN layer 2
    launch_wgemm<128, 128, 1, 0>(pP, pH, g2_w, g2_bn_g, g2_bn_b, nullptr, 4);
    k_gather128<true><<<1152, 256>>>(pH, g2_b, pP, 5);

    // GCN layer 3 (128 -> 64)
    launch_wgemm<128, 64, 1, 0>(pP, pH, g3_w, g3_bn_g, g3_bn_b, nullptr, 5);
    k_gather64<<<(N_ * 32) / 256, 256>>>(pH, g3_b, pP);

    // head
    k_final<<<N_ / 16, 256>>>(pP, pCR, lin_w, lin_b, out);
}

// round 10
// speedup vs baseline: 1.9619x; 1.0183x over previous
#include <cuda_runtime.h>
#include <cuda_bf16.h>
#include <cuda_pipeline.h>
#include <mma.h>
#include <cstdint>
#include <cstddef>

using namespace nvcuda;

// ---------------- problem constants ----------------
#define Hh_ 384
#define Ww_ 384
#define C_ 200
#define N_ 147456           // Hh_*Ww_
#define E_ 1179648
#define HIDE_ 128
#define OUT_ 64
#define NCLS_ 16
#define EPS_ 1e-5f
#define SLOPE_ 0.01f
#define NBLK_ 576           // N_/256

// ---------------- scratch (device globals; no allocation allowed) ----------------
__device__ float g_P[(size_t)N_ * 128];
__device__ float g_Q[(size_t)N_ * 128];
__device__ float g_Hm[(size_t)N_ * 128];
__device__ float g_cnn[(size_t)N_ * 64];
__device__ float g_cnnres[(size_t)N_ * 64];
__device__ float g_dinv[N_];
__device__ float g_invn[N_];
__device__ float g_sum[6 * 256];
__device__ float g_sq[6 * 256];
// CSR
__device__ int g_degi[N_];
__device__ int g_rowptr[N_ + 1];
__device__ int g_cursor[N_];
__device__ int g_blksum[NBLK_];
__device__ int g_col[E_];

// ---------------- init: zero all stat slots + degree array ----------------
__global__ void k_init() {
    int i = blockIdx.x * 256 + threadIdx.x;
    if (i < N_) g_degi[i] = 0;
    if (i < 6 * 256) { g_sum[i] = 0.f; g_sq[i] = 0.f; }
}

// plain column stats (only used for raw input x): blockDim == C
template <int C>
__global__ void k_colstats(const float* __restrict__ X, int slot) {
    const int c = threadIdx.x;
    const int rpb = N_ / 128;
    const int r0 = blockIdx.x * rpb;
    float s = 0.f, q = 0.f;
    for (int r = r0; r < r0 + rpb; ++r) {
        float v = X[(size_t)r * C + c];
        s += v; q += v * v;
    }
    atomicAdd(&g_sum[slot * 256 + c], s);
    atomicAdd(&g_sq[slot * 256 + c], q);
}

// ---------------- tensor GEMM via wmma (bf16 hi/lo split, fp32 accum) ----------------
// cp.async double-buffered raw staging of X and W; BN fold + bf16 split from smem.
// Y[N,M] = epi( X[N,KREAL] @ (diag(scale)·W) + bf )
// EPI 0: out = leaky(acc + bf)         EPI 1: out = (acc*invn[r] + bf) * dinv[r]
// STAT (EPI0, M=128): 1 = plain col stats -> slotA; 2 = plain->slotA AND invn+norm stats->slotB
// 256 threads = 8 warps in a 4(m) x 2(n) grid. Warp tile: 32 rows x M/2 cols.
template <int KREAL, int M, int EPI, int STAT>
__global__ __launch_bounds__(256, 2)
void k_wgemm(const float* __restrict__ X, float* __restrict__ Y,
             const float* __restrict__ W, const float* __restrict__ bng,
             const float* __restrict__ bnb, const float* __restrict__ bias,
             int slotF, int slotA, int slotB) {
    constexpr int KC = 32;            // K chunk
    constexpr int AS = KC + 8;        // A smem stride (halves)
    constexpr int BS = M + 8;         // B smem stride (halves)
    constexpr int MT = 2;             // m-tiles per warp (32 rows)
    constexpr int NT2 = M / 32;       // n-tiles per warp (M/2 cols)
    constexpr int NCH = (KREAL + KC - 1) / KC;
    constexpr int LASTR = KREAL - (NCH - 1) * KC;
    constexpr int KS_LAST = (LASTR + 15) / 16;

    constexpr int SZ_A = 128 * AS * 2;        // one bf16 plane
    constexpr int SZ_B = KC * BS * 2;
    constexpr int SZ_RX = 128 * KC * 4;       // one raw X slot
    constexpr int SZ_RW = KC * M * 4;         // one raw W slot

    extern __shared__ char smraw[];
    __nv_bfloat16* Ah = (__nv_bfloat16*)smraw;
    __nv_bfloat16* Al = (__nv_bfloat16*)(smraw + SZ_A);
    __nv_bfloat16* Bh = (__nv_bfloat16*)(smraw + 2 * SZ_A);
    __nv_bfloat16* Bl = (__nv_bfloat16*)(smraw + 2 * SZ_A + SZ_B);
    float* rawX[2] = { (float*)(smraw + 2 * SZ_A + 2 * SZ_B),
                       (float*)(smraw + 2 * SZ_A + 2 * SZ_B + SZ_RX) };
    float* rawW[2] = { (float*)(smraw + 2 * SZ_A + 2 * SZ_B + 2 * SZ_RX),
                       (float*)(smraw + 2 * SZ_A + 2 * SZ_B + 2 * SZ_RX + SZ_RW) };
    float* stage = (float*)smraw;             // reused post-compute

    __shared__ float s_scale[256];
    __shared__ float s_shift[256];
    __shared__ float s_bf[128];

    const int tid = threadIdx.x, wid = tid >> 5, lane = tid & 31;
    const int wm = wid & 3, wn = wid >> 2;
    const size_t row0 = (size_t)blockIdx.x * 128;

    // fold coefficients from stats
    {
        float sc = 0.f, sh = 0.f;
        if (tid < KREAL) {
            float mean = g_sum[slotF * 256 + tid] * (1.f / N_);
            float var  = g_sq[slotF * 256 + tid] * (1.f / N_) - mean * mean;
            sc = bng[tid] * rsqrtf(var + EPS_);
            sh = bnb[tid] - mean * sc;
        }
        s_scale[tid] = sc;
        s_shift[tid] = sh;
        if (tid < M) s_bf[tid] = bias ? bias[tid] : 0.f;
    }

    wmma::fragment<wmma::accumulator, 16, 16, 16, float> acc[MT][NT2];
#pragma unroll
    for (int m = 0; m < MT; ++m)
#pragma unroll
        for (int n = 0; n < NT2; ++n) wmma::fill_fragment(acc[m][n], 0.0f);

    float pbf0 = 0.f, pbf1 = 0.f;
    const int myn2 = tid % (M / 2);

    // issue cp.async for chunk c into slot
    auto cp_chunk = [&](int c, int slot) {
        for (int p = tid; p < 128 * (KC / 4); p += 256) {
            int r = p / (KC / 4), s = p % (KC / 4);
            int col0 = c * KC + s * 4;
            int real = KREAL - col0; real = real < 0 ? 0 : (real > 4 ? 4 : real);
            const float* src = &X[(row0 + r) * KREAL + (real ? col0 : 0)];
            __pipeline_memcpy_async(&rawX[slot][r * KC + s * 4], src, 16,
                                    (size_t)(4 - real) * 4);
        }
        for (int p = tid; p < KC * (M / 4); p += 256) {
            int k = p / (M / 4), n4 = p % (M / 4);
            int kg = c * KC + k;
            bool ok = kg < KREAL;
            const float* src = &W[(size_t)(ok ? kg : 0) * M + n4 * 4];
            __pipeline_memcpy_async(&rawW[slot][k * M + n4 * 4], src, 16,
                                    ok ? 0 : 16);
        }
        __pipeline_commit();
    };

    // convert raw slot -> bf16 planes (+ bias fold from raw W)
    auto convert = [&](int c, int slot) {
        for (int p = tid; p < 128 * (KC / 2); p += 256) {
            int r = p / (KC / 2), q = p % (KC / 2);
            float2 v = *(float2*)&rawX[slot][r * KC + q * 2];
            __nv_bfloat16 h0 = __float2bfloat16(v.x);
            __nv_bfloat16 h1 = __float2bfloat16(v.y);
            __nv_bfloat16 l0 = __float2bfloat16(v.x - __bfloat162float(h0));
            __nv_bfloat16 l1 = __float2bfloat16(v.y - __bfloat162float(h1));
            *(__nv_bfloat162*)&Ah[r * AS + q * 2] = __nv_bfloat162(h0, h1);
            *(__nv_bfloat162*)&Al[r * AS + q * 2] = __nv_bfloat162(l0, l1);
        }
        for (int p = tid; p < KC * (M / 2); p += 256) {
            int kl = p / (M / 2), n2 = p % (M / 2);
            float2 w = *(float2*)&rawW[slot][kl * M + n2 * 2];
            int kg = c * KC + kl;
            float sh = s_shift[kg];
            pbf0 += sh * w.x;
            pbf1 += sh * w.y;
            float sc = s_scale[kg];
            w.x *= sc; w.y *= sc;
            __nv_bfloat16 h0 = __float2bfloat16(w.x);
            __nv_bfloat16 h1 = __float2bfloat16(w.y);
            __nv_bfloat16 l0 = __float2bfloat16(w.x - __bfloat162float(h0));
            __nv_bfloat16 l1 = __float2bfloat16(w.y - __bfloat162float(h1));
            *(__nv_bfloat162*)&Bh[kl * BS + n2 * 2] = __nv_bfloat162(h0, h1);
            *(__nv_bfloat162*)&Bl[kl * BS + n2 * 2] = __nv_bfloat162(l0, l1);
        }
    };

    auto do_ks = [&](int ks) {
        wmma::fragment<wmma::matrix_a, 16, 16, 16, __nv_bfloat16, wmma::row_major> aH[MT], aL[MT];
#pragma unroll
        for (int m = 0; m < MT; ++m) {
            int rbase = wm * 32 + m * 16;
            wmma::load_matrix_sync(aH[m], Ah + rbase * AS + ks * 16, AS);
            wmma::load_matrix_sync(aL[m], Al + rbase * AS + ks * 16, AS);
        }
#pragma unroll
        for (int n = 0; n < NT2; ++n) {
            int cbase = wn * (M / 2) + n * 16;
            wmma::fragment<wmma::matrix_b, 16, 16, 16, __nv_bfloat16, wmma::row_major> bH, bL;
            wmma::load_matrix_sync(bH, Bh + ks * 16 * BS + cbase, BS);
            wmma::load_matrix_sync(bL, Bl + ks * 16 * BS + cbase, BS);
#pragma unroll
            for (int m = 0; m < MT; ++m) {
                wmma::mma_sync(acc[m][n], aH[m], bH, acc[m][n]);
                wmma::mma_sync(acc[m][n], aH[m], bL, acc[m][n]);
                wmma::mma_sync(acc[m][n], aL[m], bH, acc[m][n]);
            }
        }
    };

    cp_chunk(0, 0);
    for (int c = 0; c < NCH; ++c) {
        const int slot = c & 1;
        if (c + 1 < NCH) cp_chunk(c + 1, (c + 1) & 1);
        __pipeline_wait_prior((c + 1 < NCH) ? 1 : 0);
        __syncthreads();
        convert(c, slot);
        __syncthreads();
        const int nks = (c == NCH - 1) ? KS_LAST : 2;
        for (int ks = 0; ks < nks; ++ks) do_ks(ks);
        __syncthreads();
    }

    // finish folded bias (threads sharing a column pair combine)
    atomicAdd(&s_bf[myn2 * 2 + 0], pbf0);
    atomicAdd(&s_bf[myn2 * 2 + 1], pbf1);

    // stage accumulators to smem, then coalesced epi + store
#pragma unroll
    for (int m = 0; m < MT; ++m)
#pragma unroll
        for (int n = 0; n < NT2; ++n)
            wmma::store_matrix_sync(stage + (wm * 32 + m * 16) * (M + 8) + wn * (M / 2) + n * 16,
                                    acc[m][n], M + 8, wmma::mem_row_major);
    __syncthreads();

    float s1[4] = {0.f, 0.f, 0.f, 0.f}, q1[4] = {0.f, 0.f, 0.f, 0.f};
    float s2[4] = {0.f, 0.f, 0.f, 0.f}, q2[4] = {0.f, 0.f, 0.f, 0.f};

    for (int idx = tid; idx < 128 * (M / 4); idx += 256) {
        int r = idx / (M / 4), cq = idx % (M / 4);
        size_t gr = row0 + r;
        float4 v = *(float4*)&stage[r * (M + 8) + cq * 4];
        float4 b = *(const float4*)&s_bf[cq * 4];
        if (EPI == 0) {
            v.x += b.x; v.y += b.y; v.z += b.z; v.w += b.w;
            v.x = v.x > 0.f ? v.x : SLOPE_ * v.x;
            v.y = v.y > 0.f ? v.y : SLOPE_ * v.y;
            v.z = v.z > 0.f ? v.z : SLOPE_ * v.z;
            v.w = v.w > 0.f ? v.w : SLOPE_ * v.w;
            if (STAT >= 1) {
                s1[0] += v.x; s1[1] += v.y; s1[2] += v.z; s1[3] += v.w;
                q1[0] += v.x * v.x; q1[1] += v.y * v.y; q1[2] += v.z * v.z; q1[3] += v.w * v.w;
            }
            if (STAT == 2) {
                float ss = v.x * v.x + v.y * v.y + v.z * v.z + v.w * v.w;
#pragma unroll
                for (int o = 16; o > 0; o >>= 1) ss += __shfl_xor_sync(0xffffffffu, ss, o);
                float inv = 1.0f / fmaxf(sqrtf(ss), 1e-12f);
                if (lane == 0) g_invn[gr] = inv;
                float nx = v.x * inv, ny = v.y * inv, nz = v.z * inv, nw = v.w * inv;
                s2[0] += nx; s2[1] += ny; s2[2] += nz; s2[3] += nw;
                q2[0] += nx * nx; q2[1] += ny * ny; q2[2] += nz * nz; q2[3] += nw * nw;
            }
        } else {
            float sr = g_invn[gr], dv = g_dinv[gr];
            v.x = (v.x * sr + b.x) * dv;
            v.y = (v.y * sr + b.y) * dv;
            v.z = (v.z * sr + b.z) * dv;
            v.w = (v.w * sr + b.w) * dv;
        }
        *(float4*)&Y[gr * M + cq * 4] = v;
    }

    if (EPI == 0 && STAT >= 1) {
        __syncthreads();
        float* red = stage;
#pragma unroll
        for (int j = 0; j < 4; ++j) {
            red[0 * 1024 + wid * 128 + lane * 4 + j] = s1[j];
            red[1 * 1024 + wid * 128 + lane * 4 + j] = q1[j];
            if (STAT == 2) {
                red[2 * 1024 + wid * 128 + lane * 4 + j] = s2[j];
                red[3 * 1024 + wid * 128 + lane * 4 + j] = q2[j];
            }
        }
        __syncthreads();
        if (tid < 128) {
            float a = 0.f, b = 0.f, c2 = 0.f, d2 = 0.f;
#pragma unroll
            for (int w = 0; w < 8; ++w) {
                a  += red[0 * 1024 + w * 128 + tid];
                b  += red[1 * 1024 + w * 128 + tid];
                if (STAT == 2) {
                    c2 += red[2 * 1024 + w * 128 + tid];
                    d2 += red[3 * 1024 + w * 128 + tid];
                }
            }
            atomicAdd(&g_sum[slotA * 256 + tid], a);
            atomicAdd(&g_sq[slotA * 256 + tid], b);
            if (STAT == 2) {
                atomicAdd(&g_sum[slotB * 256 + tid], c2);
                atomicAdd(&g_sq[slotB * 256 + tid], d2);
            }
        }
    }
}

// ---------------- CSR build ----------------
__global__ void k_deg_count(const int* __restrict__ dst) {
    int e = blockIdx.x * blockDim.x + threadIdx.x;
    if (e < E_) atomicAdd(&g_degi[dst[e]], 1);
}
__global__ void k_scan1() {
    __shared__ int s[256];
    int t = threadIdx.x;
    int idx = blockIdx.x * 256 + t;
    int v = g_degi[idx];
    s[t] = v;
    __syncthreads();
#pragma unroll
    for (int off = 1; off < 256; off <<= 1) {
        int a = 0;
        if (t >= off) a = s[t - off];
        __syncthreads();
        s[t] += a;
        __syncthreads();
    }
    g_rowptr[idx] = s[t] - v;
    if (t == 255) g_blksum[blockIdx.x] = s[255];
}
__global__ void k_scan2() {
    __shared__ int s[NBLK_];
    int t = threadIdx.x;
    if (t < NBLK_) s[t] = g_blksum[t];
    __syncthreads();
    for (int off = 1; off < NBLK_; off <<= 1) {
        int a = 0;
        if (t >= off && t < NBLK_) a = s[t - off];
        __syncthreads();
        if (t < NBLK_) s[t] += a;
        __syncthreads();
    }
    if (t < NBLK_) g_blksum[t] = s[t];
}
__global__ void k_scan3() {
    int idx = blockIdx.x * 256 + threadIdx.x;
    int off = blockIdx.x == 0 ? 0 : g_blksum[blockIdx.x - 1];
    int rp = g_rowptr[idx] + off;
    g_rowptr[idx] = rp;
    g_cursor[idx] = rp;
    g_dinv[idx] = rsqrtf((float)g_degi[idx] + 1.0f);
    if (idx == 0) g_rowptr[N_] = E_;
}
__global__ void k_csr_fill(const int* __restrict__ src, const int* __restrict__ dst) {
    int e = blockIdx.x * blockDim.x + threadIdx.x;
    if (e < E_) {
        int pos = atomicAdd(&g_cursor[dst[e]], 1);
        g_col[pos] = src[e];
    }
}

// ---------------- GCN gather (fused: bias + scale + leaky [+ rownorm stats]) ----------------
template <bool RSTAT>
__global__ void k_gather128(const float* __restrict__ Hs, const float* __restrict__ gb,
                            float* __restrict__ out, int slot) {
    __shared__ float sred[2][8][128];
    const int tid = threadIdx.x, wid = tid >> 5, lane = tid & 31;
    const float4 b = *(const float4*)&gb[lane * 4];
    float4 s4 = {0.f, 0.f, 0.f, 0.f}, q4 = {0.f, 0.f, 0.f, 0.f};

    for (int i = blockIdx.x * 8 + wid; i < N_; i += 9216) {
        int beg = __ldg(&g_rowptr[i]), end = __ldg(&g_rowptr[i + 1]);
        float4 acc = *(const float4*)&Hs[(size_t)i * 128 + lane * 4];
        for (int base = beg; base < end; base += 32) {
            int e = base + lane;
            int sidx = (e < end) ? g_col[e] : 0;
            int cnt = min(32, end - base);
            int j = 0;
            for (; j + 8 <= cnt; j += 8) {
                int s0 = __shfl_sync(0xffffffffu, sidx, j);
                int s1 = __shfl_sync(0xffffffffu, sidx, j + 1);
                int s2 = __shfl_sync(0xffffffffu, sidx, j + 2);
                int s3 = __shfl_sync(0xffffffffu, sidx, j + 3);
                int s4i = __shfl_sync(0xffffffffu, sidx, j + 4);
                int s5 = __shfl_sync(0xffffffffu, sidx, j + 5);
                int s6 = __shfl_sync(0xffffffffu, sidx, j + 6);
                int s7 = __shfl_sync(0xffffffffu, sidx, j + 7);
                float4 v0 = *(const float4*)&Hs[(size_t)s0 * 128 + lane * 4];
                float4 v1 = *(const float4*)&Hs[(size_t)s1 * 128 + lane * 4];
                float4 v2 = *(const float4*)&Hs[(size_t)s2 * 128 + lane * 4];
                float4 v3 = *(const float4*)&Hs[(size_t)s3 * 128 + lane * 4];
                float4 v4 = *(const float4*)&Hs[(size_t)s4i * 128 + lane * 4];
                float4 v5 = *(const float4*)&Hs[(size_t)s5 * 128 + lane * 4];
                float4 v6 = *(const float4*)&Hs[(size_t)s6 * 128 + lane * 4];
                float4 v7 = *(const float4*)&Hs[(size_t)s7 * 128 + lane * 4];
                acc.x += (v0.x + v1.x) + (v2.x + v3.x) + ((v4.x + v5.x) + (v6.x + v7.x));
                acc.y += (v0.y + v1.y) + (v2.y + v3.y) + ((v4.y + v5.y) + (v6.y + v7.y));
                acc.z += (v0.z + v1.z) + (v2.z + v3.z) + ((v4.z + v5.z) + (v6.z + v7.z));
                acc.w += (v0.w + v1.w) + (v2.w + v3.w) + ((v4.w + v5.w) + (v6.w + v7.w));
            }
            for (; j < cnt; ++j) {
                int s = __shfl_sync(0xffffffffu, sidx, j);
                float4 v = *(const float4*)&Hs[(size_t)s * 128 + lane * 4];
                acc.x += v.x; acc.y += v.y; acc.z += v.z; acc.w += v.w;
            }
        }
        float di = g_dinv[i];
        acc.x = b.x + di * acc.x;
        acc.y = b.y + di * acc.y;
        acc.z = b.z + di * acc.z;
        acc.w = b.w + di * acc.w;
        acc.x = acc.x > 0.f ? acc.x : SLOPE_ * acc.x;
        acc.y = acc.y > 0.f ? acc.y : SLOPE_ * acc.y;
        acc.z = acc.z > 0.f ? acc.z : SLOPE_ * acc.z;
        acc.w = acc.w > 0.f ? acc.w : SLOPE_ * acc.w;
        if (RSTAT) {
            float ss = acc.x * acc.x + acc.y * acc.y + acc.z * acc.z + acc.w * acc.w;
#pragma unroll
            for (int o = 16; o > 0; o >>= 1) ss += __shfl_xor_sync(0xffffffffu, ss, o);
            float inv = 1.0f / fmaxf(sqrtf(ss), 1e-12f);
            if (lane == 0) g_invn[i] = inv;
            float nx = acc.x * inv, ny = acc.y * inv, nz = acc.z * inv, nw = acc.w * inv;
            s4.x += nx; s4.y += ny; s4.z += nz; s4.w += nw;
            q4.x += nx * nx; q4.y += ny * ny; q4.z += nz * nz; q4.w += nw * nw;
        }
        *(float4*)&out[(size_t)i * 128 + lane * 4] = acc;
    }

    if (RSTAT) {
        sred[0][wid][lane * 4 + 0] = s4.x; sred[0][wid][lane * 4 + 1] = s4.y;
        sred[0][wid][lane * 4 + 2] = s4.z; sred[0][wid][lane * 4 + 3] = s4.w;
        sred[1][wid][lane * 4 + 0] = q4.x; sred[1][wid][lane * 4 + 1] = q4.y;
        sred[1][wid][lane * 4 + 2] = q4.z; sred[1][wid][lane * 4 + 3] = q4.w;
        __syncthreads();
        if (tid < 128) {
            float a = 0.f, b2 = 0.f;
#pragma unroll
            for (int w = 0; w < 8; ++w) { a += sred[0][w][tid]; b2 += sred[1][w][tid]; }
            atomicAdd(&g_sum[slot * 256 + tid], a);
            atomicAdd(&g_sq[slot * 256 + tid], b2);
        }
    }
}

// gather64: bias + scale + leaky fused
__global__ void k_gather64(const float* __restrict__ Hs, const float* __restrict__ gb,
                           float* __restrict__ out) {
    int i = (int)(((size_t)blockIdx.x * blockDim.x + threadIdx.x) >> 5);
    if (i >= N_) return;
    int lane = threadIdx.x & 31;
    int beg = __ldg(&g_rowptr[i]), end = __ldg(&g_rowptr[i + 1]);
    float2 acc = *(const float2*)&Hs[(size_t)i * 64 + lane * 2];
    for (int base = beg; base < end; base += 32) {
        int e = base + lane;
        int sidx = (e < end) ? g_col[e] : 0;
        int cnt = min(32, end - base);
        int j = 0;
        for (; j + 8 <= cnt; j += 8) {
            int s0 = __shfl_sync(0xffffffffu, sidx, j);
            int s1 = __shfl_sync(0xffffffffu, sidx, j + 1);
            int s2 = __shfl_sync(0xffffffffu, sidx, j + 2);
            int s3 = __shfl_sync(0xffffffffu, sidx, j + 3);
            int s4 = __shfl_sync(0xffffffffu, sidx, j + 4);
            int s5 = __shfl_sync(0xffffffffu, sidx, j + 5);
            int s6 = __shfl_sync(0xffffffffu, sidx, j + 6);
            int s7 = __shfl_sync(0xffffffffu, sidx, j + 7);
            float2 v0 = *(const float2*)&Hs[(size_t)s0 * 64 + lane * 2];
            float2 v1 = *(const float2*)&Hs[(size_t)s1 * 64 + lane * 2];
            float2 v2 = *(const float2*)&Hs[(size_t)s2 * 64 + lane * 2];
            float2 v3 = *(const float2*)&Hs[(size_t)s3 * 64 + lane * 2];
            float2 v4 = *(const float2*)&Hs[(size_t)s4 * 64 + lane * 2];
            float2 v5 = *(const float2*)&Hs[(size_t)s5 * 64 + lane * 2];
            float2 v6 = *(const float2*)&Hs[(size_t)s6 * 64 + lane * 2];
            float2 v7 = *(const float2*)&Hs[(size_t)s7 * 64 + lane * 2];
            acc.x += (v0.x + v1.x) + (v2.x + v3.x) + ((v4.x + v5.x) + (v6.x + v7.x));
            acc.y += (v0.y + v1.y) + (v2.y + v3.y) + ((v4.y + v5.y) + (v6.y + v7.y));
        }
        for (; j < cnt; ++j) {
            int s = __shfl_sync(0xffffffffu, sidx, j);
            float2 v = *(const float2*)&Hs[(size_t)s * 64 + lane * 2];
            acc.x += v.x; acc.y += v.y;
        }
    }
    float di = g_dinv[i];
    float2 b = *(const float2*)&gb[lane * 2];
    acc.x = b.x + di * acc.x;
    acc.y = b.y + di * acc.y;
    acc.x = acc.x > 0.f ? acc.x : SLOPE_ * acc.x;
    acc.y = acc.y > 0.f ? acc.y : SLOPE_ * acc.y;
    *(float2*)&out[(size_t)i * 64 + lane * 2] = acc;
}

// ---------------- depthwise 5x5 conv ----------------
__global__ void k_dwconv(const float* __restrict__ In, const float* __restrict__ dw,
                         const float* __restrict__ db, float* __restrict__ Out) {
    __shared__ float wt[25 * 64];
    int tid = threadIdx.x;
    for (int i = tid; i < 25 * 64; i += 256) {
        int t = i >> 6, c = i & 63;
        wt[i] = dw[c * 25 + t];
    }
    __syncthreads();
    int c4 = tid & 15;
    int p = blockIdx.x * 16 + (tid >> 4);
    int y = p / Ww_, x = p % Ww_;
    float4 acc = {0.f, 0.f, 0.f, 0.f};
#pragma unroll
    for (int ky = 0; ky < 5; ++ky) {
        int yy = y + ky - 2;
        if (yy < 0 || yy >= Hh_) continue;
#pragma unroll
        for (int kx = 0; kx < 5; ++kx) {
            int xx = x + kx - 2;
            if (xx < 0 || xx >= Ww_) continue;
            float4 v  = *(const float4*)&In[((size_t)yy * Ww_ + xx) * 64 + c4 * 4];
            float4 wv = *(const float4*)&wt[(ky * 5 + kx) * 64 + c4 * 4];
            acc.x += v.x * wv.x; acc.y += v.y * wv.y;
            acc.z += v.z * wv.z; acc.w += v.w * wv.w;
        }
    }
    float4 b = *(const float4*)&db[c4 * 4];
    acc.x += b.x; acc.y += b.y; acc.z += b.z; acc.w += b.w;
    acc.x = acc.x > 0.f ? acc.x : SLOPE_ * acc.x;
    acc.y = acc.y > 0.f ? acc.y : SLOPE_ * acc.y;
    acc.z = acc.z > 0.f ? acc.z : SLOPE_ * acc.z;
    acc.w = acc.w > 0.f ? acc.w : SLOPE_ * acc.w;
    *(float4*)&Out[(size_t)p * 64 + c4 * 4] = acc;
}

// ---------------- head: G (already leaky) concat Cn -> linear -> softmax ----------------
__global__ void k_final(const float* __restrict__ G, const float* __restrict__ Cn,
                        const float* __restrict__ lw, const float* __restrict__ lb,
                        float* __restrict__ out) {
    __shared__ float slw[128 * 16];
    __shared__ float slb[16];
    __shared__ float sg[16][64];
    __shared__ float sc[16][64];
    int tid = threadIdx.x;
    for (int i = tid; i < 2048; i += 256) slw[i] = lw[i];
    if (tid < 16) slb[tid] = lb[tid];
    int tx = tid & 15, ty = tid >> 4;
    size_t row = (size_t)blockIdx.x * 16 + ty;
    *(float4*)&sg[ty][tx * 4] = *(const float4*)&G[row * 64 + tx * 4];
    *(float4*)&sc[ty][tx * 4] = *(const float4*)&Cn[row * 64 + tx * 4];
    __syncthreads();
    float acc = slb[tx];
#pragma unroll 4
    for (int k = 0; k < 64; ++k) acc += sg[ty][k] * slw[k * 16 + tx];
#pragma unroll 4
    for (int k = 0; k < 64; ++k) acc += sc[ty][k] * slw[(64 + k) * 16 + tx];
    float mx = acc;
#pragma unroll
    for (int o = 8; o > 0; o >>= 1) mx = fmaxf(mx, __shfl_xor_sync(0xffffffffu, mx, o));
    float e = __expf(acc - mx);
    float sum = e;
#pragma unroll
    for (int o = 8; o > 0; o >>= 1) sum += __shfl_xor_sync(0xffffffffu, sum, o);
    out[row * 16 + tx] = e / sum;
}

// ---------------- host launchers ----------------
template <int KREAL, int M, int EPI, int STAT>
static void launch_wgemm(cudaStream_t st, const float* X, float* Y, const float* W,
                         const float* bng, const float* bnb, const float* bias, int slotF,
                         int slotA = 0, int slotB = 0) {
    constexpr int KC = 32;
    constexpr size_t comp = (size_t)(2 * 128 * (KC + 8) + 2 * KC * (M + 8)) * 2
                          + (size_t)2 * 128 * KC * 4 + (size_t)2 * KC * M * 4;
    constexpr size_t stg  = (size_t)128 * (M + 8) * 4;
    constexpr size_t smem = comp > stg ? comp : stg;
    cudaFuncSetAttribute(k_wgemm<KREAL, M, EPI, STAT>,
                         cudaFuncAttributeMaxDynamicSharedMemorySize, (int)smem);
    k_wgemm<KREAL, M, EPI, STAT><<<N_ / 128, 256, smem, st>>>(X, Y, W, bng, bnb, bias,
                                                              slotF, slotA, slotB);
}

extern "C" void kernel_launch(void* const* d_in, const int* in_sizes, int n_in,
                              void* d_out, int out_size) {
    const float* x   = (const float*)d_in[0];
    const int*   ei  = (const int*)d_in[1];
    const int*   src = ei;
    const int*   dst = ei + E_;
    const float* dn_bn1_g = (const float*)d_in[2];
    const float* dn_bn1_b = (const float*)d_in[3];
    const float* dn_w1    = (const float*)d_in[4];
    const float* dn_b1    = (const float*)d_in[5];
    const float* dn_bn2_g = (const float*)d_in[6];
    const float* dn_bn2_b = (const float*)d_in[7];
    const float* dn_w2    = (const float*)d_in[8];
    const float* dn_b2    = (const float*)d_in[9];
    const float* cnn_bn_g = (const float*)d_in[10];
    const float* cnn_bn_b = (const float*)d_in[11];
    const float* cnn_pw   = (const float*)d_in[12];
    const float* cnn_dw   = (const float*)d_in[13];
    const float* cnn_db   = (const float*)d_in[14];
    const float* g1_bn_g  = (const float*)d_in[15];
    const float* g1_bn_b  = (const float*)d_in[16];
    const float* g1_w     = (const float*)d_in[17];
    const float* g1_b     = (const float*)d_in[18];
    const float* g2_bn_g  = (const float*)d_in[19];
    const float* g2_bn_b  = (const float*)d_in[20];
    const float* g2_w     = (const float*)d_in[21];
    const float* g2_b     = (const float*)d_in[22];
    const float* g3_bn_g  = (const float*)d_in[23];
    const float* g3_bn_b  = (const float*)d_in[24];
    const float* g3_w     = (const float*)d_in[25];
    const float* g3_b     = (const float*)d_in[26];
    const float* lin_w    = (const float*)d_in[27];
    const float* lin_b    = (const float*)d_in[28];
    float* out = (float*)d_out;

    float *pP, *pQ, *pH, *pC, *pCR;
    cudaGetSymbolAddress((void**)&pP, g_P);
    cudaGetSymbolAddress((void**)&pQ, g_Q);
    cudaGetSymbolAddress((void**)&pH, g_Hm);
    cudaGetSymbolAddress((void**)&pC, g_cnn);
    cudaGetSymbolAddress((void**)&pCR, g_cnnres);

    // side stream + events, created once (outside graph capture: first call is
    // the plain correctness run). Handles are reused; captured work is identical
    // every call.
    static cudaStream_t s1 = nullptr;
    static cudaEvent_t evA = nullptr, evCSR = nullptr, evD2 = nullptr,
                       evCNNG = nullptr, evCNN = nullptr;
    if (s1 == nullptr) {
        cudaStreamCreate(&s1);
        cudaEventCreateWithFlags(&evA,    cudaEventDisableTiming);
        cudaEventCreateWithFlags(&evCSR,  cudaEventDisableTiming);
        cudaEventCreateWithFlags(&evD2,   cudaEventDisableTiming);
        cudaEventCreateWithFlags(&evCNNG, cudaEventDisableTiming);
        cudaEventCreateWithFlags(&evCNN,  cudaEventDisableTiming);
    }
    cudaStream_t s0 = 0;   // capture (default) stream

    // ---- main stream: stats + denoise; side stream: CSR build ----
    k_init<<<NBLK_ + 1, 256, 0, s0>>>();
    cudaEventRecord(evA, s0);
    k_colstats<200><<<128, 200, 0, s0>>>(x, 0);

    cudaStreamWaitEvent(s1, evA, 0);
    k_deg_count<<<(E_ + 255) / 256, 256, 0, s1>>>(dst);

    // launch #4 = big tensor GEMM (profiling target)
    launch_wgemm<200, 128, 0, 1>(s0, x, pQ, dn_w1, dn_bn1_g, dn_bn1_b, dn_b1, 0, 1);

    k_scan1<<<NBLK_, 256, 0, s1>>>();
    k_scan2<<<1, 1024, 0, s1>>>();
    k_scan3<<<NBLK_, 256, 0, s1>>>();
    k_csr_fill<<<(E_ + 255) / 256, 256, 0, s1>>>(src, dst);
    cudaEventRecord(evCSR, s1);

    // denoise layer 2 on s0: epilogue -> plain stats (slot 2) + invn/norm stats (slot 3)
    launch_wgemm<128, 128, 0, 2>(s0, pQ, pP, dn_w2, dn_bn2_g, dn_bn2_b, dn_b2, 1, 2, 3);
    cudaEventRecord(evD2, s0);

    // ---- CNN branch on side stream (reads pP + slot2) ----
    cudaStreamWaitEvent(s1, evD2, 0);
    launch_wgemm<128, 64, 0, 0>(s1, pP, pC, cnn_pw, cnn_bn_g, cnn_bn_b, nullptr, 2);
    cudaEventRecord(evCNNG, s1);          // pP no longer read by CNN branch
    k_dwconv<<<N_ / 16, 256, 0, s1>>>(pC, cnn_dw, cnn_db, pCR);
    cudaEventRecord(evCNN, s1);

    // ---- GCN chain on main stream ----
    cudaStreamWaitEvent(s0, evCSR, 0);    // g_dinv/rowptr/col ready
    launch_wgemm<128, 128, 1, 0>(s0, pP, pH, g1_w, g1_bn_g, g1_bn_b, nullptr, 3);
    cudaStreamWaitEvent(s0, evCNNG, 0);   // CNN GEMM done reading pP before we overwrite
    k_gather128<true><<<1152, 256, 0, s0>>>(pH, g1_b, pP, 4);

    launch_wgemm<128, 128, 1, 0>(s0, pP, pH, g2_w, g2_bn_g, g2_bn_b, nullptr, 4);
    k_gather128<true><<<1152, 256, 0, s0>>>(pH, g2_b, pP, 5);

    launch_wgemm<128, 64, 1, 0>(s0, pP, pH, g3_w, g3_bn_g, g3_bn_b, nullptr, 5);
    k_gather64<<<(N_ * 32) / 256, 256, 0, s0>>>(pH, g3_b, pP);

    // ---- head (needs CNN result) ----
    cudaStreamWaitEvent(s0, evCNN, 0);
    k_final<<<N_ / 16, 256, 0, s0>>>(pP, pCR, lin_w, lin_b, out);
}

// round 11
// speedup vs baseline: 2.3556x; 1.2006x over previous
#include <cuda_runtime.h>
#include <cuda_fp16.h>
#include <cuda_pipeline.h>
#include <mma.h>
#include <cstdint>
#include <cstddef>

using namespace nvcuda;

// ---------------- problem constants ----------------
#define Hh_ 384
#define Ww_ 384
#define C_ 200
#define N_ 147456           // Hh_*Ww_
#define E_ 1179648
#define HIDE_ 128
#define OUT_ 64
#define NCLS_ 16
#define EPS_ 1e-5f
#define SLOPE_ 0.01f
#define NBLK_ 576           // N_/256

// ---------------- scratch (device globals; no allocation allowed) ----------------
__device__ float g_P[(size_t)N_ * 128];
__device__ float g_Q[(size_t)N_ * 128];
__device__ float g_Hm[(size_t)N_ * 128];
__device__ float g_cnn[(size_t)N_ * 64];
__device__ float g_cnnres[(size_t)N_ * 64];
__device__ float g_dinv[N_];
__device__ float g_invn[N_];
__device__ float g_sum[6 * 256];
__device__ float g_sq[6 * 256];
// CSR
__device__ int g_degi[N_];
__device__ int g_rowptr[N_ + 1];
__device__ int g_cursor[N_];
__device__ int g_blksum[NBLK_];
__device__ int g_col[E_];

// ---------------- init: zero all stat slots + degree array ----------------
__global__ void k_init() {
    int i = blockIdx.x * 256 + threadIdx.x;
    if (i < N_) g_degi[i] = 0;
    if (i < 6 * 256) { g_sum[i] = 0.f; g_sq[i] = 0.f; }
}

// plain column stats (only used for raw input x): blockDim == C
template <int C>
__global__ void k_colstats(const float* __restrict__ X, int slot) {
    const int c = threadIdx.x;
    const int rpb = N_ / 128;
    const int r0 = blockIdx.x * rpb;
    float s = 0.f, q = 0.f;
    for (int r = r0; r < r0 + rpb; ++r) {
        float v = X[(size_t)r * C + c];
        s += v; q += v * v;
    }
    atomicAdd(&g_sum[slot * 256 + c], s);
    atomicAdd(&g_sq[slot * 256 + c], q);
}

// ---------------- tensor GEMM via wmma (fp16 hi/lo-A x fp16-B, fp32 accum) ----------------
// cp.async double-buffered raw staging of X and W; BN fold + fp16 split from smem.
// 2 products: D = Ah*B + Al*B  (A error ~2^-22, B error ~2^-12 -> rel_err ~1e-4)
// Y[N,M] = epi( X[N,KREAL] @ (diag(scale)·W) + bf )
// EPI 0: out = leaky(acc + bf)         EPI 1: out = (acc*invn[r] + bf) * dinv[r]
// STAT (EPI0, M=128): 1 = plain col stats -> slotA; 2 = plain->slotA AND invn+norm stats->slotB
// 256 threads = 8 warps in a 4(m) x 2(n) grid. Warp tile: 32 rows x M/2 cols.
template <int KREAL, int M, int EPI, int STAT>
__global__ __launch_bounds__(256, 2)
void k_wgemm(const float* __restrict__ X, float* __restrict__ Y,
             const float* __restrict__ W, const float* __restrict__ bng,
             const float* __restrict__ bnb, const float* __restrict__ bias,
             int slotF, int slotA, int slotB) {
    constexpr int KC = 32;            // K chunk
    constexpr int AS = KC + 8;        // A smem stride (halves)
    constexpr int BS = M + 8;         // B smem stride (halves)
    constexpr int MT = 2;             // m-tiles per warp (32 rows)
    constexpr int NT2 = M / 32;       // n-tiles per warp (M/2 cols)
    constexpr int NCH = (KREAL + KC - 1) / KC;
    constexpr int LASTR = KREAL - (NCH - 1) * KC;
    constexpr int KS_LAST = (LASTR + 15) / 16;

    constexpr int SZ_A = 128 * AS * 2;        // one fp16 plane
    constexpr int SZ_B = KC * BS * 2;
    constexpr int SZ_RX = 128 * KC * 4;       // one raw X slot
    constexpr int SZ_RW = KC * M * 4;         // one raw W slot

    extern __shared__ char smraw[];
    __half* Ah = (__half*)smraw;
    __half* Al = (__half*)(smraw + SZ_A);
    __half* Bs = (__half*)(smraw + 2 * SZ_A);
    float* rawX[2] = { (float*)(smraw + 2 * SZ_A + SZ_B),
                       (float*)(smraw + 2 * SZ_A + SZ_B + SZ_RX) };
    float* rawW[2] = { (float*)(smraw + 2 * SZ_A + SZ_B + 2 * SZ_RX),
                       (float*)(smraw + 2 * SZ_A + SZ_B + 2 * SZ_RX + SZ_RW) };
    float* stage = (float*)smraw;             // reused post-compute

    __shared__ float s_scale[256];
    __shared__ float s_shift[256];
    __shared__ float s_bf[128];

    const int tid = threadIdx.x, wid = tid >> 5, lane = tid & 31;
    const int wm = wid & 3, wn = wid >> 2;
    const size_t row0 = (size_t)blockIdx.x * 128;

    // fold coefficients from stats
    {
        float sc = 0.f, sh = 0.f;
        if (tid < KREAL) {
            float mean = g_sum[slotF * 256 + tid] * (1.f / N_);
            float var  = g_sq[slotF * 256 + tid] * (1.f / N_) - mean * mean;
            sc = bng[tid] * rsqrtf(var + EPS_);
            sh = bnb[tid] - mean * sc;
        }
        s_scale[tid] = sc;
        s_shift[tid] = sh;
        if (tid < M) s_bf[tid] = bias ? bias[tid] : 0.f;
    }

    wmma::fragment<wmma::accumulator, 16, 16, 16, float> acc[MT][NT2];
#pragma unroll
    for (int m = 0; m < MT; ++m)
#pragma unroll
        for (int n = 0; n < NT2; ++n) wmma::fill_fragment(acc[m][n], 0.0f);

    float pbf0 = 0.f, pbf1 = 0.f;
    const int myn2 = tid % (M / 2);

    // issue cp.async for chunk c into slot
    auto cp_chunk = [&](int c, int slot) {
        for (int p = tid; p < 128 * (KC / 4); p += 256) {
            int r = p / (KC / 4), s = p % (KC / 4);
            int col0 = c * KC + s * 4;
            int real = KREAL - col0; real = real < 0 ? 0 : (real > 4 ? 4 : real);
            const float* src = &X[(row0 + r) * KREAL + (real ? col0 : 0)];
            __pipeline_memcpy_async(&rawX[slot][r * KC + s * 4], src, 16,
                                    (size_t)(4 - real) * 4);
        }
        for (int p = tid; p < KC * (M / 4); p += 256) {
            int k = p / (M / 4), n4 = p % (M / 4);
            int kg = c * KC + k;
            bool ok = kg < KREAL;
            const float* src = &W[(size_t)(ok ? kg : 0) * M + n4 * 4];
            __pipeline_memcpy_async(&rawW[slot][k * M + n4 * 4], src, 16,
                                    ok ? 0 : 16);
        }
        __pipeline_commit();
    };

    // convert raw slot -> fp16 planes (+ bias fold from raw W)
    auto convert = [&](int c, int slot) {
        for (int p = tid; p < 128 * (KC / 2); p += 256) {
            int r = p / (KC / 2), q = p % (KC / 2);
            float2 v = *(float2*)&rawX[slot][r * KC + q * 2];
            __half h0 = __float2half_rn(v.x);
            __half h1 = __float2half_rn(v.y);
            __half l0 = __float2half_rn(v.x - __half2float(h0));
            __half l1 = __float2half_rn(v.y - __half2float(h1));
            *(__half2*)&Ah[r * AS + q * 2] = __half2(h0, h1);
            *(__half2*)&Al[r * AS + q * 2] = __half2(l0, l1);
        }
        for (int p = tid; p < KC * (M / 2); p += 256) {
            int kl = p / (M / 2), n2 = p % (M / 2);
            float2 w = *(float2*)&rawW[slot][kl * M + n2 * 2];
            int kg = c * KC + kl;
            float sh = s_shift[kg];
            pbf0 += sh * w.x;
            pbf1 += sh * w.y;
            float sc = s_scale[kg];
            w.x *= sc; w.y *= sc;
            *(__half2*)&Bs[kl * BS + n2 * 2] =
                __half2(__float2half_rn(w.x), __float2half_rn(w.y));
        }
    };

    auto do_ks = [&](int ks) {
        wmma::fragment<wmma::matrix_a, 16, 16, 16, __half, wmma::row_major> aH[MT], aL[MT];
#pragma unroll
        for (int m = 0; m < MT; ++m) {
            int rbase = wm * 32 + m * 16;
            wmma::load_matrix_sync(aH[m], Ah + rbase * AS + ks * 16, AS);
            wmma::load_matrix_sync(aL[m], Al + rbase * AS + ks * 16, AS);
        }
#pragma unroll
        for (int n = 0; n < NT2; ++n) {
            int cbase = wn * (M / 2) + n * 16;
            wmma::fragment<wmma::matrix_b, 16, 16, 16, __half, wmma::row_major> bF;
            wmma::load_matrix_sync(bF, Bs + ks * 16 * BS + cbase, BS);
#pragma unroll
            for (int m = 0; m < MT; ++m) {
                wmma::mma_sync(acc[m][n], aH[m], bF, acc[m][n]);
                wmma::mma_sync(acc[m][n], aL[m], bF, acc[m][n]);
            }
        }
    };

    cp_chunk(0, 0);
    for (int c = 0; c < NCH; ++c) {
        const int slot = c & 1;
        if (c + 1 < NCH) cp_chunk(c + 1, (c + 1) & 1);
        __pipeline_wait_prior((c + 1 < NCH) ? 1 : 0);
        __syncthreads();
        convert(c, slot);
        __syncthreads();
        const int nks = (c == NCH - 1) ? KS_LAST : 2;
        for (int ks = 0; ks < nks; ++ks) do_ks(ks);
        __syncthreads();
    }

    // finish folded bias (threads sharing a column pair combine)
    atomicAdd(&s_bf[myn2 * 2 + 0], pbf0);
    atomicAdd(&s_bf[myn2 * 2 + 1], pbf1);

    // stage accumulators to smem, then coalesced epi + store
#pragma unroll
    for (int m = 0; m < MT; ++m)
#pragma unroll
        for (int n = 0; n < NT2; ++n)
            wmma::store_matrix_sync(stage + (wm * 32 + m * 16) * (M + 8) + wn * (M / 2) + n * 16,
                                    acc[m][n], M + 8, wmma::mem_row_major);
    __syncthreads();

    float s1[4] = {0.f, 0.f, 0.f, 0.f}, q1[4] = {0.f, 0.f, 0.f, 0.f};
    float s2[4] = {0.f, 0.f, 0.f, 0.f}, q2[4] = {0.f, 0.f, 0.f, 0.f};

    for (int idx = tid; idx < 128 * (M / 4); idx += 256) {
        int r = idx / (M / 4), cq = idx % (M / 4);
        size_t gr = row0 + r;
        float4 v = *(float4*)&stage[r * (M + 8) + cq * 4];
        float4 b = *(const float4*)&s_bf[cq * 4];
        if (EPI == 0) {
            v.x += b.x; v.y += b.y; v.z += b.z; v.w += b.w;
            v.x = v.x > 0.f ? v.x : SLOPE_ * v.x;
            v.y = v.y > 0.f ? v.y : SLOPE_ * v.y;
            v.z = v.z > 0.f ? v.z : SLOPE_ * v.z;
            v.w = v.w > 0.f ? v.w : SLOPE_ * v.w;
            if (STAT >= 1) {
                s1[0] += v.x; s1[1] += v.y; s1[2] += v.z; s1[3] += v.w;
                q1[0] += v.x * v.x; q1[1] += v.y * v.y; q1[2] += v.z * v.z; q1[3] += v.w * v.w;
            }
            if (STAT == 2) {
                float ss = v.x * v.x + v.y * v.y + v.z * v.z + v.w * v.w;
#pragma unroll
                for (int o = 16; o > 0; o >>= 1) ss += __shfl_xor_sync(0xffffffffu, ss, o);
                float inv = 1.0f / fmaxf(sqrtf(ss), 1e-12f);
                if (lane == 0) g_invn[gr] = inv;
                float nx = v.x * inv, ny = v.y * inv, nz = v.z * inv, nw = v.w * inv;
                s2[0] += nx; s2[1] += ny; s2[2] += nz; s2[3] += nw;
                q2[0] += nx * nx; q2[1] += ny * ny; q2[2] += nz * nz; q2[3] += nw * nw;
            }
        } else {
            float sr = g_invn[gr], dv = g_dinv[gr];
            v.x = (v.x * sr + b.x) * dv;
            v.y = (v.y * sr + b.y) * dv;
            v.z = (v.z * sr + b.z) * dv;
            v.w = (v.w * sr + b.w) * dv;
        }
        *(float4*)&Y[gr * M + cq * 4] = v;
    }

    if (EPI == 0 && STAT >= 1) {
        __syncthreads();
        float* red = stage;
#pragma unroll
        for (int j = 0; j < 4; ++j) {
            red[0 * 1024 + wid * 128 + lane * 4 + j] = s1[j];
            red[1 * 1024 + wid * 128 + lane * 4 + j] = q1[j];
            if (STAT == 2) {
                red[2 * 1024 + wid * 128 + lane * 4 + j] = s2[j];
                red[3 * 1024 + wid * 128 + lane * 4 + j] = q2[j];
            }
        }
        __syncthreads();
        if (tid < 128) {
            float a = 0.f, b = 0.f, c2 = 0.f, d2 = 0.f;
#pragma unroll
            for (int w = 0; w < 8; ++w) {
                a  += red[0 * 1024 + w * 128 + tid];
                b  += red[1 * 1024 + w * 128 + tid];
                if (STAT == 2) {
                    c2 += red[2 * 1024 + w * 128 + tid];
                    d2 += red[3 * 1024 + w * 128 + tid];
                }
            }
            atomicAdd(&g_sum[slotA * 256 + tid], a);
            atomicAdd(&g_sq[slotA * 256 + tid], b);
            if (STAT == 2) {
                atomicAdd(&g_sum[slotB * 256 + tid], c2);
                atomicAdd(&g_sq[slotB * 256 + tid], d2);
            }
        }
    }
}

// ---------------- CSR build ----------------
__global__ void k_deg_count(const int* __restrict__ dst) {
    int e = blockIdx.x * blockDim.x + threadIdx.x;
    if (e < E_) atomicAdd(&g_degi[dst[e]], 1);
}
__global__ void k_scan1() {
    __shared__ int s[256];
    int t = threadIdx.x;
    int idx = blockIdx.x * 256 + t;
    int v = g_degi[idx];
    s[t] = v;
    __syncthreads();
#pragma unroll
    for (int off = 1; off < 256; off <<= 1) {
        int a = 0;
        if (t >= off) a = s[t - off];
        __syncthreads();
        s[t] += a;
        __syncthreads();
    }
    g_rowptr[idx] = s[t] - v;
    if (t == 255) g_blksum[blockIdx.x] = s[255];
}
__global__ void k_scan2() {
    __shared__ int s[NBLK_];
    int t = threadIdx.x;
    if (t < NBLK_) s[t] = g_blksum[t];
    __syncthreads();
    for (int off = 1; off < NBLK_; off <<= 1) {
        int a = 0;
        if (t >= off && t < NBLK_) a = s[t - off];
        __syncthreads();
        if (t < NBLK_) s[t] += a;
        __syncthreads();
    }
    if (t < NBLK_) g_blksum[t] = s[t];
}
__global__ void k_scan3() {
    int idx = blockIdx.x * 256 + threadIdx.x;
    int off = blockIdx.x == 0 ? 0 : g_blksum[blockIdx.x - 1];
    int rp = g_rowptr[idx] + off;
    g_rowptr[idx] = rp;
    g_cursor[idx] = rp;
    g_dinv[idx] = rsqrtf((float)g_degi[idx] + 1.0f);
    if (idx == 0) g_rowptr[N_] = E_;
}
__global__ void k_csr_fill(const int* __restrict__ src, const int* __restrict__ dst) {
    int e = blockIdx.x * blockDim.x + threadIdx.x;
    if (e < E_) {
        int pos = atomicAdd(&g_cursor[dst[e]], 1);
        g_col[pos] = src[e];
    }
}

// ---------------- GCN gather (fused: bias + scale + leaky [+ rownorm stats]) ----------------
template <bool RSTAT>
__global__ void k_gather128(const float* __restrict__ Hs, const float* __restrict__ gb,
                            float* __restrict__ out, int slot) {
    __shared__ float sred[2][8][128];
    const int tid = threadIdx.x, wid = tid >> 5, lane = tid & 31;
    const float4 b = *(const float4*)&gb[lane * 4];
    float4 s4 = {0.f, 0.f, 0.f, 0.f}, q4 = {0.f, 0.f, 0.f, 0.f};

    for (int i = blockIdx.x * 8 + wid; i < N_; i += 9216) {
        int beg = __ldg(&g_rowptr[i]), end = __ldg(&g_rowptr[i + 1]);
        float4 acc = *(const float4*)&Hs[(size_t)i * 128 + lane * 4];
        for (int base = beg; base < end; base += 32) {
            int e = base + lane;
            int sidx = (e < end) ? g_col[e] : 0;
            int cnt = min(32, end - base);
            int j = 0;
            for (; j + 8 <= cnt; j += 8) {
                int s0 = __shfl_sync(0xffffffffu, sidx, j);
                int s1 = __shfl_sync(0xffffffffu, sidx, j + 1);
                int s2 = __shfl_sync(0xffffffffu, sidx, j + 2);
                int s3 = __shfl_sync(0xffffffffu, sidx, j + 3);
                int s4i = __shfl_sync(0xffffffffu, sidx, j + 4);
                int s5 = __shfl_sync(0xffffffffu, sidx, j + 5);
                int s6 = __shfl_sync(0xffffffffu, sidx, j + 6);
                int s7 = __shfl_sync(0xffffffffu, sidx, j + 7);
                float4 v0 = *(const float4*)&Hs[(size_t)s0 * 128 + lane * 4];
                float4 v1 = *(const float4*)&Hs[(size_t)s1 * 128 + lane * 4];
                float4 v2 = *(const float4*)&Hs[(size_t)s2 * 128 + lane * 4];
                float4 v3 = *(const float4*)&Hs[(size_t)s3 * 128 + lane * 4];
                float4 v4 = *(const float4*)&Hs[(size_t)s4i * 128 + lane * 4];
                float4 v5 = *(const float4*)&Hs[(size_t)s5 * 128 + lane * 4];
                float4 v6 = *(const float4*)&Hs[(size_t)s6 * 128 + lane * 4];
                float4 v7 = *(const float4*)&Hs[(size_t)s7 * 128 + lane * 4];
                acc.x += (v0.x + v1.x) + (v2.x + v3.x) + ((v4.x + v5.x) + (v6.x + v7.x));
                acc.y += (v0.y + v1.y) + (v2.y + v3.y) + ((v4.y + v5.y) + (v6.y + v7.y));
                acc.z += (v0.z + v1.z) + (v2.z + v3.z) + ((v4.z + v5.z) + (v6.z + v7.z));
                acc.w += (v0.w + v1.w) + (v2.w + v3.w) + ((v4.w + v5.w) + (v6.w + v7.w));
            }
            for (; j < cnt; ++j) {
                int s = __shfl_sync(0xffffffffu, sidx, j);
                float4 v = *(const float4*)&Hs[(size_t)s * 128 + lane * 4];
                acc.x += v.x; acc.y += v.y; acc.z += v.z; acc.w += v.w;
            }
        }
        float di = g_dinv[i];
        acc.x = b.x + di * acc.x;
        acc.y = b.y + di * acc.y;
        acc.z = b.z + di * acc.z;
        acc.w = b.w + di * acc.w;
        acc.x = acc.x > 0.f ? acc.x : SLOPE_ * acc.x;
        acc.y = acc.y > 0.f ? acc.y : SLOPE_ * acc.y;
        acc.z = acc.z > 0.f ? acc.z : SLOPE_ * acc.z;
        acc.w = acc.w > 0.f ? acc.w : SLOPE_ * acc.w;
        if (RSTAT) {
            float ss = acc.x * acc.x + acc.y * acc.y + acc.z * acc.z + acc.w * acc.w;
#pragma unroll
            for (int o = 16; o > 0; o >>= 1) ss += __shfl_xor_sync(0xffffffffu, ss, o);
            float inv = 1.0f / fmaxf(sqrtf(ss), 1e-12f);
            if (lane == 0) g_invn[i] = inv;
            float nx = acc.x * inv, ny = acc.y * inv, nz = acc.z * inv, nw = acc.w * inv;
            s4.x += nx; s4.y += ny; s4.z += nz; s4.w += nw;
            q4.x += nx * nx; q4.y += ny * ny; q4.z += nz * nz; q4.w += nw * nw;
        }
        *(float4*)&out[(size_t)i * 128 + lane * 4] = acc;
    }

    if (RSTAT) {
        sred[0][wid][lane * 4 + 0] = s4.x; sred[0][wid][lane * 4 + 1] = s4.y;
        sred[0][wid][lane * 4 + 2] = s4.z; sred[0][wid][lane * 4 + 3] = s4.w;
        sred[1][wid][lane * 4 + 0] = q4.x; sred[1][wid][lane * 4 + 1] = q4.y;
        sred[1][wid][lane * 4 + 2] = q4.z; sred[1][wid][lane * 4 + 3] = q4.w;
        __syncthreads();
        if (tid < 128) {
            float a = 0.f, b2 = 0.f;
#pragma unroll
            for (int w = 0; w < 8; ++w) { a += sred[0][w][tid]; b2 += sred[1][w][tid]; }
            atomicAdd(&g_sum[slot * 256 + tid], a);
            atomicAdd(&g_sq[slot * 256 + tid], b2);
        }
    }
}

// gather64: bias + scale + leaky fused
__global__ void k_gather64(const float* __restrict__ Hs, const float* __restrict__ gb,
                           float* __restrict__ out) {
    int i = (int)(((size_t)blockIdx.x * blockDim.x + threadIdx.x) >> 5);
    if (i >= N_) return;
    int lane = threadIdx.x & 31;
    int beg = __ldg(&g_rowptr[i]), end = __ldg(&g_rowptr[i + 1]);
    float2 acc = *(const float2*)&Hs[(size_t)i * 64 + lane * 2];
    for (int base = beg; base < end; base += 32) {
        int e = base + lane;
        int sidx = (e < end) ? g_col[e] : 0;
        int cnt = min(32, end - base);
        int j = 0;
        for (; j + 8 <= cnt; j += 8) {
            int s0 = __shfl_sync(0xffffffffu, sidx, j);
            int s1 = __shfl_sync(0xffffffffu, sidx, j + 1);
            int s2 = __shfl_sync(0xffffffffu, sidx, j + 2);
            int s3 = __shfl_sync(0xffffffffu, sidx, j + 3);
            int s4 = __shfl_sync(0xffffffffu, sidx, j + 4);
            int s5 = __shfl_sync(0xffffffffu, sidx, j + 5);
            int s6 = __shfl_sync(0xffffffffu, sidx, j + 6);
            int s7 = __shfl_sync(0xffffffffu, sidx, j + 7);
            float2 v0 = *(const float2*)&Hs[(size_t)s0 * 64 + lane * 2];
            float2 v1 = *(const float2*)&Hs[(size_t)s1 * 64 + lane * 2];
            float2 v2 = *(const float2*)&Hs[(size_t)s2 * 64 + lane * 2];
            float2 v3 = *(const float2*)&Hs[(size_t)s3 * 64 + lane * 2];
            float2 v4 = *(const float2*)&Hs[(size_t)s4 * 64 + lane * 2];
            float2 v5 = *(const float2*)&Hs[(size_t)s5 * 64 + lane * 2];
            float2 v6 = *(const float2*)&Hs[(size_t)s6 * 64 + lane * 2];
            float2 v7 = *(const float2*)&Hs[(size_t)s7 * 64 + lane * 2];
            acc.x += (v0.x + v1.x) + (v2.x + v3.x) + ((v4.x + v5.x) + (v6.x + v7.x));
            acc.y += (v0.y + v1.y) + (v2.y + v3.y) + ((v4.y + v5.y) + (v6.y + v7.y));
        }
        for (; j < cnt; ++j) {
            int s = __shfl_sync(0xffffffffu, sidx, j);
            float2 v = *(const float2*)&Hs[(size_t)s * 64 + lane * 2];
            acc.x += v.x; acc.y += v.y;
        }
    }
    float di = g_dinv[i];
    float2 b = *(const float2*)&gb[lane * 2];
    acc.x = b.x + di * acc.x;
    acc.y = b.y + di * acc.y;
    acc.x = acc.x > 0.f ? acc.x : SLOPE_ * acc.x;
    acc.y = acc.y > 0.f ? acc.y : SLOPE_ * acc.y;
    *(float2*)&out[(size_t)i * 64 + lane * 2] = acc;
}

// ---------------- depthwise 5x5 conv ----------------
__global__ void k_dwconv(const float* __restrict__ In, const float* __restrict__ dw,
                         const float* __restrict__ db, float* __restrict__ Out) {
    __shared__ float wt[25 * 64];
    int tid = threadIdx.x;
    for (int i = tid; i < 25 * 64; i += 256) {
        int t = i >> 6, c = i & 63;
        wt[i] = dw[c * 25 + t];
    }
    __syncthreads();
    int c4 = tid & 15;
    int p = blockIdx.x * 16 + (tid >> 4);
    int y = p / Ww_, x = p % Ww_;
    float4 acc = {0.f, 0.f, 0.f, 0.f};
#pragma unroll
    for (int ky = 0; ky < 5; ++ky) {
        int yy = y + ky - 2;
        if (yy < 0 || yy >= Hh_) continue;
#pragma unroll
        for (int kx = 0; kx < 5; ++kx) {
            int xx = x + kx - 2;
            if (xx < 0 || xx >= Ww_) continue;
            float4 v  = *(const float4*)&In[((size_t)yy * Ww_ + xx) * 64 + c4 * 4];
            float4 wv = *(const float4*)&wt[(ky * 5 + kx) * 64 + c4 * 4];
            acc.x += v.x * wv.x; acc.y += v.y * wv.y;
            acc.z += v.z * wv.z; acc.w += v.w * wv.w;
        }
    }
    float4 b = *(const float4*)&db[c4 * 4];
    acc.x += b.x; acc.y += b.y; acc.z += b.z; acc.w += b.w;
    acc.x = acc.x > 0.f ? acc.x : SLOPE_ * acc.x;
    acc.y = acc.y > 0.f ? acc.y : SLOPE_ * acc.y;
    acc.z = acc.z > 0.f ? acc.z : SLOPE_ * acc.z;
    acc.w = acc.w > 0.f ? acc.w : SLOPE_ * acc.w;
    *(float4*)&Out[(size_t)p * 64 + c4 * 4] = acc;
}

// ---------------- head: G (already leaky) concat Cn -> linear -> softmax ----------------
__global__ void k_final(const float* __restrict__ G, const float* __restrict__ Cn,
                        const float* __restrict__ lw, const float* __restrict__ lb,
                        float* __restrict__ out) {
    __shared__ float slw[128 * 16];
    __shared__ float slb[16];
    __shared__ float sg[16][64];
    __shared__ float sc[16][64];
    int tid = threadIdx.x;
    for (int i = tid; i < 2048; i += 256) slw[i] = lw[i];
    if (tid < 16) slb[tid] = lb[tid];
    int tx = tid & 15, ty = tid >> 4;
    size_t row = (size_t)blockIdx.x * 16 + ty;
    *(float4*)&sg[ty][tx * 4] = *(const float4*)&G[row * 64 + tx * 4];
    *(float4*)&sc[ty][tx * 4] = *(const float4*)&Cn[row * 64 + tx * 4];
    __syncthreads();
    float acc = slb[tx];
#pragma unroll 4
    for (int k = 0; k < 64; ++k) acc += sg[ty][k] * slw[k * 16 + tx];
#pragma unroll 4
    for (int k = 0; k < 64; ++k) acc += sc[ty][k] * slw[(64 + k) * 16 + tx];
    float mx = acc;
#pragma unroll
    for (int o = 8; o > 0; o >>= 1) mx = fmaxf(mx, __shfl_xor_sync(0xffffffffu, mx, o));
    float e = __expf(acc - mx);
    float sum = e;
#pragma unroll
    for (int o = 8; o > 0; o >>= 1) sum += __shfl_xor_sync(0xffffffffu, sum, o);
    out[row * 16 + tx] = e / sum;
}

// ---------------- host launchers ----------------
template <int KREAL, int M, int EPI, int STAT>
static void launch_wgemm(cudaStream_t st, const float* X, float* Y, const float* W,
                         const float* bng, const float* bnb, const float* bias, int slotF,
                         int slotA = 0, int slotB = 0) {
    constexpr int KC = 32;
    constexpr size_t comp = (size_t)(2 * 128 * (KC + 8) + KC * (M + 8)) * 2
                          + (size_t)2 * 128 * KC * 4 + (size_t)2 * KC * M * 4;
    constexpr size_t stg  = (size_t)128 * (M + 8) * 4;
    constexpr size_t smem = comp > stg ? comp : stg;
    cudaFuncSetAttribute(k_wgemm<KREAL, M, EPI, STAT>,
                         cudaFuncAttributeMaxDynamicSharedMemorySize, (int)smem);
    k_wgemm<KREAL, M, EPI, STAT><<<N_ / 128, 256, smem, st>>>(X, Y, W, bng, bnb, bias,
                                                              slotF, slotA, slotB);
}

extern "C" void kernel_launch(void* const* d_in, const int* in_sizes, int n_in,
                              void* d_out, int out_size) {
    const float* x   = (const float*)d_in[0];
    const int*   ei  = (const int*)d_in[1];
    const int*   src = ei;
    const int*   dst = ei + E_;
    const float* dn_bn1_g = (const float*)d_in[2];
    const float* dn_bn1_b = (const float*)d_in[3];
    const float* dn_w1    = (const float*)d_in[4];
    const float* dn_b1    = (const float*)d_in[5];
    const float* dn_bn2_g = (const float*)d_in[6];
    const float* dn_bn2_b = (const float*)d_in[7];
    const float* dn_w2    = (const float*)d_in[8];
    const float* dn_b2    = (const float*)d_in[9];
    const float* cnn_bn_g = (const float*)d_in[10];
    const float* cnn_bn_b = (const float*)d_in[11];
    const float* cnn_pw   = (const float*)d_in[12];
    const float* cnn_dw   = (const float*)d_in[13];
    const float* cnn_db   = (const float*)d_in[14];
    const float* g1_bn_g  = (const float*)d_in[15];
    const float* g1_bn_b  = (const float*)d_in[16];
    const float* g1_w     = (const float*)d_in[17];
    const float* g1_b     = (const float*)d_in[18];
    const float* g2_bn_g  = (const float*)d_in[19];
    const float* g2_bn_b  = (const float*)d_in[20];
    const float* g2_w     = (const float*)d_in[21];
    const float* g2_b     = (const float*)d_in[22];
    const float* g3_bn_g  = (const float*)d_in[23];
    const float* g3_bn_b  = (const float*)d_in[24];
    const float* g3_w     = (const float*)d_in[25];
    const float* g3_b     = (const float*)d_in[26];
    const float* lin_w    = (const float*)d_in[27];
    const float* lin_b    = (const float*)d_in[28];
    float* out = (float*)d_out;

    float *pP, *pQ, *pH, *pC, *pCR;
    cudaGetSymbolAddress((void**)&pP, g_P);
    cudaGetSymbolAddress((void**)&pQ, g_Q);
    cudaGetSymbolAddress((void**)&pH, g_Hm);
    cudaGetSymbolAddress((void**)&pC, g_cnn);
    cudaGetSymbolAddress((void**)&pCR, g_cnnres);

    static cudaStream_t s1 = nullptr;
    static cudaEvent_t evA = nullptr, evCSR = nullptr, evD2 = nullptr,
                       evCNNG = nullptr, evCNN = nullptr;
    if (s1 == nullptr) {
        cudaStreamCreate(&s1);
        cudaEventCreateWithFlags(&evA,    cudaEventDisableTiming);
        cudaEventCreateWithFlags(&evCSR,  cudaEventDisableTiming);
        cudaEventCreateWithFlags(&evD2,   cudaEventDisableTiming);
        cudaEventCreateWithFlags(&evCNNG, cudaEventDisableTiming);
        cudaEventCreateWithFlags(&evCNN,  cudaEventDisableTiming);
    }
    cudaStream_t s0 = 0;   // capture (default) stream

    // ---- main stream: stats + denoise; side stream: CSR build ----
    k_init<<<NBLK_ + 1, 256, 0, s0>>>();
    cudaEventRecord(evA, s0);
    k_colstats<200><<<128, 200, 0, s0>>>(x, 0);

    cudaStreamWaitEvent(s1, evA, 0);
    k_deg_count<<<(E_ + 255) / 256, 256, 0, s1>>>(dst);

    // launch #4 = big tensor GEMM (profiling target)
    launch_wgemm<200, 128, 0, 1>(s0, x, pQ, dn_w1, dn_bn1_g, dn_bn1_b, dn_b1, 0, 1);

    k_scan1<<<NBLK_, 256, 0, s1>>>();
    k_scan2<<<1, 1024, 0, s1>>>();
    k_scan3<<<NBLK_, 256, 0, s1>>>();
    k_csr_fill<<<(E_ + 255) / 256, 256, 0, s1>>>(src, dst);
    cudaEventRecord(evCSR, s1);

    // denoise layer 2 on s0: epilogue -> plain stats (slot 2) + invn/norm stats (slot 3)
    launch_wgemm<128, 128, 0, 2>(s0, pQ, pP, dn_w2, dn_bn2_b == nullptr ? nullptr : dn_w2 == nullptr ? nullptr : dn_bn2_g, dn_bn2_b, dn_b2, 1, 2, 3);
    cudaEventRecord(evD2, s0);

    // ---- CNN branch on side stream (reads pP + slot2) ----
    cudaStreamWaitEvent(s1, evD2, 0);
    launch_wgemm<128, 64, 0, 0>(s1, pP, pC, cnn_pw, cnn_bn_g, cnn_bn_b, nullptr, 2);
    cudaEventRecord(evCNNG, s1);          // pP no longer read by CNN branch
    k_dwconv<<<N_ / 16, 256, 0, s1>>>(pC, cnn_dw, cnn_db, pCR);
    cudaEventRecord(evCNN, s1);

    // ---- GCN chain on main stream ----
    cudaStreamWaitEvent(s0, evCSR, 0);    // g_dinv/rowptr/col ready
    launch_wgemm<128, 128, 1, 0>(s0, pP, pH, g1_w, g1_bn_g, g1_bn_b, nullptr, 3);
    cudaStreamWaitEvent(s0, evCNNG, 0);   // CNN GEMM done reading pP before we overwrite
    k_gather128<true><<<1152, 256, 0, s0>>>(pH, g1_b, pP, 4);

    launch_wgemm<128, 128, 1, 0>(s0, pP, pH, g2_w, g2_bn_g, g2_bn_b, nullptr, 4);
    k_gather128<true><<<1152, 256, 0, s0>>>(pH, g2_b, pP, 5);

    launch_wgemm<128, 64, 1, 0>(s0, pP, pH, g3_w, g3_bn_g, g3_bn_b, nullptr, 5);
    k_gather64<<<(N_ * 32) / 256, 256, 0, s0>>>(pH, g3_b, pP);

    // ---- head (needs CNN result) ----
    cudaStreamWaitEvent(s0, evCNN, 0);
    k_final<<<N_ / 16, 256, 0, s0>>>(pP, pCR, lin_w, lin_b, out);
}

// round 12
// speedup vs baseline: 2.4710x; 1.0490x over previous
#include <cuda_runtime.h>
#include <cuda_fp16.h>
#include <cuda_pipeline.h>
#include <mma.h>
#include <cstdint>
#include <cstddef>

using namespace nvcuda;

// ---------------- problem constants ----------------
#define Hh_ 384
#define Ww_ 384
#define C_ 200
#define N_ 147456           // Hh_*Ww_
#define E_ 1179648
#define HIDE_ 128
#define OUT_ 64
#define NCLS_ 16
#define EPS_ 1e-5f
#define SLOPE_ 0.01f
#define NBLK_ 576           // N_/256

// ---------------- scratch (device globals; no allocation allowed) ----------------
__device__ float g_P[(size_t)N_ * 128];
__device__ float g_Q[(size_t)N_ * 128];
__device__ float g_Hm[(size_t)N_ * 128];
__device__ float g_cnn[(size_t)N_ * 64];
__device__ float g_cnnres[(size_t)N_ * 64];
__device__ float g_dinv[N_];
__device__ float g_invn[N_];
__device__ float g_sum[6 * 256];
__device__ float g_sq[6 * 256];
// CSR
__device__ int g_degi[N_];
__device__ int g_rowptr[N_ + 1];
__device__ int g_cursor[N_];
__device__ int g_blksum[NBLK_];
__device__ int g_col[E_];

// ---------------- init: zero all stat slots + degree array ----------------
__global__ void k_init() {
    int i = blockIdx.x * 256 + threadIdx.x;
    if (i < N_) g_degi[i] = 0;
    if (i < 6 * 256) { g_sum[i] = 0.f; g_sq[i] = 0.f; }
}

// plain column stats (only used for raw input x): blockDim == C
template <int C>
__global__ void k_colstats(const float* __restrict__ X, int slot) {
    const int c = threadIdx.x;
    const int rpb = N_ / 128;
    const int r0 = blockIdx.x * rpb;
    float s = 0.f, q = 0.f;
    for (int r = r0; r < r0 + rpb; ++r) {
        float v = X[(size_t)r * C + c];
        s += v; q += v * v;
    }
    atomicAdd(&g_sum[slot * 256 + c], s);
    atomicAdd(&g_sq[slot * 256 + c], q);
}

// ---------------- tensor GEMM via wmma (fp16 x fp16, fp32 accum, 1 product) ----------------
// cp.async double-buffered raw staging of X and W; BN fold + fp16 convert from smem.
// Y[N,M] = epi( X[N,KREAL] @ (diag(scale)·W) + bf )
// EPI 0: out = leaky(acc + bf)         EPI 1: out = (acc*invn[r] + bf) * dinv[r]
// STAT (EPI0, M=128): 1 = plain col stats -> slotA; 2 = plain->slotA AND invn+norm stats->slotB
// 256 threads = 8 warps in a 4(m) x 2(n) grid. Warp tile: 32 rows x M/2 cols.
template <int KREAL, int M, int EPI, int STAT>
__global__ __launch_bounds__(256, 2)
void k_wgemm(const float* __restrict__ X, float* __restrict__ Y,
             const float* __restrict__ W, const float* __restrict__ bng,
             const float* __restrict__ bnb, const float* __restrict__ bias,
             int slotF, int slotA, int slotB) {
    constexpr int KC = 32;            // K chunk
    constexpr int AS = KC + 8;        // A smem stride (halves)
    constexpr int BS = M + 8;         // B smem stride (halves)
    constexpr int MT = 2;             // m-tiles per warp (32 rows)
    constexpr int NT2 = M / 32;       // n-tiles per warp (M/2 cols)
    constexpr int NCH = (KREAL + KC - 1) / KC;
    constexpr int LASTR = KREAL - (NCH - 1) * KC;
    constexpr int KS_LAST = (LASTR + 15) / 16;

    constexpr int SZ_A = 128 * AS * 2;        // fp16 A plane
    constexpr int SZ_B = KC * BS * 2;
    constexpr int SZ_RX = 128 * KC * 4;       // one raw X slot
    constexpr int SZ_RW = KC * M * 4;         // one raw W slot

    extern __shared__ char smraw[];
    __half* As = (__half*)smraw;
    __half* Bs = (__half*)(smraw + SZ_A);
    float* rawX[2] = { (float*)(smraw + SZ_A + SZ_B),
                       (float*)(smraw + SZ_A + SZ_B + SZ_RX) };
    float* rawW[2] = { (float*)(smraw + SZ_A + SZ_B + 2 * SZ_RX),
                       (float*)(smraw + SZ_A + SZ_B + 2 * SZ_RX + SZ_RW) };
    float* stage = (float*)smraw;             // reused post-compute

    __shared__ float s_scale[256];
    __shared__ float s_shift[256];
    __shared__ float s_bf[128];

    const int tid = threadIdx.x, wid = tid >> 5, lane = tid & 31;
    const int wm = wid & 3, wn = wid >> 2;
    const size_t row0 = (size_t)blockIdx.x * 128;

    // fold coefficients from stats
    {
        float sc = 0.f, sh = 0.f;
        if (tid < KREAL) {
            float mean = g_sum[slotF * 256 + tid] * (1.f / N_);
            float var  = g_sq[slotF * 256 + tid] * (1.f / N_) - mean * mean;
            sc = bng[tid] * rsqrtf(var + EPS_);
            sh = bnb[tid] - mean * sc;
        }
        s_scale[tid] = sc;
        s_shift[tid] = sh;
        if (tid < M) s_bf[tid] = bias ? bias[tid] : 0.f;
    }

    wmma::fragment<wmma::accumulator, 16, 16, 16, float> acc[MT][NT2];
#pragma unroll
    for (int m = 0; m < MT; ++m)
#pragma unroll
        for (int n = 0; n < NT2; ++n) wmma::fill_fragment(acc[m][n], 0.0f);

    float pbf0 = 0.f, pbf1 = 0.f;
    const int myn2 = tid % (M / 2);

    // issue cp.async for chunk c into slot
    auto cp_chunk = [&](int c, int slot) {
        for (int p = tid; p < 128 * (KC / 4); p += 256) {
            int r = p / (KC / 4), s = p % (KC / 4);
            int col0 = c * KC + s * 4;
            int real = KREAL - col0; real = real < 0 ? 0 : (real > 4 ? 4 : real);
            const float* src = &X[(row0 + r) * KREAL + (real ? col0 : 0)];
            __pipeline_memcpy_async(&rawX[slot][r * KC + s * 4], src, 16,
                                    (size_t)(4 - real) * 4);
        }
        for (int p = tid; p < KC * (M / 4); p += 256) {
            int k = p / (M / 4), n4 = p % (M / 4);
            int kg = c * KC + k;
            bool ok = kg < KREAL;
            const float* src = &W[(size_t)(ok ? kg : 0) * M + n4 * 4];
            __pipeline_memcpy_async(&rawW[slot][k * M + n4 * 4], src, 16,
                                    ok ? 0 : 16);
        }
        __pipeline_commit();
    };

    // convert raw slot -> fp16 planes (+ bias fold from raw W)
    auto convert = [&](int c, int slot) {
        for (int p = tid; p < 128 * (KC / 2); p += 256) {
            int r = p / (KC / 2), q = p % (KC / 2);
            float2 v = *(float2*)&rawX[slot][r * KC + q * 2];
            *(__half2*)&As[r * AS + q * 2] =
                __half2(__float2half_rn(v.x), __float2half_rn(v.y));
        }
        for (int p = tid; p < KC * (M / 2); p += 256) {
            int kl = p / (M / 2), n2 = p % (M / 2);
            float2 w = *(float2*)&rawW[slot][kl * M + n2 * 2];
            int kg = c * KC + kl;
            float sh = s_shift[kg];
            pbf0 += sh * w.x;
            pbf1 += sh * w.y;
            float sc = s_scale[kg];
            w.x *= sc; w.y *= sc;
            *(__half2*)&Bs[kl * BS + n2 * 2] =
                __half2(__float2half_rn(w.x), __float2half_rn(w.y));
        }
    };

    auto do_ks = [&](int ks) {
        wmma::fragment<wmma::matrix_a, 16, 16, 16, __half, wmma::row_major> aF[MT];
#pragma unroll
        for (int m = 0; m < MT; ++m) {
            int rbase = wm * 32 + m * 16;
            wmma::load_matrix_sync(aF[m], As + rbase * AS + ks * 16, AS);
        }
#pragma unroll
        for (int n = 0; n < NT2; ++n) {
            int cbase = wn * (M / 2) + n * 16;
            wmma::fragment<wmma::matrix_b, 16, 16, 16, __half, wmma::row_major> bF;
            wmma::load_matrix_sync(bF, Bs + ks * 16 * BS + cbase, BS);
#pragma unroll
            for (int m = 0; m < MT; ++m)
                wmma::mma_sync(acc[m][n], aF[m], bF, acc[m][n]);
        }
    };

    cp_chunk(0, 0);
    for (int c = 0; c < NCH; ++c) {
        const int slot = c & 1;
        if (c + 1 < NCH) cp_chunk(c + 1, (c + 1) & 1);
        __pipeline_wait_prior((c + 1 < NCH) ? 1 : 0);
        __syncthreads();
        convert(c, slot);
        __syncthreads();
        const int nks = (c == NCH - 1) ? KS_LAST : 2;
        for (int ks = 0; ks < nks; ++ks) do_ks(ks);
        __syncthreads();
    }

    // finish folded bias (threads sharing a column pair combine)
    atomicAdd(&s_bf[myn2 * 2 + 0], pbf0);
    atomicAdd(&s_bf[myn2 * 2 + 1], pbf1);

    // stage accumulators to smem, then coalesced epi + store
#pragma unroll
    for (int m = 0; m < MT; ++m)
#pragma unroll
        for (int n = 0; n < NT2; ++n)
            wmma::store_matrix_sync(stage + (wm * 32 + m * 16) * (M + 8) + wn * (M / 2) + n * 16,
                                    acc[m][n], M + 8, wmma::mem_row_major);
    __syncthreads();

    float s1[4] = {0.f, 0.f, 0.f, 0.f}, q1[4] = {0.f, 0.f, 0.f, 0.f};
    float s2[4] = {0.f, 0.f, 0.f, 0.f}, q2[4] = {0.f, 0.f, 0.f, 0.f};

    for (int idx = tid; idx < 128 * (M / 4); idx += 256) {
        int r = idx / (M / 4), cq = idx % (M / 4);
        size_t gr = row0 + r;
        float4 v = *(float4*)&stage[r * (M + 8) + cq * 4];
        float4 b = *(const float4*)&s_bf[cq * 4];
        if (EPI == 0) {
            v.x += b.x; v.y += b.y; v.z += b.z; v.w += b.w;
            v.x = v.x > 0.f ? v.x : SLOPE_ * v.x;
            v.y = v.y > 0.f ? v.y : SLOPE_ * v.y;
            v.z = v.z > 0.f ? v.z : SLOPE_ * v.z;
            v.w = v.w > 0.f ? v.w : SLOPE_ * v.w;
            if (STAT >= 1) {
                s1[0] += v.x; s1[1] += v.y; s1[2] += v.z; s1[3] += v.w;
                q1[0] += v.x * v.x; q1[1] += v.y * v.y; q1[2] += v.z * v.z; q1[3] += v.w * v.w;
            }
            if (STAT == 2) {
                float ss = v.x * v.x + v.y * v.y + v.z * v.z + v.w * v.w;
#pragma unroll
                for (int o = 16; o > 0; o >>= 1) ss += __shfl_xor_sync(0xffffffffu, ss, o);
                float inv = 1.0f / fmaxf(sqrtf(ss), 1e-12f);
                if (lane == 0) g_invn[gr] = inv;
                float nx = v.x * inv, ny = v.y * inv, nz = v.z * inv, nw = v.w * inv;
                s2[0] += nx; s2[1] += ny; s2[2] += nz; s2[3] += nw;
                q2[0] += nx * nx; q2[1] += ny * ny; q2[2] += nz * nz; q2[3] += nw * nw;
            }
        } else {
            float sr = g_invn[gr], dv = g_dinv[gr];
            v.x = (v.x * sr + b.x) * dv;
            v.y = (v.y * sr + b.y) * dv;
            v.z = (v.z * sr + b.z) * dv;
            v.w = (v.w * sr + b.w) * dv;
        }
        *(float4*)&Y[gr * M + cq * 4] = v;
    }

    if (EPI == 0 && STAT >= 1) {
        __syncthreads();
        float* red = stage;
#pragma unroll
        for (int j = 0; j < 4; ++j) {
            red[0 * 1024 + wid * 128 + lane * 4 + j] = s1[j];
            red[1 * 1024 + wid * 128 + lane * 4 + j] = q1[j];
            if (STAT == 2) {
                red[2 * 1024 + wid * 128 + lane * 4 + j] = s2[j];
                red[3 * 1024 + wid * 128 + lane * 4 + j] = q2[j];
            }
        }
        __syncthreads();
        if (tid < 128) {
            float a = 0.f, b = 0.f, c2 = 0.f, d2 = 0.f;
#pragma unroll
            for (int w = 0; w < 8; ++w) {
                a  += red[0 * 1024 + w * 128 + tid];
                b  += red[1 * 1024 + w * 128 + tid];
                if (STAT == 2) {
                    c2 += red[2 * 1024 + w * 128 + tid];
                    d2 += red[3 * 1024 + w * 128 + tid];
                }
            }
            atomicAdd(&g_sum[slotA * 256 + tid], a);
            atomicAdd(&g_sq[slotA * 256 + tid], b);
            if (STAT == 2) {
                atomicAdd(&g_sum[slotB * 256 + tid], c2);
                atomicAdd(&g_sq[slotB * 256 + tid], d2);
            }
        }
    }
}

// ---------------- CSR build ----------------
__global__ void k_deg_count(const int* __restrict__ dst) {
    int e = blockIdx.x * blockDim.x + threadIdx.x;
    if (e < E_) atomicAdd(&g_degi[dst[e]], 1);
}
__global__ void k_scan1() {
    __shared__ int s[256];
    int t = threadIdx.x;
    int idx = blockIdx.x * 256 + t;
    int v = g_degi[idx];
    s[t] = v;
    __syncthreads();
#pragma unroll
    for (int off = 1; off < 256; off <<= 1) {
        int a = 0;
        if (t >= off) a = s[t - off];
        __syncthreads();
        s[t] += a;
        __syncthreads();
    }
    g_rowptr[idx] = s[t] - v;
    if (t == 255) g_blksum[blockIdx.x] = s[255];
}
__global__ void k_scan2() {
    __shared__ int s[NBLK_];
    int t = threadIdx.x;
    if (t < NBLK_) s[t] = g_blksum[t];
    __syncthreads();
    for (int off = 1; off < NBLK_; off <<= 1) {
        int a = 0;
        if (t >= off && t < NBLK_) a = s[t - off];
        __syncthreads();
        if (t < NBLK_) s[t] += a;
        __syncthreads();
    }
    if (t < NBLK_) g_blksum[t] = s[t];
}
__global__ void k_scan3() {
    int idx = blockIdx.x * 256 + threadIdx.x;
    int off = blockIdx.x == 0 ? 0 : g_blksum[blockIdx.x - 1];
    int rp = g_rowptr[idx] + off;
    g_rowptr[idx] = rp;
    g_cursor[idx] = rp;
    g_dinv[idx] = rsqrtf((float)g_degi[idx] + 1.0f);
    if (idx == 0) g_rowptr[N_] = E_;
}
__global__ void k_csr_fill(const int* __restrict__ src, const int* __restrict__ dst) {
    int e = blockIdx.x * blockDim.x + threadIdx.x;
    if (e < E_) {
        int pos = atomicAdd(&g_cursor[dst[e]], 1);
        g_col[pos] = src[e];
    }
}

// ---------------- GCN gather (fused: bias + scale + leaky [+ rownorm stats]) ----------------
template <bool RSTAT>
__global__ void k_gather128(const float* __restrict__ Hs, const float* __restrict__ gb,
                            float* __restrict__ out, int slot) {
    __shared__ float sred[2][8][128];
    const int tid = threadIdx.x, wid = tid >> 5, lane = tid & 31;
    const float4 b = *(const float4*)&gb[lane * 4];
    float4 s4 = {0.f, 0.f, 0.f, 0.f}, q4 = {0.f, 0.f, 0.f, 0.f};

    for (int i = blockIdx.x * 8 + wid; i < N_; i += 9216) {
        int beg = __ldg(&g_rowptr[i]), end = __ldg(&g_rowptr[i + 1]);
        float4 acc = *(const float4*)&Hs[(size_t)i * 128 + lane * 4];
        for (int base = beg; base < end; base += 32) {
            int e = base + lane;
            int sidx = (e < end) ? g_col[e] : 0;
            int cnt = min(32, end - base);
            int j = 0;
            for (; j + 8 <= cnt; j += 8) {
                int s0 = __shfl_sync(0xffffffffu, sidx, j);
                int s1 = __shfl_sync(0xffffffffu, sidx, j + 1);
                int s2 = __shfl_sync(0xffffffffu, sidx, j + 2);
                int s3 = __shfl_sync(0xffffffffu, sidx, j + 3);
                int s4i = __shfl_sync(0xffffffffu, sidx, j + 4);
                int s5 = __shfl_sync(0xffffffffu, sidx, j + 5);
                int s6 = __shfl_sync(0xffffffffu, sidx, j + 6);
                int s7 = __shfl_sync(0xffffffffu, sidx, j + 7);
                float4 v0 = *(const float4*)&Hs[(size_t)s0 * 128 + lane * 4];
                float4 v1 = *(const float4*)&Hs[(size_t)s1 * 128 + lane * 4];
                float4 v2 = *(const float4*)&Hs[(size_t)s2 * 128 + lane * 4];
                float4 v3 = *(const float4*)&Hs[(size_t)s3 * 128 + lane * 4];
                float4 v4 = *(const float4*)&Hs[(size_t)s4i * 128 + lane * 4];
                float4 v5 = *(const float4*)&Hs[(size_t)s5 * 128 + lane * 4];
                float4 v6 = *(const float4*)&Hs[(size_t)s6 * 128 + lane * 4];
                float4 v7 = *(const float4*)&Hs[(size_t)s7 * 128 + lane * 4];
                acc.x += (v0.x + v1.x) + (v2.x + v3.x) + ((v4.x + v5.x) + (v6.x + v7.x));
                acc.y += (v0.y + v1.y) + (v2.y + v3.y) + ((v4.y + v5.y) + (v6.y + v7.y));
                acc.z += (v0.z + v1.z) + (v2.z + v3.z) + ((v4.z + v5.z) + (v6.z + v7.z));
                acc.w += (v0.w + v1.w) + (v2.w + v3.w) + ((v4.w + v5.w) + (v6.w + v7.w));
            }
            for (; j < cnt; ++j) {
                int s = __shfl_sync(0xffffffffu, sidx, j);
                float4 v = *(const float4*)&Hs[(size_t)s * 128 + lane * 4];
                acc.x += v.x; acc.y += v.y; acc.z += v.z; acc.w += v.w;
            }
        }
        float di = g_dinv[i];
        acc.x = b.x + di * acc.x;
        acc.y = b.y + di * acc.y;
        acc.z = b.z + di * acc.z;
        acc.w = b.w + di * acc.w;
        acc.x = acc.x > 0.f ? acc.x : SLOPE_ * acc.x;
        acc.y = acc.y > 0.f ? acc.y : SLOPE_ * acc.y;
        acc.z = acc.z > 0.f ? acc.z : SLOPE_ * acc.z;
        acc.w = acc.w > 0.f ? acc.w : SLOPE_ * acc.w;
        if (RSTAT) {
            float ss = acc.x * acc.x + acc.y * acc.y + acc.z * acc.z + acc.w * acc.w;
#pragma unroll
            for (int o = 16; o > 0; o >>= 1) ss += __shfl_xor_sync(0xffffffffu, ss, o);
            float inv = 1.0f / fmaxf(sqrtf(ss), 1e-12f);
            if (lane == 0) g_invn[i] = inv;
            float nx = acc.x * inv, ny = acc.y * inv, nz = acc.z * inv, nw = acc.w * inv;
            s4.x += nx; s4.y += ny; s4.z += nz; s4.w += nw;
            q4.x += nx * nx; q4.y += ny * ny; q4.z += nz * nz; q4.w += nw * nw;
        }
        *(float4*)&out[(size_t)i * 128 + lane * 4] = acc;
    }

    if (RSTAT) {
        sred[0][wid][lane * 4 + 0] = s4.x; sred[0][wid][lane * 4 + 1] = s4.y;
        sred[0][wid][lane * 4 + 2] = s4.z; sred[0][wid][lane * 4 + 3] = s4.w;
        sred[1][wid][lane * 4 + 0] = q4.x; sred[1][wid][lane * 4 + 1] = q4.y;
        sred[1][wid][lane * 4 + 2] = q4.z; sred[1][wid][lane * 4 + 3] = q4.w;
        __syncthreads();
        if (tid < 128) {
            float a = 0.f, b2 = 0.f;
#pragma unroll
            for (int w = 0; w < 8; ++w) { a += sred[0][w][tid]; b2 += sred[1][w][tid]; }
            atomicAdd(&g_sum[slot * 256 + tid], a);
            atomicAdd(&g_sq[slot * 256 + tid], b2);
        }
    }
}

// gather64: bias + scale + leaky fused
__global__ void k_gather64(const float* __restrict__ Hs, const float* __restrict__ gb,
                           float* __restrict__ out) {
    int i = (int)(((size_t)blockIdx.x * blockDim.x + threadIdx.x) >> 5);
    if (i >= N_) return;
    int lane = threadIdx.x & 31;
    int beg = __ldg(&g_rowptr[i]), end = __ldg(&g_rowptr[i + 1]);
    float2 acc = *(const float2*)&Hs[(size_t)i * 64 + lane * 2];
    for (int base = beg; base < end; base += 32) {
        int e = base + lane;
        int sidx = (e < end) ? g_col[e] : 0;
        int cnt = min(32, end - base);
        int j = 0;
        for (; j + 8 <= cnt; j += 8) {
            int s0 = __shfl_sync(0xffffffffu, sidx, j);
            int s1 = __shfl_sync(0xffffffffu, sidx, j + 1);
            int s2 = __shfl_sync(0xffffffffu, sidx, j + 2);
            int s3 = __shfl_sync(0xffffffffu, sidx, j + 3);
            int s4 = __shfl_sync(0xffffffffu, sidx, j + 4);
            int s5 = __shfl_sync(0xffffffffu, sidx, j + 5);
            int s6 = __shfl_sync(0xffffffffu, sidx, j + 6);
            int s7 = __shfl_sync(0xffffffffu, sidx, j + 7);
            float2 v0 = *(const float2*)&Hs[(size_t)s0 * 64 + lane * 2];
            float2 v1 = *(const float2*)&Hs[(size_t)s1 * 64 + lane * 2];
            float2 v2 = *(const float2*)&Hs[(size_t)s2 * 64 + lane * 2];
            float2 v3 = *(const float2*)&Hs[(size_t)s3 * 64 + lane * 2];
            float2 v4 = *(const float2*)&Hs[(size_t)s4 * 64 + lane * 2];
            float2 v5 = *(const float2*)&Hs[(size_t)s5 * 64 + lane * 2];
            float2 v6 = *(const float2*)&Hs[(size_t)s6 * 64 + lane * 2];
            float2 v7 = *(const float2*)&Hs[(size_t)s7 * 64 + lane * 2];
            acc.x += (v0.x + v1.x) + (v2.x + v3.x) + ((v4.x + v5.x) + (v6.x + v7.x));
            acc.y += (v0.y + v1.y) + (v2.y + v3.y) + ((v4.y + v5.y) + (v6.y + v7.y));
        }
        for (; j < cnt; ++j) {
            int s = __shfl_sync(0xffffffffu, sidx, j);
            float2 v = *(const float2*)&Hs[(size_t)s * 64 + lane * 2];
            acc.x += v.x; acc.y += v.y;
        }
    }
    float di = g_dinv[i];
    float2 b = *(const float2*)&gb[lane * 2];
    acc.x = b.x + di * acc.x;
    acc.y = b.y + di * acc.y;
    acc.x = acc.x > 0.f ? acc.x : SLOPE_ * acc.x;
    acc.y = acc.y > 0.f ? acc.y : SLOPE_ * acc.y;
    *(float2*)&out[(size_t)i * 64 + lane * 2] = acc;
}

// ---------------- depthwise 5x5 conv ----------------
__global__ void k_dwconv(const float* __restrict__ In, const float* __restrict__ dw,
                         const float* __restrict__ db, float* __restrict__ Out) {
    __shared__ float wt[25 * 64];
    int tid = threadIdx.x;
    for (int i = tid; i < 25 * 64; i += 256) {
        int t = i >> 6, c = i & 63;
        wt[i] = dw[c * 25 + t];
    }
    __syncthreads();
    int c4 = tid & 15;
    int p = blockIdx.x * 16 + (tid >> 4);
    int y = p / Ww_, x = p % Ww_;
    float4 acc = {0.f, 0.f, 0.f, 0.f};
#pragma unroll
    for (int ky = 0; ky < 5; ++ky) {
        int yy = y + ky - 2;
        if (yy < 0 || yy >= Hh_) continue;
#pragma unroll
        for (int kx = 0; kx < 5; ++kx) {
            int xx = x + kx - 2;
            if (xx < 0 || xx >= Ww_) continue;
            float4 v  = *(const float4*)&In[((size_t)yy * Ww_ + xx) * 64 + c4 * 4];
            float4 wv = *(const float4*)&wt[(ky * 5 + kx) * 64 + c4 * 4];
            acc.x += v.x * wv.x; acc.y += v.y * wv.y;
            acc.z += v.z * wv.z; acc.w += v.w * wv.w;
        }
    }
    float4 b = *(const float4*)&db[c4 * 4];
    acc.x += b.x; acc.y += b.y; acc.z += b.z; acc.w += b.w;
    acc.x = acc.x > 0.f ? acc.x : SLOPE_ * acc.x;
    acc.y = acc.y > 0.f ? acc.y : SLOPE_ * acc.y;
    acc.z = acc.z > 0.f ? acc.z : SLOPE_ * acc.z;
    acc.w = acc.w > 0.f ? acc.w : SLOPE_ * acc.w;
    *(float4*)&Out[(size_t)p * 64 + c4 * 4] = acc;
}

// ---------------- head: G (already leaky) concat Cn -> linear -> softmax ----------------
__global__ void k_final(const float* __restrict__ G, const float* __restrict__ Cn,
                        const float* __restrict__ lw, const float* __restrict__ lb,
                        float* __restrict__ out) {
    __shared__ float slw[128 * 16];
    __shared__ float slb[16];
    __shared__ float sg[16][64];
    __shared__ float sc[16][64];
    int tid = threadIdx.x;
    for (int i = tid; i < 2048; i += 256) slw[i] = lw[i];
    if (tid < 16) slb[tid] = lb[tid];
    int tx = tid & 15, ty = tid >> 4;
    size_t row = (size_t)blockIdx.x * 16 + ty;
    *(float4*)&sg[ty][tx * 4] = *(const float4*)&G[row * 64 + tx * 4];
    *(float4*)&sc[ty][tx * 4] = *(const float4*)&Cn[row * 64 + tx * 4];
    __syncthreads();
    float acc = slb[tx];
#pragma unroll 4
    for (int k = 0; k < 64; ++k) acc += sg[ty][k] * slw[k * 16 + tx];
#pragma unroll 4
    for (int k = 0; k < 64; ++k) acc += sc[ty][k] * slw[(64 + k) * 16 + tx];
    float mx = acc;
#pragma unroll
    for (int o = 8; o > 0; o >>= 1) mx = fmaxf(mx, __shfl_xor_sync(0xffffffffu, mx, o));
    float e = __expf(acc - mx);
    float sum = e;
#pragma unroll
    for (int o = 8; o > 0; o >>= 1) sum += __shfl_xor_sync(0xffffffffu, sum, o);
    out[row * 16 + tx] = e / sum;
}

// ---------------- host launchers ----------------
template <int KREAL, int M, int EPI, int STAT>
static void launch_wgemm(cudaStream_t st, const float* X, float* Y, const float* W,
                         const float* bng, const float* bnb, const float* bias, int slotF,
                         int slotA = 0, int slotB = 0) {
    constexpr int KC = 32;
    constexpr size_t comp = (size_t)(128 * (KC + 8) + KC * (M + 8)) * 2
                          + (size_t)2 * 128 * KC * 4 + (size_t)2 * KC * M * 4;
    constexpr size_t stg  = (size_t)128 * (M + 8) * 4;
    constexpr size_t smem = comp > stg ? comp : stg;
    cudaFuncSetAttribute(k_wgemm<KREAL, M, EPI, STAT>,
                         cudaFuncAttributeMaxDynamicSharedMemorySize, (int)smem);
    k_wgemm<KREAL, M, EPI, STAT><<<N_ / 128, 256, smem, st>>>(X, Y, W, bng, bnb, bias,
                                                              slotF, slotA, slotB);
}

extern "C" void kernel_launch(void* const* d_in, const int* in_sizes, int n_in,
                              void* d_out, int out_size) {
    const float* x   = (const float*)d_in[0];
    const int*   ei  = (const int*)d_in[1];
    const int*   src = ei;
    const int*   dst = ei + E_;
    const float* dn_bn1_g = (const float*)d_in[2];
    const float* dn_bn1_b = (const float*)d_in[3];
    const float* dn_w1    = (const float*)d_in[4];
    const float* dn_b1    = (const float*)d_in[5];
    const float* dn_bn2_g = (const float*)d_in[6];
    const float* dn_bn2_b = (const float*)d_in[7];
    const float* dn_w2    = (const float*)d_in[8];
    const float* dn_b2    = (const float*)d_in[9];
    const float* cnn_bn_g = (const float*)d_in[10];
    const float* cnn_bn_b = (const float*)d_in[11];
    const float* cnn_pw   = (const float*)d_in[12];
    const float* cnn_dw   = (const float*)d_in[13];
    const float* cnn_db   = (const float*)d_in[14];
    const float* g1_bn_g  = (const float*)d_in[15];
    const float* g1_bn_b  = (const float*)d_in[16];
    const float* g1_w     = (const float*)d_in[17];
    const float* g1_b     = (const float*)d_in[18];
    const float* g2_bn_g  = (const float*)d_in[19];
    const float* g2_bn_b  = (const float*)d_in[20];
    const float* g2_w     = (const float*)d_in[21];
    const float* g2_b     = (const float*)d_in[22];
    const float* g3_bn_g  = (const float*)d_in[23];
    const float* g3_bn_b  = (const float*)d_in[24];
    const float* g3_w     = (const float*)d_in[25];
    const float* g3_b     = (const float*)d_in[26];
    const float* lin_w    = (const float*)d_in[27];
    const float* lin_b    = (const float*)d_in[28];
    float* out = (float*)d_out;

    float *pP, *pQ, *pH, *pC, *pCR;
    cudaGetSymbolAddress((void**)&pP, g_P);
    cudaGetSymbolAddress((void**)&pQ, g_Q);
    cudaGetSymbolAddress((void**)&pH, g_Hm);
    cudaGetSymbolAddress((void**)&pC, g_cnn);
    cudaGetSymbolAddress((void**)&pCR, g_cnnres);

    static cudaStream_t s1 = nullptr;
    static cudaEvent_t evA = nullptr, evCSR = nullptr, evD2 = nullptr,
                       evCNNG = nullptr, evCNN = nullptr;
    if (s1 == nullptr) {
        cudaStreamCreate(&s1);
        cudaEventCreateWithFlags(&evA,    cudaEventDisableTiming);
        cudaEventCreateWithFlags(&evCSR,  cudaEventDisableTiming);
        cudaEventCreateWithFlags(&evD2,   cudaEventDisableTiming);
        cudaEventCreateWithFlags(&evCNNG, cudaEventDisableTiming);
        cudaEventCreateWithFlags(&evCNN,  cudaEventDisableTiming);
    }
    cudaStream_t s0 = 0;   // capture (default) stream

    // ---- main stream: stats + denoise; side stream: CSR build ----
    k_init<<<NBLK_ + 1, 256, 0, s0>>>();
    cudaEventRecord(evA, s0);
    k_colstats<200><<<128, 200, 0, s0>>>(x, 0);

    cudaStreamWaitEvent(s1, evA, 0);
    k_deg_count<<<(E_ + 255) / 256, 256, 0, s1>>>(dst);

    // launch #4 = big tensor GEMM (profiling target)
    launch_wgemm<200, 128, 0, 1>(s0, x, pQ, dn_w1, dn_bn1_g, dn_bn1_b, dn_b1, 0, 1);

    k_scan1<<<NBLK_, 256, 0, s1>>>();
    k_scan2<<<1, 1024, 0, s1>>>();
    k_scan3<<<NBLK_, 256, 0, s1>>>();
    k_csr_fill<<<(E_ + 255) / 256, 256, 0, s1>>>(src, dst);
    cudaEventRecord(evCSR, s1);

    // denoise layer 2 on s0: epilogue -> plain stats (slot 2) + invn/norm stats (slot 3)
    launch_wgemm<128, 128, 0, 2>(s0, pQ, pP, dn_w2, dn_bn2_g, dn_bn2_b, dn_b2, 1, 2, 3);
    cudaEventRecord(evD2, s0);

    // ---- CNN branch on side stream (reads pP + slot2) ----
    cudaStreamWaitEvent(s1, evD2, 0);
    launch_wgemm<128, 64, 0, 0>(s1, pP, pC, cnn_pw, cnn_bn_g, cnn_bn_b, nullptr, 2);
    cudaEventRecord(evCNNG, s1);          // pP no longer read by CNN branch
    k_dwconv<<<N_ / 16, 256, 0, s1>>>(pC, cnn_dw, cnn_db, pCR);
    cudaEventRecord(evCNN, s1);

    // ---- GCN chain on main stream ----
    cudaStreamWaitEvent(s0, evCSR, 0);    // g_dinv/rowptr/col ready
    launch_wgemm<128, 128, 1, 0>(s0, pP, pH, g1_w, g1_bn_g, g1_bn_b, nullptr, 3);
    cudaStreamWaitEvent(s0, evCNNG, 0);   // CNN GEMM done reading pP before we overwrite
    k_gather128<true><<<1152, 256, 0, s0>>>(pH, g1_b, pP, 4);

    launch_wgemm<128, 128, 1, 0>(s0, pP, pH, g2_w, g2_bn_g, g2_bn_b, nullptr, 4);
    k_gather128<true><<<1152, 256, 0, s0>>>(pH, g2_b, pP, 5);

    launch_wgemm<128, 64, 1, 0>(s0, pP, pH, g3_w, g3_bn_g, g3_bn_b, nullptr, 5);
    k_gather64<<<(N_ * 32) / 256, 256, 0, s0>>>(pH, g3_b, pP);

    // ---- head (needs CNN result) ----
    cudaStreamWaitEvent(s0, evCNN, 0);
    k_final<<<N_ / 16, 256, 0, s0>>>(pP, pCR, lin_w, lin_b, out);
}

// round 13
// speedup vs baseline: 2.5960x; 1.0506x over previous
#include <cuda_runtime.h>
#include <cuda_fp16.h>
#include <cuda_pipeline.h>
#include <mma.h>
#include <cstdint>
#include <cstddef>

using namespace nvcuda;

// ---------------- problem constants ----------------
#define Hh_ 384
#define Ww_ 384
#define C_ 200
#define N_ 147456           // Hh_*Ww_
#define E_ 1179648
#define HIDE_ 128
#define OUT_ 64
#define NCLS_ 16
#define EPS_ 1e-5f
#define SLOPE_ 0.01f
#define NBLK_ 576           // N_/256

// ---------------- scratch (device globals; no allocation allowed) ----------------
__device__ float g_P[(size_t)N_ * 128];
__device__ float g_Q[(size_t)N_ * 128];
__device__ float g_Hm[(size_t)N_ * 128];    // holds fp16 Hs for GCN layers (reinterpreted)
__device__ float g_cnn[(size_t)N_ * 64];
__device__ float g_cnnres[(size_t)N_ * 64];
__device__ float g_dinv[N_];
__device__ float g_invn[N_];
__device__ float g_sum[6 * 256];
__device__ float g_sq[6 * 256];
// CSR
__device__ int g_degi[N_];
__device__ int g_rowptr[N_ + 1];
__device__ int g_cursor[N_];
__device__ int g_blksum[NBLK_];
__device__ int g_col[E_];

// ---------------- init: zero all stat slots + degree array ----------------
__global__ void k_init() {
    int i = blockIdx.x * 256 + threadIdx.x;
    if (i < N_) g_degi[i] = 0;
    if (i < 6 * 256) { g_sum[i] = 0.f; g_sq[i] = 0.f; }
}

// plain column stats (only used for raw input x): blockDim == C
template <int C>
__global__ void k_colstats(const float* __restrict__ X, int slot) {
    const int c = threadIdx.x;
    const int rpb = N_ / 128;
    const int r0 = blockIdx.x * rpb;
    float s = 0.f, q = 0.f;
    for (int r = r0; r < r0 + rpb; ++r) {
        float v = X[(size_t)r * C + c];
        s += v; q += v * v;
    }
    atomicAdd(&g_sum[slot * 256 + c], s);
    atomicAdd(&g_sq[slot * 256 + c], q);
}

// ---------------- tensor GEMM via wmma (fp16 x fp16, fp32 accum, 1 product) ----------------
// cp.async double-buffered raw staging of X and W; BN fold + fp16 convert from smem.
// Y[N,M] = epi( X[N,KREAL] @ (diag(scale)·W) + bf )
// EPI 0: out = leaky(acc + bf)         EPI 1: out = (acc*invn[r] + bf) * dinv[r]
// HOUT (EPI 1 only): write output as fp16 (__half) instead of fp32.
// STAT (EPI0, M=128): 1 = plain col stats -> slotA; 2 = plain->slotA AND invn+norm stats->slotB
// 256 threads = 8 warps in a 4(m) x 2(n) grid. Warp tile: 32 rows x M/2 cols.
template <int KREAL, int M, int EPI, int STAT, bool HOUT>
__global__ __launch_bounds__(256, 2)
void k_wgemm(const float* __restrict__ X, void* __restrict__ Yv,
             const float* __restrict__ W, const float* __restrict__ bng,
             const float* __restrict__ bnb, const float* __restrict__ bias,
             int slotF, int slotA, int slotB) {
    constexpr int KC = 32;            // K chunk
    constexpr int AS = KC + 8;        // A smem stride (halves)
    constexpr int BS = M + 8;         // B smem stride (halves)
    constexpr int MT = 2;             // m-tiles per warp (32 rows)
    constexpr int NT2 = M / 32;       // n-tiles per warp (M/2 cols)
    constexpr int NCH = (KREAL + KC - 1) / KC;
    constexpr int LASTR = KREAL - (NCH - 1) * KC;
    constexpr int KS_LAST = (LASTR + 15) / 16;

    constexpr int SZ_A = 128 * AS * 2;        // fp16 A plane
    constexpr int SZ_B = KC * BS * 2;
    constexpr int SZ_RX = 128 * KC * 4;       // one raw X slot
    constexpr int SZ_RW = KC * M * 4;         // one raw W slot

    extern __shared__ char smraw[];
    __half* As = (__half*)smraw;
    __half* Bs = (__half*)(smraw + SZ_A);
    float* rawX[2] = { (float*)(smraw + SZ_A + SZ_B),
                       (float*)(smraw + SZ_A + SZ_B + SZ_RX) };
    float* rawW[2] = { (float*)(smraw + SZ_A + SZ_B + 2 * SZ_RX),
                       (float*)(smraw + SZ_A + SZ_B + 2 * SZ_RX + SZ_RW) };
    float* stage = (float*)smraw;             // reused post-compute

    __shared__ float s_scale[256];
    __shared__ float s_shift[256];
    __shared__ float s_bf[128];

    const int tid = threadIdx.x, wid = tid >> 5, lane = tid & 31;
    const int wm = wid & 3, wn = wid >> 2;
    const size_t row0 = (size_t)blockIdx.x * 128;

    // fold coefficients from stats
    {
        float sc = 0.f, sh = 0.f;
        if (tid < KREAL) {
            float mean = g_sum[slotF * 256 + tid] * (1.f / N_);
            float var  = g_sq[slotF * 256 + tid] * (1.f / N_) - mean * mean;
            sc = bng[tid] * rsqrtf(var + EPS_);
            sh = bnb[tid] - mean * sc;
        }
        s_scale[tid] = sc;
        s_shift[tid] = sh;
        if (tid < M) s_bf[tid] = bias ? bias[tid] : 0.f;
    }

    wmma::fragment<wmma::accumulator, 16, 16, 16, float> acc[MT][NT2];
#pragma unroll
    for (int m = 0; m < MT; ++m)
#pragma unroll
        for (int n = 0; n < NT2; ++n) wmma::fill_fragment(acc[m][n], 0.0f);

    float pbf0 = 0.f, pbf1 = 0.f;
    const int myn2 = tid % (M / 2);

    // issue cp.async for chunk c into slot
    auto cp_chunk = [&](int c, int slot) {
        for (int p = tid; p < 128 * (KC / 4); p += 256) {
            int r = p / (KC / 4), s = p % (KC / 4);
            int col0 = c * KC + s * 4;
            int real = KREAL - col0; real = real < 0 ? 0 : (real > 4 ? 4 : real);
            const float* src = &X[(row0 + r) * KREAL + (real ? col0 : 0)];
            __pipeline_memcpy_async(&rawX[slot][r * KC + s * 4], src, 16,
                                    (size_t)(4 - real) * 4);
        }
        for (int p = tid; p < KC * (M / 4); p += 256) {
            int k = p / (M / 4), n4 = p % (M / 4);
            int kg = c * KC + k;
            bool ok = kg < KREAL;
            const float* src = &W[(size_t)(ok ? kg : 0) * M + n4 * 4];
            __pipeline_memcpy_async(&rawW[slot][k * M + n4 * 4], src, 16,
                                    ok ? 0 : 16);
        }
        __pipeline_commit();
    };

    // convert raw slot -> fp16 planes (+ bias fold from raw W)
    auto convert = [&](int c, int slot) {
        for (int p = tid; p < 128 * (KC / 2); p += 256) {
            int r = p / (KC / 2), q = p % (KC / 2);
            float2 v = *(float2*)&rawX[slot][r * KC + q * 2];
            *(__half2*)&As[r * AS + q * 2] =
                __half2(__float2half_rn(v.x), __float2half_rn(v.y));
        }
        for (int p = tid; p < KC * (M / 2); p += 256) {
            int kl = p / (M / 2), n2 = p % (M / 2);
            float2 w = *(float2*)&rawW[slot][kl * M + n2 * 2];
            int kg = c * KC + kl;
            float sh = s_shift[kg];
            pbf0 += sh * w.x;
            pbf1 += sh * w.y;
            float sc = s_scale[kg];
            w.x *= sc; w.y *= sc;
            *(__half2*)&Bs[kl * BS + n2 * 2] =
                __half2(__float2half_rn(w.x), __float2half_rn(w.y));
        }
    };

    auto do_ks = [&](int ks) {
        wmma::fragment<wmma::matrix_a, 16, 16, 16, __half, wmma::row_major> aF[MT];
#pragma unroll
        for (int m = 0; m < MT; ++m) {
            int rbase = wm * 32 + m * 16;
            wmma::load_matrix_sync(aF[m], As + rbase * AS + ks * 16, AS);
        }
#pragma unroll
        for (int n = 0; n < NT2; ++n) {
            int cbase = wn * (M / 2) + n * 16;
            wmma::fragment<wmma::matrix_b, 16, 16, 16, __half, wmma::row_major> bF;
            wmma::load_matrix_sync(bF, Bs + ks * 16 * BS + cbase, BS);
#pragma unroll
            for (int m = 0; m < MT; ++m)
                wmma::mma_sync(acc[m][n], aF[m], bF, acc[m][n]);
        }
    };

    cp_chunk(0, 0);
    for (int c = 0; c < NCH; ++c) {
        const int slot = c & 1;
        if (c + 1 < NCH) cp_chunk(c + 1, (c + 1) & 1);
        __pipeline_wait_prior((c + 1 < NCH) ? 1 : 0);
        __syncthreads();
        convert(c, slot);
        __syncthreads();
        const int nks = (c == NCH - 1) ? KS_LAST : 2;
        for (int ks = 0; ks < nks; ++ks) do_ks(ks);
        __syncthreads();
    }

    // finish folded bias (threads sharing a column pair combine)
    atomicAdd(&s_bf[myn2 * 2 + 0], pbf0);
    atomicAdd(&s_bf[myn2 * 2 + 1], pbf1);

    // stage accumulators to smem, then coalesced epi + store
#pragma unroll
    for (int m = 0; m < MT; ++m)
#pragma unroll
        for (int n = 0; n < NT2; ++n)
            wmma::store_matrix_sync(stage + (wm * 32 + m * 16) * (M + 8) + wn * (M / 2) + n * 16,
                                    acc[m][n], M + 8, wmma::mem_row_major);
    __syncthreads();

    float s1[4] = {0.f, 0.f, 0.f, 0.f}, q1[4] = {0.f, 0.f, 0.f, 0.f};
    float s2[4] = {0.f, 0.f, 0.f, 0.f}, q2[4] = {0.f, 0.f, 0.f, 0.f};

    for (int idx = tid; idx < 128 * (M / 4); idx += 256) {
        int r = idx / (M / 4), cq = idx % (M / 4);
        size_t gr = row0 + r;
        float4 v = *(float4*)&stage[r * (M + 8) + cq * 4];
        float4 b = *(const float4*)&s_bf[cq * 4];
        if (EPI == 0) {
            v.x += b.x; v.y += b.y; v.z += b.z; v.w += b.w;
            v.x = v.x > 0.f ? v.x : SLOPE_ * v.x;
            v.y = v.y > 0.f ? v.y : SLOPE_ * v.y;
            v.z = v.z > 0.f ? v.z : SLOPE_ * v.z;
            v.w = v.w > 0.f ? v.w : SLOPE_ * v.w;
            if (STAT >= 1) {
                s1[0] += v.x; s1[1] += v.y; s1[2] += v.z; s1[3] += v.w;
                q1[0] += v.x * v.x; q1[1] += v.y * v.y; q1[2] += v.z * v.z; q1[3] += v.w * v.w;
            }
            if (STAT == 2) {
                float ss = v.x * v.x + v.y * v.y + v.z * v.z + v.w * v.w;
#pragma unroll
                for (int o = 16; o > 0; o >>= 1) ss += __shfl_xor_sync(0xffffffffu, ss, o);
                float inv = 1.0f / fmaxf(sqrtf(ss), 1e-12f);
                if (lane == 0) g_invn[gr] = inv;
                float nx = v.x * inv, ny = v.y * inv, nz = v.z * inv, nw = v.w * inv;
                s2[0] += nx; s2[1] += ny; s2[2] += nz; s2[3] += nw;
                q2[0] += nx * nx; q2[1] += ny * ny; q2[2] += nz * nz; q2[3] += nw * nw;
            }
        } else {
            float sr = g_invn[gr], dv = g_dinv[gr];
            v.x = (v.x * sr + b.x) * dv;
            v.y = (v.y * sr + b.y) * dv;
            v.z = (v.z * sr + b.z) * dv;
            v.w = (v.w * sr + b.w) * dv;
        }
        if (HOUT) {
            __half* yh = (__half*)Yv;
            __half2 h01 = __half2(__float2half_rn(v.x), __float2half_rn(v.y));
            __half2 h23 = __half2(__float2half_rn(v.z), __float2half_rn(v.w));
            uint2 pk;
            pk.x = *(uint32_t*)&h01;
            pk.y = *(uint32_t*)&h23;
            *(uint2*)&yh[gr * M + cq * 4] = pk;
        } else {
            float* Y = (float*)Yv;
            *(float4*)&Y[gr * M + cq * 4] = v;
        }
    }

    if (EPI == 0 && STAT >= 1) {
        __syncthreads();
        float* red = stage;
#pragma unroll
        for (int j = 0; j < 4; ++j) {
            red[0 * 1024 + wid * 128 + lane * 4 + j] = s1[j];
            red[1 * 1024 + wid * 128 + lane * 4 + j] = q1[j];
            if (STAT == 2) {
                red[2 * 1024 + wid * 128 + lane * 4 + j] = s2[j];
                red[3 * 1024 + wid * 128 + lane * 4 + j] = q2[j];
            }
        }
        __syncthreads();
        if (tid < 128) {
            float a = 0.f, b = 0.f, c2 = 0.f, d2 = 0.f;
#pragma unroll
            for (int w = 0; w < 8; ++w) {
                a  += red[0 * 1024 + w * 128 + tid];
                b  += red[1 * 1024 + w * 128 + tid];
                if (STAT == 2) {
                    c2 += red[2 * 1024 + w * 128 + tid];
                    d2 += red[3 * 1024 + w * 128 + tid];
                }
            }
            atomicAdd(&g_sum[slotA * 256 + tid], a);
            atomicAdd(&g_sq[slotA * 256 + tid], b);
            if (STAT == 2) {
                atomicAdd(&g_sum[slotB * 256 + tid], c2);
                atomicAdd(&g_sq[slotB * 256 + tid], d2);
            }
        }
    }
}

// ---------------- CSR build ----------------
__global__ void k_deg_count(const int* __restrict__ dst) {
    int e = blockIdx.x * blockDim.x + threadIdx.x;
    if (e < E_) atomicAdd(&g_degi[dst[e]], 1);
}
__global__ void k_scan1() {
    __shared__ int s[256];
    int t = threadIdx.x;
    int idx = blockIdx.x * 256 + t;
    int v = g_degi[idx];
    s[t] = v;
    __syncthreads();
#pragma unroll
    for (int off = 1; off < 256; off <<= 1) {
        int a = 0;
        if (t >= off) a = s[t - off];
        __syncthreads();
        s[t] += a;
        __syncthreads();
    }
    g_rowptr[idx] = s[t] - v;
    if (t == 255) g_blksum[blockIdx.x] = s[255];
}
__global__ void k_scan2() {
    __shared__ int s[NBLK_];
    int t = threadIdx.x;
    if (t < NBLK_) s[t] = g_blksum[t];
    __syncthreads();
    for (int off = 1; off < NBLK_; off <<= 1) {
        int a = 0;
        if (t >= off && t < NBLK_) a = s[t - off];
        __syncthreads();
        if (t < NBLK_) s[t] += a;
        __syncthreads();
    }
    if (t < NBLK_) g_blksum[t] = s[t];
}
__global__ void k_scan3() {
    int idx = blockIdx.x * 256 + threadIdx.x;
    int off = blockIdx.x == 0 ? 0 : g_blksum[blockIdx.x - 1];
    int rp = g_rowptr[idx] + off;
    g_rowptr[idx] = rp;
    g_cursor[idx] = rp;
    g_dinv[idx] = rsqrtf((float)g_degi[idx] + 1.0f);
    if (idx == 0) g_rowptr[N_] = E_;
}
__global__ void k_csr_fill(const int* __restrict__ src, const int* __restrict__ dst) {
    int e = blockIdx.x * blockDim.x + threadIdx.x;
    if (e < E_) {
        int pos = atomicAdd(&g_cursor[dst[e]], 1);
        g_col[pos] = src[e];
    }
}

// ---------------- GCN gather (fp16 Hs; fused bias + scale + leaky [+ rownorm stats]) ----------------
__device__ __forceinline__ float4 ld_h4(const __half* p) {
    uint2 u = *(const uint2*)p;
    __half2 a = *(__half2*)&u.x, b = *(__half2*)&u.y;
    float2 f0 = __half22float2(a), f1 = __half22float2(b);
    return make_float4(f0.x, f0.y, f1.x, f1.y);
}

template <bool RSTAT>
__global__ void k_gather128(const __half* __restrict__ Hs, const float* __restrict__ gb,
                            float* __restrict__ out, int slot) {
    __shared__ float sred[2][8][128];
    const int tid = threadIdx.x, wid = tid >> 5, lane = tid & 31;
    const float4 b = *(const float4*)&gb[lane * 4];
    float4 s4 = {0.f, 0.f, 0.f, 0.f}, q4 = {0.f, 0.f, 0.f, 0.f};

    for (int i = blockIdx.x * 8 + wid; i < N_; i += 9216) {
        int beg = __ldg(&g_rowptr[i]), end = __ldg(&g_rowptr[i + 1]);
        float4 acc = ld_h4(&Hs[(size_t)i * 128 + lane * 4]);
        for (int base = beg; base < end; base += 32) {
            int e = base + lane;
            int sidx = (e < end) ? g_col[e] : 0;
            int cnt = min(32, end - base);
            int j = 0;
            for (; j + 8 <= cnt; j += 8) {
                int s0 = __shfl_sync(0xffffffffu, sidx, j);
                int s1 = __shfl_sync(0xffffffffu, sidx, j + 1);
                int s2 = __shfl_sync(0xffffffffu, sidx, j + 2);
                int s3 = __shfl_sync(0xffffffffu, sidx, j + 3);
                int s4i = __shfl_sync(0xffffffffu, sidx, j + 4);
                int s5 = __shfl_sync(0xffffffffu, sidx, j + 5);
                int s6 = __shfl_sync(0xffffffffu, sidx, j + 6);
                int s7 = __shfl_sync(0xffffffffu, sidx, j + 7);
                float4 v0 = ld_h4(&Hs[(size_t)s0 * 128 + lane * 4]);
                float4 v1 = ld_h4(&Hs[(size_t)s1 * 128 + lane * 4]);
                float4 v2 = ld_h4(&Hs[(size_t)s2 * 128 + lane * 4]);
                float4 v3 = ld_h4(&Hs[(size_t)s3 * 128 + lane * 4]);
                float4 v4 = ld_h4(&Hs[(size_t)s4i * 128 + lane * 4]);
                float4 v5 = ld_h4(&Hs[(size_t)s5 * 128 + lane * 4]);
                float4 v6 = ld_h4(&Hs[(size_t)s6 * 128 + lane * 4]);
                float4 v7 = ld_h4(&Hs[(size_t)s7 * 128 + lane * 4]);
                acc.x += (v0.x + v1.x) + (v2.x + v3.x) + ((v4.x + v5.x) + (v6.x + v7.x));
                acc.y += (v0.y + v1.y) + (v2.y + v3.y) + ((v4.y + v5.y) + (v6.y + v7.y));
                acc.z += (v0.z + v1.z) + (v2.z + v3.z) + ((v4.z + v5.z) + (v6.z + v7.z));
                acc.w += (v0.w + v1.w) + (v2.w + v3.w) + ((v4.w + v5.w) + (v6.w + v7.w));
            }
            for (; j < cnt; ++j) {
                int s = __shfl_sync(0xffffffffu, sidx, j);
                float4 v = ld_h4(&Hs[(size_t)s * 128 + lane * 4]);
                acc.x += v.x; acc.y += v.y; acc.z += v.z; acc.w += v.w;
            }
        }
        float di = g_dinv[i];
        acc.x = b.x + di * acc.x;
        acc.y = b.y + di * acc.y;
        acc.z = b.z + di * acc.z;
        acc.w = b.w + di * acc.w;
        acc.x = acc.x > 0.f ? acc.x : SLOPE_ * acc.x;
        acc.y = acc.y > 0.f ? acc.y : SLOPE_ * acc.y;
        acc.z = acc.z > 0.f ? acc.z : SLOPE_ * acc.z;
        acc.w = acc.w > 0.f ? acc.w : SLOPE_ * acc.w;
        if (RSTAT) {
            float ss = acc.x * acc.x + acc.y * acc.y + acc.z * acc.z + acc.w * acc.w;
#pragma unroll
            for (int o = 16; o > 0; o >>= 1) ss += __shfl_xor_sync(0xffffffffu, ss, o);
            float inv = 1.0f / fmaxf(sqrtf(ss), 1e-12f);
            if (lane == 0) g_invn[i] = inv;
            float nx = acc.x * inv, ny = acc.y * inv, nz = acc.z * inv, nw = acc.w * inv;
            s4.x += nx; s4.y += ny; s4.z += nz; s4.w += nw;
            q4.x += nx * nx; q4.y += ny * ny; q4.z += nz * nz; q4.w += nw * nw;
        }
        *(float4*)&out[(size_t)i * 128 + lane * 4] = acc;
    }

    if (RSTAT) {
        sred[0][wid][lane * 4 + 0] = s4.x; sred[0][wid][lane * 4 + 1] = s4.y;
        sred[0][wid][lane * 4 + 2] = s4.z; sred[0][wid][lane * 4 + 3] = s4.w;
        sred[1][wid][lane * 4 + 0] = q4.x; sred[1][wid][lane * 4 + 1] = q4.y;
        sred[1][wid][lane * 4 + 2] = q4.z; sred[1][wid][lane * 4 + 3] = q4.w;
        __syncthreads();
        if (tid < 128) {
            float a = 0.f, b2 = 0.f;
#pragma unroll
            for (int w = 0; w < 8; ++w) { a += sred[0][w][tid]; b2 += sred[1][w][tid]; }
            atomicAdd(&g_sum[slot * 256 + tid], a);
            atomicAdd(&g_sq[slot * 256 + tid], b2);
        }
    }
}

// gather64 (fp16 Hs): bias + scale + leaky fused
__global__ void k_gather64(const __half* __restrict__ Hs, const float* __restrict__ gb,
                           float* __restrict__ out) {
    int i = (int)(((size_t)blockIdx.x * blockDim.x + threadIdx.x) >> 5);
    if (i >= N_) return;
    int lane = threadIdx.x & 31;
    int beg = __ldg(&g_rowptr[i]), end = __ldg(&g_rowptr[i + 1]);
    float2 acc = __half22float2(*(const __half2*)&Hs[(size_t)i * 64 + lane * 2]);
    for (int base = beg; base < end; base += 32) {
        int e = base + lane;
        int sidx = (e < end) ? g_col[e] : 0;
        int cnt = min(32, end - base);
        int j = 0;
        for (; j + 8 <= cnt; j += 8) {
            int s0 = __shfl_sync(0xffffffffu, sidx, j);
            int s1 = __shfl_sync(0xffffffffu, sidx, j + 1);
            int s2 = __shfl_sync(0xffffffffu, sidx, j + 2);
            int s3 = __shfl_sync(0xffffffffu, sidx, j + 3);
            int s4 = __shfl_sync(0xffffffffu, sidx, j + 4);
            int s5 = __shfl_sync(0xffffffffu, sidx, j + 5);
            int s6 = __shfl_sync(0xffffffffu, sidx, j + 6);
            int s7 = __shfl_sync(0xffffffffu, sidx, j + 7);
            float2 v0 = __half22float2(*(const __half2*)&Hs[(size_t)s0 * 64 + lane * 2]);
            float2 v1 = __half22float2(*(const __half2*)&Hs[(size_t)s1 * 64 + lane * 2]);
            float2 v2 = __half22float2(*(const __half2*)&Hs[(size_t)s2 * 64 + lane * 2]);
            float2 v3 = __half22float2(*(const __half2*)&Hs[(size_t)s3 * 64 + lane * 2]);
            float2 v4 = __half22float2(*(const __half2*)&Hs[(size_t)s4 * 64 + lane * 2]);
            float2 v5 = __half22float2(*(const __half2*)&Hs[(size_t)s5 * 64 + lane * 2]);
            float2 v6 = __half22float2(*(const __half2*)&Hs[(size_t)s6 * 64 + lane * 2]);
            float2 v7 = __half22float2(*(const __half2*)&Hs[(size_t)s7 * 64 + lane * 2]);
            acc.x += (v0.x + v1.x) + (v2.x + v3.x) + ((v4.x + v5.x) + (v6.x + v7.x));
            acc.y += (v0.y + v1.y) + (v2.y + v3.y) + ((v4.y + v5.y) + (v6.y + v7.y));
        }
        for (; j < cnt; ++j) {
            int s = __shfl_sync(0xffffffffu, sidx, j);
            float2 v = __half22float2(*(const __half2*)&Hs[(size_t)s * 64 + lane * 2]);
            acc.x += v.x; acc.y += v.y;
        }
    }
    float di = g_dinv[i];
    float2 b = *(const float2*)&gb[lane * 2];
    acc.x = b.x + di * acc.x;
    acc.y = b.y + di * acc.y;
    acc.x = acc.x > 0.f ? acc.x : SLOPE_ * acc.x;
    acc.y = acc.y > 0.f ? acc.y : SLOPE_ * acc.y;
    *(float2*)&out[(size_t)i * 64 + lane * 2] = acc;
}

// ---------------- depthwise 5x5 conv ----------------
__global__ void k_dwconv(const float* __restrict__ In, const float* __restrict__ dw,
                         const float* __restrict__ db, float* __restrict__ Out) {
    __shared__ float wt[25 * 64];
    int tid = threadIdx.x;
    for (int i = tid; i < 25 * 64; i += 256) {
        int t = i >> 6, c = i & 63;
        wt[i] = dw[c * 25 + t];
    }
    __syncthreads();
    int c4 = tid & 15;
    int p = blockIdx.x * 16 + (tid >> 4);
    int y = p / Ww_, x = p % Ww_;
    float4 acc = {0.f, 0.f, 0.f, 0.f};
#pragma unroll
    for (int ky = 0; ky < 5; ++ky) {
        int yy = y + ky - 2;
        if (yy < 0 || yy >= Hh_) continue;
#pragma unroll
        for (int kx = 0; kx < 5; ++kx) {
            int xx = x + kx - 2;
            if (xx < 0 || xx >= Ww_) continue;
            float4 v  = *(const float4*)&In[((size_t)yy * Ww_ + xx) * 64 + c4 * 4];
            float4 wv = *(const float4*)&wt[(ky * 5 + kx) * 64 + c4 * 4];
            acc.x += v.x * wv.x; acc.y += v.y * wv.y;
            acc.z += v.z * wv.z; acc.w += v.w * wv.w;
        }
    }
    float4 b = *(const float4*)&db[c4 * 4];
    acc.x += b.x; acc.y += b.y; acc.z += b.z; acc.w += b.w;
    acc.x = acc.x > 0.f ? acc.x : SLOPE_ * acc.x;
    acc.y = acc.y > 0.f ? acc.y : SLOPE_ * acc.y;
    acc.z = acc.z > 0.f ? acc.z : SLOPE_ * acc.z;
    acc.w = acc.w > 0.f ? acc.w : SLOPE_ * acc.w;
    *(float4*)&Out[(size_t)p * 64 + c4 * 4] = acc;
}

// ---------------- head: G (already leaky) concat Cn -> linear -> softmax ----------------
__global__ void k_final(const float* __restrict__ G, const float* __restrict__ Cn,
                        const float* __restrict__ lw, const float* __restrict__ lb,
                        float* __restrict__ out) {
    __shared__ float slw[128 * 16];
    __shared__ float slb[16];
    __shared__ float sg[16][64];
    __shared__ float sc[16][64];
    int tid = threadIdx.x;
    for (int i = tid; i < 2048; i += 256) slw[i] = lw[i];
    if (tid < 16) slb[tid] = lb[tid];
    int tx = tid & 15, ty = tid >> 4;
    size_t row = (size_t)blockIdx.x * 16 + ty;
    *(float4*)&sg[ty][tx * 4] = *(const float4*)&G[row * 64 + tx * 4];
    *(float4*)&sc[ty][tx * 4] = *(const float4*)&Cn[row * 64 + tx * 4];
    __syncthreads();
    float acc = slb[tx];
#pragma unroll 4
    for (int k = 0; k < 64; ++k) acc += sg[ty][k] * slw[k * 16 + tx];
#pragma unroll 4
    for (int k = 0; k < 64; ++k) acc += sc[ty][k] * slw[(64 + k) * 16 + tx];
    float mx = acc;
#pragma unroll
    for (int o = 8; o > 0; o >>= 1) mx = fmaxf(mx, __shfl_xor_sync(0xffffffffu, mx, o));
    float e = __expf(acc - mx);
    float sum = e;
#pragma unroll
    for (int o = 8; o > 0; o >>= 1) sum += __shfl_xor_sync(0xffffffffu, sum, o);
    out[row * 16 + tx] = e / sum;
}

// ---------------- host launchers ----------------
template <int KREAL, int M, int EPI, int STAT, bool HOUT>
static void launch_wgemm(cudaStream_t st, const float* X, void* Y, const float* W,
                         const float* bng, const float* bnb, const float* bias, int slotF,
                         int slotA = 0, int slotB = 0) {
    constexpr int KC = 32;
    constexpr size_t comp = (size_t)(128 * (KC + 8) + KC * (M + 8)) * 2
                          + (size_t)2 * 128 * KC * 4 + (size_t)2 * KC * M * 4;
    constexpr size_t stg  = (size_t)128 * (M + 8) * 4;
    constexpr size_t smem = comp > stg ? comp : stg;
    cudaFuncSetAttribute(k_wgemm<KREAL, M, EPI, STAT, HOUT>,
                         cudaFuncAttributeMaxDynamicSharedMemorySize, (int)smem);
    k_wgemm<KREAL, M, EPI, STAT, HOUT><<<N_ / 128, 256, smem, st>>>(X, Y, W, bng, bnb, bias,
                                                                    slotF, slotA, slotB);
}

extern "C" void kernel_launch(void* const* d_in, const int* in_sizes, int n_in,
                              void* d_out, int out_size) {
    const float* x   = (const float*)d_in[0];
    const int*   ei  = (const int*)d_in[1];
    const int*   src = ei;
    const int*   dst = ei + E_;
    const float* dn_bn1_g = (const float*)d_in[2];
    const float* dn_bn1_b = (const float*)d_in[3];
    const float* dn_w1    = (const float*)d_in[4];
    const float* dn_b1    = (const float*)d_in[5];
    const float* dn_bn2_g = (const float*)d_in[6];
    const float* dn_bn2_b = (const float*)d_in[7];
    const float* dn_w2    = (const float*)d_in[8];
    const float* dn_b2    = (const float*)d_in[9];
    const float* cnn_bn_g = (const float*)d_in[10];
    const float* cnn_bn_b = (const float*)d_in[11];
    const float* cnn_pw   = (const float*)d_in[12];
    const float* cnn_dw   = (const float*)d_in[13];
    const float* cnn_db   = (const float*)d_in[14];
    const float* g1_bn_g  = (const float*)d_in[15];
    const float* g1_bn_b  = (const float*)d_in[16];
    const float* g1_w     = (const float*)d_in[17];
    const float* g1_b     = (const float*)d_in[18];
    const float* g2_bn_g  = (const float*)d_in[19];
    const float* g2_bn_b  = (const float*)d_in[20];
    const float* g2_w     = (const float*)d_in[21];
    const float* g2_b     = (const float*)d_in[22];
    const float* g3_bn_g  = (const float*)d_in[23];
    const float* g3_bn_b  = (const float*)d_in[24];
    const float* g3_w     = (const float*)d_in[25];
    const float* g3_b     = (const float*)d_in[26];
    const float* lin_w    = (const float*)d_in[27];
    const float* lin_b    = (const float*)d_in[28];
    float* out = (float*)d_out;

    float *pP, *pQ, *pH, *pC, *pCR;
    cudaGetSymbolAddress((void**)&pP, g_P);
    cudaGetSymbolAddress((void**)&pQ, g_Q);
    cudaGetSymbolAddress((void**)&pH, g_Hm);
    cudaGetSymbolAddress((void**)&pC, g_cnn);
    cudaGetSymbolAddress((void**)&pCR, g_cnnres);
    __half* pHh = (__half*)pH;

    static cudaStream_t s1 = nullptr;
    static cudaEvent_t evA = nullptr, evCSR = nullptr, evD2 = nullptr,
                       evCNNG = nullptr, evCNN = nullptr;
    if (s1 == nullptr) {
        cudaStreamCreate(&s1);
        cudaEventCreateWithFlags(&evA,    cudaEventDisableTiming);
        cudaEventCreateWithFlags(&evCSR,  cudaEventDisableTiming);
        cudaEventCreateWithFlags(&evD2,   cudaEventDisableTiming);
        cudaEventCreateWithFlags(&evCNNG, cudaEventDisableTiming);
        cudaEventCreateWithFlags(&evCNN,  cudaEventDisableTiming);
    }
    cudaStream_t s0 = 0;   // capture (default) stream

    // ---- main stream: stats + denoise; side stream: CSR build ----
    k_init<<<NBLK_ + 1, 256, 0, s0>>>();
    cudaEventRecord(evA, s0);
    k_colstats<200><<<128, 200, 0, s0>>>(x, 0);

    cudaStreamWaitEvent(s1, evA, 0);
    k_deg_count<<<(E_ + 255) / 256, 256, 0, s1>>>(dst);

    // launch #4 = big tensor GEMM (profiling target)
    launch_wgemm<200, 128, 0, 1, false>(s0, x, pQ, dn_w1, dn_bn1_g, dn_bn1_b, dn_b1, 0, 1);

    k_scan1<<<NBLK_, 256, 0, s1>>>();
    k_scan2<<<1, 1024, 0, s1>>>();
    k_scan3<<<NBLK_, 256, 0, s1>>>();
    k_csr_fill<<<(E_ + 255) / 256, 256, 0, s1>>>(src, dst);
    cudaEventRecord(evCSR, s1);

    // denoise layer 2 on s0: epilogue -> plain stats (slot 2) + invn/norm stats (slot 3)
    launch_wgemm<128, 128, 0, 2, false>(s0, pQ, pP, dn_w2, dn_bn2_g, dn_bn2_b, dn_b2, 1, 2, 3);
    cudaEventRecord(evD2, s0);

    // ---- CNN branch on side stream (reads pP + slot2) ----
    cudaStreamWaitEvent(s1, evD2, 0);
    launch_wgemm<128, 64, 0, 0, false>(s1, pP, pC, cnn_pw, cnn_bn_g, cnn_bn_b, nullptr, 2);
    cudaEventRecord(evCNNG, s1);          // pP no longer read by CNN branch
    k_dwconv<<<N_ / 16, 256, 0, s1>>>(pC, cnn_dw, cnn_db, pCR);
    cudaEventRecord(evCNN, s1);

    // ---- GCN chain on main stream (fp16 Hs) ----
    cudaStreamWaitEvent(s0, evCSR, 0);    // g_dinv/rowptr/col ready
    launch_wgemm<128, 128, 1, 0, true>(s0, pP, pHh, g1_w, g1_bn_g, g1_bn_b, nullptr, 3);
    cudaStreamWaitEvent(s0, evCNNG, 0);   // CNN GEMM done reading pP before we overwrite
    k_gather128<true><<<1152, 256, 0, s0>>>(pHh, g1_b, pP, 4);

    launch_wgemm<128, 128, 1, 0, true>(s0, pP, pHh, g2_w, g2_bn_g, g2_bn_b, nullptr, 4);
    k_gather128<true><<<1152, 256, 0, s0>>>(pHh, g2_b, pP, 5);

    launch_wgemm<128, 64, 1, 0, true>(s0, pP, pHh, g3_w, g3_bn_g, g3_bn_b, nullptr, 5);
    k_gather64<<<(N_ * 32) / 256, 256, 0, s0>>>(pHh, g3_b, pP);

    // ---- head (needs CNN result) ----
    cudaStreamWaitEvent(s0, evCNN, 0);
    k_final<<<N_ / 16, 256, 0, s0>>>(pP, pCR, lin_w, lin_b, out);
}

// round 14
// speedup vs baseline: 2.6951x; 1.0382x over previous
#include <cuda_runtime.h>
#include <cuda_fp16.h>
#include <cuda_pipeline.h>
#include <mma.h>
#include <cstdint>
#include <cstddef>

using namespace nvcuda;

// ---------------- problem constants ----------------
#define Hh_ 384
#define Ww_ 384
#define C_ 200
#define N_ 147456           // Hh_*Ww_
#define E_ 1179648
#define HIDE_ 128
#define OUT_ 64
#define NCLS_ 16
#define EPS_ 1e-5f
#define SLOPE_ 0.01f
#define NBLK_ 576           // N_/256

// ---------------- scratch (device globals; no allocation allowed) ----------------
__device__ float g_P[(size_t)N_ * 128];     // fp32 or fp16 (reinterpreted) per stage
__device__ float g_Q[(size_t)N_ * 128];     // fp16 after denoise1
__device__ float g_Hm[(size_t)N_ * 128];    // fp16 Hs
__device__ float g_cnn[(size_t)N_ * 64];
__device__ float g_cnnres[(size_t)N_ * 64];
__device__ float g_dinv[N_];
__device__ float g_invn[N_];
__device__ float g_sum[6 * 256];
__device__ float g_sq[6 * 256];
__device__ __half g_WfA[224 * 128];         // prepped weights, s0 chain
__device__ __half g_WfB[224 * 128];         // prepped weights, CNN branch
__device__ float g_bfA[128];
__device__ float g_bfB[128];
// CSR
__device__ int g_degi[N_];
__device__ int g_rowptr[N_ + 1];
__device__ int g_cursor[N_];
__device__ int g_blksum[NBLK_];
__device__ int g_col[E_];

// ---------------- init ----------------
__global__ void k_init() {
    int i = blockIdx.x * 256 + threadIdx.x;
    if (i < N_) g_degi[i] = 0;
    if (i < 6 * 256) { g_sum[i] = 0.f; g_sq[i] = 0.f; }
}

// plain column stats (raw input x): blockDim == C
template <int C>
__global__ void k_colstats(const float* __restrict__ X, int slot) {
    const int c = threadIdx.x;
    const int rpb = N_ / 128;
    const int r0 = blockIdx.x * rpb;
    float s = 0.f, q = 0.f;
    for (int r = r0; r < r0 + rpb; ++r) {
        float v = X[(size_t)r * C + c];
        s += v; q += v * v;
    }
    atomicAdd(&g_sum[slot * 256 + c], s);
    atomicAdd(&g_sq[slot * 256 + c], q);
}

// ---------------- weight prep: BN fold + fp16, padded to KPAD rows; folded bias ----------------
template <int KREAL, int KPAD, int M>
__global__ void k_prepw(const float* __restrict__ W, const float* __restrict__ bng,
                        const float* __restrict__ bnb, const float* __restrict__ bias,
                        int slotF, __half* __restrict__ outW, float* __restrict__ outB) {
    const float* su = &g_sum[slotF * 256];
    const float* qu = &g_sq[slotF * 256];
    constexpr int NW = KPAD * M;
    if (blockIdx.x == NW / 256) {
        int m = threadIdx.x;
        if (m < M) {
            float acc = bias ? bias[m] : 0.f;
            for (int c = 0; c < KREAL; ++c) {
                float mean = su[c] * (1.f / N_);
                float var  = qu[c] * (1.f / N_) - mean * mean;
                float scale = bng[c] * rsqrtf(var + EPS_);
                acc += (bnb[c] - mean * scale) * W[c * M + m];
            }
            outB[m] = acc;
        }
        return;
    }
    int e = blockIdx.x * 256 + threadIdx.x;
    int k = e / M, n = e % M;
    float w = 0.f;
    if (k < KREAL) {
        float mean = su[k] * (1.f / N_);
        float var  = qu[k] * (1.f / N_) - mean * mean;
        float scale = bng[k] * rsqrtf(var + EPS_);
        w = scale * W[k * M + n];
    }
    outW[e] = __float2half_rn(w);
}

// ---------------- tensor GEMM (fp16 x fp16, fp32 accum) ----------------
// W prepped fp16, cp.async'd straight into B planes. A: HIN ? direct fp16 cp : fp32 raw+convert.
// EPI 0: out = leaky(acc + bf)   EPI 1: out = (acc*invn[r] + bf)*dinv[r]
// HOUT: write fp16.  STAT (EPI0, M=128): 1 = plain stats->slotA; 2 = +invn/norm stats->slotB
template <int KREAL, int M, int EPI, int STAT, bool HIN, bool HOUT>
__global__ __launch_bounds__(256, 2)
void k_wgemm(const void* __restrict__ Xv, void* __restrict__ Yv,
             const __half* __restrict__ Wh, const float* __restrict__ bfp,
             int slotA, int slotB) {
    constexpr int KC = 32, AS = KC + 8, BS = M + 8, MT = 2, NT2 = M / 32;
    constexpr int NCH = (KREAL + KC - 1) / KC;
    constexpr int LASTR = KREAL - (NCH - 1) * KC;
    constexpr int KS_LAST = (LASTR + 15) / 16;
    constexpr int SZ_APL = 128 * AS * 2;
    constexpr int SZ_BPL = KC * BS * 2;

    extern __shared__ char smraw[];
    __half* Apl[2];
    __half* Bpl[2];
    float* rawX[2];
    if (HIN) {
        Apl[0] = (__half*)smraw;
        Apl[1] = (__half*)(smraw + SZ_APL);
        Bpl[0] = (__half*)(smraw + 2 * SZ_APL);
        Bpl[1] = (__half*)(smraw + 2 * SZ_APL + SZ_BPL);
        rawX[0] = rawX[1] = (float*)smraw;          // unused
    } else {
        Apl[0] = Apl[1] = (__half*)smraw;           // single A plane
        Bpl[0] = (__half*)(smraw + SZ_APL);
        Bpl[1] = (__half*)(smraw + SZ_APL + SZ_BPL);
        rawX[0] = (float*)(smraw + SZ_APL + 2 * SZ_BPL);
        rawX[1] = rawX[0] + 128 * KC;
    }
    float* stage = (float*)smraw;                   // reused post-compute
    __shared__ float s_bf[128];

    const int tid = threadIdx.x, wid = tid >> 5, lane = tid & 31;
    const int wm = wid & 3, wn = wid >> 2;
    const size_t row0 = (size_t)blockIdx.x * 128;

    if (tid < M) s_bf[tid] = bfp[tid];

    wmma::fragment<wmma::accumulator, 16, 16, 16, float> acc[MT][NT2];
#pragma unroll
    for (int m = 0; m < MT; ++m)
#pragma unroll
        for (int n = 0; n < NT2; ++n) wmma::fill_fragment(acc[m][n], 0.0f);

    auto cp_chunk = [&](int c, int slot) {
        if (HIN) {
            const __half* Xh = (const __half*)Xv;
            for (int p = tid; p < 128 * (KC / 8); p += 256) {
                int r = p >> 2, s = p & 3;
                __pipeline_memcpy_async(&Apl[slot][r * AS + s * 8],
                                        &Xh[(row0 + r) * KREAL + c * KC + s * 8], 16, 0);
            }
        } else {
            const float* X = (const float*)Xv;
            for (int p = tid; p < 128 * (KC / 4); p += 256) {
                int r = p / (KC / 4), s = p % (KC / 4);
                int col0 = c * KC + s * 4;
                int real = KREAL - col0; real = real < 0 ? 0 : (real > 4 ? 4 : real);
                __pipeline_memcpy_async(&rawX[slot][r * KC + s * 4],
                                        &X[(row0 + r) * KREAL + (real ? col0 : 0)], 16,
                                        (size_t)(4 - real) * 4);
            }
        }
        for (int p = tid; p < KC * (M / 8); p += 256) {
            int k = p / (M / 8), s = p % (M / 8);
            __pipeline_memcpy_async(&Bpl[slot][k * BS + s * 8],
                                    &Wh[(size_t)(c * KC + k) * M + s * 8], 16, 0);
        }
        __pipeline_commit();
    };

    auto convert = [&](int slot) {      // !HIN only: rawX -> fp16 A plane
        for (int p = tid; p < 128 * (KC / 2); p += 256) {
            int r = p / (KC / 2), q = p % (KC / 2);
            float2 v = *(float2*)&rawX[slot][r * KC + q * 2];
            *(__half2*)&Apl[0][r * AS + q * 2] =
                __half2(__float2half_rn(v.x), __float2half_rn(v.y));
        }
    };

    auto do_ks = [&](int ks, int slot) {
        const __half* Ap = HIN ? Apl[slot] : Apl[0];
        wmma::fragment<wmma::matrix_a, 16, 16, 16, __half, wmma::row_major> aF[MT];
#pragma unroll
        for (int m = 0; m < MT; ++m)
            wmma::load_matrix_sync(aF[m], Ap + (wm * 32 + m * 16) * AS + ks * 16, AS);
#pragma unroll
        for (int n = 0; n < NT2; ++n) {
            wmma::fragment<wmma::matrix_b, 16, 16, 16, __half, wmma::row_major> bF;
            wmma::load_matrix_sync(bF, Bpl[slot] + ks * 16 * BS + wn * (M / 2) + n * 16, BS);
#pragma unroll
            for (int m = 0; m < MT; ++m)
                wmma::mma_sync(acc[m][n], aF[m], bF, acc[m][n]);
        }
    };

    cp_chunk(0, 0);
    for (int c = 0; c < NCH; ++c) {
        const int slot = c & 1;
        if (c + 1 < NCH) cp_chunk(c + 1, slot ^ 1);
        __pipeline_wait_prior((c + 1 < NCH) ? 1 : 0);
        __syncthreads();
        if (!HIN) { convert(slot); __syncthreads(); }
        const int nks = (c == NCH - 1) ? KS_LAST : 2;
        for (int ks = 0; ks < nks; ++ks) do_ks(ks, slot);
        __syncthreads();
    }

    // stage accumulators to smem, then coalesced epi + store
#pragma unroll
    for (int m = 0; m < MT; ++m)
#pragma unroll
        for (int n = 0; n < NT2; ++n)
            wmma::store_matrix_sync(stage + (wm * 32 + m * 16) * (M + 8) + wn * (M / 2) + n * 16,
                                    acc[m][n], M + 8, wmma::mem_row_major);
    __syncthreads();

    float s1[4] = {0.f, 0.f, 0.f, 0.f}, q1[4] = {0.f, 0.f, 0.f, 0.f};
    float s2[4] = {0.f, 0.f, 0.f, 0.f}, q2[4] = {0.f, 0.f, 0.f, 0.f};

    for (int idx = tid; idx < 128 * (M / 4); idx += 256) {
        int r = idx / (M / 4), cq = idx % (M / 4);
        size_t gr = row0 + r;
        float4 v = *(float4*)&stage[r * (M + 8) + cq * 4];
        float4 b = *(const float4*)&s_bf[cq * 4];
        if (EPI == 0) {
            v.x += b.x; v.y += b.y; v.z += b.z; v.w += b.w;
            v.x = v.x > 0.f ? v.x : SLOPE_ * v.x;
            v.y = v.y > 0.f ? v.y : SLOPE_ * v.y;
            v.z = v.z > 0.f ? v.z : SLOPE_ * v.z;
            v.w = v.w > 0.f ? v.w : SLOPE_ * v.w;
            if (STAT >= 1) {
                s1[0] += v.x; s1[1] += v.y; s1[2] += v.z; s1[3] += v.w;
                q1[0] += v.x * v.x; q1[1] += v.y * v.y; q1[2] += v.z * v.z; q1[3] += v.w * v.w;
            }
            if (STAT == 2) {
                float ss = v.x * v.x + v.y * v.y + v.z * v.z + v.w * v.w;
#pragma unroll
                for (int o = 16; o > 0; o >>= 1) ss += __shfl_xor_sync(0xffffffffu, ss, o);
                float inv = 1.0f / fmaxf(sqrtf(ss), 1e-12f);
                if (lane == 0) g_invn[gr] = inv;
                float nx = v.x * inv, ny = v.y * inv, nz = v.z * inv, nw = v.w * inv;
                s2[0] += nx; s2[1] += ny; s2[2] += nz; s2[3] += nw;
                q2[0] += nx * nx; q2[1] += ny * ny; q2[2] += nz * nz; q2[3] += nw * nw;
            }
        } else {
            float sr = g_invn[gr], dv = g_dinv[gr];
            v.x = (v.x * sr + b.x) * dv;
            v.y = (v.y * sr + b.y) * dv;
            v.z = (v.z * sr + b.z) * dv;
            v.w = (v.w * sr + b.w) * dv;
        }
        if (HOUT) {
            __half* yh = (__half*)Yv;
            __half2 h01 = __half2(__float2half_rn(v.x), __float2half_rn(v.y));
            __half2 h23 = __half2(__float2half_rn(v.z), __float2half_rn(v.w));
            uint2 pk;
            pk.x = *(uint32_t*)&h01;
            pk.y = *(uint32_t*)&h23;
            *(uint2*)&yh[gr * M + cq * 4] = pk;
        } else {
            float* Y = (float*)Yv;
            *(float4*)&Y[gr * M + cq * 4] = v;
        }
    }

    if (EPI == 0 && STAT >= 1) {
        __syncthreads();
        float* red = stage;
#pragma unroll
        for (int j = 0; j < 4; ++j) {
            red[0 * 1024 + wid * 128 + lane * 4 + j] = s1[j];
            red[1 * 1024 + wid * 128 + lane * 4 + j] = q1[j];
            if (STAT == 2) {
                red[2 * 1024 + wid * 128 + lane * 4 + j] = s2[j];
                red[3 * 1024 + wid * 128 + lane * 4 + j] = q2[j];
            }
        }
        __syncthreads();
        if (tid < 128) {
            float a = 0.f, b = 0.f, c2 = 0.f, d2 = 0.f;
#pragma unroll
            for (int w = 0; w < 8; ++w) {
                a  += red[0 * 1024 + w * 128 + tid];
                b  += red[1 * 1024 + w * 128 + tid];
                if (STAT == 2) {
                    c2 += red[2 * 1024 + w * 128 + tid];
                    d2 += red[3 * 1024 + w * 128 + tid];
                }
            }
            atomicAdd(&g_sum[slotA * 256 + tid], a);
            atomicAdd(&g_sq[slotA * 256 + tid], b);
            if (STAT == 2) {
                atomicAdd(&g_sum[slotB * 256 + tid], c2);
                atomicAdd(&g_sq[slotB * 256 + tid], d2);
            }
        }
    }
}

// ---------------- CSR build ----------------
__global__ void k_deg_count(const int* __restrict__ dst) {
    int e = blockIdx.x * blockDim.x + threadIdx.x;
    if (e < E_) atomicAdd(&g_degi[dst[e]], 1);
}
__global__ void k_scan1() {
    __shared__ int s[256];
    int t = threadIdx.x;
    int idx = blockIdx.x * 256 + t;
    int v = g_degi[idx];
    s[t] = v;
    __syncthreads();
#pragma unroll
    for (int off = 1; off < 256; off <<= 1) {
        int a = 0;
        if (t >= off) a = s[t - off];
        __syncthreads();
        s[t] += a;
        __syncthreads();
    }
    g_rowptr[idx] = s[t] - v;
    if (t == 255) g_blksum[blockIdx.x] = s[255];
}
__global__ void k_scan2() {
    __shared__ int s[NBLK_];
    int t = threadIdx.x;
    if (t < NBLK_) s[t] = g_blksum[t];
    __syncthreads();
    for (int off = 1; off < NBLK_; off <<= 1) {
        int a = 0;
        if (t >= off && t < NBLK_) a = s[t - off];
        __syncthreads();
        if (t < NBLK_) s[t] += a;
        __syncthreads();
    }
    if (t < NBLK_) g_blksum[t] = s[t];
}
__global__ void k_scan3() {
    int idx = blockIdx.x * 256 + threadIdx.x;
    int off = blockIdx.x == 0 ? 0 : g_blksum[blockIdx.x - 1];
    int rp = g_rowptr[idx] + off;
    g_rowptr[idx] = rp;
    g_cursor[idx] = rp;
    g_dinv[idx] = rsqrtf((float)g_degi[idx] + 1.0f);
    if (idx == 0) g_rowptr[N_] = E_;
}
__global__ void k_csr_fill(const int* __restrict__ src, const int* __restrict__ dst) {
    int e = blockIdx.x * blockDim.x + threadIdx.x;
    if (e < E_) {
        int pos = atomicAdd(&g_cursor[dst[e]], 1);
        g_col[pos] = src[e];
    }
}

// ---------------- GCN gather (fp16 in/out; fused bias + scale + leaky + rownorm stats) ----------------
__device__ __forceinline__ float4 ld_h4(const __half* p) {
    uint2 u = *(const uint2*)p;
    __half2 a = *(__half2*)&u.x, b = *(__half2*)&u.y;
    float2 f0 = __half22float2(a), f1 = __half22float2(b);
    return make_float4(f0.x, f0.y, f1.x, f1.y);
}

__global__ void k_gather128(const __half* __restrict__ Hs, const float* __restrict__ gb,
                            __half* __restrict__ out, int slot) {
    __shared__ float sred[2][8][128];
    const int tid = threadIdx.x, wid = tid >> 5, lane = tid & 31;
    const float4 b = *(const float4*)&gb[lane * 4];
    float4 s4 = {0.f, 0.f, 0.f, 0.f}, q4 = {0.f, 0.f, 0.f, 0.f};

    for (int i = blockIdx.x * 8 + wid; i < N_; i += 9216) {
        int beg = __ldg(&g_rowptr[i]), end = __ldg(&g_rowptr[i + 1]);
        float4 acc = ld_h4(&Hs[(size_t)i * 128 + lane * 4]);
        for (int base = beg; base < end; base += 32) {
            int e = base + lane;
            int sidx = (e < end) ? g_col[e] : 0;
            int cnt = min(32, end - base);
            int j = 0;
            for (; j + 8 <= cnt; j += 8) {
                int s0 = __shfl_sync(0xffffffffu, sidx, j);
                int s1 = __shfl_sync(0xffffffffu, sidx, j + 1);
                int s2 = __shfl_sync(0xffffffffu, sidx, j + 2);
                int s3 = __shfl_sync(0xffffffffu, sidx, j + 3);
                int s4i = __shfl_sync(0xffffffffu, sidx, j + 4);
                int s5 = __shfl_sync(0xffffffffu, sidx, j + 5);
                int s6 = __shfl_sync(0xffffffffu, sidx, j + 6);
                int s7 = __shfl_sync(0xffffffffu, sidx, j + 7);
                float4 v0 = ld_h4(&Hs[(size_t)s0 * 128 + lane * 4]);
                float4 v1 = ld_h4(&Hs[(size_t)s1 * 128 + lane * 4]);
                float4 v2 = ld_h4(&Hs[(size_t)s2 * 128 + lane * 4]);
                float4 v3 = ld_h4(&Hs[(size_t)s3 * 128 + lane * 4]);
                float4 v4 = ld_h4(&Hs[(size_t)s4i * 128 + lane * 4]);
                float4 v5 = ld_h4(&Hs[(size_t)s5 * 128 + lane * 4]);
                float4 v6 = ld_h4(&Hs[(size_t)s6 * 128 + lane * 4]);
                float4 v7 = ld_h4(&Hs[(size_t)s7 * 128 + lane * 4]);
                acc.x += (v0.x + v1.x) + (v2.x + v3.x) + ((v4.x + v5.x) + (v6.x + v7.x));
                acc.y += (v0.y + v1.y) + (v2.y + v3.y) + ((v4.y + v5.y) + (v6.y + v7.y));
                acc.z += (v0.z + v1.z) + (v2.z + v3.z) + ((v4.z + v5.z) + (v6.z + v7.z));
                acc.w += (v0.w + v1.w) + (v2.w + v3.w) + ((v4.w + v5.w) + (v6.w + v7.w));
            }
            for (; j < cnt; ++j) {
                int s = __shfl_sync(0xffffffffu, sidx, j);
                float4 v = ld_h4(&Hs[(size_t)s * 128 + lane * 4]);
                acc.x += v.x; acc.y += v.y; acc.z += v.z; acc.w += v.w;
            }
        }
        float di = g_dinv[i];
        acc.x = b.x + di * acc.x;
        acc.y = b.y + di * acc.y;
        acc.z = b.z + di * acc.z;
        acc.w = b.w + di * acc.w;
        acc.x = acc.x > 0.f ? acc.x : SLOPE_ * acc.x;
        acc.y = acc.y > 0.f ? acc.y : SLOPE_ * acc.y;
        acc.z = acc.z > 0.f ? acc.z : SLOPE_ * acc.z;
        acc.w = acc.w > 0.f ? acc.w : SLOPE_ * acc.w;
        {
            float ss = acc.x * acc.x + acc.y * acc.y + acc.z * acc.z + acc.w * acc.w;
#pragma unroll
            for (int o = 16; o > 0; o >>= 1) ss += __shfl_xor_sync(0xffffffffu, ss, o);
            float inv = 1.0f / fmaxf(sqrtf(ss), 1e-12f);
            if (lane == 0) g_invn[i] = inv;
            float nx = acc.x * inv, ny = acc.y * inv, nz = acc.z * inv, nw = acc.w * inv;
            s4.x += nx; s4.y += ny; s4.z += nz; s4.w += nw;
            q4.x += nx * nx; q4.y += ny * ny; q4.z += nz * nz; q4.w += nw * nw;
        }
        __half2 h01 = __half2(__float2half_rn(acc.x), __float2half_rn(acc.y));
        __half2 h23 = __half2(__float2half_rn(acc.z), __float2half_rn(acc.w));
        uint2 pk;
        pk.x = *(uint32_t*)&h01;
        pk.y = *(uint32_t*)&h23;
        *(uint2*)&out[(size_t)i * 128 + lane * 4] = pk;
    }

    sred[0][wid][lane * 4 + 0] = s4.x; sred[0][wid][lane * 4 + 1] = s4.y;
    sred[0][wid][lane * 4 + 2] = s4.z; sred[0][wid][lane * 4 + 3] = s4.w;
    sred[1][wid][lane * 4 + 0] = q4.x; sred[1][wid][lane * 4 + 1] = q4.y;
    sred[1][wid][lane * 4 + 2] = q4.z; sred[1][wid][lane * 4 + 3] = q4.w;
    __syncthreads();
    if (tid < 128) {
        float a = 0.f, b2 = 0.f;
#pragma unroll
        for (int w = 0; w < 8; ++w) { a += sred[0][w][tid]; b2 += sred[1][w][tid]; }
        atomicAdd(&g_sum[slot * 256 + tid], a);
        atomicAdd(&g_sq[slot * 256 + tid], b2);
    }
}

// gather64 (fp16 Hs, fp32 out): bias + scale + leaky fused
__global__ void k_gather64(const __half* __restrict__ Hs, const float* __restrict__ gb,
                           float* __restrict__ out) {
    int i = (int)(((size_t)blockIdx.x * blockDim.x + threadIdx.x) >> 5);
    if (i >= N_) return;
    int lane = threadIdx.x & 31;
    int beg = __ldg(&g_rowptr[i]), end = __ldg(&g_rowptr[i + 1]);
    float2 acc = __half22float2(*(const __half2*)&Hs[(size_t)i * 64 + lane * 2]);
    for (int base = beg; base < end; base += 32) {
        int e = base + lane;
        int sidx = (e < end) ? g_col[e] : 0;
        int cnt = min(32, end - base);
        int j = 0;
        for (; j + 8 <= cnt; j += 8) {
            int s0 = __shfl_sync(0xffffffffu, sidx, j);
            int s1 = __shfl_sync(0xffffffffu, sidx, j + 1);
            int s2 = __shfl_sync(0xffffffffu, sidx, j + 2);
            int s3 = __shfl_sync(0xffffffffu, sidx, j + 3);
            int s4 = __shfl_sync(0xffffffffu, sidx, j + 4);
            int s5 = __shfl_sync(0xffffffffu, sidx, j + 5);
            int s6 = __shfl_sync(0xffffffffu, sidx, j + 6);
            int s7 = __shfl_sync(0xffffffffu, sidx, j + 7);
            float2 v0 = __half22float2(*(const __half2*)&Hs[(size_t)s0 * 64 + lane * 2]);
            float2 v1 = __half22float2(*(const __half2*)&Hs[(size_t)s1 * 64 + lane * 2]);
            float2 v2 = __half22float2(*(const __half2*)&Hs[(size_t)s2 * 64 + lane * 2]);
            float2 v3 = __half22float2(*(const __half2*)&Hs[(size_t)s3 * 64 + lane * 2]);
            float2 v4 = __half22float2(*(const __half2*)&Hs[(size_t)s4 * 64 + lane * 2]);
            float2 v5 = __half22float2(*(const __half2*)&Hs[(size_t)s5 * 64 + lane * 2]);
            float2 v6 = __half22float2(*(const __half2*)&Hs[(size_t)s6 * 64 + lane * 2]);
            float2 v7 = __half22float2(*(const __half2*)&Hs[(size_t)s7 * 64 + lane * 2]);
            acc.x += (v0.x + v1.x) + (v2.x + v3.x) + ((v4.x + v5.x) + (v6.x + v7.x));
            acc.y += (v0.y + v1.y) + (v2.y + v3.y) + ((v4.y + v5.y) + (v6.y + v7.y));
        }
        for (; j < cnt; ++j) {
            int s = __shfl_sync(0xffffffffu, sidx, j);
            float2 v = __half22float2(*(const __half2*)&Hs[(size_t)s * 64 + lane * 2]);
            acc.x += v.x; acc.y += v.y;
        }
    }
    float di = g_dinv[i];
    float2 b = *(const float2*)&gb[lane * 2];
    acc.x = b.x + di * acc.x;
    acc.y = b.y + di * acc.y;
    acc.x = acc.x > 0.f ? acc.x : SLOPE_ * acc.x;
    acc.y = acc.y > 0.f ? acc.y : SLOPE_ * acc.y;
    *(float2*)&out[(size_t)i * 64 + lane * 2] = acc;
}

// ---------------- depthwise 5x5 conv ----------------
__global__ void k_dwconv(const float* __restrict__ In, const float* __restrict__ dw,
                         const float* __restrict__ db, float* __restrict__ Out) {
    __shared__ float wt[25 * 64];
    int tid = threadIdx.x;
    for (int i = tid; i < 25 * 64; i += 256) {
        int t = i >> 6, c = i & 63;
        wt[i] = dw[c * 25 + t];
    }
    __syncthreads();
    int c4 = tid & 15;
    int p = blockIdx.x * 16 + (tid >> 4);
    int y = p / Ww_, x = p % Ww_;
    float4 acc = {0.f, 0.f, 0.f, 0.f};
#pragma unroll
    for (int ky = 0; ky < 5; ++ky) {
        int yy = y + ky - 2;
        if (yy < 0 || yy >= Hh_) continue;
#pragma unroll
        for (int kx = 0; kx < 5; ++kx) {
            int xx = x + kx - 2;
            if (xx < 0 || xx >= Ww_) continue;
            float4 v  = *(const float4*)&In[((size_t)yy * Ww_ + xx) * 64 + c4 * 4];
            float4 wv = *(const float4*)&wt[(ky * 5 + kx) * 64 + c4 * 4];
            acc.x += v.x * wv.x; acc.y += v.y * wv.y;
            acc.z += v.z * wv.z; acc.w += v.w * wv.w;
        }
    }
    float4 b = *(const float4*)&db[c4 * 4];
    acc.x += b.x; acc.y += b.y; acc.z += b.z; acc.w += b.w;
    acc.x = acc.x > 0.f ? acc.x : SLOPE_ * acc.x;
    acc.y = acc.y > 0.f ? acc.y : SLOPE_ * acc.y;
    acc.z = acc.z > 0.f ? acc.z : SLOPE_ * acc.z;
    acc.w = acc.w > 0.f ? acc.w : SLOPE_ * acc.w;
    *(float4*)&Out[(size_t)p * 64 + c4 * 4] = acc;
}

// ---------------- head: G (already leaky) concat Cn -> linear -> softmax ----------------
__global__ void k_final(const float* __restrict__ G, const float* __restrict__ Cn,
                        const float* __restrict__ lw, const float* __restrict__ lb,
                        float* __restrict__ out) {
    __shared__ float slw[128 * 16];
    __shared__ float slb[16];
    __shared__ float sg[16][64];
    __shared__ float sc[16][64];
    int tid = threadIdx.x;
    for (int i = tid; i < 2048; i += 256) slw[i] = lw[i];
    if (tid < 16) slb[tid] = lb[tid];
    int tx = tid & 15, ty = tid >> 4;
    size_t row = (size_t)blockIdx.x * 16 + ty;
    *(float4*)&sg[ty][tx * 4] = *(const float4*)&G[row * 64 + tx * 4];
    *(float4*)&sc[ty][tx * 4] = *(const float4*)&Cn[row * 64 + tx * 4];
    __syncthreads();
    float acc = slb[tx];
#pragma unroll 4
    for (int k = 0; k < 64; ++k) acc += sg[ty][k] * slw[k * 16 + tx];
#pragma unroll 4
    for (int k = 0; k < 64; ++k) acc += sc[ty][k] * slw[(64 + k) * 16 + tx];
    float mx = acc;
#pragma unroll
    for (int o = 8; o > 0; o >>= 1) mx = fmaxf(mx, __shfl_xor_sync(0xffffffffu, mx, o));
    float e = __expf(acc - mx);
    float sum = e;
#pragma unroll
    for (int o = 8; o > 0; o >>= 1) sum += __shfl_xor_sync(0xffffffffu, sum, o);
    out[row * 16 + tx] = e / sum;
}

// ---------------- host launchers ----------------
template <int KREAL, int M, int EPI, int STAT, bool HIN, bool HOUT>
static void launch_wgemm(cudaStream_t st, const void* X, void* Y, const __half* Wh,
                         const float* bf, int slotA = 0, int slotB = 0) {
    constexpr int KC = 32, AS = KC + 8, BS = M + 8;
    constexpr size_t a_sz = (size_t)128 * AS * 2;
    constexpr size_t b_sz = (size_t)KC * BS * 2;
    constexpr size_t comp = HIN ? (2 * a_sz + 2 * b_sz)
                                : (a_sz + 2 * b_sz + (size_t)2 * 128 * KC * 4);
    constexpr size_t stg = (size_t)128 * (M + 8) * 4;
    constexpr size_t smem = comp > stg ? comp : stg;
    cudaFuncSetAttribute(k_wgemm<KREAL, M, EPI, STAT, HIN, HOUT>,
                         cudaFuncAttributeMaxDynamicSharedMemorySize, (int)smem);
    k_wgemm<KREAL, M, EPI, STAT, HIN, HOUT><<<N_ / 128, 256, smem, st>>>(X, Y, Wh, bf,
                                                                         slotA, slotB);
}

extern "C" void kernel_launch(void* const* d_in, const int* in_sizes, int n_in,
                              void* d_out, int out_size) {
    const float* x   = (const float*)d_in[0];
    const int*   ei  = (const int*)d_in[1];
    const int*   src = ei;
    const int*   dst = ei + E_;
    const float* dn_bn1_g = (const float*)d_in[2];
    const float* dn_bn1_b = (const float*)d_in[3];
    const float* dn_w1    = (const float*)d_in[4];
    const float* dn_b1    = (const float*)d_in[5];
    const float* dn_bn2_g = (const float*)d_in[6];
    const float* dn_bn2_b = (const float*)d_in[7];
    const float* dn_w2    = (const float*)d_in[8];
    const float* dn_b2    = (const float*)d_in[9];
    const float* cnn_bn_g = (const float*)d_in[10];
    const float* cnn_bn_b = (const float*)d_in[11];
    const float* cnn_pw   = (const float*)d_in[12];
    const float* cnn_dw   = (const float*)d_in[13];
    const float* cnn_db   = (const float*)d_in[14];
    const float* g1_bn_g  = (const float*)d_in[15];
    const float* g1_bn_b  = (const float*)d_in[16];
    const float* g1_w     = (const float*)d_in[17];
    const float* g1_b     = (const float*)d_in[18];
    const float* g2_bn_g  = (const float*)d_in[19];
    const float* g2_bn_b  = (const float*)d_in[20];
    const float* g2_w     = (const float*)d_in[21];
    const float* g2_b     = (const float*)d_in[22];
    const float* g3_bn_g  = (const float*)d_in[23];
    const float* g3_bn_b  = (const float*)d_in[24];
    const float* g3_w     = (const float*)d_in[25];
    const float* g3_b     = (const float*)d_in[26];
    const float* lin_w    = (const float*)d_in[27];
    const float* lin_b    = (const float*)d_in[28];
    float* out = (float*)d_out;

    float *pP, *pQ, *pH, *pC, *pCR;
    cudaGetSymbolAddress((void**)&pP, g_P);
    cudaGetSymbolAddress((void**)&pQ, g_Q);
    cudaGetSymbolAddress((void**)&pH, g_Hm);
    cudaGetSymbolAddress((void**)&pC, g_cnn);
    cudaGetSymbolAddress((void**)&pCR, g_cnnres);
    __half *wA, *wB;
    float *bA, *bB;
    cudaGetSymbolAddress((void**)&wA, g_WfA);
    cudaGetSymbolAddress((void**)&wB, g_WfB);
    cudaGetSymbolAddress((void**)&bA, g_bfA);
    cudaGetSymbolAddress((void**)&bB, g_bfB);
    __half* pQh = (__half*)pQ;
    __half* pPh = (__half*)pP;
    __half* pHh = (__half*)pH;

    static cudaStream_t s1 = nullptr;
    static cudaEvent_t evA = nullptr, evCSR = nullptr, evD2 = nullptr,
                       evCNNG = nullptr, evCNN = nullptr;
    if (s1 == nullptr) {
        cudaStreamCreate(&s1);
        cudaEventCreateWithFlags(&evA,    cudaEventDisableTiming);
        cudaEventCreateWithFlags(&evCSR,  cudaEventDisableTiming);
        cudaEventCreateWithFlags(&evD2,   cudaEventDisableTiming);
        cudaEventCreateWithFlags(&evCNNG, cudaEventDisableTiming);
        cudaEventCreateWithFlags(&evCNN,  cudaEventDisableTiming);
    }
    cudaStream_t s0 = 0;   // capture (default) stream

    // ---- main stream: stats + denoise; side stream: CSR build ----
    k_init<<<NBLK_ + 1, 256, 0, s0>>>();
    cudaEventRecord(evA, s0);
    k_colstats<200><<<128, 200, 0, s0>>>(x, 0);

    cudaStreamWaitEvent(s1, evA, 0);
    k_deg_count<<<(E_ + 255) / 256, 256, 0, s1>>>(dst);

    // denoise layer 1 (fp32 in, fp16 out + stats slot1)
    k_prepw<200, 224, 128><<<113, 256, 0, s0>>>(dn_w1, dn_bn1_g, dn_bn1_b, dn_b1, 0, wA, bA);
    launch_wgemm<200, 128, 0, 1, false, true>(s0, x, pQh, wA, bA, 1);

    k_scan1<<<NBLK_, 256, 0, s1>>>();
    k_scan2<<<1, 1024, 0, s1>>>();
    k_scan3<<<NBLK_, 256, 0, s1>>>();
    k_csr_fill<<<(E_ + 255) / 256, 256, 0, s1>>>(src, dst);
    cudaEventRecord(evCSR, s1);

    // denoise layer 2 (fp16 in/out; stats slot2 + invn/norm stats slot3)
    k_prepw<128, 128, 128><<<65, 256, 0, s0>>>(dn_w2, dn_bn2_g, dn_bn2_b, dn_b2, 1, wA, bA);
    launch_wgemm<128, 128, 0, 2, true, true>(s0, pQh, pPh, wA, bA, 2, 3);
    cudaEventRecord(evD2, s0);

    // ---- CNN branch on side stream (fp16 in, fp32 out) ----
    cudaStreamWaitEvent(s1, evD2, 0);
    k_prepw<128, 128, 64><<<33, 256, 0, s1>>>(cnn_pw, cnn_bn_g, cnn_bn_b, nullptr, 2, wB, bB);
    launch_wgemm<128, 64, 0, 0, true, false>(s1, pPh, pC, wB, bB);
    cudaEventRecord(evCNNG, s1);          // pP no longer read by CNN branch
    k_dwconv<<<N_ / 16, 256, 0, s1>>>(pC, cnn_dw, cnn_db, pCR);
    cudaEventRecord(evCNN, s1);

    // ---- GCN chain on main stream (fp16 everywhere) ----
    cudaStreamWaitEvent(s0, evCSR, 0);
    k_prepw<128, 128, 128><<<65, 256, 0, s0>>>(g1_w, g1_bn_g, g1_bn_b, nullptr, 3, wA, bA);
    launch_wgemm<128, 128, 1, 0, true, true>(s0, pPh, pHh, wA, bA);
    cudaStreamWaitEvent(s0, evCNNG, 0);   // CNN GEMM done reading pPh before we overwrite
    k_gather128<<<1152, 256, 0, s0>>>(pHh, g1_b, pPh, 4);

    k_prepw<128, 128, 128><<<65, 256, 0, s0>>>(g2_w, g2_bn_g, g2_bn_b, nullptr, 4, wA, bA);
    launch_wgemm<128, 128, 1, 0, true, true>(s0, pPh, pHh, wA, bA);
    k_gather128<<<1152, 256, 0, s0>>>(pHh, g2_b, pPh, 5);

    k_prepw<128, 128, 64><<<33, 256, 0, s0>>>(g3_w, g3_bn_g, g3_bn_b, nullptr, 5, wA, bA);
    launch_wgemm<128, 64, 1, 0, true, true>(s0, pPh, pHh, wA, bA);
    k_gather64<<<(N_ * 32) / 256, 256, 0, s0>>>(pHh, g3_b, pP);

    // ---- head (needs CNN result) ----
    cudaStreamWaitEvent(s0, evCNN, 0);
    k_final<<<N_ / 16, 256, 0, s0>>>(pP, pCR, lin_w, lin_b, out);
}

// round 15
// speedup vs baseline: 3.0520x; 1.1324x over previous
#include <cuda_runtime.h>
#include <cuda_fp16.h>
#include <cuda_pipeline.h>
#include <mma.h>
#include <cstdint>
#include <cstddef>

using namespace nvcuda;

// ---------------- problem constants ----------------
#define Hh_ 384
#define Ww_ 384
#define C_ 200
#define N_ 147456           // Hh_*Ww_
#define E_ 1179648
#define HIDE_ 128
#define OUT_ 64
#define NCLS_ 16
#define EPS_ 1e-5f
#define SLOPE_ 0.01f
#define NBLK_ 576           // N_/256

// ---------------- scratch (device globals; no allocation allowed) ----------------
__device__ float g_P[(size_t)N_ * 128];     // fp32 or fp16 (reinterpreted) per stage
__device__ float g_Q[(size_t)N_ * 128];     // fp16 after denoise1
__device__ float g_Hm[(size_t)N_ * 128];    // fp16 Hs
__device__ float g_cnn[(size_t)N_ * 64];
__device__ float g_cnnres[(size_t)N_ * 64];
__device__ float g_dinv[N_];
__device__ float g_invn[N_];
__device__ float g_sum[6 * 256];
__device__ float g_sq[6 * 256];
__device__ __half g_WfA[224 * 128];         // prepped weights, s0 chain
__device__ __half g_WfB[224 * 128];         // prepped weights, CNN branch
__device__ float g_bfs[6 * 128];            // per-layer folded bias
// CSR
__device__ int g_degi[N_];
__device__ int g_rowptr[N_ + 1];
__device__ int g_cursor[N_];
__device__ int g_blksum[NBLK_];
__device__ int g_col[E_];

// ---------------- init: stats, degrees, per-layer bias seeds ----------------
__global__ void k_init(const float* __restrict__ b0, const float* __restrict__ b1) {
    int i = blockIdx.x * 256 + threadIdx.x;
    if (i < N_) g_degi[i] = 0;
    if (i < 6 * 256) { g_sum[i] = 0.f; g_sq[i] = 0.f; }
    if (i < 128) {
        g_bfs[0 * 128 + i] = b0[i];
        g_bfs[1 * 128 + i] = b1[i];
        g_bfs[2 * 128 + i] = 0.f;
        g_bfs[3 * 128 + i] = 0.f;
        g_bfs[4 * 128 + i] = 0.f;
        g_bfs[5 * 128 + i] = 0.f;
    }
}

// plain column stats (raw input x): blockDim == C
template <int C>
__global__ void k_colstats(const float* __restrict__ X, int slot) {
    const int c = threadIdx.x;
    const int rpb = N_ / 128;
    const int r0 = blockIdx.x * rpb;
    float s = 0.f, q = 0.f;
    for (int r = r0; r < r0 + rpb; ++r) {
        float v = X[(size_t)r * C + c];
        s += v; q += v * v;
    }
    atomicAdd(&g_sum[slot * 256 + c], s);
    atomicAdd(&g_sq[slot * 256 + c], q);
}

// ---------------- weight prep: BN fold + fp16 image; bias folded via block-parallel atomics ----------------
// outB must be pre-seeded (k_init) with the layer's torch bias (or 0).
template <int KREAL, int KPAD, int M>
__global__ void k_prepw(const float* __restrict__ W, const float* __restrict__ bng,
                        const float* __restrict__ bnb,
                        int slotF, __half* __restrict__ outW, float* __restrict__ outB) {
    __shared__ float sbf[M];
    const float* su = &g_sum[slotF * 256];
    const float* qu = &g_sq[slotF * 256];
    const int tid = threadIdx.x;
    if (tid < M) sbf[tid] = 0.f;
    __syncthreads();
    int e = blockIdx.x * 256 + tid;
    int k = e / M, n = e % M;
    float contrib = 0.f;
    if (k < KREAL) {
        float mean = su[k] * (1.f / N_);
        float var  = qu[k] * (1.f / N_) - mean * mean;
        float scale = bng[k] * rsqrtf(var + EPS_);
        float sh = bnb[k] - mean * scale;
        float w = W[k * M + n];
        contrib = sh * w;
        outW[e] = __float2half_rn(scale * w);
    } else {
        outW[e] = __float2half_rn(0.f);
    }
    atomicAdd(&sbf[n], contrib);
    __syncthreads();
    if (tid < M) atomicAdd(&outB[tid], sbf[tid]);
}

// ---------------- tensor GEMM (fp16 x fp16, fp32 accum) ----------------
// W prepped fp16, cp.async'd straight into B planes. A: HIN ? direct fp16 cp : fp32 raw+convert.
// EPI 0: out = leaky(acc + bf)   EPI 1: out = (acc*invn[r] + bf)*dinv[r]
// HOUT: write fp16.  STAT (EPI0, M=128): 1 = plain stats->slotA; 2 = +invn/norm stats->slotB
template <int KREAL, int M, int EPI, int STAT, bool HIN, bool HOUT>
__global__ __launch_bounds__(256, 2)
void k_wgemm(const void* __restrict__ Xv, void* __restrict__ Yv,
             const __half* __restrict__ Wh, const float* __restrict__ bfp,
             int slotA, int slotB) {
    constexpr int KC = 32, AS = KC + 8, BS = M + 8, MT = 2, NT2 = M / 32;
    constexpr int NCH = (KREAL + KC - 1) / KC;
    constexpr int LASTR = KREAL - (NCH - 1) * KC;
    constexpr int KS_LAST = (LASTR + 15) / 16;
    constexpr int SZ_APL = 128 * AS * 2;
    constexpr int SZ_BPL = KC * BS * 2;

    extern __shared__ char smraw[];
    __half* Apl[2];
    __half* Bpl[2];
    float* rawX[2];
    if (HIN) {
        Apl[0] = (__half*)smraw;
        Apl[1] = (__half*)(smraw + SZ_APL);
        Bpl[0] = (__half*)(smraw + 2 * SZ_APL);
        Bpl[1] = (__half*)(smraw + 2 * SZ_APL + SZ_BPL);
        rawX[0] = rawX[1] = (float*)smraw;          // unused
    } else {
        Apl[0] = Apl[1] = (__half*)smraw;           // single A plane
        Bpl[0] = (__half*)(smraw + SZ_APL);
        Bpl[1] = (__half*)(smraw + SZ_APL + SZ_BPL);
        rawX[0] = (float*)(smraw + SZ_APL + 2 * SZ_BPL);
        rawX[1] = rawX[0] + 128 * KC;
    }
    float* stage = (float*)smraw;                   // reused post-compute
    __shared__ float s_bf[128];

    const int tid = threadIdx.x, wid = tid >> 5, lane = tid & 31;
    const int wm = wid & 3, wn = wid >> 2;
    const size_t row0 = (size_t)blockIdx.x * 128;

    if (tid < M) s_bf[tid] = bfp[tid];

    wmma::fragment<wmma::accumulator, 16, 16, 16, float> acc[MT][NT2];
#pragma unroll
    for (int m = 0; m < MT; ++m)
#pragma unroll
        for (int n = 0; n < NT2; ++n) wmma::fill_fragment(acc[m][n], 0.0f);

    auto cp_chunk = [&](int c, int slot) {
        if (HIN) {
            const __half* Xh = (const __half*)Xv;
            for (int p = tid; p < 128 * (KC / 8); p += 256) {
                int r = p >> 2, s = p & 3;
                __pipeline_memcpy_async(&Apl[slot][r * AS + s * 8],
                                        &Xh[(row0 + r) * KREAL + c * KC + s * 8], 16, 0);
            }
        } else {
            const float* X = (const float*)Xv;
            for (int p = tid; p < 128 * (KC / 4); p += 256) {
                int r = p / (KC / 4), s = p % (KC / 4);
                int col0 = c * KC + s * 4;
                int real = KREAL - col0; real = real < 0 ? 0 : (real > 4 ? 4 : real);
                __pipeline_memcpy_async(&rawX[slot][r * KC + s * 4],
                                        &X[(row0 + r) * KREAL + (real ? col0 : 0)], 16,
                                        (size_t)(4 - real) * 4);
            }
        }
        for (int p = tid; p < KC * (M / 8); p += 256) {
            int k = p / (M / 8), s = p % (M / 8);
            __pipeline_memcpy_async(&Bpl[slot][k * BS + s * 8],
                                    &Wh[(size_t)(c * KC + k) * M + s * 8], 16, 0);
        }
        __pipeline_commit();
    };

    auto convert = [&](int slot) {      // !HIN only: rawX -> fp16 A plane
        for (int p = tid; p < 128 * (KC / 2); p += 256) {
            int r = p / (KC / 2), q = p % (KC / 2);
            float2 v = *(float2*)&rawX[slot][r * KC + q * 2];
            *(__half2*)&Apl[0][r * AS + q * 2] =
                __half2(__float2half_rn(v.x), __float2half_rn(v.y));
        }
    };

    auto do_ks = [&](int ks, int slot) {
        const __half* Ap = HIN ? Apl[slot] : Apl[0];
        wmma::fragment<wmma::matrix_a, 16, 16, 16, __half, wmma::row_major> aF[MT];
#pragma unroll
        for (int m = 0; m < MT; ++m)
            wmma::load_matrix_sync(aF[m], Ap + (wm * 32 + m * 16) * AS + ks * 16, AS);
#pragma unroll
        for (int n = 0; n < NT2; ++n) {
            wmma::fragment<wmma::matrix_b, 16, 16, 16, __half, wmma::row_major> bF;
            wmma::load_matrix_sync(bF, Bpl[slot] + ks * 16 * BS + wn * (M / 2) + n * 16, BS);
#pragma unroll
            for (int m = 0; m < MT; ++m)
                wmma::mma_sync(acc[m][n], aF[m], bF, acc[m][n]);
        }
    };

    cp_chunk(0, 0);
    for (int c = 0; c < NCH; ++c) {
        const int slot = c & 1;
        if (c + 1 < NCH) cp_chunk(c + 1, slot ^ 1);
        __pipeline_wait_prior((c + 1 < NCH) ? 1 : 0);
        __syncthreads();
        if (!HIN) { convert(slot); __syncthreads(); }
        const int nks = (c == NCH - 1) ? KS_LAST : 2;
        for (int ks = 0; ks < nks; ++ks) do_ks(ks, slot);
        __syncthreads();
    }

    // stage accumulators to smem, then coalesced epi + store
#pragma unroll
    for (int m = 0; m < MT; ++m)
#pragma unroll
        for (int n = 0; n < NT2; ++n)
            wmma::store_matrix_sync(stage + (wm * 32 + m * 16) * (M + 8) + wn * (M / 2) + n * 16,
                                    acc[m][n], M + 8, wmma::mem_row_major);
    __syncthreads();

    float s1[4] = {0.f, 0.f, 0.f, 0.f}, q1[4] = {0.f, 0.f, 0.f, 0.f};
    float s2[4] = {0.f, 0.f, 0.f, 0.f}, q2[4] = {0.f, 0.f, 0.f, 0.f};

    for (int idx = tid; idx < 128 * (M / 4); idx += 256) {
        int r = idx / (M / 4), cq = idx % (M / 4);
        size_t gr = row0 + r;
        float4 v = *(float4*)&stage[r * (M + 8) + cq * 4];
        float4 b = *(const float4*)&s_bf[cq * 4];
        if (EPI == 0) {
            v.x += b.x; v.y += b.y; v.z += b.z; v.w += b.w;
            v.x = v.x > 0.f ? v.x : SLOPE_ * v.x;
            v.y = v.y > 0.f ? v.y : SLOPE_ * v.y;
            v.z = v.z > 0.f ? v.z : SLOPE_ * v.z;
            v.w = v.w > 0.f ? v.w : SLOPE_ * v.w;
            if (STAT >= 1) {
                s1[0] += v.x; s1[1] += v.y; s1[2] += v.z; s1[3] += v.w;
                q1[0] += v.x * v.x; q1[1] += v.y * v.y; q1[2] += v.z * v.z; q1[3] += v.w * v.w;
            }
            if (STAT == 2) {
                float ss = v.x * v.x + v.y * v.y + v.z * v.z + v.w * v.w;
#pragma unroll
                for (int o = 16; o > 0; o >>= 1) ss += __shfl_xor_sync(0xffffffffu, ss, o);
                float inv = 1.0f / fmaxf(sqrtf(ss), 1e-12f);
                if (lane == 0) g_invn[gr] = inv;
                float nx = v.x * inv, ny = v.y * inv, nz = v.z * inv, nw = v.w * inv;
                s2[0] += nx; s2[1] += ny; s2[2] += nz; s2[3] += nw;
                q2[0] += nx * nx; q2[1] += ny * ny; q2[2] += nz * nz; q2[3] += nw * nw;
            }
        } else {
            float sr = g_invn[gr], dv = g_dinv[gr];
            v.x = (v.x * sr + b.x) * dv;
            v.y = (v.y * sr + b.y) * dv;
            v.z = (v.z * sr + b.z) * dv;
            v.w = (v.w * sr + b.w) * dv;
        }
        if (HOUT) {
            __half* yh = (__half*)Yv;
            __half2 h01 = __half2(__float2half_rn(v.x), __float2half_rn(v.y));
            __half2 h23 = __half2(__float2half_rn(v.z), __float2half_rn(v.w));
            uint2 pk;
            pk.x = *(uint32_t*)&h01;
            pk.y = *(uint32_t*)&h23;
            *(uint2*)&yh[gr * M + cq * 4] = pk;
        } else {
            float* Y = (float*)Yv;
            *(float4*)&Y[gr * M + cq * 4] = v;
        }
    }

    if (EPI == 0 && STAT >= 1) {
        __syncthreads();
        float* red = stage;
#pragma unroll
        for (int j = 0; j < 4; ++j) {
            red[0 * 1024 + wid * 128 + lane * 4 + j] = s1[j];
            red[1 * 1024 + wid * 128 + lane * 4 + j] = q1[j];
            if (STAT == 2) {
                red[2 * 1024 + wid * 128 + lane * 4 + j] = s2[j];
                red[3 * 1024 + wid * 128 + lane * 4 + j] = q2[j];
            }
        }
        __syncthreads();
        if (tid < 128) {
            float a = 0.f, b = 0.f, c2 = 0.f, d2 = 0.f;
#pragma unroll
            for (int w = 0; w < 8; ++w) {
                a  += red[0 * 1024 + w * 128 + tid];
                b  += red[1 * 1024 + w * 128 + tid];
                if (STAT == 2) {
                    c2 += red[2 * 1024 + w * 128 + tid];
                    d2 += red[3 * 1024 + w * 128 + tid];
                }
            }
            atomicAdd(&g_sum[slotA * 256 + tid], a);
            atomicAdd(&g_sq[slotA * 256 + tid], b);
            if (STAT == 2) {
                atomicAdd(&g_sum[slotB * 256 + tid], c2);
                atomicAdd(&g_sq[slotB * 256 + tid], d2);
            }
        }
    }
}

// ---------------- CSR build ----------------
__global__ void k_deg_count(const int* __restrict__ dst) {
    int e = blockIdx.x * blockDim.x + threadIdx.x;
    if (e < E_) atomicAdd(&g_degi[dst[e]], 1);
}
__global__ void k_scan1() {
    __shared__ int s[256];
    int t = threadIdx.x;
    int idx = blockIdx.x * 256 + t;
    int v = g_degi[idx];
    s[t] = v;
    __syncthreads();
#pragma unroll
    for (int off = 1; off < 256; off <<= 1) {
        int a = 0;
        if (t >= off) a = s[t - off];
        __syncthreads();
        s[t] += a;
        __syncthreads();
    }
    g_rowptr[idx] = s[t] - v;
    if (t == 255) g_blksum[blockIdx.x] = s[255];
}
__global__ void k_scan2() {
    __shared__ int s[NBLK_];
    int t = threadIdx.x;
    if (t < NBLK_) s[t] = g_blksum[t];
    __syncthreads();
    for (int off = 1; off < NBLK_; off <<= 1) {
        int a = 0;
        if (t >= off && t < NBLK_) a = s[t - off];
        __syncthreads();
        if (t < NBLK_) s[t] += a;
        __syncthreads();
    }
    if (t < NBLK_) g_blksum[t] = s[t];
}
__global__ void k_scan3() {
    int idx = blockIdx.x * 256 + threadIdx.x;
    int off = blockIdx.x == 0 ? 0 : g_blksum[blockIdx.x - 1];
    int rp = g_rowptr[idx] + off;
    g_rowptr[idx] = rp;
    g_cursor[idx] = rp;
    g_dinv[idx] = rsqrtf((float)g_degi[idx] + 1.0f);
    if (idx == 0) g_rowptr[N_] = E_;
}
__global__ void k_csr_fill(const int* __restrict__ src, const int* __restrict__ dst) {
    int e = blockIdx.x * blockDim.x + threadIdx.x;
    if (e < E_) {
        int pos = atomicAdd(&g_cursor[dst[e]], 1);
        g_col[pos] = src[e];
    }
}

// ---------------- GCN gather (fp16 in/out; fused bias + scale + leaky + rownorm stats) ----------------
__device__ __forceinline__ float4 ld_h4(const __half* p) {
    uint2 u = *(const uint2*)p;
    __half2 a = *(__half2*)&u.x, b = *(__half2*)&u.y;
    float2 f0 = __half22float2(a), f1 = __half22float2(b);
    return make_float4(f0.x, f0.y, f1.x, f1.y);
}

__global__ void k_gather128(const __half* __restrict__ Hs, const float* __restrict__ gb,
                            __half* __restrict__ out, int slot) {
    __shared__ float sred[2][8][128];
    const int tid = threadIdx.x, wid = tid >> 5, lane = tid & 31;
    const float4 b = *(const float4*)&gb[lane * 4];
    float4 s4 = {0.f, 0.f, 0.f, 0.f}, q4 = {0.f, 0.f, 0.f, 0.f};

    for (int i = blockIdx.x * 8 + wid; i < N_; i += 9216) {
        int beg = __ldg(&g_rowptr[i]), end = __ldg(&g_rowptr[i + 1]);
        float4 acc = ld_h4(&Hs[(size_t)i * 128 + lane * 4]);
        for (int base = beg; base < end; base += 32) {
            int e = base + lane;
            int sidx = (e < end) ? g_col[e] : 0;
            int cnt = min(32, end - base);
            int j = 0;
            for (; j + 8 <= cnt; j += 8) {
                int s0 = __shfl_sync(0xffffffffu, sidx, j);
                int s1 = __shfl_sync(0xffffffffu, sidx, j + 1);
                int s2 = __shfl_sync(0xffffffffu, sidx, j + 2);
                int s3 = __shfl_sync(0xffffffffu, sidx, j + 3);
                int s4i = __shfl_sync(0xffffffffu, sidx, j + 4);
                int s5 = __shfl_sync(0xffffffffu, sidx, j + 5);
                int s6 = __shfl_sync(0xffffffffu, sidx, j + 6);
                int s7 = __shfl_sync(0xffffffffu, sidx, j + 7);
                float4 v0 = ld_h4(&Hs[(size_t)s0 * 128 + lane * 4]);
                float4 v1 = ld_h4(&Hs[(size_t)s1 * 128 + lane * 4]);
                float4 v2 = ld_h4(&Hs[(size_t)s2 * 128 + lane * 4]);
                float4 v3 = ld_h4(&Hs[(size_t)s3 * 128 + lane * 4]);
                float4 v4 = ld_h4(&Hs[(size_t)s4i * 128 + lane * 4]);
                float4 v5 = ld_h4(&Hs[(size_t)s5 * 128 + lane * 4]);
                float4 v6 = ld_h4(&Hs[(size_t)s6 * 128 + lane * 4]);
                float4 v7 = ld_h4(&Hs[(size_t)s7 * 128 + lane * 4]);
                acc.x += (v0.x + v1.x) + (v2.x + v3.x) + ((v4.x + v5.x) + (v6.x + v7.x));
                acc.y += (v0.y + v1.y) + (v2.y + v3.y) + ((v4.y + v5.y) + (v6.y + v7.y));
                acc.z += (v0.z + v1.z) + (v2.z + v3.z) + ((v4.z + v5.z) + (v6.z + v7.z));
                acc.w += (v0.w + v1.w) + (v2.w + v3.w) + ((v4.w + v5.w) + (v6.w + v7.w));
            }
            for (; j < cnt; ++j) {
                int s = __shfl_sync(0xffffffffu, sidx, j);
                float4 v = ld_h4(&Hs[(size_t)s * 128 + lane * 4]);
                acc.x += v.x; acc.y += v.y; acc.z += v.z; acc.w += v.w;
            }
        }
        float di = g_dinv[i];
        acc.x = b.x + di * acc.x;
        acc.y = b.y + di * acc.y;
        acc.z = b.z + di * acc.z;
        acc.w = b.w + di * acc.w;
        acc.x = acc.x > 0.f ? acc.x : SLOPE_ * acc.x;
        acc.y = acc.y > 0.f ? acc.y : SLOPE_ * acc.y;
        acc.z = acc.z > 0.f ? acc.z : SLOPE_ * acc.z;
        acc.w = acc.w > 0.f ? acc.w : SLOPE_ * acc.w;
        {
            float ss = acc.x * acc.x + acc.y * acc.y + acc.z * acc.z + acc.w * acc.w;
#pragma unroll
            for (int o = 16; o > 0; o >>= 1) ss += __shfl_xor_sync(0xffffffffu, ss, o);
            float inv = 1.0f / fmaxf(sqrtf(ss), 1e-12f);
            if (lane == 0) g_invn[i] = inv;
            float nx = acc.x * inv, ny = acc.y * inv, nz = acc.z * inv, nw = acc.w * inv;
            s4.x += nx; s4.y += ny; s4.z += nz; s4.w += nw;
            q4.x += nx * nx; q4.y += ny * ny; q4.z += nz * nz; q4.w += nw * nw;
        }
        __half2 h01 = __half2(__float2half_rn(acc.x), __float2half_rn(acc.y));
        __half2 h23 = __half2(__float2half_rn(acc.z), __float2half_rn(acc.w));
        uint2 pk;
        pk.x = *(uint32_t*)&h01;
        pk.y = *(uint32_t*)&h23;
        *(uint2*)&out[(size_t)i * 128 + lane * 4] = pk;
    }

    sred[0][wid][lane * 4 + 0] = s4.x; sred[0][wid][lane * 4 + 1] = s4.y;
    sred[0][wid][lane * 4 + 2] = s4.z; sred[0][wid][lane * 4 + 3] = s4.w;
    sred[1][wid][lane * 4 + 0] = q4.x; sred[1][wid][lane * 4 + 1] = q4.y;
    sred[1][wid][lane * 4 + 2] = q4.z; sred[1][wid][lane * 4 + 3] = q4.w;
    __syncthreads();
    if (tid < 128) {
        float a = 0.f, b2 = 0.f;
#pragma unroll
        for (int w = 0; w < 8; ++w) { a += sred[0][w][tid]; b2 += sred[1][w][tid]; }
        atomicAdd(&g_sum[slot * 256 + tid], a);
        atomicAdd(&g_sq[slot * 256 + tid], b2);
    }
}

// gather64 (fp16 Hs, fp32 out): bias + scale + leaky fused
__global__ void k_gather64(const __half* __restrict__ Hs, const float* __restrict__ gb,
                           float* __restrict__ out) {
    int i = (int)(((size_t)blockIdx.x * blockDim.x + threadIdx.x) >> 5);
    if (i >= N_) return;
    int lane = threadIdx.x & 31;
    int beg = __ldg(&g_rowptr[i]), end = __ldg(&g_rowptr[i + 1]);
    float2 acc = __half22float2(*(const __half2*)&Hs[(size_t)i * 64 + lane * 2]);
    for (int base = beg; base < end; base += 32) {
        int e = base + lane;
        int sidx = (e < end) ? g_col[e] : 0;
        int cnt = min(32, end - base);
        int j = 0;
        for (; j + 8 <= cnt; j += 8) {
            int s0 = __shfl_sync(0xffffffffu, sidx, j);
            int s1 = __shfl_sync(0xffffffffu, sidx, j + 1);
            int s2 = __shfl_sync(0xffffffffu, sidx, j + 2);
            int s3 = __shfl_sync(0xffffffffu, sidx, j + 3);
            int s4 = __shfl_sync(0xffffffffu, sidx, j + 4);
            int s5 = __shfl_sync(0xffffffffu, sidx, j + 5);
            int s6 = __shfl_sync(0xffffffffu, sidx, j + 6);
            int s7 = __shfl_sync(0xffffffffu, sidx, j + 7);
            float2 v0 = __half22float2(*(const __half2*)&Hs[(size_t)s0 * 64 + lane * 2]);
            float2 v1 = __half22float2(*(const __half2*)&Hs[(size_t)s1 * 64 + lane * 2]);
            float2 v2 = __half22float2(*(const __half2*)&Hs[(size_t)s2 * 64 + lane * 2]);
            float2 v3 = __half22float2(*(const __half2*)&Hs[(size_t)s3 * 64 + lane * 2]);
            float2 v4 = __half22float2(*(const __half2*)&Hs[(size_t)s4 * 64 + lane * 2]);
            float2 v5 = __half22float2(*(const __half2*)&Hs[(size_t)s5 * 64 + lane * 2]);
            float2 v6 = __half22float2(*(const __half2*)&Hs[(size_t)s6 * 64 + lane * 2]);
            float2 v7 = __half22float2(*(const __half2*)&Hs[(size_t)s7 * 64 + lane * 2]);
            acc.x += (v0.x + v1.x) + (v2.x + v3.x) + ((v4.x + v5.x) + (v6.x + v7.x));
            acc.y += (v0.y + v1.y) + (v2.y + v3.y) + ((v4.y + v5.y) + (v6.y + v7.y));
        }
        for (; j < cnt; ++j) {
            int s = __shfl_sync(0xffffffffu, sidx, j);
            float2 v = __half22float2(*(const __half2*)&Hs[(size_t)s * 64 + lane * 2]);
            acc.x += v.x; acc.y += v.y;
        }
    }
    float di = g_dinv[i];
    float2 b = *(const float2*)&gb[lane * 2];
    acc.x = b.x + di * acc.x;
    acc.y = b.y + di * acc.y;
    acc.x = acc.x > 0.f ? acc.x : SLOPE_ * acc.x;
    acc.y = acc.y > 0.f ? acc.y : SLOPE_ * acc.y;
    *(float2*)&out[(size_t)i * 64 + lane * 2] = acc;
}

// ---------------- depthwise 5x5 conv ----------------
__global__ void k_dwconv(const float* __restrict__ In, const float* __restrict__ dw,
                         const float* __restrict__ db, float* __restrict__ Out) {
    __shared__ float wt[25 * 64];
    int tid = threadIdx.x;
    for (int i = tid; i < 25 * 64; i += 256) {
        int t = i >> 6, c = i & 63;
        wt[i] = dw[c * 25 + t];
    }
    __syncthreads();
    int c4 = tid & 15;
    int p = blockIdx.x * 16 + (tid >> 4);
    int y = p / Ww_, x = p % Ww_;
    float4 acc = {0.f, 0.f, 0.f, 0.f};
#pragma unroll
    for (int ky = 0; ky < 5; ++ky) {
        int yy = y + ky - 2;
        if (yy < 0 || yy >= Hh_) continue;
#pragma unroll
        for (int kx = 0; kx < 5; ++kx) {
            int xx = x + kx - 2;
            if (xx < 0 || xx >= Ww_) continue;
            float4 v  = *(const float4*)&In[((size_t)yy * Ww_ + xx) * 64 + c4 * 4];
            float4 wv = *(const float4*)&wt[(ky * 5 + kx) * 64 + c4 * 4];
            acc.x += v.x * wv.x; acc.y += v.y * wv.y;
            acc.z += v.z * wv.z; acc.w += v.w * wv.w;
        }
    }
    float4 b = *(const float4*)&db[c4 * 4];
    acc.x += b.x; acc.y += b.y; acc.z += b.z; acc.w += b.w;
    acc.x = acc.x > 0.f ? acc.x : SLOPE_ * acc.x;
    acc.y = acc.y > 0.f ? acc.y : SLOPE_ * acc.y;
    acc.z = acc.z > 0.f ? acc.z : SLOPE_ * acc.z;
    acc.w = acc.w > 0.f ? acc.w : SLOPE_ * acc.w;
    *(float4*)&Out[(size_t)p * 64 + c4 * 4] = acc;
}

// ---------------- head: G (already leaky) concat Cn -> linear -> softmax ----------------
__global__ void k_final(const float* __restrict__ G, const float* __restrict__ Cn,
                        const float* __restrict__ lw, const float* __restrict__ lb,
                        float* __restrict__ out) {
    __shared__ float slw[128 * 16];
    __shared__ float slb[16];
    __shared__ float sg[16][64];
    __shared__ float sc[16][64];
    int tid = threadIdx.x;
    for (int i = tid; i < 2048; i += 256) slw[i] = lw[i];
    if (tid < 16) slb[tid] = lb[tid];
    int tx = tid & 15, ty = tid >> 4;
    size_t row = (size_t)blockIdx.x * 16 + ty;
    *(float4*)&sg[ty][tx * 4] = *(const float4*)&G[row * 64 + tx * 4];
    *(float4*)&sc[ty][tx * 4] = *(const float4*)&Cn[row * 64 + tx * 4];
    __syncthreads();
    float acc = slb[tx];
#pragma unroll 4
    for (int k = 0; k < 64; ++k) acc += sg[ty][k] * slw[k * 16 + tx];
#pragma unroll 4
    for (int k = 0; k < 64; ++k) acc += sc[ty][k] * slw[(64 + k) * 16 + tx];
    float mx = acc;
#pragma unroll
    for (int o = 8; o > 0; o >>= 1) mx = fmaxf(mx, __shfl_xor_sync(0xffffffffu, mx, o));
    float e = __expf(acc - mx);
    float sum = e;
#pragma unroll
    for (int o = 8; o > 0; o >>= 1) sum += __shfl_xor_sync(0xffffffffu, sum, o);
    out[row * 16 + tx] = e / sum;
}

// ---------------- host launchers ----------------
template <int KREAL, int M, int EPI, int STAT, bool HIN, bool HOUT>
static void launch_wgemm(cudaStream_t st, const void* X, void* Y, const __half* Wh,
                         const float* bf, int slotA = 0, int slotB = 0) {
    constexpr int KC = 32, AS = KC + 8, BS = M + 8;
    constexpr size_t a_sz = (size_t)128 * AS * 2;
    constexpr size_t b_sz = (size_t)KC * BS * 2;
    constexpr size_t comp = HIN ? (2 * a_sz + 2 * b_sz)
                                : (a_sz + 2 * b_sz + (size_t)2 * 128 * KC * 4);
    constexpr size_t stg = (size_t)128 * (M + 8) * 4;
    constexpr size_t smem = comp > stg ? comp : stg;
    cudaFuncSetAttribute(k_wgemm<KREAL, M, EPI, STAT, HIN, HOUT>,
                         cudaFuncAttributeMaxDynamicSharedMemorySize, (int)smem);
    k_wgemm<KREAL, M, EPI, STAT, HIN, HOUT><<<N_ / 128, 256, smem, st>>>(X, Y, Wh, bf,
                                                                         slotA, slotB);
}

extern "C" void kernel_launch(void* const* d_in, const int* in_sizes, int n_in,
                              void* d_out, int out_size) {
    const float* x   = (const float*)d_in[0];
    const int*   ei  = (const int*)d_in[1];
    const int*   src = ei;
    const int*   dst = ei + E_;
    const float* dn_bn1_g = (const float*)d_in[2];
    const float* dn_bn1_b = (const float*)d_in[3];
    const float* dn_w1    = (const float*)d_in[4];
    const float* dn_b1    = (const float*)d_in[5];
    const float* dn_bn2_g = (const float*)d_in[6];
    const float* dn_bn2_b = (const float*)d_in[7];
    const float* dn_w2    = (const float*)d_in[8];
    const float* dn_b2    = (const float*)d_in[9];
    const float* cnn_bn_g = (const float*)d_in[10];
    const float* cnn_bn_b = (const float*)d_in[11];
    const float* cnn_pw   = (const float*)d_in[12];
    const float* cnn_dw   = (const float*)d_in[13];
    const float* cnn_db   = (const float*)d_in[14];
    const float* g1_bn_g  = (const float*)d_in[15];
    const float* g1_bn_b  = (const float*)d_in[16];
    const float* g1_w     = (const float*)d_in[17];
    const float* g1_b     = (const float*)d_in[18];
    const float* g2_bn_g  = (const float*)d_in[19];
    const float* g2_bn_b  = (const float*)d_in[20];
    const float* g2_w     = (const float*)d_in[21];
    const float* g2_b     = (const float*)d_in[22];
    const float* g3_bn_g  = (const float*)d_in[23];
    const float* g3_bn_b  = (const float*)d_in[24];
    const float* g3_w     = (const float*)d_in[25];
    const float* g3_b     = (const float*)d_in[26];
    const float* lin_w    = (const float*)d_in[27];
    const float* lin_b    = (const float*)d_in[28];
    float* out = (float*)d_out;

    float *pP, *pQ, *pH, *pC, *pCR, *bS;
    cudaGetSymbolAddress((void**)&pP, g_P);
    cudaGetSymbolAddress((void**)&pQ, g_Q);
    cudaGetSymbolAddress((void**)&pH, g_Hm);
    cudaGetSymbolAddress((void**)&pC, g_cnn);
    cudaGetSymbolAddress((void**)&pCR, g_cnnres);
    cudaGetSymbolAddress((void**)&bS, g_bfs);
    __half *wA, *wB;
    cudaGetSymbolAddress((void**)&wA, g_WfA);
    cudaGetSymbolAddress((void**)&wB, g_WfB);
    __half* pQh = (__half*)pQ;
    __half* pPh = (__half*)pP;
    __half* pHh = (__half*)pH;

    static cudaStream_t s1 = nullptr;
    static cudaEvent_t evA = nullptr, evCSR = nullptr, evD2 = nullptr,
                       evCNNG = nullptr, evCNN = nullptr;
    if (s1 == nullptr) {
        cudaStreamCreate(&s1);
        cudaEventCreateWithFlags(&evA,    cudaEventDisableTiming);
        cudaEventCreateWithFlags(&evCSR,  cudaEventDisableTiming);
        cudaEventCreateWithFlags(&evD2,   cudaEventDisableTiming);
        cudaEventCreateWithFlags(&evCNNG, cudaEventDisableTiming);
        cudaEventCreateWithFlags(&evCNN,  cudaEventDisableTiming);
    }
    cudaStream_t s0 = 0;   // capture (default) stream

    // ---- main stream: stats + denoise; side stream: CSR build ----
    k_init<<<NBLK_ + 1, 256, 0, s0>>>(dn_b1, dn_b2);
    cudaEventRecord(evA, s0);
    k_colstats<200><<<128, 200, 0, s0>>>(x, 0);

    cudaStreamWaitEvent(s1, evA, 0);
    k_deg_count<<<(E_ + 255) / 256, 256, 0, s1>>>(dst);

    // denoise layer 1 (fp32 in, fp16 out + stats slot1)
    k_prepw<200, 224, 128><<<112, 256, 0, s0>>>(dn_w1, dn_bn1_g, dn_bn1_b, 0, wA, bS + 0 * 128);
    launch_wgemm<200, 128, 0, 1, false, true>(s0, x, pQh, wA, bS + 0 * 128, 1);

    k_scan1<<<NBLK_, 256, 0, s1>>>();
    k_scan2<<<1, 1024, 0, s1>>>();
    k_scan3<<<NBLK_, 256, 0, s1>>>();
    k_csr_fill<<<(E_ + 255) / 256, 256, 0, s1>>>(src, dst);
    cudaEventRecord(evCSR, s1);

    // denoise layer 2 (fp16 in/out; stats slot2 + invn/norm stats slot3)
    k_prepw<128, 128, 128><<<64, 256, 0, s0>>>(dn_w2, dn_bn2_g, dn_bn2_b, 1, wA, bS + 1 * 128);
    launch_wgemm<128, 128, 0, 2, true, true>(s0, pQh, pPh, wA, bS + 1 * 128, 2, 3);
    cudaEventRecord(evD2, s0);

    // ---- CNN branch on side stream (fp16 in, fp32 out) ----
    cudaStreamWaitEvent(s1, evD2, 0);
    k_prepw<128, 128, 64><<<32, 256, 0, s1>>>(cnn_pw, cnn_bn_g, cnn_bn_b, 2, wB, bS + 2 * 128);
    launch_wgemm<128, 64, 0, 0, true, false>(s1, pPh, pC, wB, bS + 2 * 128);
    cudaEventRecord(evCNNG, s1);          // pP no longer read by CNN branch
    k_dwconv<<<N_ / 16, 256, 0, s1>>>(pC, cnn_dw, cnn_db, pCR);
    cudaEventRecord(evCNN, s1);

    // ---- GCN chain on main stream (fp16 everywhere) ----
    cudaStreamWaitEvent(s0, evCSR, 0);
    k_prepw<128, 128, 128><<<64, 256, 0, s0>>>(g1_w, g1_bn_g, g1_bn_b, 3, wA, bS + 3 * 128);
    launch_wgemm<128, 128, 1, 0, true, true>(s0, pPh, pHh, wA, bS + 3 * 128);
    cudaStreamWaitEvent(s0, evCNNG, 0);   // CNN GEMM done reading pPh before we overwrite
    k_gather128<<<1152, 256, 0, s0>>>(pHh, g1_b, pPh, 4);

    k_prepw<128, 128, 128><<<64, 256, 0, s0>>>(g2_w, g2_bn_g, g2_bn_b, 4, wA, bS + 4 * 128);
    launch_wgemm<128, 128, 1, 0, true, true>(s0, pPh, pHh, wA, bS + 4 * 128);
    k_gather128<<<1152, 256, 0, s0>>>(pHh, g2_b, pPh, 5);

    k_prepw<128, 128, 64><<<32, 256, 0, s0>>>(g3_w, g3_bn_g, g3_bn_b, 5, wA, bS + 5 * 128);
    launch_wgemm<128, 64, 1, 0, true, true>(s0, pPh, pHh, wA, bS + 5 * 128);
    k_gather64<<<(N_ * 32) / 256, 256, 0, s0>>>(pHh, g3_b, pP);

    // ---- head (needs CNN result) ----
    cudaStreamWaitEvent(s0, evCNN, 0);
    k_final<<<N_ / 16, 256, 0, s0>>>(pP, pCR, lin_w, lin_b, out);
}

// round 16
// speedup vs baseline: 3.2333x; 1.0594x over previous
#include <cuda_runtime.h>
#include <cuda_fp16.h>
#include <cuda_pipeline.h>
#include <mma.h>
#include <cstdint>
#include <cstddef>

using namespace nvcuda;

// ---------------- problem constants ----------------
#define Hh_ 384
#define Ww_ 384
#define C_ 200
#define N_ 147456           // Hh_*Ww_
#define E_ 1179648
#define HIDE_ 128
#define OUT_ 64
#define NCLS_ 16
#define EPS_ 1e-5f
#define SLOPE_ 0.01f
#define NBLK_ 576           // N_/256

// ---------------- scratch (device globals; no allocation allowed) ----------------
__device__ float g_P[(size_t)N_ * 128];     // fp32 or fp16 (reinterpreted) per stage
__device__ float g_Q[(size_t)N_ * 128];     // fp16 after denoise1
__device__ float g_Hm[(size_t)N_ * 128];    // fp16 Hs
__device__ float g_cnn[(size_t)N_ * 64];
__device__ float g_cnnres[(size_t)N_ * 64];
__device__ float g_dinv[N_];
__device__ float g_invn[N_];
__device__ float g_sum[6 * 256];
__device__ float g_sq[6 * 256];
__device__ __half g_WfA[224 * 128];         // prepped weights, s0 chain
__device__ __half g_WfB[224 * 128];         // prepped weights, CNN branch
__device__ float g_bfs[6 * 128];            // per-layer folded bias
// CSR
__device__ int g_degi[N_];
__device__ int g_rowptr[N_ + 1];
__device__ int g_cursor[N_];
__device__ int g_blksum[NBLK_];
__device__ int g_col[E_];

// ---------------- init: stats, degrees, per-layer bias seeds ----------------
__global__ void k_init(const float* __restrict__ b0, const float* __restrict__ b1) {
    int i = blockIdx.x * 256 + threadIdx.x;
    if (i < N_) g_degi[i] = 0;
    if (i < 6 * 256) { g_sum[i] = 0.f; g_sq[i] = 0.f; }
    if (i < 128) {
        g_bfs[0 * 128 + i] = b0[i];
        g_bfs[1 * 128 + i] = b1[i];
        g_bfs[2 * 128 + i] = 0.f;
        g_bfs[3 * 128 + i] = 0.f;
        g_bfs[4 * 128 + i] = 0.f;
        g_bfs[5 * 128 + i] = 0.f;
    }
}

// plain column stats (raw input x): blockDim == C, 1152 blocks x 128 rows
template <int C>
__global__ void k_colstats(const float* __restrict__ X, int slot) {
    const int c = threadIdx.x;
    const int rpb = N_ / 1152;
    const int r0 = blockIdx.x * rpb;
    float s = 0.f, q = 0.f;
    for (int r = r0; r < r0 + rpb; ++r) {
        float v = X[(size_t)r * C + c];
        s += v; q += v * v;
    }
    atomicAdd(&g_sum[slot * 256 + c], s);
    atomicAdd(&g_sq[slot * 256 + c], q);
}

// ---------------- weight prep: BN fold + fp16 image; bias folded via block-parallel atomics ----------------
// outB must be pre-seeded (k_init) with the layer's torch bias (or 0).
template <int KREAL, int KPAD, int M>
__global__ void k_prepw(const float* __restrict__ W, const float* __restrict__ bng,
                        const float* __restrict__ bnb,
                        int slotF, __half* __restrict__ outW, float* __restrict__ outB) {
    __shared__ float sbf[M];
    const float* su = &g_sum[slotF * 256];
    const float* qu = &g_sq[slotF * 256];
    const int tid = threadIdx.x;
    if (tid < M) sbf[tid] = 0.f;
    __syncthreads();
    int e = blockIdx.x * 256 + tid;
    int k = e / M, n = e % M;
    float contrib = 0.f;
    if (k < KREAL) {
        float mean = su[k] * (1.f / N_);
        float var  = qu[k] * (1.f / N_) - mean * mean;
        float scale = bng[k] * rsqrtf(var + EPS_);
        float sh = bnb[k] - mean * scale;
        float w = W[k * M + n];
        contrib = sh * w;
        outW[e] = __float2half_rn(scale * w);
    } else {
        outW[e] = __float2half_rn(0.f);
    }
    atomicAdd(&sbf[n], contrib);
    __syncthreads();
    if (tid < M) atomicAdd(&outB[tid], sbf[tid]);
}

// ---------------- tensor GEMM (fp16 x fp16, fp32 accum) ----------------
// W prepped fp16, cp.async'd straight into B planes. A: HIN ? direct fp16 cp : fp32 raw+convert.
// KC = 64 for fp16 inputs (fewer barriers), 32 for fp32 input path.
// EPI 0: out = leaky(acc + bf)   EPI 1: out = (acc*invn[r] + bf)*dinv[r]
// HOUT: write fp16.  STAT (EPI0, M=128): 1 = plain stats->slotA; 2 = +invn/norm stats->slotB
template <int KREAL, int M, int EPI, int STAT, bool HIN, bool HOUT>
__global__ __launch_bounds__(256, 2)
void k_wgemm(const void* __restrict__ Xv, void* __restrict__ Yv,
             const __half* __restrict__ Wh, const float* __restrict__ bfp,
             int slotA, int slotB) {
    constexpr int KC = HIN ? 64 : 32;
    constexpr int AS = KC + 8, BS = M + 8, MT = 2, NT2 = M / 32;
    constexpr int NCH = (KREAL + KC - 1) / KC;
    constexpr int LASTR = KREAL - (NCH - 1) * KC;
    constexpr int KS_LAST = (LASTR + 15) / 16;
    constexpr int SZ_APL = 128 * AS * 2;
    constexpr int SZ_BPL = KC * BS * 2;

    extern __shared__ char smraw[];
    __half* Apl[2];
    __half* Bpl[2];
    float* rawX[2];
    if (HIN) {
        Apl[0] = (__half*)smraw;
        Apl[1] = (__half*)(smraw + SZ_APL);
        Bpl[0] = (__half*)(smraw + 2 * SZ_APL);
        Bpl[1] = (__half*)(smraw + 2 * SZ_APL + SZ_BPL);
        rawX[0] = rawX[1] = (float*)smraw;          // unused
    } else {
        Apl[0] = Apl[1] = (__half*)smraw;           // single A plane
        Bpl[0] = (__half*)(smraw + SZ_APL);
        Bpl[1] = (__half*)(smraw + SZ_APL + SZ_BPL);
        rawX[0] = (float*)(smraw + SZ_APL + 2 * SZ_BPL);
        rawX[1] = rawX[0] + 128 * KC;
    }
    float* stage = (float*)smraw;                   // reused post-compute
    __shared__ float s_bf[128];

    const int tid = threadIdx.x, wid = tid >> 5, lane = tid & 31;
    const int wm = wid & 3, wn = wid >> 2;
    const size_t row0 = (size_t)blockIdx.x * 128;

    if (tid < M) s_bf[tid] = bfp[tid];

    wmma::fragment<wmma::accumulator, 16, 16, 16, float> acc[MT][NT2];
#pragma unroll
    for (int m = 0; m < MT; ++m)
#pragma unroll
        for (int n = 0; n < NT2; ++n) wmma::fill_fragment(acc[m][n], 0.0f);

    auto cp_chunk = [&](int c, int slot) {
        if (HIN) {
            const __half* Xh = (const __half*)Xv;
            constexpr int SEG = KC / 8;
            for (int p = tid; p < 128 * SEG; p += 256) {
                int r = p / SEG, s = p % SEG;
                __pipeline_memcpy_async(&Apl[slot][r * AS + s * 8],
                                        &Xh[(row0 + r) * KREAL + c * KC + s * 8], 16, 0);
            }
        } else {
            const float* X = (const float*)Xv;
            for (int p = tid; p < 128 * (KC / 4); p += 256) {
                int r = p / (KC / 4), s = p % (KC / 4);
                int col0 = c * KC + s * 4;
                int real = KREAL - col0; real = real < 0 ? 0 : (real > 4 ? 4 : real);
                __pipeline_memcpy_async(&rawX[slot][r * KC + s * 4],
                                        &X[(row0 + r) * KREAL + (real ? col0 : 0)], 16,
                                        (size_t)(4 - real) * 4);
            }
        }
        for (int p = tid; p < KC * (M / 8); p += 256) {
            int k = p / (M / 8), s = p % (M / 8);
            __pipeline_memcpy_async(&Bpl[slot][k * BS + s * 8],
                                    &Wh[(size_t)(c * KC + k) * M + s * 8], 16, 0);
        }
        __pipeline_commit();
    };

    auto convert = [&](int slot) {      // !HIN only: rawX -> fp16 A plane
        for (int p = tid; p < 128 * (KC / 2); p += 256) {
            int r = p / (KC / 2), q = p % (KC / 2);
            float2 v = *(float2*)&rawX[slot][r * KC + q * 2];
            *(__half2*)&Apl[0][r * AS + q * 2] =
                __half2(__float2half_rn(v.x), __float2half_rn(v.y));
        }
    };

    auto do_ks = [&](int ks, int slot) {
        const __half* Ap = HIN ? Apl[slot] : Apl[0];
        wmma::fragment<wmma::matrix_a, 16, 16, 16, __half, wmma::row_major> aF[MT];
#pragma unroll
        for (int m = 0; m < MT; ++m)
            wmma::load_matrix_sync(aF[m], Ap + (wm * 32 + m * 16) * AS + ks * 16, AS);
#pragma unroll
        for (int n = 0; n < NT2; ++n) {
            wmma::fragment<wmma::matrix_b, 16, 16, 16, __half, wmma::row_major> bF;
            wmma::load_matrix_sync(bF, Bpl[slot] + ks * 16 * BS + wn * (M / 2) + n * 16, BS);
#pragma unroll
            for (int m = 0; m < MT; ++m)
                wmma::mma_sync(acc[m][n], aF[m], bF, acc[m][n]);
        }
    };

    cp_chunk(0, 0);
    for (int c = 0; c < NCH; ++c) {
        const int slot = c & 1;
        if (c + 1 < NCH) cp_chunk(c + 1, slot ^ 1);
        __pipeline_wait_prior((c + 1 < NCH) ? 1 : 0);
        __syncthreads();
        if (!HIN) { convert(slot); __syncthreads(); }
        const int nks = (c == NCH - 1) ? KS_LAST : (KC / 16);
        for (int ks = 0; ks < nks; ++ks) do_ks(ks, slot);
        __syncthreads();
    }

    // stage accumulators to smem, then coalesced epi + store
#pragma unroll
    for (int m = 0; m < MT; ++m)
#pragma unroll
        for (int n = 0; n < NT2; ++n)
            wmma::store_matrix_sync(stage + (wm * 32 + m * 16) * (M + 8) + wn * (M / 2) + n * 16,
                                    acc[m][n], M + 8, wmma::mem_row_major);
    __syncthreads();

    float s1[4] = {0.f, 0.f, 0.f, 0.f}, q1[4] = {0.f, 0.f, 0.f, 0.f};
    float s2[4] = {0.f, 0.f, 0.f, 0.f}, q2[4] = {0.f, 0.f, 0.f, 0.f};

    for (int idx = tid; idx < 128 * (M / 4); idx += 256) {
        int r = idx / (M / 4), cq = idx % (M / 4);
        size_t gr = row0 + r;
        float4 v = *(float4*)&stage[r * (M + 8) + cq * 4];
        float4 b = *(const float4*)&s_bf[cq * 4];
        if (EPI == 0) {
            v.x += b.x; v.y += b.y; v.z += b.z; v.w += b.w;
            v.x = v.x > 0.f ? v.x : SLOPE_ * v.x;
            v.y = v.y > 0.f ? v.y : SLOPE_ * v.y;
            v.z = v.z > 0.f ? v.z : SLOPE_ * v.z;
            v.w = v.w > 0.f ? v.w : SLOPE_ * v.w;
            if (STAT >= 1) {
                s1[0] += v.x; s1[1] += v.y; s1[2] += v.z; s1[3] += v.w;
                q1[0] += v.x * v.x; q1[1] += v.y * v.y; q1[2] += v.z * v.z; q1[3] += v.w * v.w;
            }
            if (STAT == 2) {
                float ss = v.x * v.x + v.y * v.y + v.z * v.z + v.w * v.w;
#pragma unroll
                for (int o = 16; o > 0; o >>= 1) ss += __shfl_xor_sync(0xffffffffu, ss, o);
                float inv = 1.0f / fmaxf(sqrtf(ss), 1e-12f);
                if (lane == 0) g_invn[gr] = inv;
                float nx = v.x * inv, ny = v.y * inv, nz = v.z * inv, nw = v.w * inv;
                s2[0] += nx; s2[1] += ny; s2[2] += nz; s2[3] += nw;
                q2[0] += nx * nx; q2[1] += ny * ny; q2[2] += nz * nz; q2[3] += nw * nw;
            }
        } else {
            float sr = g_invn[gr], dv = g_dinv[gr];
            v.x = (v.x * sr + b.x) * dv;
            v.y = (v.y * sr + b.y) * dv;
            v.z = (v.z * sr + b.z) * dv;
            v.w = (v.w * sr + b.w) * dv;
        }
        if (HOUT) {
            __half* yh = (__half*)Yv;
            __half2 h01 = __half2(__float2half_rn(v.x), __float2half_rn(v.y));
            __half2 h23 = __half2(__float2half_rn(v.z), __float2half_rn(v.w));
            uint2 pk;
            pk.x = *(uint32_t*)&h01;
            pk.y = *(uint32_t*)&h23;
            *(uint2*)&yh[gr * M + cq * 4] = pk;
        } else {
            float* Y = (float*)Yv;
            *(float4*)&Y[gr * M + cq * 4] = v;
        }
    }

    if (EPI == 0 && STAT >= 1) {
        __syncthreads();
        float* red = stage;
#pragma unroll
        for (int j = 0; j < 4; ++j) {
            red[0 * 1024 + wid * 128 + lane * 4 + j] = s1[j];
            red[1 * 1024 + wid * 128 + lane * 4 + j] = q1[j];
            if (STAT == 2) {
                red[2 * 1024 + wid * 128 + lane * 4 + j] = s2[j];
                red[3 * 1024 + wid * 128 + lane * 4 + j] = q2[j];
            }
        }
        __syncthreads();
        if (tid < 128) {
            float a = 0.f, b = 0.f, c2 = 0.f, d2 = 0.f;
#pragma unroll
            for (int w = 0; w < 8; ++w) {
                a  += red[0 * 1024 + w * 128 + tid];
                b  += red[1 * 1024 + w * 128 + tid];
                if (STAT == 2) {
                    c2 += red[2 * 1024 + w * 128 + tid];
                    d2 += red[3 * 1024 + w * 128 + tid];
                }
            }
            atomicAdd(&g_sum[slotA * 256 + tid], a);
            atomicAdd(&g_sq[slotA * 256 + tid], b);
            if (STAT == 2) {
                atomicAdd(&g_sum[slotB * 256 + tid], c2);
                atomicAdd(&g_sq[slotB * 256 + tid], d2);
            }
        }
    }
}

// ---------------- CSR build ----------------
__global__ void k_deg_count(const int* __restrict__ dst) {
    int e = blockIdx.x * blockDim.x + threadIdx.x;
    if (e < E_) atomicAdd(&g_degi[dst[e]], 1);
}
__global__ void k_scan1() {
    __shared__ int s[256];
    int t = threadIdx.x;
    int idx = blockIdx.x * 256 + t;
    int v = g_degi[idx];
    s[t] = v;
    __syncthreads();
#pragma unroll
    for (int off = 1; off < 256; off <<= 1) {
        int a = 0;
        if (t >= off) a = s[t - off];
        __syncthreads();
        s[t] += a;
        __syncthreads();
    }
    g_rowptr[idx] = s[t] - v;
    if (t == 255) g_blksum[blockIdx.x] = s[255];
}
__global__ void k_scan2() {
    __shared__ int s[NBLK_];
    int t = threadIdx.x;
    if (t < NBLK_) s[t] = g_blksum[t];
    __syncthreads();
    for (int off = 1; off < NBLK_; off <<= 1) {
        int a = 0;
        if (t >= off && t < NBLK_) a = s[t - off];
        __syncthreads();
        if (t < NBLK_) s[t] += a;
        __syncthreads();
    }
    if (t < NBLK_) g_blksum[t] = s[t];
}
__global__ void k_scan3() {
    int idx = blockIdx.x * 256 + threadIdx.x;
    int off = blockIdx.x == 0 ? 0 : g_blksum[blockIdx.x - 1];
    int rp = g_rowptr[idx] + off;
    g_rowptr[idx] = rp;
    g_cursor[idx] = rp;
    g_dinv[idx] = rsqrtf((float)g_degi[idx] + 1.0f);
    if (idx == 0) g_rowptr[N_] = E_;
}
__global__ void k_csr_fill(const int* __restrict__ src, const int* __restrict__ dst) {
    int e = blockIdx.x * blockDim.x + threadIdx.x;
    if (e < E_) {
        int pos = atomicAdd(&g_cursor[dst[e]], 1);
        g_col[pos] = src[e];
    }
}

// ---------------- GCN gather (fp16 in/out; fused bias + scale + leaky + rownorm stats) ----------------
__device__ __forceinline__ float4 ld_h4(const __half* p) {
    uint2 u = *(const uint2*)p;
    __half2 a = *(__half2*)&u.x, b = *(__half2*)&u.y;
    float2 f0 = __half22float2(a), f1 = __half22float2(b);
    return make_float4(f0.x, f0.y, f1.x, f1.y);
}

__global__ void k_gather128(const __half* __restrict__ Hs, const float* __restrict__ gb,
                            __half* __restrict__ out, int slot) {
    __shared__ float sred[2][8][128];
    const int tid = threadIdx.x, wid = tid >> 5, lane = tid & 31;
    const float4 b = *(const float4*)&gb[lane * 4];
    float4 s4 = {0.f, 0.f, 0.f, 0.f}, q4 = {0.f, 0.f, 0.f, 0.f};

    for (int i = blockIdx.x * 8 + wid; i < N_; i += 9216) {
        int beg = __ldg(&g_rowptr[i]), end = __ldg(&g_rowptr[i + 1]);
        float4 acc = ld_h4(&Hs[(size_t)i * 128 + lane * 4]);
        for (int base = beg; base < end; base += 32) {
            int e = base + lane;
            int sidx = (e < end) ? g_col[e] : 0;
            int cnt = min(32, end - base);
            int j = 0;
            for (; j + 8 <= cnt; j += 8) {
                int s0 = __shfl_sync(0xffffffffu, sidx, j);
                int s1 = __shfl_sync(0xffffffffu, sidx, j + 1);
                int s2 = __shfl_sync(0xffffffffu, sidx, j + 2);
                int s3 = __shfl_sync(0xffffffffu, sidx, j + 3);
                int s4i = __shfl_sync(0xffffffffu, sidx, j + 4);
                int s5 = __shfl_sync(0xffffffffu, sidx, j + 5);
                int s6 = __shfl_sync(0xffffffffu, sidx, j + 6);
                int s7 = __shfl_sync(0xffffffffu, sidx, j + 7);
                float4 v0 = ld_h4(&Hs[(size_t)s0 * 128 + lane * 4]);
                float4 v1 = ld_h4(&Hs[(size_t)s1 * 128 + lane * 4]);
                float4 v2 = ld_h4(&Hs[(size_t)s2 * 128 + lane * 4]);
                float4 v3 = ld_h4(&Hs[(size_t)s3 * 128 + lane * 4]);
                float4 v4 = ld_h4(&Hs[(size_t)s4i * 128 + lane * 4]);
                float4 v5 = ld_h4(&Hs[(size_t)s5 * 128 + lane * 4]);
                float4 v6 = ld_h4(&Hs[(size_t)s6 * 128 + lane * 4]);
                float4 v7 = ld_h4(&Hs[(size_t)s7 * 128 + lane * 4]);
                acc.x += (v0.x + v1.x) + (v2.x + v3.x) + ((v4.x + v5.x) + (v6.x + v7.x));
                acc.y += (v0.y + v1.y) + (v2.y + v3.y) + ((v4.y + v5.y) + (v6.y + v7.y));
                acc.z += (v0.z + v1.z) + (v2.z + v3.z) + ((v4.z + v5.z) + (v6.z + v7.z));
                acc.w += (v0.w + v1.w) + (v2.w + v3.w) + ((v4.w + v5.w) + (v6.w + v7.w));
            }
            for (; j < cnt; ++j) {
                int s = __shfl_sync(0xffffffffu, sidx, j);
                float4 v = ld_h4(&Hs[(size_t)s * 128 + lane * 4]);
                acc.x += v.x; acc.y += v.y; acc.z += v.z; acc.w += v.w;
            }
        }
        float di = g_dinv[i];
        acc.x = b.x + di * acc.x;
        acc.y = b.y + di * acc.y;
        acc.z = b.z + di * acc.z;
        acc.w = b.w + di * acc.w;
        acc.x = acc.x > 0.f ? acc.x : SLOPE_ * acc.x;
        acc.y = acc.y > 0.f ? acc.y : SLOPE_ * acc.y;
        acc.z = acc.z > 0.f ? acc.z : SLOPE_ * acc.z;
        acc.w = acc.w > 0.f ? acc.w : SLOPE_ * acc.w;
        {
            float ss = acc.x * acc.x + acc.y * acc.y + acc.z * acc.z + acc.w * acc.w;
#pragma unroll
            for (int o = 16; o > 0; o >>= 1) ss += __shfl_xor_sync(0xffffffffu, ss, o);
            float inv = 1.0f / fmaxf(sqrtf(ss), 1e-12f);
            if (lane == 0) g_invn[i] = inv;
            float nx = acc.x * inv, ny = acc.y * inv, nz = acc.z * inv, nw = acc.w * inv;
            s4.x += nx; s4.y += ny; s4.z += nz; s4.w += nw;
            q4.x += nx * nx; q4.y += ny * ny; q4.z += nz * nz; q4.w += nw * nw;
        }
        __half2 h01 = __half2(__float2half_rn(acc.x), __float2half_rn(acc.y));
        __half2 h23 = __half2(__float2half_rn(acc.z), __float2half_rn(acc.w));
        uint2 pk;
        pk.x = *(uint32_t*)&h01;
        pk.y = *(uint32_t*)&h23;
        *(uint2*)&out[(size_t)i * 128 + lane * 4] = pk;
    }

    sred[0][wid][lane * 4 + 0] = s4.x; sred[0][wid][lane * 4 + 1] = s4.y;
    sred[0][wid][lane * 4 + 2] = s4.z; sred[0][wid][lane * 4 + 3] = s4.w;
    sred[1][wid][lane * 4 + 0] = q4.x; sred[1][wid][lane * 4 + 1] = q4.y;
    sred[1][wid][lane * 4 + 2] = q4.z; sred[1][wid][lane * 4 + 3] = q4.w;
    __syncthreads();
    if (tid < 128) {
        float a = 0.f, b2 = 0.f;
#pragma unroll
        for (int w = 0; w < 8; ++w) { a += sred[0][w][tid]; b2 += sred[1][w][tid]; }
        atomicAdd(&g_sum[slot * 256 + tid], a);
        atomicAdd(&g_sq[slot * 256 + tid], b2);
    }
}

// gather64 (fp16 Hs, fp32 out): bias + scale + leaky fused
__global__ void k_gather64(const __half* __restrict__ Hs, const float* __restrict__ gb,
                           float* __restrict__ out) {
    int i = (int)(((size_t)blockIdx.x * blockDim.x + threadIdx.x) >> 5);
    if (i >= N_) return;
    int lane = threadIdx.x & 31;
    int beg = __ldg(&g_rowptr[i]), end = __ldg(&g_rowptr[i + 1]);
    float2 acc = __half22float2(*(const __half2*)&Hs[(size_t)i * 64 + lane * 2]);
    for (int base = beg; base < end; base += 32) {
        int e = base + lane;
        int sidx = (e < end) ? g_col[e] : 0;
        int cnt = min(32, end - base);
        int j = 0;
        for (; j + 8 <= cnt; j += 8) {
            int s0 = __shfl_sync(0xffffffffu, sidx, j);
            int s1 = __shfl_sync(0xffffffffu, sidx, j + 1);
            int s2 = __shfl_sync(0xffffffffu, sidx, j + 2);
            int s3 = __shfl_sync(0xffffffffu, sidx, j + 3);
            int s4 = __shfl_sync(0xffffffffu, sidx, j + 4);
            int s5 = __shfl_sync(0xffffffffu, sidx, j + 5);
            int s6 = __shfl_sync(0xffffffffu, sidx, j + 6);
            int s7 = __shfl_sync(0xffffffffu, sidx, j + 7);
            float2 v0 = __half22float2(*(const __half2*)&Hs[(size_t)s0 * 64 + lane * 2]);
            float2 v1 = __half22float2(*(const __half2*)&Hs[(size_t)s1 * 64 + lane * 2]);
            float2 v2 = __half22float2(*(const __half2*)&Hs[(size_t)s2 * 64 + lane * 2]);
            float2 v3 = __half22float2(*(const __half2*)&Hs[(size_t)s3 * 64 + lane * 2]);
            float2 v4 = __half22float2(*(const __half2*)&Hs[(size_t)s4 * 64 + lane * 2]);
            float2 v5 = __half22float2(*(const __half2*)&Hs[(size_t)s5 * 64 + lane * 2]);
            float2 v6 = __half22float2(*(const __half2*)&Hs[(size_t)s6 * 64 + lane * 2]);
            float2 v7 = __half22float2(*(const __half2*)&Hs[(size_t)s7 * 64 + lane * 2]);
            acc.x += (v0.x + v1.x) + (v2.x + v3.x) + ((v4.x + v5.x) + (v6.x + v7.x));
            acc.y += (v0.y + v1.y) + (v2.y + v3.y) + ((v4.y + v5.y) + (v6.y + v7.y));
        }
        for (; j < cnt; ++j) {
            int s = __shfl_sync(0xffffffffu, sidx, j);
            float2 v = __half22float2(*(const __half2*)&Hs[(size_t)s * 64 + lane * 2]);
            acc.x += v.x; acc.y += v.y;
        }
    }
    float di = g_dinv[i];
    float2 b = *(const float2*)&gb[lane * 2];
    acc.x = b.x + di * acc.x;
    acc.y = b.y + di * acc.y;
    acc.x = acc.x > 0.f ? acc.x : SLOPE_ * acc.x;
    acc.y = acc.y > 0.f ? acc.y : SLOPE_ * acc.y;
    *(float2*)&out[(size_t)i * 64 + lane * 2] = acc;
}

// ---------------- depthwise 5x5 conv ----------------
__global__ void k_dwconv(const float* __restrict__ In, const float* __restrict__ dw,
                         const float* __restrict__ db, float* __restrict__ Out) {
    __shared__ float wt[25 * 64];
    int tid = threadIdx.x;
    for (int i = tid; i < 25 * 64; i += 256) {
        int t = i >> 6, c = i & 63;
        wt[i] = dw[c * 25 + t];
    }
    __syncthreads();
    int c4 = tid & 15;
    int p = blockIdx.x * 16 + (tid >> 4);
    int y = p / Ww_, x = p % Ww_;
    float4 acc = {0.f, 0.f, 0.f, 0.f};
#pragma unroll
    for (int ky = 0; ky < 5; ++ky) {
        int yy = y + ky - 2;
        if (yy < 0 || yy >= Hh_) continue;
#pragma unroll
        for (int kx = 0; kx < 5; ++kx) {
            int xx = x + kx - 2;
            if (xx < 0 || xx >= Ww_) continue;
            float4 v  = *(const float4*)&In[((size_t)yy * Ww_ + xx) * 64 + c4 * 4];
            float4 wv = *(const float4*)&wt[(ky * 5 + kx) * 64 + c4 * 4];
            acc.x += v.x * wv.x; acc.y += v.y * wv.y;
            acc.z += v.z * wv.z; acc.w += v.w * wv.w;
        }
    }
    float4 b = *(const float4*)&db[c4 * 4];
    acc.x += b.x; acc.y += b.y; acc.z += b.z; acc.w += b.w;
    acc.x = acc.x > 0.f ? acc.x : SLOPE_ * acc.x;
    acc.y = acc.y > 0.f ? acc.y : SLOPE_ * acc.y;
    acc.z = acc.z > 0.f ? acc.z : SLOPE_ * acc.z;
    acc.w = acc.w > 0.f ? acc.w : SLOPE_ * acc.w;
    *(float4*)&Out[(size_t)p * 64 + c4 * 4] = acc;
}

// ---------------- head: G (already leaky) concat Cn -> linear -> softmax ----------------
__global__ void k_final(const float* __restrict__ G, const float* __restrict__ Cn,
                        const float* __restrict__ lw, const float* __restrict__ lb,
                        float* __restrict__ out) {
    __shared__ float slw[128 * 16];
    __shared__ float slb[16];
    __shared__ float sg[16][64];
    __shared__ float sc[16][64];
    int tid = threadIdx.x;
    for (int i = tid; i < 2048; i += 256) slw[i] = lw[i];
    if (tid < 16) slb[tid] = lb[tid];
    int tx = tid & 15, ty = tid >> 4;
    size_t row = (size_t)blockIdx.x * 16 + ty;
    *(float4*)&sg[ty][tx * 4] = *(const float4*)&G[row * 64 + tx * 4];
    *(float4*)&sc[ty][tx * 4] = *(const float4*)&Cn[row * 64 + tx * 4];
    __syncthreads();
    float acc = slb[tx];
#pragma unroll 4
    for (int k = 0; k < 64; ++k) acc += sg[ty][k] * slw[k * 16 + tx];
#pragma unroll 4
    for (int k = 0; k < 64; ++k) acc += sc[ty][k] * slw[(64 + k) * 16 + tx];
    float mx = acc;
#pragma unroll
    for (int o = 8; o > 0; o >>= 1) mx = fmaxf(mx, __shfl_xor_sync(0xffffffffu, mx, o));
    float e = __expf(acc - mx);
    float sum = e;
#pragma unroll
    for (int o = 8; o > 0; o >>= 1) sum += __shfl_xor_sync(0xffffffffu, sum, o);
    out[row * 16 + tx] = e / sum;
}

// ---------------- host launchers ----------------
template <int KREAL, int M, int EPI, int STAT, bool HIN, bool HOUT>
static void launch_wgemm(cudaStream_t st, const void* X, void* Y, const __half* Wh,
                         const float* bf, int slotA = 0, int slotB = 0) {
    constexpr int KC = HIN ? 64 : 32;
    constexpr int AS = KC + 8, BS = M + 8;
    constexpr size_t a_sz = (size_t)128 * AS * 2;
    constexpr size_t b_sz = (size_t)KC * BS * 2;
    constexpr size_t comp = HIN ? (2 * a_sz + 2 * b_sz)
                                : (a_sz + 2 * b_sz + (size_t)2 * 128 * KC * 4);
    constexpr size_t stg = (size_t)128 * (M + 8) * 4;
    constexpr size_t smem = comp > stg ? comp : stg;
    cudaFuncSetAttribute(k_wgemm<KREAL, M, EPI, STAT, HIN, HOUT>,
                         cudaFuncAttributeMaxDynamicSharedMemorySize, (int)smem);
    k_wgemm<KREAL, M, EPI, STAT, HIN, HOUT><<<N_ / 128, 256, smem, st>>>(X, Y, Wh, bf,
                                                                         slotA, slotB);
}

extern "C" void kernel_launch(void* const* d_in, const int* in_sizes, int n_in,
                              void* d_out, int out_size) {
    const float* x   = (const float*)d_in[0];
    const int*   ei  = (const int*)d_in[1];
    const int*   src = ei;
    const int*   dst = ei + E_;
    const float* dn_bn1_g = (const float*)d_in[2];
    const float* dn_bn1_b = (const float*)d_in[3];
    const float* dn_w1    = (const float*)d_in[4];
    const float* dn_b1    = (const float*)d_in[5];
    const float* dn_bn2_g = (const float*)d_in[6];
    const float* dn_bn2_b = (const float*)d_in[7];
    const float* dn_w2    = (const float*)d_in[8];
    const float* dn_b2    = (const float*)d_in[9];
    const float* cnn_bn_g = (const float*)d_in[10];
    const float* cnn_bn_b = (const float*)d_in[11];
    const float* cnn_pw   = (const float*)d_in[12];
    const float* cnn_dw   = (const float*)d_in[13];
    const float* cnn_db   = (const float*)d_in[14];
    const float* g1_bn_g  = (const float*)d_in[15];
    const float* g1_bn_b  = (const float*)d_in[16];
    const float* g1_w     = (const float*)d_in[17];
    const float* g1_b     = (const float*)d_in[18];
    const float* g2_bn_g  = (const float*)d_in[19];
    const float* g2_bn_b  = (const float*)d_in[20];
    const float* g2_w     = (const float*)d_in[21];
    const float* g2_b     = (const float*)d_in[22];
    const float* g3_bn_g  = (const float*)d_in[23];
    const float* g3_bn_b  = (const float*)d_in[24];
    const float* g3_w     = (const float*)d_in[25];
    const float* g3_b     = (const float*)d_in[26];
    const float* lin_w    = (const float*)d_in[27];
    const float* lin_b    = (const float*)d_in[28];
    float* out = (float*)d_out;

    float *pP, *pQ, *pH, *pC, *pCR, *bS;
    cudaGetSymbolAddress((void**)&pP, g_P);
    cudaGetSymbolAddress((void**)&pQ, g_Q);
    cudaGetSymbolAddress((void**)&pH, g_Hm);
    cudaGetSymbolAddress((void**)&pC, g_cnn);
    cudaGetSymbolAddress((void**)&pCR, g_cnnres);
    cudaGetSymbolAddress((void**)&bS, g_bfs);
    __half *wA, *wB;
    cudaGetSymbolAddress((void**)&wA, g_WfA);
    cudaGetSymbolAddress((void**)&wB, g_WfB);
    __half* pQh = (__half*)pQ;
    __half* pPh = (__half*)pP;
    __half* pHh = (__half*)pH;

    static cudaStream_t s1 = nullptr;
    static cudaEvent_t evA = nullptr, evCSR = nullptr, evD2 = nullptr,
                       evCNNG = nullptr, evCNN = nullptr;
    if (s1 == nullptr) {
        cudaStreamCreate(&s1);
        cudaEventCreateWithFlags(&evA,    cudaEventDisableTiming);
        cudaEventCreateWithFlags(&evCSR,  cudaEventDisableTiming);
        cudaEventCreateWithFlags(&evD2,   cudaEventDisableTiming);
        cudaEventCreateWithFlags(&evCNNG, cudaEventDisableTiming);
        cudaEventCreateWithFlags(&evCNN,  cudaEventDisableTiming);
    }
    cudaStream_t s0 = 0;   // capture (default) stream

    // ---- main stream: stats + denoise; side stream: CSR build ----
    k_init<<<NBLK_ + 1, 256, 0, s0>>>(dn_b1, dn_b2);
    cudaEventRecord(evA, s0);
    k_colstats<200><<<1152, 200, 0, s0>>>(x, 0);

    cudaStreamWaitEvent(s1, evA, 0);
    k_deg_count<<<(E_ + 255) / 256, 256, 0, s1>>>(dst);

    // denoise layer 1 (fp32 in, fp16 out + stats slot1)
    k_prepw<200, 224, 128><<<112, 256, 0, s0>>>(dn_w1, dn_bn1_g, dn_bn1_b, 0, wA, bS + 0 * 128);
    launch_wgemm<200, 128, 0, 1, false, true>(s0, x, pQh, wA, bS + 0 * 128, 1);

    k_scan1<<<NBLK_, 256, 0, s1>>>();
    k_scan2<<<1, 1024, 0, s1>>>();
    k_scan3<<<NBLK_, 256, 0, s1>>>();
    k_csr_fill<<<(E_ + 255) / 256, 256, 0, s1>>>(src, dst);
    cudaEventRecord(evCSR, s1);

    // denoise layer 2 (fp16 in/out; stats slot2 + invn/norm stats slot3)
    k_prepw<128, 128, 128><<<64, 256, 0, s0>>>(dn_w2, dn_bn2_g, dn_bn2_b, 1, wA, bS + 1 * 128);
    launch_wgemm<128, 128, 0, 2, true, true>(s0, pQh, pPh, wA, bS + 1 * 128, 2, 3);
    cudaEventRecord(evD2, s0);

    // ---- CNN branch on side stream (fp16 in, fp32 out) ----
    cudaStreamWaitEvent(s1, evD2, 0);
    k_prepw<128, 128, 64><<<32, 256, 0, s1>>>(cnn_pw, cnn_bn_g, cnn_bn_b, 2, wB, bS + 2 * 128);
    launch_wgemm<128, 64, 0, 0, true, false>(s1, pPh, pC, wB, bS + 2 * 128);
    cudaEventRecord(evCNNG, s1);          // pP no longer read by CNN branch
    k_dwconv<<<N_ / 16, 256, 0, s1>>>(pC, cnn_dw, cnn_db, pCR);
    cudaEventRecord(evCNN, s1);

    // ---- GCN chain on main stream (fp16 everywhere) ----
    cudaStreamWaitEvent(s0, evCSR, 0);
    k_prepw<128, 128, 128><<<64, 256, 0, s0>>>(g1_w, g1_bn_g, g1_bn_b, 3, wA, bS + 3 * 128);
    launch_wgemm<128, 128, 1, 0, true, true>(s0, pPh, pHh, wA, bS + 3 * 128);
    cudaStreamWaitEvent(s0, evCNNG, 0);   // CNN GEMM done reading pPh before we overwrite
    k_gather128<<<1152, 256, 0, s0>>>(pHh, g1_b, pPh, 4);

    k_prepw<128, 128, 128><<<64, 256, 0, s0>>>(g2_w, g2_bn_g, g2_bn_b, 4, wA, bS + 4 * 128);
    launch_wgemm<128, 128, 1, 0, true, true>(s0, pPh, pHh, wA, bS + 4 * 128);
    k_gather128<<<1152, 256, 0, s0>>>(pHh, g2_b, pPh, 5);

    k_prepw<128, 128, 64><<<32, 256, 0, s0>>>(g3_w, g3_bn_g, g3_bn_b, 5, wA, bS + 5 * 128);
    launch_wgemm<128, 64, 1, 0, true, true>(s0, pPh, pHh, wA, bS + 5 * 128);
    k_gather64<<<(N_ * 32) / 256, 256, 0, s0>>>(pHh, g3_b, pP);

    // ---- head (needs CNN result) ----
    cudaStreamWaitEvent(s0, evCNN, 0);
    k_final<<<N_ / 16, 256, 0, s0>>>(pP, pCR, lin_w, lin_b, out);
}

// round 17
// speedup vs baseline: 3.2960x; 1.0194x over previous
#include <cuda_runtime.h>
#include <cuda_fp16.h>
#include <cuda_pipeline.h>
#include <mma.h>
#include <cstdint>
#include <cstddef>

using namespace nvcuda;

// ---------------- problem constants ----------------
#define Hh_ 384
#define Ww_ 384
#define C_ 200
#define N_ 147456           // Hh_*Ww_
#define E_ 1179648
#define HIDE_ 128
#define OUT_ 64
#define NCLS_ 16
#define EPS_ 1e-5f
#define SLOPE_ 0.01f
#define NBLK_ 576           // N_/256

// ---------------- scratch (device globals; no allocation allowed) ----------------
__device__ float g_P[(size_t)N_ * 128];     // fp32 or fp16 (reinterpreted) per stage
__device__ float g_Q[(size_t)N_ * 128];     // fp16 after denoise1
__device__ float g_Hm[(size_t)N_ * 128];    // fp16 Hs
__device__ float g_cnn[(size_t)N_ * 64];
__device__ float g_cnnres[(size_t)N_ * 64];
__device__ float g_dinv[N_];
__device__ float g_invn[N_];
__device__ float g_sum[6 * 256];
__device__ float g_sq[6 * 256];
__device__ __half g_WfA[224 * 128];         // prepped weights, s0 chain
__device__ __half g_WfB[224 * 128];         // prepped weights, CNN branch
__device__ float g_bfs[6 * 128];            // per-layer folded bias
// CSR
__device__ int g_degi[N_];
__device__ int g_rowptr[N_ + 1];
__device__ int g_cursor[N_];
__device__ int g_blksum[NBLK_];
__device__ int g_col[E_];

// ---------------- init: stats, degrees, per-layer bias seeds ----------------
__global__ void k_init(const float* __restrict__ b0, const float* __restrict__ b1) {
    int i = blockIdx.x * 256 + threadIdx.x;
    if (i < N_) g_degi[i] = 0;
    if (i < 6 * 256) { g_sum[i] = 0.f; g_sq[i] = 0.f; }
    if (i < 128) {
        g_bfs[0 * 128 + i] = b0[i];
        g_bfs[1 * 128 + i] = b1[i];
        g_bfs[2 * 128 + i] = 0.f;
        g_bfs[3 * 128 + i] = 0.f;
        g_bfs[4 * 128 + i] = 0.f;
        g_bfs[5 * 128 + i] = 0.f;
    }
}

// plain column stats (raw input x): blockDim == C, 1152 blocks x 128 rows
template <int C>
__global__ void k_colstats(const float* __restrict__ X, int slot) {
    const int c = threadIdx.x;
    const int rpb = N_ / 1152;
    const int r0 = blockIdx.x * rpb;
    float s = 0.f, q = 0.f;
    for (int r = r0; r < r0 + rpb; ++r) {
        float v = X[(size_t)r * C + c];
        s += v; q += v * v;
    }
    atomicAdd(&g_sum[slot * 256 + c], s);
    atomicAdd(&g_sq[slot * 256 + c], q);
}

// ---------------- weight prep: BN fold + fp16 image; bias folded via block-parallel atomics ----------------
// outB must be pre-seeded (k_init) with the layer's torch bias (or 0).
template <int KREAL, int KPAD, int M>
__global__ void k_prepw(const float* __restrict__ W, const float* __restrict__ bng,
                        const float* __restrict__ bnb,
                        int slotF, __half* __restrict__ outW, float* __restrict__ outB) {
    __shared__ float sbf[M];
    const float* su = &g_sum[slotF * 256];
    const float* qu = &g_sq[slotF * 256];
    const int tid = threadIdx.x;
    if (tid < M) sbf[tid] = 0.f;
    __syncthreads();
    int e = blockIdx.x * 256 + tid;
    int k = e / M, n = e % M;
    float contrib = 0.f;
    if (k < KREAL) {
        float mean = su[k] * (1.f / N_);
        float var  = qu[k] * (1.f / N_) - mean * mean;
        float scale = bng[k] * rsqrtf(var + EPS_);
        float sh = bnb[k] - mean * scale;
        float w = W[k * M + n];
        contrib = sh * w;
        outW[e] = __float2half_rn(scale * w);
    } else {
        outW[e] = __float2half_rn(0.f);
    }
    atomicAdd(&sbf[n], contrib);
    __syncthreads();
    if (tid < M) atomicAdd(&outB[tid], sbf[tid]);
}

// ---------------- tensor GEMM (fp16 x fp16, fp32 accum) ----------------
// W prepped fp16, cp.async'd straight into B planes. A: HIN ? direct fp16 cp : fp32 raw+convert.
// KC = 64 for fp16 inputs (fewer barriers), 32 for fp32 input path.
// EPI 0: out = leaky(acc + bf)   EPI 1: out = (acc*invn[r] + bf)*dinv[r]
// HOUT: write fp16.  STAT (EPI0, M=128): 1 = plain stats->slotA; 2 = +invn/norm stats->slotB
template <int KREAL, int M, int EPI, int STAT, bool HIN, bool HOUT>
__global__ __launch_bounds__(256, 2)
void k_wgemm(const void* __restrict__ Xv, void* __restrict__ Yv,
             const __half* __restrict__ Wh, const float* __restrict__ bfp,
             int slotA, int slotB) {
    constexpr int KC = HIN ? 64 : 32;
    constexpr int AS = KC + 8, BS = M + 8, MT = 2, NT2 = M / 32;
    constexpr int NCH = (KREAL + KC - 1) / KC;
    constexpr int LASTR = KREAL - (NCH - 1) * KC;
    constexpr int KS_LAST = (LASTR + 15) / 16;
    constexpr int SZ_APL = 128 * AS * 2;
    constexpr int SZ_BPL = KC * BS * 2;

    extern __shared__ char smraw[];
    __half* Apl[2];
    __half* Bpl[2];
    float* rawX[2];
    if (HIN) {
        Apl[0] = (__half*)smraw;
        Apl[1] = (__half*)(smraw + SZ_APL);
        Bpl[0] = (__half*)(smraw + 2 * SZ_APL);
        Bpl[1] = (__half*)(smraw + 2 * SZ_APL + SZ_BPL);
        rawX[0] = rawX[1] = (float*)smraw;          // unused
    } else {
        Apl[0] = Apl[1] = (__half*)smraw;           // single A plane
        Bpl[0] = (__half*)(smraw + SZ_APL);
        Bpl[1] = (__half*)(smraw + SZ_APL + SZ_BPL);
        rawX[0] = (float*)(smraw + SZ_APL + 2 * SZ_BPL);
        rawX[1] = rawX[0] + 128 * KC;
    }
    float* stage = (float*)smraw;                   // reused post-compute
    __shared__ float s_bf[128];

    const int tid = threadIdx.x, wid = tid >> 5, lane = tid & 31;
    const int wm = wid & 3, wn = wid >> 2;
    const size_t row0 = (size_t)blockIdx.x * 128;

    if (tid < M) s_bf[tid] = bfp[tid];

    wmma::fragment<wmma::accumulator, 16, 16, 16, float> acc[MT][NT2];
#pragma unroll
    for (int m = 0; m < MT; ++m)
#pragma unroll
        for (int n = 0; n < NT2; ++n) wmma::fill_fragment(acc[m][n], 0.0f);

    auto cp_chunk = [&](int c, int slot) {
        if (HIN) {
            const __half* Xh = (const __half*)Xv;
            constexpr int SEG = KC / 8;
            for (int p = tid; p < 128 * SEG; p += 256) {
                int r = p / SEG, s = p % SEG;
                __pipeline_memcpy_async(&Apl[slot][r * AS + s * 8],
                                        &Xh[(row0 + r) * KREAL + c * KC + s * 8], 16, 0);
            }
        } else {
            const float* X = (const float*)Xv;
            for (int p = tid; p < 128 * (KC / 4); p += 256) {
                int r = p / (KC / 4), s = p % (KC / 4);
                int col0 = c * KC + s * 4;
                int real = KREAL - col0; real = real < 0 ? 0 : (real > 4 ? 4 : real);
                __pipeline_memcpy_async(&rawX[slot][r * KC + s * 4],
                                        &X[(row0 + r) * KREAL + (real ? col0 : 0)], 16,
                                        (size_t)(4 - real) * 4);
            }
        }
        for (int p = tid; p < KC * (M / 8); p += 256) {
            int k = p / (M / 8), s = p % (M / 8);
            __pipeline_memcpy_async(&Bpl[slot][k * BS + s * 8],
                                    &Wh[(size_t)(c * KC + k) * M + s * 8], 16, 0);
        }
        __pipeline_commit();
    };

    auto convert = [&](int slot) {      // !HIN only: rawX -> fp16 A plane
        for (int p = tid; p < 128 * (KC / 2); p += 256) {
            int r = p / (KC / 2), q = p % (KC / 2);
            float2 v = *(float2*)&rawX[slot][r * KC + q * 2];
            *(__half2*)&Apl[0][r * AS + q * 2] =
                __half2(__float2half_rn(v.x), __float2half_rn(v.y));
        }
    };

    auto do_ks = [&](int ks, int slot) {
        const __half* Ap = HIN ? Apl[slot] : Apl[0];
        wmma::fragment<wmma::matrix_a, 16, 16, 16, __half, wmma::row_major> aF[MT];
#pragma unroll
        for (int m = 0; m < MT; ++m)
            wmma::load_matrix_sync(aF[m], Ap + (wm * 32 + m * 16) * AS + ks * 16, AS);
#pragma unroll
        for (int n = 0; n < NT2; ++n) {
            wmma::fragment<wmma::matrix_b, 16, 16, 16, __half, wmma::row_major> bF;
            wmma::load_matrix_sync(bF, Bpl[slot] + ks * 16 * BS + wn * (M / 2) + n * 16, BS);
#pragma unroll
            for (int m = 0; m < MT; ++m)
                wmma::mma_sync(acc[m][n], aF[m], bF, acc[m][n]);
        }
    };

    cp_chunk(0, 0);
    for (int c = 0; c < NCH; ++c) {
        const int slot = c & 1;
        if (c + 1 < NCH) cp_chunk(c + 1, slot ^ 1);
        __pipeline_wait_prior((c + 1 < NCH) ? 1 : 0);
        __syncthreads();
        if (!HIN) { convert(slot); __syncthreads(); }
        const int nks = (c == NCH - 1) ? KS_LAST : (KC / 16);
        for (int ks = 0; ks < nks; ++ks) do_ks(ks, slot);
        __syncthreads();
    }

    // stage accumulators to smem, then coalesced epi + store
#pragma unroll
    for (int m = 0; m < MT; ++m)
#pragma unroll
        for (int n = 0; n < NT2; ++n)
            wmma::store_matrix_sync(stage + (wm * 32 + m * 16) * (M + 8) + wn * (M / 2) + n * 16,
                                    acc[m][n], M + 8, wmma::mem_row_major);
    __syncthreads();

    float s1[4] = {0.f, 0.f, 0.f, 0.f}, q1[4] = {0.f, 0.f, 0.f, 0.f};
    float s2[4] = {0.f, 0.f, 0.f, 0.f}, q2[4] = {0.f, 0.f, 0.f, 0.f};

    for (int idx = tid; idx < 128 * (M / 4); idx += 256) {
        int r = idx / (M / 4), cq = idx % (M / 4);
        size_t gr = row0 + r;
        float4 v = *(float4*)&stage[r * (M + 8) + cq * 4];
        float4 b = *(const float4*)&s_bf[cq * 4];
        if (EPI == 0) {
            v.x += b.x; v.y += b.y; v.z += b.z; v.w += b.w;
            v.x = v.x > 0.f ? v.x : SLOPE_ * v.x;
            v.y = v.y > 0.f ? v.y : SLOPE_ * v.y;
            v.z = v.z > 0.f ? v.z : SLOPE_ * v.z;
            v.w = v.w > 0.f ? v.w : SLOPE_ * v.w;
            if (STAT >= 1) {
                s1[0] += v.x; s1[1] += v.y; s1[2] += v.z; s1[3] += v.w;
                q1[0] += v.x * v.x; q1[1] += v.y * v.y; q1[2] += v.z * v.z; q1[3] += v.w * v.w;
            }
            if (STAT == 2) {
                float ss = v.x * v.x + v.y * v.y + v.z * v.z + v.w * v.w;
#pragma unroll
                for (int o = 16; o > 0; o >>= 1) ss += __shfl_xor_sync(0xffffffffu, ss, o);
                float inv = 1.0f / fmaxf(sqrtf(ss), 1e-12f);
                if (lane == 0) g_invn[gr] = inv;
                float nx = v.x * inv, ny = v.y * inv, nz = v.z * inv, nw = v.w * inv;
                s2[0] += nx; s2[1] += ny; s2[2] += nz; s2[3] += nw;
                q2[0] += nx * nx; q2[1] += ny * ny; q2[2] += nz * nz; q2[3] += nw * nw;
            }
        } else {
            float sr = g_invn[gr], dv = g_dinv[gr];
            v.x = (v.x * sr + b.x) * dv;
            v.y = (v.y * sr + b.y) * dv;
            v.z = (v.z * sr + b.z) * dv;
            v.w = (v.w * sr + b.w) * dv;
        }
        if (HOUT) {
            __half* yh = (__half*)Yv;
            __half2 h01 = __half2(__float2half_rn(v.x), __float2half_rn(v.y));
            __half2 h23 = __half2(__float2half_rn(v.z), __float2half_rn(v.w));
            uint2 pk;
            pk.x = *(uint32_t*)&h01;
            pk.y = *(uint32_t*)&h23;
            *(uint2*)&yh[gr * M + cq * 4] = pk;
        } else {
            float* Y = (float*)Yv;
            *(float4*)&Y[gr * M + cq * 4] = v;
        }
    }

    if (EPI == 0 && STAT >= 1) {
        __syncthreads();
        float* red = stage;
#pragma unroll
        for (int j = 0; j < 4; ++j) {
            red[0 * 1024 + wid * 128 + lane * 4 + j] = s1[j];
            red[1 * 1024 + wid * 128 + lane * 4 + j] = q1[j];
            if (STAT == 2) {
                red[2 * 1024 + wid * 128 + lane * 4 + j] = s2[j];
                red[3 * 1024 + wid * 128 + lane * 4 + j] = q2[j];
            }
        }
        __syncthreads();
        if (tid < 128) {
            float a = 0.f, b = 0.f, c2 = 0.f, d2 = 0.f;
#pragma unroll
            for (int w = 0; w < 8; ++w) {
                a  += red[0 * 1024 + w * 128 + tid];
                b  += red[1 * 1024 + w * 128 + tid];
                if (STAT == 2) {
                    c2 += red[2 * 1024 + w * 128 + tid];
                    d2 += red[3 * 1024 + w * 128 + tid];
                }
            }
            atomicAdd(&g_sum[slotA * 256 + tid], a);
            atomicAdd(&g_sq[slotA * 256 + tid], b);
            if (STAT == 2) {
                atomicAdd(&g_sum[slotB * 256 + tid], c2);
                atomicAdd(&g_sq[slotB * 256 + tid], d2);
            }
        }
    }
}

// ---------------- CSR build ----------------
__global__ void k_deg_count(const int* __restrict__ dst) {
    int e = blockIdx.x * blockDim.x + threadIdx.x;
    if (e < E_) atomicAdd(&g_degi[dst[e]], 1);
}
__global__ void k_scan1() {
    __shared__ int s[256];
    int t = threadIdx.x;
    int idx = blockIdx.x * 256 + t;
    int v = g_degi[idx];
    s[t] = v;
    __syncthreads();
#pragma unroll
    for (int off = 1; off < 256; off <<= 1) {
        int a = 0;
        if (t >= off) a = s[t - off];
        __syncthreads();
        s[t] += a;
        __syncthreads();
    }
    g_rowptr[idx] = s[t] - v;
    if (t == 255) g_blksum[blockIdx.x] = s[255];
}
__global__ void k_scan2() {
    __shared__ int s[NBLK_];
    int t = threadIdx.x;
    if (t < NBLK_) s[t] = g_blksum[t];
    __syncthreads();
    for (int off = 1; off < NBLK_; off <<= 1) {
        int a = 0;
        if (t >= off && t < NBLK_) a = s[t - off];
        __syncthreads();
        if (t < NBLK_) s[t] += a;
        __syncthreads();
    }
    if (t < NBLK_) g_blksum[t] = s[t];
}
__global__ void k_scan3() {
    int idx = blockIdx.x * 256 + threadIdx.x;
    int off = blockIdx.x == 0 ? 0 : g_blksum[blockIdx.x - 1];
    int rp = g_rowptr[idx] + off;
    g_rowptr[idx] = rp;
    g_cursor[idx] = rp;
    g_dinv[idx] = rsqrtf((float)g_degi[idx] + 1.0f);
    if (idx == 0) g_rowptr[N_] = E_;
}
__global__ void k_csr_fill(const int* __restrict__ src, const int* __restrict__ dst) {
    int e = blockIdx.x * blockDim.x + threadIdx.x;
    if (e < E_) {
        int pos = atomicAdd(&g_cursor[dst[e]], 1);
        g_col[pos] = src[e];
    }
}

// ---------------- GCN gather (fp16 in/out; fused bias + scale + leaky + rownorm stats) ----------------
__device__ __forceinline__ float4 ld_h4(const __half* p) {
    uint2 u = *(const uint2*)p;
    __half2 a = *(__half2*)&u.x, b = *(__half2*)&u.y;
    float2 f0 = __half22float2(a), f1 = __half22float2(b);
    return make_float4(f0.x, f0.y, f1.x, f1.y);
}

__global__ void k_gather128(const __half* __restrict__ Hs, const float* __restrict__ gb,
                            __half* __restrict__ out, int slot) {
    __shared__ float sred[2][8][128];
    const int tid = threadIdx.x, wid = tid >> 5, lane = tid & 31;
    const float4 b = *(const float4*)&gb[lane * 4];
    float4 s4 = {0.f, 0.f, 0.f, 0.f}, q4 = {0.f, 0.f, 0.f, 0.f};

    for (int i = blockIdx.x * 8 + wid; i < N_; i += 9216) {
        int beg = __ldg(&g_rowptr[i]), end = __ldg(&g_rowptr[i + 1]);
        float4 acc = ld_h4(&Hs[(size_t)i * 128 + lane * 4]);
        for (int base = beg; base < end; base += 32) {
            int e = base + lane;
            int sidx = (e < end) ? g_col[e] : 0;
            int cnt = min(32, end - base);
            int j = 0;
            for (; j + 8 <= cnt; j += 8) {
                int s0 = __shfl_sync(0xffffffffu, sidx, j);
                int s1 = __shfl_sync(0xffffffffu, sidx, j + 1);
                int s2 = __shfl_sync(0xffffffffu, sidx, j + 2);
                int s3 = __shfl_sync(0xffffffffu, sidx, j + 3);
                int s4i = __shfl_sync(0xffffffffu, sidx, j + 4);
                int s5 = __shfl_sync(0xffffffffu, sidx, j + 5);
                int s6 = __shfl_sync(0xffffffffu, sidx, j + 6);
                int s7 = __shfl_sync(0xffffffffu, sidx, j + 7);
                float4 v0 = ld_h4(&Hs[(size_t)s0 * 128 + lane * 4]);
                float4 v1 = ld_h4(&Hs[(size_t)s1 * 128 + lane * 4]);
                float4 v2 = ld_h4(&Hs[(size_t)s2 * 128 + lane * 4]);
                float4 v3 = ld_h4(&Hs[(size_t)s3 * 128 + lane * 4]);
                float4 v4 = ld_h4(&Hs[(size_t)s4i * 128 + lane * 4]);
                float4 v5 = ld_h4(&Hs[(size_t)s5 * 128 + lane * 4]);
                float4 v6 = ld_h4(&Hs[(size_t)s6 * 128 + lane * 4]);
                float4 v7 = ld_h4(&Hs[(size_t)s7 * 128 + lane * 4]);
                acc.x += (v0.x + v1.x) + (v2.x + v3.x) + ((v4.x + v5.x) + (v6.x + v7.x));
                acc.y += (v0.y + v1.y) + (v2.y + v3.y) + ((v4.y + v5.y) + (v6.y + v7.y));
                acc.z += (v0.z + v1.z) + (v2.z + v3.z) + ((v4.z + v5.z) + (v6.z + v7.z));
                acc.w += (v0.w + v1.w) + (v2.w + v3.w) + ((v4.w + v5.w) + (v6.w + v7.w));
            }
            if (j + 4 <= cnt) {
                int s0 = __shfl_sync(0xffffffffu, sidx, j);
                int s1 = __shfl_sync(0xffffffffu, sidx, j + 1);
                int s2 = __shfl_sync(0xffffffffu, sidx, j + 2);
                int s3 = __shfl_sync(0xffffffffu, sidx, j + 3);
                float4 v0 = ld_h4(&Hs[(size_t)s0 * 128 + lane * 4]);
                float4 v1 = ld_h4(&Hs[(size_t)s1 * 128 + lane * 4]);
                float4 v2 = ld_h4(&Hs[(size_t)s2 * 128 + lane * 4]);
                float4 v3 = ld_h4(&Hs[(size_t)s3 * 128 + lane * 4]);
                acc.x += (v0.x + v1.x) + (v2.x + v3.x);
                acc.y += (v0.y + v1.y) + (v2.y + v3.y);
                acc.z += (v0.z + v1.z) + (v2.z + v3.z);
                acc.w += (v0.w + v1.w) + (v2.w + v3.w);
                j += 4;
            }
            if (j + 2 <= cnt) {
                int s0 = __shfl_sync(0xffffffffu, sidx, j);
                int s1 = __shfl_sync(0xffffffffu, sidx, j + 1);
                float4 v0 = ld_h4(&Hs[(size_t)s0 * 128 + lane * 4]);
                float4 v1 = ld_h4(&Hs[(size_t)s1 * 128 + lane * 4]);
                acc.x += v0.x + v1.x;
                acc.y += v0.y + v1.y;
                acc.z += v0.z + v1.z;
                acc.w += v0.w + v1.w;
                j += 2;
            }
            if (j < cnt) {
                int s = __shfl_sync(0xffffffffu, sidx, j);
                float4 v = ld_h4(&Hs[(size_t)s * 128 + lane * 4]);
                acc.x += v.x; acc.y += v.y; acc.z += v.z; acc.w += v.w;
            }
        }
        float di = g_dinv[i];
        acc.x = b.x + di * acc.x;
        acc.y = b.y + di * acc.y;
        acc.z = b.z + di * acc.z;
        acc.w = b.w + di * acc.w;
        acc.x = acc.x > 0.f ? acc.x : SLOPE_ * acc.x;
        acc.y = acc.y > 0.f ? acc.y : SLOPE_ * acc.y;
        acc.z = acc.z > 0.f ? acc.z : SLOPE_ * acc.z;
        acc.w = acc.w > 0.f ? acc.w : SLOPE_ * acc.w;
        {
            float ss = acc.x * acc.x + acc.y * acc.y + acc.z * acc.z + acc.w * acc.w;
#pragma unroll
            for (int o = 16; o > 0; o >>= 1) ss += __shfl_xor_sync(0xffffffffu, ss, o);
            float inv = 1.0f / fmaxf(sqrtf(ss), 1e-12f);
            if (lane == 0) g_invn[i] = inv;
            float nx = acc.x * inv, ny = acc.y * inv, nz = acc.z * inv, nw = acc.w * inv;
            s4.x += nx; s4.y += ny; s4.z += nz; s4.w += nw;
            q4.x += nx * nx; q4.y += ny * ny; q4.z += nz * nz; q4.w += nw * nw;
        }
        __half2 h01 = __half2(__float2half_rn(acc.x), __float2half_rn(acc.y));
        __half2 h23 = __half2(__float2half_rn(acc.z), __float2half_rn(acc.w));
        uint2 pk;
        pk.x = *(uint32_t*)&h01;
        pk.y = *(uint32_t*)&h23;
        *(uint2*)&out[(size_t)i * 128 + lane * 4] = pk;
    }

    sred[0][wid][lane * 4 + 0] = s4.x; sred[0][wid][lane * 4 + 1] = s4.y;
    sred[0][wid][lane * 4 + 2] = s4.z; sred[0][wid][lane * 4 + 3] = s4.w;
    sred[1][wid][lane * 4 + 0] = q4.x; sred[1][wid][lane * 4 + 1] = q4.y;
    sred[1][wid][lane * 4 + 2] = q4.z; sred[1][wid][lane * 4 + 3] = q4.w;
    __syncthreads();
    if (tid < 128) {
        float a = 0.f, b2 = 0.f;
#pragma unroll
        for (int w = 0; w < 8; ++w) { a += sred[0][w][tid]; b2 += sred[1][w][tid]; }
        atomicAdd(&g_sum[slot * 256 + tid], a);
        atomicAdd(&g_sq[slot * 256 + tid], b2);
    }
}

// gather64 (fp16 Hs, fp32 out): bias + scale + leaky fused
__global__ void k_gather64(const __half* __restrict__ Hs, const float* __restrict__ gb,
                           float* __restrict__ out) {
    int i = (int)(((size_t)blockIdx.x * blockDim.x + threadIdx.x) >> 5);
    if (i >= N_) return;
    int lane = threadIdx.x & 31;
    int beg = __ldg(&g_rowptr[i]), end = __ldg(&g_rowptr[i + 1]);
    float2 acc = __half22float2(*(const __half2*)&Hs[(size_t)i * 64 + lane * 2]);
    for (int base = beg; base < end; base += 32) {
        int e = base + lane;
        int sidx = (e < end) ? g_col[e] : 0;
        int cnt = min(32, end - base);
        int j = 0;
        for (; j + 8 <= cnt; j += 8) {
            int s0 = __shfl_sync(0xffffffffu, sidx, j);
            int s1 = __shfl_sync(0xffffffffu, sidx, j + 1);
            int s2 = __shfl_sync(0xffffffffu, sidx, j + 2);
            int s3 = __shfl_sync(0xffffffffu, sidx, j + 3);
            int s4 = __shfl_sync(0xffffffffu, sidx, j + 4);
            int s5 = __shfl_sync(0xffffffffu, sidx, j + 5);
            int s6 = __shfl_sync(0xffffffffu, sidx, j + 6);
            int s7 = __shfl_sync(0xffffffffu, sidx, j + 7);
            float2 v0 = __half22float2(*(const __half2*)&Hs[(size_t)s0 * 64 + lane * 2]);
            float2 v1 = __half22float2(*(const __half2*)&Hs[(size_t)s1 * 64 + lane * 2]);
            float2 v2 = __half22float2(*(const __half2*)&Hs[(size_t)s2 * 64 + lane * 2]);
            float2 v3 = __half22float2(*(const __half2*)&Hs[(size_t)s3 * 64 + lane * 2]);
            float2 v4 = __half22float2(*(const __half2*)&Hs[(size_t)s4 * 64 + lane * 2]);
            float2 v5 = __half22float2(*(const __half2*)&Hs[(size_t)s5 * 64 + lane * 2]);
            float2 v6 = __half22float2(*(const __half2*)&Hs[(size_t)s6 * 64 + lane * 2]);
            float2 v7 = __half22float2(*(const __half2*)&Hs[(size_t)s7 * 64 + lane * 2]);
            acc.x += (v0.x + v1.x) + (v2.x + v3.x) + ((v4.x + v5.x) + (v6.x + v7.x));
            acc.y += (v0.y + v1.y) + (v2.y + v3.y) + ((v4.y + v5.y) + (v6.y + v7.y));
        }
        if (j + 4 <= cnt) {
            int s0 = __shfl_sync(0xffffffffu, sidx, j);
            int s1 = __shfl_sync(0xffffffffu, sidx, j + 1);
            int s2 = __shfl_sync(0xffffffffu, sidx, j + 2);
            int s3 = __shfl_sync(0xffffffffu, sidx, j + 3);
            float2 v0 = __half22float2(*(const __half2*)&Hs[(size_t)s0 * 64 + lane * 2]);
            float2 v1 = __half22float2(*(const __half2*)&Hs[(size_t)s1 * 64 + lane * 2]);
            float2 v2 = __half22float2(*(const __half2*)&Hs[(size_t)s2 * 64 + lane * 2]);
            float2 v3 = __half22float2(*(const __half2*)&Hs[(size_t)s3 * 64 + lane * 2]);
            acc.x += (v0.x + v1.x) + (v2.x + v3.x);
            acc.y += (v0.y + v1.y) + (v2.y + v3.y);
            j += 4;
        }
        if (j + 2 <= cnt) {
            int s0 = __shfl_sync(0xffffffffu, sidx, j);
            int s1 = __shfl_sync(0xffffffffu, sidx, j + 1);
            float2 v0 = __half22float2(*(const __half2*)&Hs[(size_t)s0 * 64 + lane * 2]);
            float2 v1 = __half22float2(*(const __half2*)&Hs[(size_t)s1 * 64 + lane * 2]);
            acc.x += v0.x + v1.x;
            acc.y += v0.y + v1.y;
            j += 2;
        }
        if (j < cnt) {
            int s = __shfl_sync(0xffffffffu, sidx, j);
            float2 v = __half22float2(*(const __half2*)&Hs[(size_t)s * 64 + lane * 2]);
            acc.x += v.x; acc.y += v.y;
        }
    }
    float di = g_dinv[i];
    float2 b = *(const float2*)&gb[lane * 2];
    acc.x = b.x + di * acc.x;
    acc.y = b.y + di * acc.y;
    acc.x = acc.x > 0.f ? acc.x : SLOPE_ * acc.x;
    acc.y = acc.y > 0.f ? acc.y : SLOPE_ * acc.y;
    *(float2*)&out[(size_t)i * 64 + lane * 2] = acc;
}

// ---------------- depthwise 5x5 conv ----------------
__global__ void k_dwconv(const float* __restrict__ In, const float* __restrict__ dw,
                         const float* __restrict__ db, float* __restrict__ Out) {
    __shared__ float wt[25 * 64];
    int tid = threadIdx.x;
    for (int i = tid; i < 25 * 64; i += 256) {
        int t = i >> 6, c = i & 63;
        wt[i] = dw[c * 25 + t];
    }
    __syncthreads();
    int c4 = tid & 15;
    int p = blockIdx.x * 16 + (tid >> 4);
    int y = p / Ww_, x = p % Ww_;
    float4 acc = {0.f, 0.f, 0.f, 0.f};
#pragma unroll
    for (int ky = 0; ky < 5; ++ky) {
        int yy = y + ky - 2;
        if (yy < 0 || yy >= Hh_) continue;
#pragma unroll
        for (int kx = 0; kx < 5; ++kx) {
            int xx = x + kx - 2;
            if (xx < 0 || xx >= Ww_) continue;
            float4 v  = *(const float4*)&In[((size_t)yy * Ww_ + xx) * 64 + c4 * 4];
            float4 wv = *(const float4*)&wt[(ky * 5 + kx) * 64 + c4 * 4];
            acc.x += v.x * wv.x; acc.y += v.y * wv.y;
            acc.z += v.z * wv.z; acc.w += v.w * wv.w;
        }
    }
    float4 b = *(const float4*)&db[c4 * 4];
    acc.x += b.x; acc.y += b.y; acc.z += b.z; acc.w += b.w;
    acc.x = acc.x > 0.f ? acc.x : SLOPE_ * acc.x;
    acc.y = acc.y > 0.f ? acc.y : SLOPE_ * acc.y;
    acc.z = acc.z > 0.f ? acc.z : SLOPE_ * acc.z;
    acc.w = acc.w > 0.f ? acc.w : SLOPE_ * acc.w;
    *(float4*)&Out[(size_t)p * 64 + c4 * 4] = acc;
}

// ---------------- head: G (already leaky) concat Cn -> linear -> softmax ----------------
__global__ void k_final(const float* __restrict__ G, const float* __restrict__ Cn,
                        const float* __restrict__ lw, const float* __restrict__ lb,
                        float* __restrict__ out) {
    __shared__ float slw[128 * 16];
    __shared__ float slb[16];
    __shared__ float sg[16][64];
    __shared__ float sc[16][64];
    int tid = threadIdx.x;
    for (int i = tid; i < 2048; i += 256) slw[i] = lw[i];
    if (tid < 16) slb[tid] = lb[tid];
    int tx = tid & 15, ty = tid >> 4;
    size_t row = (size_t)blockIdx.x * 16 + ty;
    *(float4*)&sg[ty][tx * 4] = *(const float4*)&G[row * 64 + tx * 4];
    *(float4*)&sc[ty][tx * 4] = *(const float4*)&Cn[row * 64 + tx * 4];
    __syncthreads();
    float acc = slb[tx];
#pragma unroll 4
    for (int k = 0; k < 64; ++k) acc += sg[ty][k] * slw[k * 16 + tx];
#pragma unroll 4
    for (int k = 0; k < 64; ++k) acc += sc[ty][k] * slw[(64 + k) * 16 + tx];
    float mx = acc;
#pragma unroll
    for (int o = 8; o > 0; o >>= 1) mx = fmaxf(mx, __shfl_xor_sync(0xffffffffu, mx, o));
    float e = __expf(acc - mx);
    float sum = e;
#pragma unroll
    for (int o = 8; o > 0; o >>= 1) sum += __shfl_xor_sync(0xffffffffu, sum, o);
    out[row * 16 + tx] = e / sum;
}

// ---------------- host launchers ----------------
template <int KREAL, int M, int EPI, int STAT, bool HIN, bool HOUT>
static void launch_wgemm(cudaStream_t st, const void* X, void* Y, const __half* Wh,
                         const float* bf, int slotA = 0, int slotB = 0) {
    constexpr int KC = HIN ? 64 : 32;
    constexpr int AS = KC + 8, BS = M + 8;
    constexpr size_t a_sz = (size_t)128 * AS * 2;
    constexpr size_t b_sz = (size_t)KC * BS * 2;
    constexpr size_t comp = HIN ? (2 * a_sz + 2 * b_sz)
                                : (a_sz + 2 * b_sz + (size_t)2 * 128 * KC * 4);
    constexpr size_t stg = (size_t)128 * (M + 8) * 4;
    constexpr size_t smem = comp > stg ? comp : stg;
    cudaFuncSetAttribute(k_wgemm<KREAL, M, EPI, STAT, HIN, HOUT>,
                         cudaFuncAttributeMaxDynamicSharedMemorySize, (int)smem);
    k_wgemm<KREAL, M, EPI, STAT, HIN, HOUT><<<N_ / 128, 256, smem, st>>>(X, Y, Wh, bf,
                                                                         slotA, slotB);
}

extern "C" void kernel_launch(void* const* d_in, const int* in_sizes, int n_in,
                              void* d_out, int out_size) {
    const float* x   = (const float*)d_in[0];
    const int*   ei  = (const int*)d_in[1];
    const int*   src = ei;
    const int*   dst = ei + E_;
    const float* dn_bn1_g = (const float*)d_in[2];
    const float* dn_bn1_b = (const float*)d_in[3];
    const float* dn_w1    = (const float*)d_in[4];
    const float* dn_b1    = (const float*)d_in[5];
    const float* dn_bn2_g = (const float*)d_in[6];
    const float* dn_bn2_b = (const float*)d_in[7];
    const float* dn_w2    = (const float*)d_in[8];
    const float* dn_b2    = (const float*)d_in[9];
    const float* cnn_bn_g = (const float*)d_in[10];
    const float* cnn_bn_b = (const float*)d_in[11];
    const float* cnn_pw   = (const float*)d_in[12];
    const float* cnn_dw   = (const float*)d_in[13];
    const float* cnn_db   = (const float*)d_in[14];
    const float* g1_bn_g  = (const float*)d_in[15];
    const float* g1_bn_b  = (const float*)d_in[16];
    const float* g1_w     = (const float*)d_in[17];
    const float* g1_b     = (const float*)d_in[18];
    const float* g2_bn_g  = (const float*)d_in[19];
    const float* g2_bn_b  = (const float*)d_in[20];
    const float* g2_w     = (const float*)d_in[21];
    const float* g2_b     = (const float*)d_in[22];
    const float* g3_bn_g  = (const float*)d_in[23];
    const float* g3_bn_b  = (const float*)d_in[24];
    const float* g3_w     = (const float*)d_in[25];
    const float* g3_b     = (const float*)d_in[26];
    const float* lin_w    = (const float*)d_in[27];
    const float* lin_b    = (const float*)d_in[28];
    float* out = (float*)d_out;

    float *pP, *pQ, *pH, *pC, *pCR, *bS;
    cudaGetSymbolAddress((void**)&pP, g_P);
    cudaGetSymbolAddress((void**)&pQ, g_Q);
    cudaGetSymbolAddress((void**)&pH, g_Hm);
    cudaGetSymbolAddress((void**)&pC, g_cnn);
    cudaGetSymbolAddress((void**)&pCR, g_cnnres);
    cudaGetSymbolAddress((void**)&bS, g_bfs);
    __half *wA, *wB;
    cudaGetSymbolAddress((void**)&wA, g_WfA);
    cudaGetSymbolAddress((void**)&wB, g_WfB);
    __half* pQh = (__half*)pQ;
    __half* pPh = (__half*)pP;
    __half* pHh = (__half*)pH;

    static cudaStream_t s1 = nullptr;
    static cudaEvent_t evA = nullptr, evCSR = nullptr, evD2 = nullptr,
                       evCNNG = nullptr, evCNN = nullptr;
    if (s1 == nullptr) {
        cudaStreamCreate(&s1);
        cudaEventCreateWithFlags(&evA,    cudaEventDisableTiming);
        cudaEventCreateWithFlags(&evCSR,  cudaEventDisableTiming);
        cudaEventCreateWithFlags(&evD2,   cudaEventDisableTiming);
        cudaEventCreateWithFlags(&evCNNG, cudaEventDisableTiming);
        cudaEventCreateWithFlags(&evCNN,  cudaEventDisableTiming);
    }
    cudaStream_t s0 = 0;   // capture (default) stream

    // ---- main stream: stats + denoise; side stream: CSR build ----
    k_init<<<NBLK_ + 1, 256, 0, s0>>>(dn_b1, dn_b2);
    cudaEventRecord(evA, s0);
    k_colstats<200><<<1152, 200, 0, s0>>>(x, 0);

    cudaStreamWaitEvent(s1, evA, 0);
    k_deg_count<<<(E_ + 255) / 256, 256, 0, s1>>>(dst);

    // denoise layer 1 (fp32 in, fp16 out + stats slot1)
    k_prepw<200, 224, 128><<<112, 256, 0, s0>>>(dn_w1, dn_bn1_g, dn_bn1_b, 0, wA, bS + 0 * 128);
    launch_wgemm<200, 128, 0, 1, false, true>(s0, x, pQh, wA, bS + 0 * 128, 1);

    k_scan1<<<NBLK_, 256, 0, s1>>>();
    k_scan2<<<1, 1024, 0, s1>>>();
    k_scan3<<<NBLK_, 256, 0, s1>>>();
    k_csr_fill<<<(E_ + 255) / 256, 256, 0, s1>>>(src, dst);
    cudaEventRecord(evCSR, s1);

    // denoise layer 2 (fp16 in/out; stats slot2 + invn/norm stats slot3)
    k_prepw<128, 128, 128><<<64, 256, 0, s0>>>(dn_w2, dn_bn2_g, dn_bn2_b, 1, wA, bS + 1 * 128);
    launch_wgemm<128, 128, 0, 2, true, true>(s0, pQh, pPh, wA, bS + 1 * 128, 2, 3);
    cudaEventRecord(evD2, s0);

    // ---- CNN branch on side stream (fp16 in, fp32 out) ----
    cudaStreamWaitEvent(s1, evD2, 0);
    k_prepw<128, 128, 64><<<32, 256, 0, s1>>>(cnn_pw, cnn_bn_g, cnn_bn_b, 2, wB, bS + 2 * 128);
    launch_wgemm<128, 64, 0, 0, true, false>(s1, pPh, pC, wB, bS + 2 * 128);
    cudaEventRecord(evCNNG, s1);          // pP no longer read by CNN branch
    k_dwconv<<<N_ / 16, 256, 0, s1>>>(pC, cnn_dw, cnn_db, pCR);
    cudaEventRecord(evCNN, s1);

    // ---- GCN chain on main stream (fp16 everywhere) ----
    cudaStreamWaitEvent(s0, evCSR, 0);
    k_prepw<128, 128, 128><<<64, 256, 0, s0>>>(g1_w, g1_bn_g, g1_bn_b, 3, wA, bS + 3 * 128);
    launch_wgemm<128, 128, 1, 0, true, true>(s0, pPh, pHh, wA, bS + 3 * 128);
    cudaStreamWaitEvent(s0, evCNNG, 0);   // CNN GEMM done reading pPh before we overwrite
    k_gather128<<<1152, 256, 0, s0>>>(pHh, g1_b, pPh, 4);

    k_prepw<128, 128, 128><<<64, 256, 0, s0>>>(g2_w, g2_bn_g, g2_bn_b, 4, wA, bS + 4 * 128);
    launch_wgemm<128, 128, 1, 0, true, true>(s0, pPh, pHh, wA, bS + 4 * 128);
    k_gather128<<<1152, 256, 0, s0>>>(pHh, g2_b, pPh, 5);

    k_prepw<128, 128, 64><<<32, 256, 0, s0>>>(g3_w, g3_bn_g, g3_bn_b, 5, wA, bS + 5 * 128);
    launch_wgemm<128, 64, 1, 0, true, true>(s0, pPh, pHh, wA, bS + 5 * 128);
    k_gather64<<<(N_ * 32) / 256, 256, 0, s0>>>(pHh, g3_b, pP);

    // ---- head (needs CNN result) ----
    cudaStreamWaitEvent(s0, evCNN, 0);
    k_final<<<N_ / 16, 256, 0, s0>>>(pP, pCR, lin_w, lin_b, out);
}